// round 1
// baseline (speedup 1.0000x reference)
#include <cuda_runtime.h>
#include <math.h>

#define T_LEN 1024
#define HID   2048
#define NHEAD 32
#define HEADD 64
#define NTOK_EL (T_LEN * HID)   // 2097152

// ---------------- scratch (static device memory, no allocations) ----------------
// 17 big slots of T*HID floats each (~142 MB) + one small hidden buffer.
__device__ float g_scratch[17u * (unsigned)NTOK_EL];
__device__ float g_hbuf[T_LEN * 256];

#define S_XN  0
#define S_XR  1   // reused later as zbuf
#define S_XW  2
#define S_XK  3
#define S_XV  4
#define S_XA  5
#define S_XG  6
#define S_R   7
#define S_K   8
#define S_V   9
#define S_KK  10
#define S_K2  11
#define S_G   12
#define S_A   13
#define S_W   14
#define S_TMP 15
#define S_Y   16

// ---------------- helpers ----------------
__device__ __forceinline__ float blk_sum256(float v) {
    __shared__ float sh[8];
    int tid = threadIdx.x;
#pragma unroll
    for (int o = 16; o; o >>= 1) v += __shfl_xor_sync(0xffffffffu, v, o);
    if ((tid & 31) == 0) sh[tid >> 5] = v;
    __syncthreads();
    if (tid == 0) {
        float s = 0.f;
#pragma unroll
        for (int i = 0; i < 8; i++) s += sh[i];
        sh[0] = s;
    }
    __syncthreads();
    float r = sh[0];
    __syncthreads();
    return r;
}

__device__ __forceinline__ float warp_sum(float v) {
#pragma unroll
    for (int o = 16; o; o >>= 1) v += __shfl_xor_sync(0xffffffffu, v, o);
    return v;
}

__device__ __forceinline__ float sigmoidf(float v) {
    return 1.f / (1.f + __expf(-v));
}

// ---------------- LayerNorm over HID (eps 1e-5) ----------------
__global__ void __launch_bounds__(256) ln1_kernel(
    const float* __restrict__ x, const float* __restrict__ w,
    const float* __restrict__ b, float* __restrict__ xn,
    float* __restrict__ state1_out)
{
    int t = blockIdx.x;
    const float* xt = x + (size_t)t * HID;
    float s = 0.f;
    for (int c = threadIdx.x; c < HID; c += 256) s += xt[c];
    float mu = blk_sum256(s) * (1.f / HID);
    float vs = 0.f;
    for (int c = threadIdx.x; c < HID; c += 256) {
        float d = xt[c] - mu;
        vs += d * d;
    }
    float var = blk_sum256(vs) * (1.f / HID);
    float inv = rsqrtf(var + 1e-5f);
    for (int c = threadIdx.x; c < HID; c += 256) {
        float v = (xt[c] - mu) * inv * w[c] + b[c];
        xn[(size_t)t * HID + c] = v;
        if (state1_out && t == T_LEN - 1) state1_out[c] = v;
    }
}

// ---------------- token-shift mix: 6 outputs ----------------
__global__ void __launch_bounds__(256) mix_kernel(
    const float* __restrict__ xn, const float* __restrict__ state1,
    const float* __restrict__ cr, const float* __restrict__ cw,
    const float* __restrict__ ck, const float* __restrict__ cv,
    const float* __restrict__ ca, const float* __restrict__ cg,
    float* __restrict__ xr, float* __restrict__ xw, float* __restrict__ xk,
    float* __restrict__ xv, float* __restrict__ xa, float* __restrict__ xg)
{
    int i = blockIdx.x * 256 + threadIdx.x;
    if (i >= NTOK_EL) return;
    int c = i & (HID - 1);
    int t = i >> 11;
    float xv_ = xn[i];
    float prev = t ? xn[i - HID] : state1[c];
    float sx = prev - xv_;
    xr[i] = xv_ + cr[c] * sx;
    xw[i] = xv_ + cw[c] * sx;
    xk[i] = xv_ + ck[c] * sx;
    xv[i] = xv_ + cv[c] * sx;
    xa[i] = xv_ + ca[c] * sx;
    xg[i] = xv_ + cg[c] * sx;
}

// ---------------- generic fp32 GEMM C = A@B (+Res) ----------------
__global__ void __launch_bounds__(256) gemm_kernel(
    const float* __restrict__ A, const float* __restrict__ B,
    const float* __restrict__ Res, float* __restrict__ C,
    int M, int N, int K)
{
    __shared__ float As[16][64 + 1];
    __shared__ float Bs[16][64 + 1];
    int tid = threadIdx.x;
    int tx = tid & 15, ty = tid >> 4;
    int row0 = blockIdx.y * 64, col0 = blockIdx.x * 64;
    float acc[4][4] = {};
    for (int k0 = 0; k0 < K; k0 += 16) {
#pragma unroll
        for (int i = tid; i < 64 * 16; i += 256) {
            int r = i >> 4, c = i & 15;
            int gr = row0 + r;
            As[c][r] = (gr < M) ? A[(size_t)gr * K + k0 + c] : 0.f;
        }
#pragma unroll
        for (int i = tid; i < 16 * 64; i += 256) {
            int r = i >> 6, c = i & 63;
            int gc = col0 + c;
            Bs[r][c] = (gc < N) ? B[(size_t)(k0 + r) * N + gc] : 0.f;
        }
        __syncthreads();
#pragma unroll
        for (int kk = 0; kk < 16; kk++) {
            float a[4], b[4];
#pragma unroll
            for (int i = 0; i < 4; i++) a[i] = As[kk][ty * 4 + i];
#pragma unroll
            for (int j = 0; j < 4; j++) b[j] = Bs[kk][tx * 4 + j];
#pragma unroll
            for (int i = 0; i < 4; i++)
#pragma unroll
                for (int j = 0; j < 4; j++) acc[i][j] = fmaf(a[i], b[j], acc[i][j]);
        }
        __syncthreads();
    }
#pragma unroll
    for (int i = 0; i < 4; i++) {
        int gr = row0 + ty * 4 + i;
        if (gr >= M) continue;
#pragma unroll
        for (int j = 0; j < 4; j++) {
            int gc = col0 + tx * 4 + j;
            if (gc < N) {
                float v = acc[i][j];
                if (Res) v += Res[(size_t)gr * N + gc];
                C[(size_t)gr * N + gc] = v;
            }
        }
    }
}

// ---------------- unary: 0=sigmoid 1=tanh, in place ----------------
__global__ void __launch_bounds__(256) unary_kernel(float* __restrict__ x, int n, int mode)
{
    int i = blockIdx.x * 256 + threadIdx.x;
    if (i >= n) return;
    float v = x[i];
    x[i] = (mode == 0) ? sigmoidf(v) : tanhf(v);
}

// ---------------- biased activations over (T,HID) ----------------
// mode 0: out = sigmoid(bias[c] + tmp)                         (a)
// mode 1: out = exp(-0.606531*sigmoid(bias[c] + tmp))          (w)
// mode 2: out = out + (vf - out)*sigmoid(bias[c] + tmp)        (v lerp)
__global__ void __launch_bounds__(256) biasact_kernel(
    const float* __restrict__ tmp, const float* __restrict__ bias,
    const float* __restrict__ vf, float* __restrict__ out, int mode)
{
    int i = blockIdx.x * 256 + threadIdx.x;
    if (i >= NTOK_EL) return;
    int c = i & (HID - 1);
    float s = sigmoidf(bias[c] + tmp[i]);
    if (mode == 0) out[i] = s;
    else if (mode == 1) out[i] = __expf(-0.606531f * s);
    else {
        float v = out[i];
        out[i] = v + (vf[i] - v) * s;
    }
}

// ---------------- kk normalize + k modulation; one warp per (t,h) ----------------
__global__ void __launch_bounds__(256) prep_kernel(
    const float* __restrict__ k, const float* __restrict__ a,
    const float* __restrict__ k_k, const float* __restrict__ k_a,
    float* __restrict__ kk, float* __restrict__ k2)
{
    int gw = (blockIdx.x * 256 + threadIdx.x) >> 5;
    int lane = threadIdx.x & 31;
    if (gw >= T_LEN * NHEAD) return;
    int t = gw >> 5, h = gw & 31;
    int base = t * HID + h * HEADD;
    int cb = h * HEADD;
    float k0 = k[base + lane], k1 = k[base + lane + 32];
    float q0 = k0 * k_k[cb + lane], q1 = k1 * k_k[cb + lane + 32];
    float ss = warp_sum(q0 * q0 + q1 * q1);
    float inv = 1.f / fmaxf(sqrtf(ss), 1e-12f);
    kk[base + lane]      = q0 * inv;
    kk[base + lane + 32] = q1 * inv;
    float a0 = a[base + lane], a1 = a[base + lane + 32];
    k2[base + lane]      = k0 * (1.f + (a0 - 1.f) * k_a[cb + lane]);
    k2[base + lane + 32] = k1 * (1.f + (a1 - 1.f) * k_a[cb + lane + 32]);
}

// ---------------- sequential RWKV7 scan; block = head, thread = state row ----------------
__global__ void __launch_bounds__(64) scan_kernel(
    const float* __restrict__ w, const float* __restrict__ kk,
    const float* __restrict__ a, const float* __restrict__ k,
    const float* __restrict__ v, const float* __restrict__ r,
    const float* __restrict__ state2, float* __restrict__ ybuf,
    float* __restrict__ Sout)
{
    int h = blockIdx.x;
    int i = threadIdx.x;
    float S[HEADD];
#pragma unroll
    for (int j = 0; j < HEADD; j++) S[j] = state2[h * HEADD * HEADD + i * HEADD + j];

    __shared__ float sw[HEADD], skk[HEADD], ska[HEADD], sk[HEADD], sr[HEADD];

    for (int t = 0; t < T_LEN; t++) {
        int base = t * HID + h * HEADD;
        float wv = w[base + i];
        float kkv = kk[base + i];
        float av = a[base + i];
        sw[i] = wv;
        skk[i] = kkv;
        ska[i] = kkv * av;
        sk[i] = k[base + i];
        sr[i] = r[base + i];
        float vi = v[base + i];
        __syncthreads();

        float p0 = 0.f, p1 = 0.f, p2 = 0.f, p3 = 0.f;
#pragma unroll
        for (int j = 0; j < HEADD; j += 4) {
            p0 = fmaf(S[j],     skk[j],     p0);
            p1 = fmaf(S[j + 1], skk[j + 1], p1);
            p2 = fmaf(S[j + 2], skk[j + 2], p2);
            p3 = fmaf(S[j + 3], skk[j + 3], p3);
        }
        float p = (p0 + p1) + (p2 + p3);

        float y0 = 0.f, y1 = 0.f, y2 = 0.f, y3 = 0.f;
#pragma unroll
        for (int j = 0; j < HEADD; j += 4) {
            float s0 = S[j]     * sw[j]     - p * ska[j]     + vi * sk[j];
            float s1 = S[j + 1] * sw[j + 1] - p * ska[j + 1] + vi * sk[j + 1];
            float s2 = S[j + 2] * sw[j + 2] - p * ska[j + 2] + vi * sk[j + 2];
            float s3 = S[j + 3] * sw[j + 3] - p * ska[j + 3] + vi * sk[j + 3];
            S[j] = s0; S[j + 1] = s1; S[j + 2] = s2; S[j + 3] = s3;
            y0 = fmaf(s0, sr[j],     y0);
            y1 = fmaf(s1, sr[j + 1], y1);
            y2 = fmaf(s2, sr[j + 2], y2);
            y3 = fmaf(s3, sr[j + 3], y3);
        }
        ybuf[base + i] = (y0 + y1) + (y2 + y3);
        __syncthreads();
    }
#pragma unroll
    for (int j = 0; j < HEADD; j++) Sout[h * HEADD * HEADD + i * HEADD + j] = S[j];
}

// ---------------- per-head groupnorm + rkv + gate; one warp per (t,h) ----------------
__global__ void __launch_bounds__(256) post_kernel(
    const float* __restrict__ y, const float* __restrict__ r,
    const float* __restrict__ k2, const float* __restrict__ v,
    const float* __restrict__ g, const float* __restrict__ r_k,
    const float* __restrict__ lnxw, const float* __restrict__ lnxb,
    float* __restrict__ z)
{
    int gw = (blockIdx.x * 256 + threadIdx.x) >> 5;
    int lane = threadIdx.x & 31;
    if (gw >= T_LEN * NHEAD) return;
    int t = gw >> 5, h = gw & 31;
    int base = t * HID + h * HEADD;
    int cb = h * HEADD;

    float y0 = y[base + lane], y1 = y[base + lane + 32];
    float mu = warp_sum(y0 + y1) * (1.f / HEADD);
    float d0 = y0 - mu, d1 = y1 - mu;
    float var = warp_sum(d0 * d0 + d1 * d1) * (1.f / HEADD);
    float inv = rsqrtf(var + 0.00064f);

    float rs = warp_sum(r[base + lane] * k2[base + lane] * r_k[cb + lane] +
                        r[base + lane + 32] * k2[base + lane + 32] * r_k[cb + lane + 32]);

    float z0 = (d0 * inv * lnxw[cb + lane] + lnxb[cb + lane] + rs * v[base + lane]) * g[base + lane];
    float z1 = (d1 * inv * lnxw[cb + lane + 32] + lnxb[cb + lane + 32] + rs * v[base + lane + 32]) * g[base + lane + 32];
    z[base + lane] = z0;
    z[base + lane + 32] = z1;
}

// ---------------- copy ----------------
__global__ void __launch_bounds__(256) copy_kernel(const float* __restrict__ src,
                                                   float* __restrict__ dst, int n)
{
    int i = blockIdx.x * 256 + threadIdx.x;
    if (i < n) dst[i] = src[i];
}

// ---------------- host launcher ----------------
extern "C" void kernel_launch(void* const* d_in, const int* in_sizes, int n_in,
                              void* d_out, int out_size)
{
    const float* x       = (const float*)d_in[0];
    const float* state1  = (const float*)d_in[1];
    const float* state2  = (const float*)d_in[2];
    const float* v_first = (const float*)d_in[3];
    const float* ln1_w   = (const float*)d_in[4];
    const float* ln1_b   = (const float*)d_in[5];
    const float* x_r     = (const float*)d_in[6];
    const float* x_w     = (const float*)d_in[7];
    const float* x_k     = (const float*)d_in[8];
    const float* x_v     = (const float*)d_in[9];
    const float* x_a     = (const float*)d_in[10];
    const float* x_g     = (const float*)d_in[11];
    const float* Wr      = (const float*)d_in[12];
    const float* Wk      = (const float*)d_in[13];
    const float* Wv      = (const float*)d_in[14];
    const float* Wo      = (const float*)d_in[15];
    const float* w0      = (const float*)d_in[16];
    const float* w1      = (const float*)d_in[17];
    const float* w2      = (const float*)d_in[18];
    const float* a0      = (const float*)d_in[19];
    const float* a1      = (const float*)d_in[20];
    const float* a2      = (const float*)d_in[21];
    const float* v0      = (const float*)d_in[22];
    const float* v1      = (const float*)d_in[23];
    const float* v2      = (const float*)d_in[24];
    const float* g1      = (const float*)d_in[25];
    const float* g2      = (const float*)d_in[26];
    const float* k_k     = (const float*)d_in[27];
    const float* k_a     = (const float*)d_in[28];
    const float* r_k     = (const float*)d_in[29];
    const float* ln_x_w  = (const float*)d_in[30];
    const float* ln_x_b  = (const float*)d_in[31];

    float* sc = nullptr;
    cudaGetSymbolAddress((void**)&sc, g_scratch);
    float* hbuf = nullptr;
    cudaGetSymbolAddress((void**)&hbuf, g_hbuf);

#define SLOT(s) (sc + (size_t)(s) * NTOK_EL)

    float* out = (float*)d_out;
    const int OFF_OUT = 0;
    const int OFF_S1  = NTOK_EL;                 // 2097152
    const int OFF_S2  = OFF_S1 + HID;            // 2099200
    const int OFF_VF  = OFF_S2 + NHEAD * HEADD * HEADD; // 2230272
    const int TOTAL   = OFF_VF + NTOK_EL;        // 4327424
    bool full = (out_size >= TOTAL);

    float* s1_out = full ? out + OFF_S1 : nullptr;
    float* s2_out = full ? out + OFF_S2 : SLOT(S_TMP); // harmless scratch if unused

    const int EW_GRID = (NTOK_EL + 255) / 256;

    // 1. LayerNorm
    ln1_kernel<<<T_LEN, 256>>>(x, ln1_w, ln1_b, SLOT(S_XN), s1_out);

    // 2. token-shift mix
    mix_kernel<<<EW_GRID, 256>>>(SLOT(S_XN), state1, x_r, x_w, x_k, x_v, x_a, x_g,
                                 SLOT(S_XR), SLOT(S_XW), SLOT(S_XK),
                                 SLOT(S_XV), SLOT(S_XA), SLOT(S_XG));

    dim3 gBig((HID + 63) / 64, (T_LEN + 63) / 64);

    // 3. big projections
    gemm_kernel<<<gBig, 256>>>(SLOT(S_XR), Wr, nullptr, SLOT(S_R), T_LEN, HID, HID);
    gemm_kernel<<<gBig, 256>>>(SLOT(S_XK), Wk, nullptr, SLOT(S_K), T_LEN, HID, HID);
    gemm_kernel<<<gBig, 256>>>(SLOT(S_XV), Wv, nullptr, SLOT(S_V), T_LEN, HID, HID);

    // 4. g = sigmoid(xg@g1)@g2
    dim3 gH256((256 + 63) / 64, (T_LEN + 63) / 64);
    gemm_kernel<<<gH256, 256>>>(SLOT(S_XG), g1, nullptr, hbuf, T_LEN, 256, HID);
    unary_kernel<<<(T_LEN * 256 + 255) / 256, 256>>>(hbuf, T_LEN * 256, 0);
    gemm_kernel<<<gBig, 256>>>(hbuf, g2, nullptr, SLOT(S_G), T_LEN, HID, 256);

    // 5. a = sigmoid(a0 + xa@a1@a2)
    dim3 gH96((96 + 63) / 64, (T_LEN + 63) / 64);
    gemm_kernel<<<gH96, 256>>>(SLOT(S_XA), a1, nullptr, hbuf, T_LEN, 96, HID);
    gemm_kernel<<<gBig, 256>>>(hbuf, a2, nullptr, SLOT(S_A), T_LEN, HID, 96);
    biasact_kernel<<<EW_GRID, 256>>>(SLOT(S_A), a0, nullptr, SLOT(S_A), 0);

    // 6. w = exp(-0.606531*sigmoid(w0 + tanh(xw@w1)@w2))
    gemm_kernel<<<gH96, 256>>>(SLOT(S_XW), w1, nullptr, hbuf, T_LEN, 96, HID);
    unary_kernel<<<(T_LEN * 96 + 255) / 256, 256>>>(hbuf, T_LEN * 96, 1);
    gemm_kernel<<<gBig, 256>>>(hbuf, w2, nullptr, SLOT(S_W), T_LEN, HID, 96);
    biasact_kernel<<<EW_GRID, 256>>>(SLOT(S_W), w0, nullptr, SLOT(S_W), 1);

    // 7. v = v + (v_first - v)*sigmoid(v0 + xv@v1@v2)
    dim3 gH64((64 + 63) / 64, (T_LEN + 63) / 64);
    gemm_kernel<<<gH64, 256>>>(SLOT(S_XV), v1, nullptr, hbuf, T_LEN, 64, HID);
    gemm_kernel<<<gBig, 256>>>(hbuf, v2, nullptr, SLOT(S_TMP), T_LEN, HID, 64);
    biasact_kernel<<<EW_GRID, 256>>>(SLOT(S_TMP), v0, v_first, SLOT(S_V), 2);

    // 8. kk / k2
    prep_kernel<<<(T_LEN * NHEAD * 32 + 255) / 256, 256>>>(
        SLOT(S_K), SLOT(S_A), k_k, k_a, SLOT(S_KK), SLOT(S_K2));

    // 9. sequential scan
    scan_kernel<<<NHEAD, HEADD>>>(SLOT(S_W), SLOT(S_KK), SLOT(S_A), SLOT(S_K2),
                                  SLOT(S_V), SLOT(S_R), state2, SLOT(S_Y), s2_out);

    // 10. groupnorm + rkv + gate -> z (reuse S_XR)
    post_kernel<<<(T_LEN * NHEAD * 32 + 255) / 256, 256>>>(
        SLOT(S_Y), SLOT(S_R), SLOT(S_K2), SLOT(S_V), SLOT(S_G),
        r_k, ln_x_w, ln_x_b, SLOT(S_XR));

    // 11. out = x + z@Wo
    gemm_kernel<<<gBig, 256>>>(SLOT(S_XR), Wo, x, out + OFF_OUT, T_LEN, HID, HID);

    // 12. passthrough v_first
    if (full)
        copy_kernel<<<EW_GRID, 256>>>(v_first, out + OFF_VF, NTOK_EL);
}

// round 3
// speedup vs baseline: 1.2218x; 1.2218x over previous
#include <cuda_runtime.h>
#include <cuda_bf16.h>
#include <math.h>
#include <stdint.h>

#define T_LEN 1024
#define HID   2048
#define NHEAD 32
#define HEADD 64
#define NTOK_EL (T_LEN * HID)   // 2097152

// ---------------- scratch (static device memory, no allocations) ----------------
__device__ float g_scratch[17u * (unsigned)NTOK_EL];
__device__ float g_hbuf[T_LEN * 256];
// bf16 split buffers: A [1024 x 6144], W [2048 x 6144]
__device__ __align__(256) __nv_bfloat16 g_abuf[(size_t)T_LEN * 3 * HID];
__device__ __align__(256) __nv_bfloat16 g_wbuf[(size_t)HID * 3 * HID];

#define S_XN  0
#define S_XR  1   // reused later as zbuf
#define S_XW  2
#define S_XK  3
#define S_XV  4
#define S_XA  5
#define S_XG  6
#define S_R   7
#define S_K   8
#define S_V   9
#define S_KK  10
#define S_K2  11
#define S_G   12
#define S_A   13
#define S_W   14
#define S_TMP 15
#define S_Y   16

// ---------------- helpers ----------------
__device__ __forceinline__ float blk_sum256(float v) {
    __shared__ float sh[8];
    int tid = threadIdx.x;
#pragma unroll
    for (int o = 16; o; o >>= 1) v += __shfl_xor_sync(0xffffffffu, v, o);
    if ((tid & 31) == 0) sh[tid >> 5] = v;
    __syncthreads();
    if (tid == 0) {
        float s = 0.f;
#pragma unroll
        for (int i = 0; i < 8; i++) s += sh[i];
        sh[0] = s;
    }
    __syncthreads();
    float r = sh[0];
    __syncthreads();
    return r;
}

__device__ __forceinline__ float warp_sum(float v) {
#pragma unroll
    for (int o = 16; o; o >>= 1) v += __shfl_xor_sync(0xffffffffu, v, o);
    return v;
}

__device__ __forceinline__ float sigmoidf(float v) {
    return 1.f / (1.f + __expf(-v));
}

__device__ __forceinline__ uint32_t smem_u32(const void* p) {
    uint32_t a;
    asm("{ .reg .u64 t; cvta.to.shared.u64 t, %1; cvt.u32.u64 %0, t; }" : "=r"(a) : "l"(p));
    return a;
}

// ======================= mma.sync bf16 GEMM (split-K3) =======================
// D[M,N] = A'[M,Kt] @ B'[N,Kt]^T, bf16 inputs, fp32 accum.
// 128x128 block tile, 8 warps (2x4), warp tile 64x32, BK=32, cp.async double buffer.

#define MMK_STRIDE 80                       // smem bytes per row (32 bf16 + pad)
#define MMK_TILE   (128 * MMK_STRIDE)       // 10240 B per tile

__device__ __forceinline__ void cp16(uint32_t dst, const void* src) {
    asm volatile("cp.async.cg.shared.global [%0], [%1], 16;" :: "r"(dst), "l"(src));
}

__device__ __forceinline__ void mma16816(float* c, const uint32_t* a, const uint32_t* b) {
    asm volatile(
        "mma.sync.aligned.m16n8k16.row.col.f32.bf16.bf16.f32 "
        "{%0,%1,%2,%3}, {%4,%5,%6,%7}, {%8,%9}, {%0,%1,%2,%3};"
        : "+f"(c[0]), "+f"(c[1]), "+f"(c[2]), "+f"(c[3])
        : "r"(a[0]), "r"(a[1]), "r"(a[2]), "r"(a[3]), "r"(b[0]), "r"(b[1]));
}

__global__ void __launch_bounds__(256) mm128_kernel(
    const __nv_bfloat16* __restrict__ A,  // [M, Kt] K-major
    const __nv_bfloat16* __restrict__ B,  // [N, Kt] K-major
    const float* __restrict__ Res,        // optional residual [M, N]
    float* __restrict__ C,                // [M, N]
    int M, int N, int Kt)
{
    __shared__ __align__(16) char smem[4 * MMK_TILE];   // A0 B0 A1 B1
    uint32_t sbase = smem_u32(smem);

    int tid = threadIdx.x;
    int wid = tid >> 5, lane = tid & 31;
    int g = lane >> 2, tig = lane & 3;
    int warp_m = wid >> 2;   // 0..1
    int warp_n = wid & 3;    // 0..3
    int m0 = blockIdx.y * 128;
    int n0 = blockIdx.x * 128;
    int nk = Kt >> 5;

    float acc[4][4][4];
#pragma unroll
    for (int i = 0; i < 4; i++)
#pragma unroll
        for (int j = 0; j < 4; j++)
#pragma unroll
            for (int q = 0; q < 4; q++) acc[i][j][q] = 0.f;

    auto load_stage = [&](int s, int kc) {
        uint32_t aB = sbase + s * 2 * MMK_TILE;
        uint32_t bB = aB + MMK_TILE;
        int k0 = kc << 5;
#pragma unroll
        for (int it = 0; it < 2; it++) {
            int idx = tid + it * 256;           // 0..511
            int r = idx >> 2, c = idx & 3;
            cp16(aB + r * MMK_STRIDE + c * 16, A + ((size_t)(m0 + r) * Kt + k0 + c * 8));
        }
#pragma unroll
        for (int it = 0; it < 2; it++) {
            int idx = tid + it * 256;
            int r = idx >> 2, c = idx & 3;
            cp16(bB + r * MMK_STRIDE + c * 16, B + ((size_t)(n0 + r) * Kt + k0 + c * 8));
        }
        asm volatile("cp.async.commit_group;" ::: "memory");
    };

    load_stage(0, 0);

    for (int kc = 0; kc < nk; kc++) {
        int s = kc & 1;
        if (kc + 1 < nk) {
            load_stage(s ^ 1, kc + 1);
            asm volatile("cp.async.wait_group 1;" ::: "memory");
        } else {
            asm volatile("cp.async.wait_group 0;" ::: "memory");
        }
        __syncthreads();

        const char* aT = smem + s * 2 * MMK_TILE;
        const char* bT = aT + MMK_TILE;
#pragma unroll
        for (int ks = 0; ks < 2; ks++) {
            uint32_t afr[4][4], bfr[4][2];
#pragma unroll
            for (int am = 0; am < 4; am++) {
                int row = warp_m * 64 + am * 16 + g;
                int off = row * MMK_STRIDE + (ks * 16 + tig * 2) * 2;
                afr[am][0] = *(const uint32_t*)(aT + off);
                afr[am][1] = *(const uint32_t*)(aT + off + 8 * MMK_STRIDE);
                afr[am][2] = *(const uint32_t*)(aT + off + 16);
                afr[am][3] = *(const uint32_t*)(aT + off + 8 * MMK_STRIDE + 16);
            }
#pragma unroll
            for (int an = 0; an < 4; an++) {
                int row = warp_n * 32 + an * 8 + g;
                int off = row * MMK_STRIDE + (ks * 16 + tig * 2) * 2;
                bfr[an][0] = *(const uint32_t*)(bT + off);
                bfr[an][1] = *(const uint32_t*)(bT + off + 16);
            }
#pragma unroll
            for (int am = 0; am < 4; am++)
#pragma unroll
                for (int an = 0; an < 4; an++)
                    mma16816(acc[am][an], afr[am], bfr[an]);
        }
        __syncthreads();
    }

    // epilogue
#pragma unroll
    for (int am = 0; am < 4; am++) {
#pragma unroll
        for (int an = 0; an < 4; an++) {
            int row = m0 + warp_m * 64 + am * 16 + g;
            int col = n0 + warp_n * 32 + an * 8 + tig * 2;
            float2 v0 = make_float2(acc[am][an][0], acc[am][an][1]);
            float2 v1 = make_float2(acc[am][an][2], acc[am][an][3]);
            if (Res) {
                const float2 r0 = *(const float2*)(Res + (size_t)row * N + col);
                const float2 r1 = *(const float2*)(Res + (size_t)(row + 8) * N + col);
                v0.x += r0.x; v0.y += r0.y;
                v1.x += r1.x; v1.y += r1.y;
            }
            *(float2*)(C + (size_t)row * N + col) = v0;
            *(float2*)(C + (size_t)(row + 8) * N + col) = v1;
        }
    }
}

// ---------------- bf16 split prep: A [M,K] fp32 -> [M,3K] bf16 {Ah|Al|Ah} ----------------
__global__ void __launch_bounds__(256) splitA_kernel(
    const float* __restrict__ A, __nv_bfloat16* __restrict__ out, int M, int K)
{
    int i = blockIdx.x * 256 + threadIdx.x;
    if (i >= M * K) return;
    int m = i / K, k = i - m * K;
    float v = A[i];
    __nv_bfloat16 hi = __float2bfloat16(v);
    __nv_bfloat16 lo = __float2bfloat16(v - __bfloat162float(hi));
    size_t base = (size_t)m * 3 * K;
    out[base + k] = hi;
    out[base + K + k] = lo;
    out[base + 2 * K + k] = hi;
}

// ---------------- W [K,N] fp32 -> transposed split [N,3K] bf16 {Bh|Bh|Bl} ----------------
__global__ void __launch_bounds__(1024) splitW_kernel(
    const float* __restrict__ W, __nv_bfloat16* __restrict__ out, int K, int N)
{
    __shared__ float tile[32][33];
    int k0 = blockIdx.y * 32, n0 = blockIdx.x * 32;
    int tx = threadIdx.x & 31, ty = threadIdx.x >> 5;
    tile[ty][tx] = W[(size_t)(k0 + ty) * N + n0 + tx];
    __syncthreads();
    int n = n0 + ty, k = k0 + tx;
    float v = tile[tx][ty];
    __nv_bfloat16 hi = __float2bfloat16(v);
    __nv_bfloat16 lo = __float2bfloat16(v - __bfloat162float(hi));
    size_t base = (size_t)n * 3 * K;
    out[base + k] = hi;
    out[base + K + k] = hi;
    out[base + 2 * K + k] = lo;
}

// ---------------- LayerNorm over HID (eps 1e-5) ----------------
__global__ void __launch_bounds__(256) ln1_kernel(
    const float* __restrict__ x, const float* __restrict__ w,
    const float* __restrict__ b, float* __restrict__ xn,
    float* __restrict__ state1_out)
{
    int t = blockIdx.x;
    const float* xt = x + (size_t)t * HID;
    float s = 0.f;
    for (int c = threadIdx.x; c < HID; c += 256) s += xt[c];
    float mu = blk_sum256(s) * (1.f / HID);
    float vs = 0.f;
    for (int c = threadIdx.x; c < HID; c += 256) {
        float d = xt[c] - mu;
        vs += d * d;
    }
    float var = blk_sum256(vs) * (1.f / HID);
    float inv = rsqrtf(var + 1e-5f);
    for (int c = threadIdx.x; c < HID; c += 256) {
        float v = (xt[c] - mu) * inv * w[c] + b[c];
        xn[(size_t)t * HID + c] = v;
        if (state1_out && t == T_LEN - 1) state1_out[c] = v;
    }
}

// ---------------- token-shift mix: 6 outputs ----------------
__global__ void __launch_bounds__(256) mix_kernel(
    const float* __restrict__ xn, const float* __restrict__ state1,
    const float* __restrict__ cr, const float* __restrict__ cw,
    const float* __restrict__ ck, const float* __restrict__ cv,
    const float* __restrict__ ca, const float* __restrict__ cg,
    float* __restrict__ xr, float* __restrict__ xw, float* __restrict__ xk,
    float* __restrict__ xv, float* __restrict__ xa, float* __restrict__ xg)
{
    int i = blockIdx.x * 256 + threadIdx.x;
    if (i >= NTOK_EL) return;
    int c = i & (HID - 1);
    int t = i >> 11;
    float xv_ = xn[i];
    float prev = t ? xn[i - HID] : state1[c];
    float sx = prev - xv_;
    xr[i] = xv_ + cr[c] * sx;
    xw[i] = xv_ + cw[c] * sx;
    xk[i] = xv_ + ck[c] * sx;
    xv[i] = xv_ + cv[c] * sx;
    xa[i] = xv_ + ca[c] * sx;
    xg[i] = xv_ + cg[c] * sx;
}

// ---------------- generic fp32 SIMT GEMM (small LoRA layers) ----------------
__global__ void __launch_bounds__(256) gemm_kernel(
    const float* __restrict__ A, const float* __restrict__ B,
    const float* __restrict__ Res, float* __restrict__ C,
    int M, int N, int K)
{
    __shared__ float As[16][64 + 1];
    __shared__ float Bs[16][64 + 1];
    int tid = threadIdx.x;
    int tx = tid & 15, ty = tid >> 4;
    int row0 = blockIdx.y * 64, col0 = blockIdx.x * 64;
    float acc[4][4] = {};
    for (int k0 = 0; k0 < K; k0 += 16) {
#pragma unroll
        for (int i = tid; i < 64 * 16; i += 256) {
            int r = i >> 4, c = i & 15;
            int gr = row0 + r;
            As[c][r] = (gr < M && k0 + c < K) ? A[(size_t)gr * K + k0 + c] : 0.f;
        }
#pragma unroll
        for (int i = tid; i < 16 * 64; i += 256) {
            int r = i >> 6, c = i & 63;
            int gc = col0 + c;
            Bs[r][c] = (gc < N && k0 + r < K) ? B[(size_t)(k0 + r) * N + gc] : 0.f;
        }
        __syncthreads();
#pragma unroll
        for (int kk = 0; kk < 16; kk++) {
            float a[4], b[4];
#pragma unroll
            for (int i = 0; i < 4; i++) a[i] = As[kk][ty * 4 + i];
#pragma unroll
            for (int j = 0; j < 4; j++) b[j] = Bs[kk][tx * 4 + j];
#pragma unroll
            for (int i = 0; i < 4; i++)
#pragma unroll
                for (int j = 0; j < 4; j++) acc[i][j] = fmaf(a[i], b[j], acc[i][j]);
        }
        __syncthreads();
    }
#pragma unroll
    for (int i = 0; i < 4; i++) {
        int gr = row0 + ty * 4 + i;
        if (gr >= M) continue;
#pragma unroll
        for (int j = 0; j < 4; j++) {
            int gc = col0 + tx * 4 + j;
            if (gc < N) {
                float v = acc[i][j];
                if (Res) v += Res[(size_t)gr * N + gc];
                C[(size_t)gr * N + gc] = v;
            }
        }
    }
}

// ---------------- unary: 0=sigmoid 1=tanh, in place ----------------
__global__ void __launch_bounds__(256) unary_kernel(float* __restrict__ x, int n, int mode)
{
    int i = blockIdx.x * 256 + threadIdx.x;
    if (i >= n) return;
    float v = x[i];
    x[i] = (mode == 0) ? sigmoidf(v) : tanhf(v);
}

// ---------------- biased activations over (T,HID) ----------------
__global__ void __launch_bounds__(256) biasact_kernel(
    const float* __restrict__ tmp, const float* __restrict__ bias,
    const float* __restrict__ vf, float* __restrict__ out, int mode)
{
    int i = blockIdx.x * 256 + threadIdx.x;
    if (i >= NTOK_EL) return;
    int c = i & (HID - 1);
    float s = sigmoidf(bias[c] + tmp[i]);
    if (mode == 0) out[i] = s;
    else if (mode == 1) out[i] = __expf(-0.606531f * s);
    else {
        float v = out[i];
        out[i] = v + (vf[i] - v) * s;
    }
}

// ---------------- kk normalize + k modulation; one warp per (t,h) ----------------
__global__ void __launch_bounds__(256) prep_kernel(
    const float* __restrict__ k, const float* __restrict__ a,
    const float* __restrict__ k_k, const float* __restrict__ k_a,
    float* __restrict__ kk, float* __restrict__ k2)
{
    int gw = (blockIdx.x * 256 + threadIdx.x) >> 5;
    int lane = threadIdx.x & 31;
    if (gw >= T_LEN * NHEAD) return;
    int t = gw >> 5, h = gw & 31;
    int base = t * HID + h * HEADD;
    int cb = h * HEADD;
    float k0 = k[base + lane], k1 = k[base + lane + 32];
    float q0 = k0 * k_k[cb + lane], q1 = k1 * k_k[cb + lane + 32];
    float ss = warp_sum(q0 * q0 + q1 * q1);
    float inv = 1.f / fmaxf(sqrtf(ss), 1e-12f);
    kk[base + lane]      = q0 * inv;
    kk[base + lane + 32] = q1 * inv;
    float a0 = a[base + lane], a1 = a[base + lane + 32];
    k2[base + lane]      = k0 * (1.f + (a0 - 1.f) * k_a[cb + lane]);
    k2[base + lane + 32] = k1 * (1.f + (a1 - 1.f) * k_a[cb + lane + 32]);
}

// ---------------- sequential RWKV7 scan; block = head, thread = state row ----------------
__global__ void __launch_bounds__(64) scan_kernel(
    const float* __restrict__ w, const float* __restrict__ kk,
    const float* __restrict__ a, const float* __restrict__ k,
    const float* __restrict__ v, const float* __restrict__ r,
    const float* __restrict__ state2, float* __restrict__ ybuf,
    float* __restrict__ Sout)
{
    int h = blockIdx.x;
    int i = threadIdx.x;
    float S[HEADD];
#pragma unroll
    for (int j = 0; j < HEADD; j++) S[j] = state2[h * HEADD * HEADD + i * HEADD + j];

    __shared__ float sw[HEADD], skk[HEADD], ska[HEADD], sk[HEADD], sr[HEADD];

    for (int t = 0; t < T_LEN; t++) {
        int base = t * HID + h * HEADD;
        float wv = w[base + i];
        float kkv = kk[base + i];
        float av = a[base + i];
        sw[i] = wv;
        skk[i] = kkv;
        ska[i] = kkv * av;
        sk[i] = k[base + i];
        sr[i] = r[base + i];
        float vi = v[base + i];
        __syncthreads();

        float p0 = 0.f, p1 = 0.f, p2 = 0.f, p3 = 0.f;
#pragma unroll
        for (int j = 0; j < HEADD; j += 4) {
            p0 = fmaf(S[j],     skk[j],     p0);
            p1 = fmaf(S[j + 1], skk[j + 1], p1);
            p2 = fmaf(S[j + 2], skk[j + 2], p2);
            p3 = fmaf(S[j + 3], skk[j + 3], p3);
        }
        float p = (p0 + p1) + (p2 + p3);

        float y0 = 0.f, y1 = 0.f, y2 = 0.f, y3 = 0.f;
#pragma unroll
        for (int j = 0; j < HEADD; j += 4) {
            float s0 = S[j]     * sw[j]     - p * ska[j]     + vi * sk[j];
            float s1 = S[j + 1] * sw[j + 1] - p * ska[j + 1] + vi * sk[j + 1];
            float s2 = S[j + 2] * sw[j + 2] - p * ska[j + 2] + vi * sk[j + 2];
            float s3 = S[j + 3] * sw[j + 3] - p * ska[j + 3] + vi * sk[j + 3];
            S[j] = s0; S[j + 1] = s1; S[j + 2] = s2; S[j + 3] = s3;
            y0 = fmaf(s0, sr[j],     y0);
            y1 = fmaf(s1, sr[j + 1], y1);
            y2 = fmaf(s2, sr[j + 2], y2);
            y3 = fmaf(s3, sr[j + 3], y3);
        }
        ybuf[base + i] = (y0 + y1) + (y2 + y3);
        __syncthreads();
    }
#pragma unroll
    for (int j = 0; j < HEADD; j++) Sout[h * HEADD * HEADD + i * HEADD + j] = S[j];
}

// ---------------- per-head groupnorm + rkv + gate; one warp per (t,h) ----------------
__global__ void __launch_bounds__(256) post_kernel(
    const float* __restrict__ y, const float* __restrict__ r,
    const float* __restrict__ k2, const float* __restrict__ v,
    const float* __restrict__ g, const float* __restrict__ r_k,
    const float* __restrict__ lnxw, const float* __restrict__ lnxb,
    float* __restrict__ z)
{
    int gw = (blockIdx.x * 256 + threadIdx.x) >> 5;
    int lane = threadIdx.x & 31;
    if (gw >= T_LEN * NHEAD) return;
    int t = gw >> 5, h = gw & 31;
    int base = t * HID + h * HEADD;
    int cb = h * HEADD;

    float y0 = y[base + lane], y1 = y[base + lane + 32];
    float mu = warp_sum(y0 + y1) * (1.f / HEADD);
    float d0 = y0 - mu, d1 = y1 - mu;
    float var = warp_sum(d0 * d0 + d1 * d1) * (1.f / HEADD);
    float inv = rsqrtf(var + 0.00064f);

    float rs = warp_sum(r[base + lane] * k2[base + lane] * r_k[cb + lane] +
                        r[base + lane + 32] * k2[base + lane + 32] * r_k[cb + lane + 32]);

    float z0 = (d0 * inv * lnxw[cb + lane] + lnxb[cb + lane] + rs * v[base + lane]) * g[base + lane];
    float z1 = (d1 * inv * lnxw[cb + lane + 32] + lnxb[cb + lane + 32] + rs * v[base + lane + 32]) * g[base + lane + 32];
    z[base + lane] = z0;
    z[base + lane + 32] = z1;
}

// ---------------- copy ----------------
__global__ void __launch_bounds__(256) copy_kernel(const float* __restrict__ src,
                                                   float* __restrict__ dst, int n)
{
    int i = blockIdx.x * 256 + threadIdx.x;
    if (i < n) dst[i] = src[i];
}

// ---------------- host launcher ----------------
extern "C" void kernel_launch(void* const* d_in, const int* in_sizes, int n_in,
                              void* d_out, int out_size)
{
    const float* x       = (const float*)d_in[0];
    const float* state1  = (const float*)d_in[1];
    const float* state2  = (const float*)d_in[2];
    const float* v_first = (const float*)d_in[3];
    const float* ln1_w   = (const float*)d_in[4];
    const float* ln1_b   = (const float*)d_in[5];
    const float* x_r     = (const float*)d_in[6];
    const float* x_w     = (const float*)d_in[7];
    const float* x_k     = (const float*)d_in[8];
    const float* x_v     = (const float*)d_in[9];
    const float* x_a     = (const float*)d_in[10];
    const float* x_g     = (const float*)d_in[11];
    const float* Wr      = (const float*)d_in[12];
    const float* Wk      = (const float*)d_in[13];
    const float* Wv      = (const float*)d_in[14];
    const float* Wo      = (const float*)d_in[15];
    const float* w0      = (const float*)d_in[16];
    const float* w1      = (const float*)d_in[17];
    const float* w2      = (const float*)d_in[18];
    const float* a0      = (const float*)d_in[19];
    const float* a1      = (const float*)d_in[20];
    const float* a2      = (const float*)d_in[21];
    const float* v0      = (const float*)d_in[22];
    const float* v1      = (const float*)d_in[23];
    const float* v2      = (const float*)d_in[24];
    const float* g1      = (const float*)d_in[25];
    const float* g2      = (const float*)d_in[26];
    const float* k_k     = (const float*)d_in[27];
    const float* k_a     = (const float*)d_in[28];
    const float* r_k     = (const float*)d_in[29];
    const float* ln_x_w  = (const float*)d_in[30];
    const float* ln_x_b  = (const float*)d_in[31];

    float* sc = nullptr;
    cudaGetSymbolAddress((void**)&sc, g_scratch);
    float* hbuf = nullptr;
    cudaGetSymbolAddress((void**)&hbuf, g_hbuf);
    __nv_bfloat16* abuf = nullptr;
    cudaGetSymbolAddress((void**)&abuf, g_abuf);
    __nv_bfloat16* wbuf = nullptr;
    cudaGetSymbolAddress((void**)&wbuf, g_wbuf);

#define SLOT(s) (sc + (size_t)(s) * NTOK_EL)

    float* out = (float*)d_out;
    const int OFF_OUT = 0;
    const int OFF_S1  = NTOK_EL;
    const int OFF_S2  = OFF_S1 + HID;
    const int OFF_VF  = OFF_S2 + NHEAD * HEADD * HEADD;
    const int TOTAL   = OFF_VF + NTOK_EL;
    bool full = (out_size >= TOTAL);

    float* s1_out = full ? out + OFF_S1 : nullptr;
    float* s2_out = full ? out + OFF_S2 : SLOT(S_TMP);

    const int EW_GRID = (NTOK_EL + 255) / 256;

    // tensor-core GEMM helper: splitA + splitW + mm128 (M,N mult of 128; K mult of 32)
    auto tmm = [&](const float* Ain, const float* Win, const float* Resp, float* Cout,
                   int M, int N, int K) {
        splitA_kernel<<<(M * K + 255) / 256, 256>>>(Ain, abuf, M, K);
        splitW_kernel<<<dim3(N / 32, K / 32), 1024>>>(Win, wbuf, K, N);
        mm128_kernel<<<dim3(N / 128, M / 128), 256>>>(abuf, wbuf, Resp, Cout, M, N, 3 * K);
    };

    // 1. LayerNorm
    ln1_kernel<<<T_LEN, 256>>>(x, ln1_w, ln1_b, SLOT(S_XN), s1_out);

    // 2. token-shift mix
    mix_kernel<<<EW_GRID, 256>>>(SLOT(S_XN), state1, x_r, x_w, x_k, x_v, x_a, x_g,
                                 SLOT(S_XR), SLOT(S_XW), SLOT(S_XK),
                                 SLOT(S_XV), SLOT(S_XA), SLOT(S_XG));

    // 3. big projections (mma.sync split-bf16)
    tmm(SLOT(S_XR), Wr, nullptr, SLOT(S_R), T_LEN, HID, HID);
    tmm(SLOT(S_XK), Wk, nullptr, SLOT(S_K), T_LEN, HID, HID);
    tmm(SLOT(S_XV), Wv, nullptr, SLOT(S_V), T_LEN, HID, HID);

    // 4. g = sigmoid(xg@g1)@g2
    tmm(SLOT(S_XG), g1, nullptr, hbuf, T_LEN, 256, HID);
    unary_kernel<<<(T_LEN * 256 + 255) / 256, 256>>>(hbuf, T_LEN * 256, 0);
    tmm(hbuf, g2, nullptr, SLOT(S_G), T_LEN, HID, 256);

    dim3 gBig((HID + 63) / 64, (T_LEN + 63) / 64);
    dim3 gH96((96 + 63) / 64, (T_LEN + 63) / 64);
    dim3 gH64((64 + 63) / 64, (T_LEN + 63) / 64);

    // 5. a = sigmoid(a0 + xa@a1@a2)   (SIMT fp32)
    gemm_kernel<<<gH96, 256>>>(SLOT(S_XA), a1, nullptr, hbuf, T_LEN, 96, HID);
    gemm_kernel<<<gBig, 256>>>(hbuf, a2, nullptr, SLOT(S_A), T_LEN, HID, 96);
    biasact_kernel<<<EW_GRID, 256>>>(SLOT(S_A), a0, nullptr, SLOT(S_A), 0);

    // 6. w = exp(-0.606531*sigmoid(w0 + tanh(xw@w1)@w2))   (SIMT fp32)
    gemm_kernel<<<gH96, 256>>>(SLOT(S_XW), w1, nullptr, hbuf, T_LEN, 96, HID);
    unary_kernel<<<(T_LEN * 96 + 255) / 256, 256>>>(hbuf, T_LEN * 96, 1);
    gemm_kernel<<<gBig, 256>>>(hbuf, w2, nullptr, SLOT(S_W), T_LEN, HID, 96);
    biasact_kernel<<<EW_GRID, 256>>>(SLOT(S_W), w0, nullptr, SLOT(S_W), 1);

    // 7. v = v + (v_first - v)*sigmoid(v0 + xv@v1@v2)   (SIMT fp32)
    gemm_kernel<<<gH64, 256>>>(SLOT(S_XV), v1, nullptr, hbuf, T_LEN, 64, HID);
    gemm_kernel<<<gBig, 256>>>(hbuf, v2, nullptr, SLOT(S_TMP), T_LEN, HID, 64);
    biasact_kernel<<<EW_GRID, 256>>>(SLOT(S_TMP), v0, v_first, SLOT(S_V), 2);

    // 8. kk / k2
    prep_kernel<<<(T_LEN * NHEAD * 32 + 255) / 256, 256>>>(
        SLOT(S_K), SLOT(S_A), k_k, k_a, SLOT(S_KK), SLOT(S_K2));

    // 9. sequential scan
    scan_kernel<<<NHEAD, HEADD>>>(SLOT(S_W), SLOT(S_KK), SLOT(S_A), SLOT(S_K2),
                                  SLOT(S_V), SLOT(S_R), state2, SLOT(S_Y), s2_out);

    // 10. groupnorm + rkv + gate -> z (reuse S_XR)
    post_kernel<<<(T_LEN * NHEAD * 32 + 255) / 256, 256>>>(
        SLOT(S_Y), SLOT(S_R), SLOT(S_K2), SLOT(S_V), SLOT(S_G),
        r_k, ln_x_w, ln_x_b, SLOT(S_XR));

    // 11. out = x + z@Wo  (mma.sync, residual fused)
    tmm(SLOT(S_XR), Wo, x, out + OFF_OUT, T_LEN, HID, HID);

    // 12. passthrough v_first
    if (full)
        copy_kernel<<<EW_GRID, 256>>>(v_first, out + OFF_VF, NTOK_EL);
}

// round 4
// speedup vs baseline: 2.4352x; 1.9931x over previous
#include <cuda_runtime.h>
#include <cuda_bf16.h>
#include <math.h>
#include <stdint.h>

#define T_LEN 1024
#define HID   2048
#define NHEAD 32
#define HEADD 64
#define NTOK_EL (T_LEN * HID)   // 2097152

#define ASLOT ((size_t)T_LEN * 3 * HID)   // 6.29M bf16 per A' slot
#define WSLOT ((size_t)HID * 3 * HID)     // 12.58M bf16 per W' slot

// ---------------- static device scratch ----------------
__device__ float g_scratch[13u * (unsigned)NTOK_EL];
__device__ float g_hbuf[T_LEN * 256];
__device__ float g_pscan[(size_t)T_LEN * NHEAD * HEADD * 8];       // packed scan input
__device__ __align__(256) __nv_bfloat16 g_abuf[4 * ASLOT];         // xr',xk',xv',xg' splits
__device__ __align__(256) __nv_bfloat16 g_wbuf[4 * WSLOT];         // Wr',Wk',Wv',Wo'
__device__ __align__(256) __nv_bfloat16 g_g1buf[(size_t)256 * 3 * HID];
__device__ __align__(256) __nv_bfloat16 g_g2buf[(size_t)HID * 3 * 256];
__device__ __align__(256) __nv_bfloat16 g_ghbuf[(size_t)T_LEN * 3 * 256];

#define S_XW  0
#define S_XA  1
#define S_XV  2
#define S_R   3
#define S_K   4
#define S_V   5
#define S_K2  6
#define S_G   7
#define S_A   8
#define S_W   9
#define S_TMP 10
#define S_Y   11
#define S_Z   12

// ---------------- helpers ----------------
__device__ __forceinline__ float blk_sum256(float v) {
    __shared__ float sh[8];
    int tid = threadIdx.x;
#pragma unroll
    for (int o = 16; o; o >>= 1) v += __shfl_xor_sync(0xffffffffu, v, o);
    if ((tid & 31) == 0) sh[tid >> 5] = v;
    __syncthreads();
    if (tid == 0) {
        float s = 0.f;
#pragma unroll
        for (int i = 0; i < 8; i++) s += sh[i];
        sh[0] = s;
    }
    __syncthreads();
    float r = sh[0];
    __syncthreads();
    return r;
}

__device__ __forceinline__ float warp_sum(float v) {
#pragma unroll
    for (int o = 16; o; o >>= 1) v += __shfl_xor_sync(0xffffffffu, v, o);
    return v;
}

__device__ __forceinline__ float sigmoidf(float v) {
    return 1.f / (1.f + __expf(-v));
}

__device__ __forceinline__ uint32_t smem_u32(const void* p) {
    uint32_t a;
    asm("{ .reg .u64 t; cvta.to.shared.u64 t, %1; cvt.u32.u64 %0, t; }" : "=r"(a) : "l"(p));
    return a;
}

// ======================= mma.sync bf16 GEMM (split-K3, ldmatrix) =======================
#define MMK_STRIDE 80
#define MMK_TILE   (128 * MMK_STRIDE)

__device__ __forceinline__ void cp16(uint32_t dst, const void* src) {
    asm volatile("cp.async.cg.shared.global [%0], [%1], 16;" :: "r"(dst), "l"(src));
}

__device__ __forceinline__ void ldsm4(uint32_t* r, uint32_t a) {
    asm volatile("ldmatrix.sync.aligned.m8n8.x4.shared.b16 {%0,%1,%2,%3}, [%4];"
                 : "=r"(r[0]), "=r"(r[1]), "=r"(r[2]), "=r"(r[3]) : "r"(a));
}

__device__ __forceinline__ void mma16816(float* c, const uint32_t* a, const uint32_t* b) {
    asm volatile(
        "mma.sync.aligned.m16n8k16.row.col.f32.bf16.bf16.f32 "
        "{%0,%1,%2,%3}, {%4,%5,%6,%7}, {%8,%9}, {%0,%1,%2,%3};"
        : "+f"(c[0]), "+f"(c[1]), "+f"(c[2]), "+f"(c[3])
        : "r"(a[0]), "r"(a[1]), "r"(a[2]), "r"(a[3]), "r"(b[0]), "r"(b[1]));
}

// mode: 0 = plain store, 1 = +Res store, 2 = sigmoid store
__global__ void __launch_bounds__(256) mm128_kernel(
    const __nv_bfloat16* __restrict__ A, size_t aStride,
    const __nv_bfloat16* __restrict__ B, size_t bStride,
    float* __restrict__ C, size_t cStride,
    const float* __restrict__ Res,
    int M, int N, int Kt, int mode)
{
    __shared__ __align__(16) char smem[4 * MMK_TILE];   // A0 B0 A1 B1
    uint32_t sbase = smem_u32(smem);

    A += blockIdx.z * aStride;
    B += blockIdx.z * bStride;
    C += blockIdx.z * cStride;

    int tid = threadIdx.x;
    int wid = tid >> 5, lane = tid & 31;
    int g = lane >> 2, tig = lane & 3;
    int warp_m = wid >> 2;   // 0..1
    int warp_n = wid & 3;    // 0..3
    int m0 = blockIdx.y * 128;
    int n0 = blockIdx.x * 128;
    int nk = Kt >> 5;

    float acc[4][4][4];
#pragma unroll
    for (int i = 0; i < 4; i++)
#pragma unroll
        for (int j = 0; j < 4; j++)
#pragma unroll
            for (int q = 0; q < 4; q++) acc[i][j][q] = 0.f;

    auto load_stage = [&](int s, int kc) {
        uint32_t aB = sbase + s * 2 * MMK_TILE;
        uint32_t bB = aB + MMK_TILE;
        int k0 = kc << 5;
#pragma unroll
        for (int it = 0; it < 2; it++) {
            int idx = tid + it * 256;
            int r = idx >> 2, c = idx & 3;
            cp16(aB + r * MMK_STRIDE + c * 16, A + ((size_t)(m0 + r) * Kt + k0 + c * 8));
        }
#pragma unroll
        for (int it = 0; it < 2; it++) {
            int idx = tid + it * 256;
            int r = idx >> 2, c = idx & 3;
            cp16(bB + r * MMK_STRIDE + c * 16, B + ((size_t)(n0 + r) * Kt + k0 + c * 8));
        }
        asm volatile("cp.async.commit_group;" ::: "memory");
    };

    load_stage(0, 0);

    // ldmatrix address components (constant across kc)
    int aRowSel = (lane & 15);
    int aColSel = (lane & 16) ? 16 : 0;
    int bRowSel = ((lane & 16) ? 8 : 0) + (lane & 7);
    int bColSel = (lane & 8) ? 16 : 0;

    for (int kc = 0; kc < nk; kc++) {
        int s = kc & 1;
        if (kc + 1 < nk) {
            load_stage(s ^ 1, kc + 1);
            asm volatile("cp.async.wait_group 1;" ::: "memory");
        } else {
            asm volatile("cp.async.wait_group 0;" ::: "memory");
        }
        __syncthreads();

        uint32_t aT = sbase + s * 2 * MMK_TILE;
        uint32_t bT = aT + MMK_TILE;
#pragma unroll
        for (int ks = 0; ks < 2; ks++) {
            uint32_t afr[4][4], bfr[2][4];
#pragma unroll
            for (int am = 0; am < 4; am++) {
                uint32_t addr = aT + (uint32_t)(warp_m * 64 + am * 16 + aRowSel) * MMK_STRIDE
                                + ks * 32 + aColSel;
                ldsm4(afr[am], addr);
            }
#pragma unroll
            for (int ap = 0; ap < 2; ap++) {
                uint32_t addr = bT + (uint32_t)(warp_n * 32 + ap * 16 + bRowSel) * MMK_STRIDE
                                + ks * 32 + bColSel;
                ldsm4(bfr[ap], addr);
            }
#pragma unroll
            for (int am = 0; am < 4; am++) {
                mma16816(acc[am][0], afr[am], &bfr[0][0]);
                mma16816(acc[am][1], afr[am], &bfr[0][2]);
                mma16816(acc[am][2], afr[am], &bfr[1][0]);
                mma16816(acc[am][3], afr[am], &bfr[1][2]);
            }
        }
        __syncthreads();
    }

    // epilogue
#pragma unroll
    for (int am = 0; am < 4; am++) {
#pragma unroll
        for (int an = 0; an < 4; an++) {
            int row = m0 + warp_m * 64 + am * 16 + g;
            int col = n0 + warp_n * 32 + an * 8 + tig * 2;
            float2 v0 = make_float2(acc[am][an][0], acc[am][an][1]);
            float2 v1 = make_float2(acc[am][an][2], acc[am][an][3]);
            if (mode == 1) {
                const float2 r0 = *(const float2*)(Res + (size_t)row * N + col);
                const float2 r1 = *(const float2*)(Res + (size_t)(row + 8) * N + col);
                v0.x += r0.x; v0.y += r0.y;
                v1.x += r1.x; v1.y += r1.y;
            } else if (mode == 2) {
                v0.x = sigmoidf(v0.x); v0.y = sigmoidf(v0.y);
                v1.x = sigmoidf(v1.x); v1.y = sigmoidf(v1.y);
            }
            *(float2*)(C + (size_t)row * N + col) = v0;
            *(float2*)(C + (size_t)(row + 8) * N + col) = v1;
        }
    }
}

// ---------------- generic bf16 split of fp32 matrix: [M,K] -> [M,3K] {h|l|h} ----------------
__global__ void __launch_bounds__(256) splitA_kernel(
    const float* __restrict__ A, __nv_bfloat16* __restrict__ out, int M, int K)
{
    int i = blockIdx.x * 256 + threadIdx.x;
    if (i >= M * K) return;
    int m = i / K, k = i - m * K;
    float v = A[i];
    __nv_bfloat16 hi = __float2bfloat16(v);
    __nv_bfloat16 lo = __float2bfloat16(v - __bfloat162float(hi));
    size_t base = (size_t)m * 3 * K;
    out[base + k] = hi;
    out[base + K + k] = lo;
    out[base + 2 * K + k] = hi;
}

// ---------------- W [K,N] fp32 -> transposed split [N,3K] bf16 {h|h|l} ----------------
__global__ void __launch_bounds__(1024) splitW_kernel(
    const float* __restrict__ W, __nv_bfloat16* __restrict__ out, int K, int N)
{
    __shared__ float tile[32][33];
    int k0 = blockIdx.y * 32, n0 = blockIdx.x * 32;
    int tx = threadIdx.x & 31, ty = threadIdx.x >> 5;
    tile[ty][tx] = W[(size_t)(k0 + ty) * N + n0 + tx];
    __syncthreads();
    int n = n0 + ty, k = k0 + tx;
    float v = tile[tx][ty];
    __nv_bfloat16 hi = __float2bfloat16(v);
    __nv_bfloat16 lo = __float2bfloat16(v - __bfloat162float(hi));
    size_t base = (size_t)n * 3 * K;
    out[base + k] = hi;
    out[base + K + k] = hi;
    out[base + 2 * K + k] = lo;
}

// batched version for the 4 big 2048x2048 weights
__global__ void __launch_bounds__(1024) splitW4_kernel(
    const float* __restrict__ W0, const float* __restrict__ W1,
    const float* __restrict__ W2, const float* __restrict__ W3,
    __nv_bfloat16* __restrict__ out)
{
    const float* W = blockIdx.z == 0 ? W0 : blockIdx.z == 1 ? W1 : blockIdx.z == 2 ? W2 : W3;
    __nv_bfloat16* o = out + blockIdx.z * WSLOT;
    __shared__ float tile[32][33];
    int k0 = blockIdx.y * 32, n0 = blockIdx.x * 32;
    int tx = threadIdx.x & 31, ty = threadIdx.x >> 5;
    tile[ty][tx] = W[(size_t)(k0 + ty) * HID + n0 + tx];
    __syncthreads();
    int n = n0 + ty, k = k0 + tx;
    float v = tile[tx][ty];
    __nv_bfloat16 hi = __float2bfloat16(v);
    __nv_bfloat16 lo = __float2bfloat16(v - __bfloat162float(hi));
    size_t base = (size_t)n * 3 * HID;
    o[base + k] = hi;
    o[base + HID + k] = hi;
    o[base + 2 * HID + k] = lo;
}

// ---------------- fused LN + token-shift mix + bf16 split ----------------
__global__ void __launch_bounds__(256) ln_mix_kernel(
    const float* __restrict__ x, const float* __restrict__ state1,
    const float* __restrict__ lnw, const float* __restrict__ lnb,
    const float* __restrict__ cr, const float* __restrict__ cw,
    const float* __restrict__ ck, const float* __restrict__ cv,
    const float* __restrict__ ca, const float* __restrict__ cg,
    __nv_bfloat16* __restrict__ abuf,
    float* __restrict__ xw, float* __restrict__ xa, float* __restrict__ xvf,
    float* __restrict__ state1_out)
{
    int t = blockIdx.x;
    const float* xt = x + (size_t)t * HID;
    const float* xp = x + (size_t)(t - 1) * HID;

    float v0[8], v1[8];
    float s0 = 0.f, s1 = 0.f;
#pragma unroll
    for (int j = 0; j < 8; j++) {
        int c = threadIdx.x + j * 256;
        v0[j] = xt[c]; s0 += v0[j];
        v1[j] = t ? xp[c] : 0.f; s1 += v1[j];
    }
    float mu0 = blk_sum256(s0) * (1.f / HID);
    float mu1 = blk_sum256(s1) * (1.f / HID);
    float q0 = 0.f, q1 = 0.f;
#pragma unroll
    for (int j = 0; j < 8; j++) {
        float d0 = v0[j] - mu0; q0 += d0 * d0;
        float d1 = v1[j] - mu1; q1 += d1 * d1;
    }
    float inv0 = rsqrtf(blk_sum256(q0) * (1.f / HID) + 1e-5f);
    float inv1 = rsqrtf(blk_sum256(q1) * (1.f / HID) + 1e-5f);

#pragma unroll
    for (int j = 0; j < 8; j++) {
        int c = threadIdx.x + j * 256;
        float wv = lnw[c], bv = lnb[c];
        float xn = (v0[j] - mu0) * inv0 * wv + bv;
        float pv = t ? (v1[j] - mu1) * inv1 * wv + bv : state1[c];
        float sx = pv - xn;

        __nv_bfloat16* arow = abuf + (size_t)t * 3 * HID + c;
#pragma unroll
        for (int s = 0; s < 4; s++) {
            float coef = (s == 0) ? cr[c] : (s == 1) ? ck[c] : (s == 2) ? cv[c] : cg[c];
            float val = xn + coef * sx;
            __nv_bfloat16 hi = __float2bfloat16(val);
            __nv_bfloat16 lo = __float2bfloat16(val - __bfloat162float(hi));
            __nv_bfloat16* p = arow + (size_t)s * ASLOT;
            p[0] = hi; p[HID] = lo; p[2 * HID] = hi;
        }
        size_t gi = (size_t)t * HID + c;
        xw[gi]  = xn + cw[c] * sx;
        xa[gi]  = xn + ca[c] * sx;
        xvf[gi] = xn + cv[c] * sx;
        if (state1_out && t == T_LEN - 1) state1_out[c] = xn;
    }
}

// ---------------- batched LoRA down: h_z = act(x_z @ B_z) ----------------
__global__ void __launch_bounds__(256) lora_down_kernel(
    const float* __restrict__ Aa, const float* __restrict__ Aw, const float* __restrict__ Av,
    const float* __restrict__ Ba, const float* __restrict__ Bw, const float* __restrict__ Bv,
    float* __restrict__ hbuf)
{
    int z = blockIdx.z;
    const float* A = z == 0 ? Aa : z == 1 ? Aw : Av;
    const float* B = z == 0 ? Ba : z == 1 ? Bw : Bv;
    int N = (z == 2) ? 64 : 96;
    int zoff = z * 96;
    const int K = HID;

    __shared__ float As[16][64 + 1];
    __shared__ float Bs[16][64 + 1];
    int tid = threadIdx.x;
    int tx = tid & 15, ty = tid >> 4;
    int row0 = blockIdx.y * 64, col0 = blockIdx.x * 64;
    if (col0 >= N) return;
    float acc[4][4] = {};
    for (int k0 = 0; k0 < K; k0 += 16) {
#pragma unroll
        for (int i = tid; i < 64 * 16; i += 256) {
            int r = i >> 4, c = i & 15;
            As[c][r] = A[(size_t)(row0 + r) * K + k0 + c];
        }
#pragma unroll
        for (int i = tid; i < 16 * 64; i += 256) {
            int r = i >> 6, c = i & 63;
            int gc = col0 + c;
            Bs[r][c] = (gc < N) ? B[(size_t)(k0 + r) * N + gc] : 0.f;
        }
        __syncthreads();
#pragma unroll
        for (int kk = 0; kk < 16; kk++) {
            float a[4], b[4];
#pragma unroll
            for (int i = 0; i < 4; i++) a[i] = As[kk][ty * 4 + i];
#pragma unroll
            for (int jj = 0; jj < 4; jj++) b[jj] = Bs[kk][tx * 4 + jj];
#pragma unroll
            for (int i = 0; i < 4; i++)
#pragma unroll
                for (int jj = 0; jj < 4; jj++) acc[i][jj] = fmaf(a[i], b[jj], acc[i][jj]);
        }
        __syncthreads();
    }
#pragma unroll
    for (int i = 0; i < 4; i++) {
        int gr = row0 + ty * 4 + i;
#pragma unroll
        for (int jj = 0; jj < 4; jj++) {
            int gc = col0 + tx * 4 + jj;
            if (gc < N) {
                float v = acc[i][jj];
                if (z == 1) v = tanhf(v);
                hbuf[(size_t)gr * 256 + zoff + gc] = v;
            }
        }
    }
}

// ---------------- batched LoRA up + fused activations ----------------
// z0: S_A = sigmoid(a0 + h_a@a2) ; z1: S_W = exp(-0.606531*sigmoid(w0 + h_w@w2))
// z2: S_V = S_V + (v_first - S_V)*sigmoid(v0 + h_v@v2)
__global__ void __launch_bounds__(256) lora_up_kernel(
    const float* __restrict__ hbuf,
    const float* __restrict__ Ba, const float* __restrict__ Bw, const float* __restrict__ Bv,
    const float* __restrict__ a0, const float* __restrict__ w0, const float* __restrict__ v0b,
    const float* __restrict__ vf,
    float* __restrict__ outA, float* __restrict__ outW, float* __restrict__ outV)
{
    int z = blockIdx.z;
    const float* B = z == 0 ? Ba : z == 1 ? Bw : Bv;
    const float* bias = z == 0 ? a0 : z == 1 ? w0 : v0b;
    int K = (z == 2) ? 64 : 96;
    int zoff = z * 96;
    const int N = HID;

    __shared__ float As[16][64 + 1];
    __shared__ float Bs[16][64 + 1];
    int tid = threadIdx.x;
    int tx = tid & 15, ty = tid >> 4;
    int row0 = blockIdx.y * 64, col0 = blockIdx.x * 64;
    float acc[4][4] = {};
    for (int k0 = 0; k0 < K; k0 += 16) {
#pragma unroll
        for (int i = tid; i < 64 * 16; i += 256) {
            int r = i >> 4, c = i & 15;
            As[c][r] = hbuf[(size_t)(row0 + r) * 256 + zoff + k0 + c];
        }
#pragma unroll
        for (int i = tid; i < 16 * 64; i += 256) {
            int r = i >> 6, c = i & 63;
            Bs[r][c] = B[(size_t)(k0 + r) * N + col0 + c];
        }
        __syncthreads();
#pragma unroll
        for (int kk = 0; kk < 16; kk++) {
            float a[4], b[4];
#pragma unroll
            for (int i = 0; i < 4; i++) a[i] = As[kk][ty * 4 + i];
#pragma unroll
            for (int jj = 0; jj < 4; jj++) b[jj] = Bs[kk][tx * 4 + jj];
#pragma unroll
            for (int i = 0; i < 4; i++)
#pragma unroll
                for (int jj = 0; jj < 4; jj++) acc[i][jj] = fmaf(a[i], b[jj], acc[i][jj]);
        }
        __syncthreads();
    }
#pragma unroll
    for (int i = 0; i < 4; i++) {
        int gr = row0 + ty * 4 + i;
#pragma unroll
        for (int jj = 0; jj < 4; jj++) {
            int gc = col0 + tx * 4 + jj;
            size_t idx = (size_t)gr * N + gc;
            float s = sigmoidf(bias[gc] + acc[i][jj]);
            if (z == 0) outA[idx] = s;
            else if (z == 1) outW[idx] = __expf(-0.606531f * s);
            else {
                float vv = outV[idx];
                outV[idx] = vv + (vf[idx] - vv) * s;
            }
        }
    }
}

// ---------------- prep: kk normalize, k2, pack scan operands ----------------
__global__ void __launch_bounds__(256) prep_kernel(
    const float* __restrict__ k, const float* __restrict__ a,
    const float* __restrict__ w, const float* __restrict__ v,
    const float* __restrict__ r,
    const float* __restrict__ k_k, const float* __restrict__ k_a,
    float* __restrict__ k2out, float* __restrict__ pscan)
{
    int gw = (blockIdx.x * 256 + threadIdx.x) >> 5;
    int lane = threadIdx.x & 31;
    if (gw >= T_LEN * NHEAD) return;
    int t = gw >> 5, h = gw & 31;
    int base = t * HID + h * HEADD;
    int cb = h * HEADD;

    float k0v = k[base + lane], k1v = k[base + lane + 32];
    float q0 = k0v * k_k[cb + lane], q1 = k1v * k_k[cb + lane + 32];
    float ss = warp_sum(q0 * q0 + q1 * q1);
    float inv = 1.f / fmaxf(sqrtf(ss), 1e-12f);
    float kk0 = q0 * inv, kk1 = q1 * inv;

    float a0v = a[base + lane], a1v = a[base + lane + 32];
    float k20 = k0v * (1.f + (a0v - 1.f) * k_a[cb + lane]);
    float k21 = k1v * (1.f + (a1v - 1.f) * k_a[cb + lane + 32]);
    k2out[base + lane] = k20;
    k2out[base + lane + 32] = k21;

    size_t pb = ((size_t)(t * NHEAD + h) * HEADD + lane) * 8;
    float4 pa0 = make_float4(w[base + lane], kk0, kk0 * a0v, k20);
    float4 pb0 = make_float4(v[base + lane], r[base + lane], 0.f, 0.f);
    *(float4*)(pscan + pb) = pa0;
    *(float4*)(pscan + pb + 4) = pb0;

    size_t pb2 = pb + 32 * 8;
    float4 pa1 = make_float4(w[base + lane + 32], kk1, kk1 * a1v, k21);
    float4 pb1 = make_float4(v[base + lane + 32], r[base + lane + 32], 0.f, 0.f);
    *(float4*)(pscan + pb2) = pa1;
    *(float4*)(pscan + pb2 + 4) = pb1;
}

// ---------------- sequential RWKV7 scan with register prefetch ----------------
__global__ void __launch_bounds__(64) scan_kernel(
    const float* __restrict__ pscan,
    const float* __restrict__ state2, float* __restrict__ ybuf,
    float* __restrict__ Sout)
{
    int h = blockIdx.x;
    int i = threadIdx.x;
    float S[HEADD];
#pragma unroll
    for (int j = 0; j < HEADD; j++) S[j] = state2[h * HEADD * HEADD + i * HEADD + j];

    __shared__ float sw[HEADD], skk[HEADD], ska[HEADD], sk[HEADD], sr[HEADD];

    const size_t tstride = (size_t)NHEAD * HEADD * 8;   // floats per timestep
    const float* base = pscan + ((size_t)h * HEADD + i) * 8;

    float4 pa = *(const float4*)(base);
    float4 pb = *(const float4*)(base + 4);

    for (int t = 0; t < T_LEN; t++) {
        sw[i] = pa.x; skk[i] = pa.y; ska[i] = pa.z; sk[i] = pa.w;
        float vi = pb.x; sr[i] = pb.y;
        __syncthreads();

        if (t + 1 < T_LEN) {
            const float* nb = base + (size_t)(t + 1) * tstride;
            pa = *(const float4*)(nb);
            pb = *(const float4*)(nb + 4);
        }

        float p0 = 0.f, p1 = 0.f, p2 = 0.f, p3 = 0.f;
#pragma unroll
        for (int j = 0; j < HEADD; j += 4) {
            p0 = fmaf(S[j],     skk[j],     p0);
            p1 = fmaf(S[j + 1], skk[j + 1], p1);
            p2 = fmaf(S[j + 2], skk[j + 2], p2);
            p3 = fmaf(S[j + 3], skk[j + 3], p3);
        }
        float p = (p0 + p1) + (p2 + p3);

        float y0 = 0.f, y1 = 0.f, y2 = 0.f, y3 = 0.f;
#pragma unroll
        for (int j = 0; j < HEADD; j += 4) {
            float s0 = S[j]     * sw[j]     - p * ska[j]     + vi * sk[j];
            float s1 = S[j + 1] * sw[j + 1] - p * ska[j + 1] + vi * sk[j + 1];
            float s2 = S[j + 2] * sw[j + 2] - p * ska[j + 2] + vi * sk[j + 2];
            float s3 = S[j + 3] * sw[j + 3] - p * ska[j + 3] + vi * sk[j + 3];
            S[j] = s0; S[j + 1] = s1; S[j + 2] = s2; S[j + 3] = s3;
            y0 = fmaf(s0, sr[j],     y0);
            y1 = fmaf(s1, sr[j + 1], y1);
            y2 = fmaf(s2, sr[j + 2], y2);
            y3 = fmaf(s3, sr[j + 3], y3);
        }
        ybuf[(size_t)t * HID + h * HEADD + i] = (y0 + y1) + (y2 + y3);
        __syncthreads();
    }
#pragma unroll
    for (int j = 0; j < HEADD; j++) Sout[h * HEADD * HEADD + i * HEADD + j] = S[j];
}

// ---------------- per-head groupnorm + rkv + gate ----------------
__global__ void __launch_bounds__(256) post_kernel(
    const float* __restrict__ y, const float* __restrict__ r,
    const float* __restrict__ k2, const float* __restrict__ v,
    const float* __restrict__ g, const float* __restrict__ r_k,
    const float* __restrict__ lnxw, const float* __restrict__ lnxb,
    float* __restrict__ z)
{
    int gw = (blockIdx.x * 256 + threadIdx.x) >> 5;
    int lane = threadIdx.x & 31;
    if (gw >= T_LEN * NHEAD) return;
    int t = gw >> 5, h = gw & 31;
    int base = t * HID + h * HEADD;
    int cb = h * HEADD;

    float y0 = y[base + lane], y1 = y[base + lane + 32];
    float mu = warp_sum(y0 + y1) * (1.f / HEADD);
    float d0 = y0 - mu, d1 = y1 - mu;
    float var = warp_sum(d0 * d0 + d1 * d1) * (1.f / HEADD);
    float inv = rsqrtf(var + 0.00064f);

    float rs = warp_sum(r[base + lane] * k2[base + lane] * r_k[cb + lane] +
                        r[base + lane + 32] * k2[base + lane + 32] * r_k[cb + lane + 32]);

    float z0 = (d0 * inv * lnxw[cb + lane] + lnxb[cb + lane] + rs * v[base + lane]) * g[base + lane];
    float z1 = (d1 * inv * lnxw[cb + lane + 32] + lnxb[cb + lane + 32] + rs * v[base + lane + 32]) * g[base + lane + 32];
    z[base + lane] = z0;
    z[base + lane + 32] = z1;
}

__global__ void __launch_bounds__(256) copy_kernel(const float* __restrict__ src,
                                                   float* __restrict__ dst, int n)
{
    int i = blockIdx.x * 256 + threadIdx.x;
    if (i < n) dst[i] = src[i];
}

// ---------------- host launcher ----------------
extern "C" void kernel_launch(void* const* d_in, const int* in_sizes, int n_in,
                              void* d_out, int out_size)
{
    const float* x       = (const float*)d_in[0];
    const float* state1  = (const float*)d_in[1];
    const float* state2  = (const float*)d_in[2];
    const float* v_first = (const float*)d_in[3];
    const float* ln1_w   = (const float*)d_in[4];
    const float* ln1_b   = (const float*)d_in[5];
    const float* x_r     = (const float*)d_in[6];
    const float* x_w     = (const float*)d_in[7];
    const float* x_k     = (const float*)d_in[8];
    const float* x_v     = (const float*)d_in[9];
    const float* x_a     = (const float*)d_in[10];
    const float* x_g     = (const float*)d_in[11];
    const float* Wr      = (const float*)d_in[12];
    const float* Wk      = (const float*)d_in[13];
    const float* Wv      = (const float*)d_in[14];
    const float* Wo      = (const float*)d_in[15];
    const float* w0      = (const float*)d_in[16];
    const float* w1      = (const float*)d_in[17];
    const float* w2      = (const float*)d_in[18];
    const float* a0      = (const float*)d_in[19];
    const float* a1      = (const float*)d_in[20];
    const float* a2      = (const float*)d_in[21];
    const float* v0      = (const float*)d_in[22];
    const float* v1      = (const float*)d_in[23];
    const float* v2      = (const float*)d_in[24];
    const float* g1      = (const float*)d_in[25];
    const float* g2      = (const float*)d_in[26];
    const float* k_k     = (const float*)d_in[27];
    const float* k_a     = (const float*)d_in[28];
    const float* r_k     = (const float*)d_in[29];
    const float* ln_x_w  = (const float*)d_in[30];
    const float* ln_x_b  = (const float*)d_in[31];

    float* sc = nullptr;        cudaGetSymbolAddress((void**)&sc, g_scratch);
    float* hbuf = nullptr;      cudaGetSymbolAddress((void**)&hbuf, g_hbuf);
    float* pscan = nullptr;     cudaGetSymbolAddress((void**)&pscan, g_pscan);
    __nv_bfloat16* abuf = nullptr;  cudaGetSymbolAddress((void**)&abuf, g_abuf);
    __nv_bfloat16* wbuf = nullptr;  cudaGetSymbolAddress((void**)&wbuf, g_wbuf);
    __nv_bfloat16* g1buf = nullptr; cudaGetSymbolAddress((void**)&g1buf, g_g1buf);
    __nv_bfloat16* g2buf = nullptr; cudaGetSymbolAddress((void**)&g2buf, g_g2buf);
    __nv_bfloat16* ghbuf = nullptr; cudaGetSymbolAddress((void**)&ghbuf, g_ghbuf);

#define SLOT(s) (sc + (size_t)(s) * NTOK_EL)

    float* out = (float*)d_out;
    const int OFF_OUT = 0;
    const int OFF_S1  = NTOK_EL;
    const int OFF_S2  = OFF_S1 + HID;
    const int OFF_VF  = OFF_S2 + NHEAD * HEADD * HEADD;
    const int TOTAL   = OFF_VF + NTOK_EL;
    bool full = (out_size >= TOTAL);

    float* s1_out = full ? out + OFF_S1 : nullptr;
    float* s2_out = full ? out + OFF_S2 : SLOT(S_TMP);

    const int EW_GRID = (NTOK_EL + 255) / 256;

    // weight splits (independent of activations)
    splitW4_kernel<<<dim3(64, 64, 4), 1024>>>(Wr, Wk, Wv, Wo, wbuf);
    splitW_kernel<<<dim3(8, 64), 1024>>>(g1, g1buf, HID, 256);
    splitW_kernel<<<dim3(64, 8), 1024>>>(g2, g2buf, 256, HID);

    // fused LN + mix + split
    ln_mix_kernel<<<T_LEN, 256>>>(x, state1, ln1_w, ln1_b,
                                  x_r, x_w, x_k, x_v, x_a, x_g,
                                  abuf, SLOT(S_XW), SLOT(S_XA), SLOT(S_XV), s1_out);

    // batched big projections r,k,v
    mm128_kernel<<<dim3(16, 8, 3), 256>>>(abuf, ASLOT, wbuf, WSLOT,
                                          SLOT(S_R), NTOK_EL, nullptr,
                                          T_LEN, HID, 3 * HID, 0);

    // g chain: sigmoid(xg@g1) -> split -> @g2
    mm128_kernel<<<dim3(2, 8, 1), 256>>>(abuf + 3 * ASLOT, 0, g1buf, 0,
                                         SLOT(S_TMP), 0, nullptr,
                                         T_LEN, 256, 3 * HID, 2);
    splitA_kernel<<<(T_LEN * 256 + 255) / 256, 256>>>(SLOT(S_TMP), ghbuf, T_LEN, 256);
    mm128_kernel<<<dim3(16, 8, 1), 256>>>(ghbuf, 0, g2buf, 0,
                                          SLOT(S_G), 0, nullptr,
                                          T_LEN, HID, 3 * 256, 0);

    // batched LoRA chains (a, w, v)
    lora_down_kernel<<<dim3(2, 16, 3), 256>>>(SLOT(S_XA), SLOT(S_XW), SLOT(S_XV),
                                              a1, w1, v1, hbuf);
    lora_up_kernel<<<dim3(32, 16, 3), 256>>>(hbuf, a2, w2, v2, a0, w0, v0, v_first,
                                             SLOT(S_A), SLOT(S_W), SLOT(S_V));

    // prep: kk/k2 + pack scan operands
    prep_kernel<<<(T_LEN * NHEAD * 32 + 255) / 256, 256>>>(
        SLOT(S_K), SLOT(S_A), SLOT(S_W), SLOT(S_V), SLOT(S_R),
        k_k, k_a, SLOT(S_K2), pscan);

    // sequential scan
    scan_kernel<<<NHEAD, HEADD>>>(pscan, state2, SLOT(S_Y), s2_out);

    // groupnorm + rkv + gate -> z
    post_kernel<<<(T_LEN * NHEAD * 32 + 255) / 256, 256>>>(
        SLOT(S_Y), SLOT(S_R), SLOT(S_K2), SLOT(S_V), SLOT(S_G),
        r_k, ln_x_w, ln_x_b, SLOT(S_Z));

    // out = x + z@Wo
    splitA_kernel<<<(NTOK_EL + 255) / 256, 256>>>(SLOT(S_Z), abuf, T_LEN, HID);
    mm128_kernel<<<dim3(16, 8, 1), 256>>>(abuf, 0, wbuf + 3 * WSLOT, 0,
                                          out + OFF_OUT, 0, x,
                                          T_LEN, HID, 3 * HID, 1);

    // passthrough v_first
    if (full)
        copy_kernel<<<EW_GRID, 256>>>(v_first, out + OFF_VF, NTOK_EL);
}

// round 5
// speedup vs baseline: 2.6341x; 1.0817x over previous
#include <cuda_runtime.h>
#include <cuda_bf16.h>
#include <math.h>
#include <stdint.h>

#define T_LEN 1024
#define HID   2048
#define NHEAD 32
#define HEADD 64
#define NTOK_EL (T_LEN * HID)   // 2097152

#define ASLOT ((size_t)T_LEN * 2 * HID)   // A' slot: [M, 2K] bf16
#define WSLOT ((size_t)HID * 2 * HID)     // W' slot: [N, 2K] bf16

// ---------------- static device scratch ----------------
__device__ float g_scratch[12u * (unsigned)NTOK_EL];
__device__ float g_hbuf[T_LEN * 256];
__device__ float g_pscan[(size_t)T_LEN * NHEAD * HEADD * 8];
__device__ __align__(256) __nv_bfloat16 g_abuf[4 * ASLOT];         // xr',xk',xv',xg'
__device__ __align__(256) __nv_bfloat16 g_wbuf[4 * WSLOT];         // Wr',Wk',Wv',Wo'
__device__ __align__(256) __nv_bfloat16 g_g1buf[(size_t)256 * 2 * HID];
__device__ __align__(256) __nv_bfloat16 g_g2buf[(size_t)HID * 2 * 256];
__device__ __align__(256) __nv_bfloat16 g_ghbuf[(size_t)T_LEN * 2 * 256];

#define S_XW  0
#define S_XA  1
#define S_XV  2
#define S_R   3
#define S_K   4
#define S_V   5
#define S_K2  6
#define S_G   7
#define S_A   8
#define S_W   9
#define S_TMP 10
#define S_Y   11

// ---------------- helpers ----------------
__device__ __forceinline__ float blk_sum256(float v) {
    __shared__ float sh[8];
    int tid = threadIdx.x;
#pragma unroll
    for (int o = 16; o; o >>= 1) v += __shfl_xor_sync(0xffffffffu, v, o);
    if ((tid & 31) == 0) sh[tid >> 5] = v;
    __syncthreads();
    if (tid == 0) {
        float s = 0.f;
#pragma unroll
        for (int i = 0; i < 8; i++) s += sh[i];
        sh[0] = s;
    }
    __syncthreads();
    float r = sh[0];
    __syncthreads();
    return r;
}

__device__ __forceinline__ float warp_sum(float v) {
#pragma unroll
    for (int o = 16; o; o >>= 1) v += __shfl_xor_sync(0xffffffffu, v, o);
    return v;
}

__device__ __forceinline__ float sigmoidf(float v) {
    return 1.f / (1.f + __expf(-v));
}

__device__ __forceinline__ uint32_t smem_u32(const void* p) {
    uint32_t a;
    asm("{ .reg .u64 t; cvta.to.shared.u64 t, %1; cvt.u32.u64 %0, t; }" : "=r"(a) : "l"(p));
    return a;
}

__device__ __forceinline__ void bfsplit(float v, __nv_bfloat16& hi, __nv_bfloat16& lo) {
    hi = __float2bfloat16(v);
    lo = __float2bfloat16(v - __bfloat162float(hi));
}

// ======================= mma.sync bf16 GEMM (virtual split-K3) =======================
// Operands stored [rows, 2K] {hi|lo}. Chunk kc -> segment: 0:(Ah,Bh) 1:(Al,Bh) 2:(Ah,Bl).
#define MMK_STRIDE 80
#define MMK_TILE   (128 * MMK_STRIDE)

struct MMJob { const __nv_bfloat16* B; float* C; const float* Res; int N; int mode; };
struct MMJobs { MMJob j[4]; };

__device__ __forceinline__ void cp16(uint32_t dst, const void* src) {
    asm volatile("cp.async.cg.shared.global [%0], [%1], 16;" :: "r"(dst), "l"(src));
}

__device__ __forceinline__ void ldsm4(uint32_t* r, uint32_t a) {
    asm volatile("ldmatrix.sync.aligned.m8n8.x4.shared.b16 {%0,%1,%2,%3}, [%4];"
                 : "=r"(r[0]), "=r"(r[1]), "=r"(r[2]), "=r"(r[3]) : "r"(a));
}

__device__ __forceinline__ void mma16816(float* c, const uint32_t* a, const uint32_t* b) {
    asm volatile(
        "mma.sync.aligned.m16n8k16.row.col.f32.bf16.bf16.f32 "
        "{%0,%1,%2,%3}, {%4,%5,%6,%7}, {%8,%9}, {%0,%1,%2,%3};"
        : "+f"(c[0]), "+f"(c[1]), "+f"(c[2]), "+f"(c[3])
        : "r"(a[0]), "r"(a[1]), "r"(a[2]), "r"(a[3]), "r"(b[0]), "r"(b[1]));
}

__global__ void __launch_bounds__(256, 2) mm128_kernel(
    const __nv_bfloat16* __restrict__ A, size_t aStride,
    MMJobs jobs, int M, int K)
{
    __shared__ __align__(16) char smem[4 * MMK_TILE];   // A0 B0 A1 B1
    uint32_t sbase = smem_u32(smem);

    const MMJob job = jobs.j[blockIdx.z];
    const int N = job.N;
    int n0 = blockIdx.x * 128;
    if (n0 >= N) return;
    int m0 = blockIdx.y * 128;

    const __nv_bfloat16* Ab = A + blockIdx.z * aStride;
    const __nv_bfloat16* Bb = job.B;
    const int K2 = 2 * K;
    const int nkK = K >> 5;
    const int nk = 3 * nkK;

    int tid = threadIdx.x;
    int wid = tid >> 5, lane = tid & 31;
    int g = lane >> 2, tig = lane & 3;
    int warp_m = wid >> 2;
    int warp_n = wid & 3;

    float acc[4][4][4];
#pragma unroll
    for (int i = 0; i < 4; i++)
#pragma unroll
        for (int j = 0; j < 4; j++)
#pragma unroll
            for (int q = 0; q < 4; q++) acc[i][j][q] = 0.f;

    auto load_stage = [&](int s, int kc) {
        int seg = kc / nkK, kk = kc - seg * nkK;
        int aOff = ((seg == 1) ? K : 0) + kk * 32;
        int bOff = ((seg == 2) ? K : 0) + kk * 32;
        uint32_t aB = sbase + s * 2 * MMK_TILE;
        uint32_t bB = aB + MMK_TILE;
#pragma unroll
        for (int it = 0; it < 2; it++) {
            int idx = tid + it * 256;
            int r = idx >> 2, c = idx & 3;
            cp16(aB + r * MMK_STRIDE + c * 16, Ab + ((size_t)(m0 + r) * K2 + aOff + c * 8));
        }
#pragma unroll
        for (int it = 0; it < 2; it++) {
            int idx = tid + it * 256;
            int r = idx >> 2, c = idx & 3;
            cp16(bB + r * MMK_STRIDE + c * 16, Bb + ((size_t)(n0 + r) * K2 + bOff + c * 8));
        }
        asm volatile("cp.async.commit_group;" ::: "memory");
    };

    load_stage(0, 0);

    int aRowSel = (lane & 15);
    int aColSel = (lane & 16) ? 16 : 0;
    int bRowSel = ((lane & 16) ? 8 : 0) + (lane & 7);
    int bColSel = (lane & 8) ? 16 : 0;

    for (int kc = 0; kc < nk; kc++) {
        int s = kc & 1;
        if (kc + 1 < nk) {
            load_stage(s ^ 1, kc + 1);
            asm volatile("cp.async.wait_group 1;" ::: "memory");
        } else {
            asm volatile("cp.async.wait_group 0;" ::: "memory");
        }
        __syncthreads();

        uint32_t aT = sbase + s * 2 * MMK_TILE;
        uint32_t bT = aT + MMK_TILE;
#pragma unroll
        for (int ks = 0; ks < 2; ks++) {
            uint32_t afr[4][4], bfr[2][4];
#pragma unroll
            for (int am = 0; am < 4; am++) {
                uint32_t addr = aT + (uint32_t)(warp_m * 64 + am * 16 + aRowSel) * MMK_STRIDE
                                + ks * 32 + aColSel;
                ldsm4(afr[am], addr);
            }
#pragma unroll
            for (int ap = 0; ap < 2; ap++) {
                uint32_t addr = bT + (uint32_t)(warp_n * 32 + ap * 16 + bRowSel) * MMK_STRIDE
                                + ks * 32 + bColSel;
                ldsm4(bfr[ap], addr);
            }
#pragma unroll
            for (int am = 0; am < 4; am++) {
                mma16816(acc[am][0], afr[am], &bfr[0][0]);
                mma16816(acc[am][1], afr[am], &bfr[0][2]);
                mma16816(acc[am][2], afr[am], &bfr[1][0]);
                mma16816(acc[am][3], afr[am], &bfr[1][2]);
            }
        }
        __syncthreads();
    }

    float* C = job.C;
    const float* Res = job.Res;
    int mode = job.mode;
#pragma unroll
    for (int am = 0; am < 4; am++) {
#pragma unroll
        for (int an = 0; an < 4; an++) {
            int row = m0 + warp_m * 64 + am * 16 + g;
            int col = n0 + warp_n * 32 + an * 8 + tig * 2;
            float2 v0 = make_float2(acc[am][an][0], acc[am][an][1]);
            float2 v1 = make_float2(acc[am][an][2], acc[am][an][3]);
            if (mode == 1) {
                const float2 r0 = *(const float2*)(Res + (size_t)row * N + col);
                const float2 r1 = *(const float2*)(Res + (size_t)(row + 8) * N + col);
                v0.x += r0.x; v0.y += r0.y;
                v1.x += r1.x; v1.y += r1.y;
            } else if (mode == 2) {
                v0.x = sigmoidf(v0.x); v0.y = sigmoidf(v0.y);
                v1.x = sigmoidf(v1.x); v1.y = sigmoidf(v1.y);
            }
            *(float2*)(C + (size_t)row * N + col) = v0;
            *(float2*)(C + (size_t)(row + 8) * N + col) = v1;
        }
    }
}

// ---------------- bf16 split: [M,K] fp32 -> [M,2K] {h|l} ----------------
__global__ void __launch_bounds__(256) splitA_kernel(
    const float* __restrict__ A, __nv_bfloat16* __restrict__ out, int M, int K)
{
    int i = blockIdx.x * 256 + threadIdx.x;
    if (i >= M * K) return;
    int m = i / K, k = i - m * K;
    __nv_bfloat16 hi, lo;
    bfsplit(A[i], hi, lo);
    size_t base = (size_t)m * 2 * K;
    out[base + k] = hi;
    out[base + K + k] = lo;
}

// ---------------- W [K,N] fp32 -> transposed split [N,2K] {h|l}, bf16x2 stores ------
__global__ void __launch_bounds__(1024) splitW_kernel(
    const float* __restrict__ W, __nv_bfloat16* __restrict__ out, int K, int N)
{
    __shared__ float tile[32][33];
    int k0 = blockIdx.y * 32, n0 = blockIdx.x * 32;
    int tx = threadIdx.x & 31, ty = threadIdx.x >> 5;
    tile[ty][tx] = W[(size_t)(k0 + ty) * N + n0 + tx];
    __syncthreads();
    int tid = threadIdx.x;
    if (tid >= 512) return;
    int nl = tid >> 4, kp = (tid & 15) * 2;
    float v0 = tile[kp][nl], v1 = tile[kp + 1][nl];
    __nv_bfloat16 h0, l0, h1, l1;
    bfsplit(v0, h0, l0);
    bfsplit(v1, h1, l1);
    size_t base = (size_t)(n0 + nl) * 2 * K + k0 + kp;
    *(__nv_bfloat162*)(out + base) = __nv_bfloat162(h0, h1);
    *(__nv_bfloat162*)(out + base + K) = __nv_bfloat162(l0, l1);
}

// batched for the 4 big 2048x2048 weights
__global__ void __launch_bounds__(1024) splitW4_kernel(
    const float* __restrict__ W0, const float* __restrict__ W1,
    const float* __restrict__ W2, const float* __restrict__ W3,
    __nv_bfloat16* __restrict__ out)
{
    const float* W = blockIdx.z == 0 ? W0 : blockIdx.z == 1 ? W1 : blockIdx.z == 2 ? W2 : W3;
    __nv_bfloat16* o = out + blockIdx.z * WSLOT;
    __shared__ float tile[32][33];
    int k0 = blockIdx.y * 32, n0 = blockIdx.x * 32;
    int tx = threadIdx.x & 31, ty = threadIdx.x >> 5;
    tile[ty][tx] = W[(size_t)(k0 + ty) * HID + n0 + tx];
    __syncthreads();
    int tid = threadIdx.x;
    if (tid >= 512) return;
    int nl = tid >> 4, kp = (tid & 15) * 2;
    float v0 = tile[kp][nl], v1 = tile[kp + 1][nl];
    __nv_bfloat16 h0, l0, h1, l1;
    bfsplit(v0, h0, l0);
    bfsplit(v1, h1, l1);
    size_t base = (size_t)(n0 + nl) * 2 * HID + k0 + kp;
    *(__nv_bfloat162*)(o + base) = __nv_bfloat162(h0, h1);
    *(__nv_bfloat162*)(o + base + HID) = __nv_bfloat162(l0, l1);
}

// ---------------- fused LN + token-shift mix + bf16 split ----------------
__global__ void __launch_bounds__(256) ln_mix_kernel(
    const float* __restrict__ x, const float* __restrict__ state1,
    const float* __restrict__ lnw, const float* __restrict__ lnb,
    const float* __restrict__ cr, const float* __restrict__ cw,
    const float* __restrict__ ck, const float* __restrict__ cv,
    const float* __restrict__ ca, const float* __restrict__ cg,
    __nv_bfloat16* __restrict__ abuf,
    float* __restrict__ xw, float* __restrict__ xa, float* __restrict__ xvf,
    float* __restrict__ state1_out)
{
    int t = blockIdx.x;
    const float* xt = x + (size_t)t * HID;
    const float* xp = x + (size_t)(t - 1) * HID;

    float2 v0[4], v1[4];
    float s0 = 0.f, s1 = 0.f;
#pragma unroll
    for (int j = 0; j < 4; j++) {
        int c = threadIdx.x * 2 + j * 512;
        v0[j] = *(const float2*)(xt + c);
        s0 += v0[j].x + v0[j].y;
        v1[j] = t ? *(const float2*)(xp + c) : make_float2(0.f, 0.f);
        s1 += v1[j].x + v1[j].y;
    }
    float mu0 = blk_sum256(s0) * (1.f / HID);
    float mu1 = blk_sum256(s1) * (1.f / HID);
    float q0 = 0.f, q1 = 0.f;
#pragma unroll
    for (int j = 0; j < 4; j++) {
        float d;
        d = v0[j].x - mu0; q0 += d * d;
        d = v0[j].y - mu0; q0 += d * d;
        d = v1[j].x - mu1; q1 += d * d;
        d = v1[j].y - mu1; q1 += d * d;
    }
    float inv0 = rsqrtf(blk_sum256(q0) * (1.f / HID) + 1e-5f);
    float inv1 = rsqrtf(blk_sum256(q1) * (1.f / HID) + 1e-5f);

#pragma unroll
    for (int j = 0; j < 4; j++) {
        int c = threadIdx.x * 2 + j * 512;
        float2 wv = *(const float2*)(lnw + c);
        float2 bv = *(const float2*)(lnb + c);
        float xn0 = (v0[j].x - mu0) * inv0 * wv.x + bv.x;
        float xn1 = (v0[j].y - mu0) * inv0 * wv.y + bv.y;
        float pv0 = t ? (v1[j].x - mu1) * inv1 * wv.x + bv.x : state1[c];
        float pv1 = t ? (v1[j].y - mu1) * inv1 * wv.y + bv.y : state1[c + 1];
        float sx0 = pv0 - xn0, sx1 = pv1 - xn1;

        __nv_bfloat16* arow = abuf + (size_t)t * 2 * HID + c;
#pragma unroll
        for (int s = 0; s < 4; s++) {
            const float* coefA = (s == 0) ? cr : (s == 1) ? ck : (s == 2) ? cv : cg;
            float a0 = xn0 + coefA[c] * sx0;
            float a1 = xn1 + coefA[c + 1] * sx1;
            __nv_bfloat16 h0, l0, h1, l1;
            bfsplit(a0, h0, l0);
            bfsplit(a1, h1, l1);
            __nv_bfloat16* p = arow + (size_t)s * ASLOT;
            *(__nv_bfloat162*)(p) = __nv_bfloat162(h0, h1);
            *(__nv_bfloat162*)(p + HID) = __nv_bfloat162(l0, l1);
        }
        size_t gi = (size_t)t * HID + c;
        *(float2*)(xw + gi)  = make_float2(xn0 + cw[c] * sx0, xn1 + cw[c + 1] * sx1);
        *(float2*)(xa + gi)  = make_float2(xn0 + ca[c] * sx0, xn1 + ca[c + 1] * sx1);
        *(float2*)(xvf + gi) = make_float2(xn0 + cv[c] * sx0, xn1 + cv[c + 1] * sx1);
        if (state1_out && t == T_LEN - 1) {
            state1_out[c] = xn0;
            state1_out[c + 1] = xn1;
        }
    }
}

// ---------------- batched LoRA down ----------------
__global__ void __launch_bounds__(256) lora_down_kernel(
    const float* __restrict__ Aa, const float* __restrict__ Aw, const float* __restrict__ Av,
    const float* __restrict__ Ba, const float* __restrict__ Bw, const float* __restrict__ Bv,
    float* __restrict__ hbuf)
{
    int z = blockIdx.z;
    const float* A = z == 0 ? Aa : z == 1 ? Aw : Av;
    const float* B = z == 0 ? Ba : z == 1 ? Bw : Bv;
    int N = (z == 2) ? 64 : 96;
    int zoff = z * 96;
    const int K = HID;

    __shared__ float As[16][64 + 1];
    __shared__ float Bs[16][64 + 1];
    int tid = threadIdx.x;
    int tx = tid & 15, ty = tid >> 4;
    int row0 = blockIdx.y * 64, col0 = blockIdx.x * 64;
    if (col0 >= N) return;
    float acc[4][4] = {};
    for (int k0 = 0; k0 < K; k0 += 16) {
#pragma unroll
        for (int i = tid; i < 64 * 16; i += 256) {
            int r = i >> 4, c = i & 15;
            As[c][r] = A[(size_t)(row0 + r) * K + k0 + c];
        }
#pragma unroll
        for (int i = tid; i < 16 * 64; i += 256) {
            int r = i >> 6, c = i & 63;
            int gc = col0 + c;
            Bs[r][c] = (gc < N) ? B[(size_t)(k0 + r) * N + gc] : 0.f;
        }
        __syncthreads();
#pragma unroll
        for (int kk = 0; kk < 16; kk++) {
            float a[4], b[4];
#pragma unroll
            for (int i = 0; i < 4; i++) a[i] = As[kk][ty * 4 + i];
#pragma unroll
            for (int jj = 0; jj < 4; jj++) b[jj] = Bs[kk][tx * 4 + jj];
#pragma unroll
            for (int i = 0; i < 4; i++)
#pragma unroll
                for (int jj = 0; jj < 4; jj++) acc[i][jj] = fmaf(a[i], b[jj], acc[i][jj]);
        }
        __syncthreads();
    }
#pragma unroll
    for (int i = 0; i < 4; i++) {
        int gr = row0 + ty * 4 + i;
#pragma unroll
        for (int jj = 0; jj < 4; jj++) {
            int gc = col0 + tx * 4 + jj;
            if (gc < N) {
                float v = acc[i][jj];
                if (z == 1) v = tanhf(v);
                hbuf[(size_t)gr * 256 + zoff + gc] = v;
            }
        }
    }
}

// ---------------- batched LoRA up + fused activations ----------------
__global__ void __launch_bounds__(256) lora_up_kernel(
    const float* __restrict__ hbuf,
    const float* __restrict__ Ba, const float* __restrict__ Bw, const float* __restrict__ Bv,
    const float* __restrict__ a0, const float* __restrict__ w0, const float* __restrict__ v0b,
    const float* __restrict__ vf,
    float* __restrict__ outA, float* __restrict__ outW, float* __restrict__ outV)
{
    int z = blockIdx.z;
    const float* B = z == 0 ? Ba : z == 1 ? Bw : Bv;
    const float* bias = z == 0 ? a0 : z == 1 ? w0 : v0b;
    int K = (z == 2) ? 64 : 96;
    int zoff = z * 96;
    const int N = HID;

    __shared__ float As[16][64 + 1];
    __shared__ float Bs[16][64 + 1];
    int tid = threadIdx.x;
    int tx = tid & 15, ty = tid >> 4;
    int row0 = blockIdx.y * 64, col0 = blockIdx.x * 64;
    float acc[4][4] = {};
    for (int k0 = 0; k0 < K; k0 += 16) {
#pragma unroll
        for (int i = tid; i < 64 * 16; i += 256) {
            int r = i >> 4, c = i & 15;
            As[c][r] = hbuf[(size_t)(row0 + r) * 256 + zoff + k0 + c];
        }
#pragma unroll
        for (int i = tid; i < 16 * 64; i += 256) {
            int r = i >> 6, c = i & 63;
            Bs[r][c] = B[(size_t)(k0 + r) * N + col0 + c];
        }
        __syncthreads();
#pragma unroll
        for (int kk = 0; kk < 16; kk++) {
            float a[4], b[4];
#pragma unroll
            for (int i = 0; i < 4; i++) a[i] = As[kk][ty * 4 + i];
#pragma unroll
            for (int jj = 0; jj < 4; jj++) b[jj] = Bs[kk][tx * 4 + jj];
#pragma unroll
            for (int i = 0; i < 4; i++)
#pragma unroll
                for (int jj = 0; jj < 4; jj++) acc[i][jj] = fmaf(a[i], b[jj], acc[i][jj]);
        }
        __syncthreads();
    }
#pragma unroll
    for (int i = 0; i < 4; i++) {
        int gr = row0 + ty * 4 + i;
#pragma unroll
        for (int jj = 0; jj < 4; jj++) {
            int gc = col0 + tx * 4 + jj;
            size_t idx = (size_t)gr * N + gc;
            float s = sigmoidf(bias[gc] + acc[i][jj]);
            if (z == 0) outA[idx] = s;
            else if (z == 1) outW[idx] = __expf(-0.606531f * s);
            else {
                float vv = outV[idx];
                outV[idx] = vv + (vf[idx] - vv) * s;
            }
        }
    }
}

// ---------------- prep: kk normalize, k2, pack scan operands ----------------
__global__ void __launch_bounds__(256) prep_kernel(
    const float* __restrict__ k, const float* __restrict__ a,
    const float* __restrict__ w, const float* __restrict__ v,
    const float* __restrict__ r,
    const float* __restrict__ k_k, const float* __restrict__ k_a,
    float* __restrict__ k2out, float* __restrict__ pscan)
{
    int gw = (blockIdx.x * 256 + threadIdx.x) >> 5;
    int lane = threadIdx.x & 31;
    if (gw >= T_LEN * NHEAD) return;
    int t = gw >> 5, h = gw & 31;
    int base = t * HID + h * HEADD;
    int cb = h * HEADD;

    float k0v = k[base + lane], k1v = k[base + lane + 32];
    float q0 = k0v * k_k[cb + lane], q1 = k1v * k_k[cb + lane + 32];
    float ss = warp_sum(q0 * q0 + q1 * q1);
    float inv = 1.f / fmaxf(sqrtf(ss), 1e-12f);
    float kk0 = q0 * inv, kk1 = q1 * inv;

    float a0v = a[base + lane], a1v = a[base + lane + 32];
    float k20 = k0v * (1.f + (a0v - 1.f) * k_a[cb + lane]);
    float k21 = k1v * (1.f + (a1v - 1.f) * k_a[cb + lane + 32]);
    k2out[base + lane] = k20;
    k2out[base + lane + 32] = k21;

    size_t pb = ((size_t)(t * NHEAD + h) * HEADD + lane) * 8;
    *(float4*)(pscan + pb)     = make_float4(w[base + lane], kk0, kk0 * a0v, k20);
    *(float4*)(pscan + pb + 4) = make_float4(v[base + lane], r[base + lane], 0.f, 0.f);

    size_t pb2 = pb + 32 * 8;
    *(float4*)(pscan + pb2)     = make_float4(w[base + lane + 32], kk1, kk1 * a1v, k21);
    *(float4*)(pscan + pb2 + 4) = make_float4(v[base + lane + 32], r[base + lane + 32], 0.f, 0.f);
}

// ---------------- scan v2: 128 CTAs (head x quarter), float4 state/thread ----------------
struct ScanBuf { float a[6][64]; };

__global__ void __launch_bounds__(256) scan2_kernel(
    const float* __restrict__ pscan,
    const float* __restrict__ state2, float* __restrict__ ybuf,
    float* __restrict__ Sout)
{
    int h = blockIdx.x >> 2;
    int q = blockIdx.x & 3;
    int tid = threadIdx.x;
    int wrp = tid >> 5, lane = tid & 31;
    int rsel = lane >> 4, colg = lane & 15;
    int row = q * 16 + 2 * wrp + rsel;   // row within head, 0..63

    float4 S = *(const float4*)(state2 + (size_t)h * 4096 + row * 64 + colg * 4);

    __shared__ ScanBuf buf[2];

    const float* pb_base = pscan + (size_t)h * 512;
    const size_t tstride = (size_t)NHEAD * 512;

    int f = tid & 3, i4 = tid >> 2;
    float2 pre = *(const float2*)(pb_base + (size_t)tid * 2);

    for (int t = 0; t < T_LEN; t++) {
        ScanBuf& b = buf[t & 1];
        if (f == 0)      { b.a[0][i4] = pre.x; b.a[1][i4] = pre.y; }
        else if (f == 1) { b.a[2][i4] = pre.x; b.a[3][i4] = pre.y; }
        else if (f == 2) { b.a[4][i4] = pre.x; b.a[5][i4] = pre.y; }
        __syncthreads();

        if (t + 1 < T_LEN)
            pre = *(const float2*)(pb_base + (size_t)(t + 1) * tstride + tid * 2);

        float4 w4  = *(const float4*)&b.a[0][colg * 4];
        float4 kk4 = *(const float4*)&b.a[1][colg * 4];
        float4 ka4 = *(const float4*)&b.a[2][colg * 4];
        float4 k4  = *(const float4*)&b.a[3][colg * 4];
        float4 r4  = *(const float4*)&b.a[5][colg * 4];
        float vi   = b.a[4][row];

        float p = S.x * kk4.x + S.y * kk4.y + S.z * kk4.z + S.w * kk4.w;
        p += __shfl_xor_sync(0xffffffffu, p, 1);
        p += __shfl_xor_sync(0xffffffffu, p, 2);
        p += __shfl_xor_sync(0xffffffffu, p, 4);
        p += __shfl_xor_sync(0xffffffffu, p, 8);

        S.x = S.x * w4.x - p * ka4.x + vi * k4.x;
        S.y = S.y * w4.y - p * ka4.y + vi * k4.y;
        S.z = S.z * w4.z - p * ka4.z + vi * k4.z;
        S.w = S.w * w4.w - p * ka4.w + vi * k4.w;

        float y = S.x * r4.x + S.y * r4.y + S.z * r4.z + S.w * r4.w;
        y += __shfl_xor_sync(0xffffffffu, y, 1);
        y += __shfl_xor_sync(0xffffffffu, y, 2);
        y += __shfl_xor_sync(0xffffffffu, y, 4);
        y += __shfl_xor_sync(0xffffffffu, y, 8);
        if (colg == 0) ybuf[(size_t)t * HID + h * HEADD + row] = y;
    }
    *(float4*)(Sout + (size_t)h * 4096 + row * 64 + colg * 4) = S;
}

// ---------------- groupnorm + rkv + gate -> directly split into abuf slot 0 ----------------
__global__ void __launch_bounds__(256) post_kernel(
    const float* __restrict__ y, const float* __restrict__ r,
    const float* __restrict__ k2, const float* __restrict__ v,
    const float* __restrict__ g, const float* __restrict__ r_k,
    const float* __restrict__ lnxw, const float* __restrict__ lnxb,
    __nv_bfloat16* __restrict__ zsplit)
{
    int gw = (blockIdx.x * 256 + threadIdx.x) >> 5;
    int lane = threadIdx.x & 31;
    if (gw >= T_LEN * NHEAD) return;
    int t = gw >> 5, h = gw & 31;
    int base = t * HID + h * HEADD;
    int cb = h * HEADD;

    float y0 = y[base + lane], y1 = y[base + lane + 32];
    float mu = warp_sum(y0 + y1) * (1.f / HEADD);
    float d0 = y0 - mu, d1 = y1 - mu;
    float var = warp_sum(d0 * d0 + d1 * d1) * (1.f / HEADD);
    float inv = rsqrtf(var + 0.00064f);

    float rs = warp_sum(r[base + lane] * k2[base + lane] * r_k[cb + lane] +
                        r[base + lane + 32] * k2[base + lane + 32] * r_k[cb + lane + 32]);

    float z0 = (d0 * inv * lnxw[cb + lane] + lnxb[cb + lane] + rs * v[base + lane]) * g[base + lane];
    float z1 = (d1 * inv * lnxw[cb + lane + 32] + lnxb[cb + lane + 32] + rs * v[base + lane + 32]) * g[base + lane + 32];

    size_t zb = (size_t)t * 2 * HID;
    __nv_bfloat16 h0, l0, h1, l1;
    bfsplit(z0, h0, l0);
    bfsplit(z1, h1, l1);
    zsplit[zb + cb + lane] = h0;
    zsplit[zb + HID + cb + lane] = l0;
    zsplit[zb + cb + lane + 32] = h1;
    zsplit[zb + HID + cb + lane + 32] = l1;
}

__global__ void __launch_bounds__(256) copy_kernel(const float* __restrict__ src,
                                                   float* __restrict__ dst, int n)
{
    int i = blockIdx.x * 256 + threadIdx.x;
    if (i < n) dst[i] = src[i];
}

// ---------------- host launcher ----------------
extern "C" void kernel_launch(void* const* d_in, const int* in_sizes, int n_in,
                              void* d_out, int out_size)
{
    const float* x       = (const float*)d_in[0];
    const float* state1  = (const float*)d_in[1];
    const float* state2  = (const float*)d_in[2];
    const float* v_first = (const float*)d_in[3];
    const float* ln1_w   = (const float*)d_in[4];
    const float* ln1_b   = (const float*)d_in[5];
    const float* x_r     = (const float*)d_in[6];
    const float* x_w     = (const float*)d_in[7];
    const float* x_k     = (const float*)d_in[8];
    const float* x_v     = (const float*)d_in[9];
    const float* x_a     = (const float*)d_in[10];
    const float* x_g     = (const float*)d_in[11];
    const float* Wr      = (const float*)d_in[12];
    const float* Wk      = (const float*)d_in[13];
    const float* Wv      = (const float*)d_in[14];
    const float* Wo      = (const float*)d_in[15];
    const float* w0      = (const float*)d_in[16];
    const float* w1      = (const float*)d_in[17];
    const float* w2      = (const float*)d_in[18];
    const float* a0      = (const float*)d_in[19];
    const float* a1      = (const float*)d_in[20];
    const float* a2      = (const float*)d_in[21];
    const float* v0      = (const float*)d_in[22];
    const float* v1      = (const float*)d_in[23];
    const float* v2      = (const float*)d_in[24];
    const float* g1      = (const float*)d_in[25];
    const float* g2      = (const float*)d_in[26];
    const float* k_k     = (const float*)d_in[27];
    const float* k_a     = (const float*)d_in[28];
    const float* r_k     = (const float*)d_in[29];
    const float* ln_x_w  = (const float*)d_in[30];
    const float* ln_x_b  = (const float*)d_in[31];

    float* sc = nullptr;        cudaGetSymbolAddress((void**)&sc, g_scratch);
    float* hbuf = nullptr;      cudaGetSymbolAddress((void**)&hbuf, g_hbuf);
    float* pscan = nullptr;     cudaGetSymbolAddress((void**)&pscan, g_pscan);
    __nv_bfloat16* abuf = nullptr;  cudaGetSymbolAddress((void**)&abuf, g_abuf);
    __nv_bfloat16* wbuf = nullptr;  cudaGetSymbolAddress((void**)&wbuf, g_wbuf);
    __nv_bfloat16* g1buf = nullptr; cudaGetSymbolAddress((void**)&g1buf, g_g1buf);
    __nv_bfloat16* g2buf = nullptr; cudaGetSymbolAddress((void**)&g2buf, g_g2buf);
    __nv_bfloat16* ghbuf = nullptr; cudaGetSymbolAddress((void**)&ghbuf, g_ghbuf);

#define SLOT(s) (sc + (size_t)(s) * NTOK_EL)

    float* out = (float*)d_out;
    const int OFF_OUT = 0;
    const int OFF_S1  = NTOK_EL;
    const int OFF_S2  = OFF_S1 + HID;
    const int OFF_VF  = OFF_S2 + NHEAD * HEADD * HEADD;
    const int TOTAL   = OFF_VF + NTOK_EL;
    bool full = (out_size >= TOTAL);

    float* s1_out = full ? out + OFF_S1 : nullptr;
    float* s2_out = full ? out + OFF_S2 : SLOT(S_TMP);

    const int EW_GRID = (NTOK_EL + 255) / 256;

    // weight splits
    splitW4_kernel<<<dim3(64, 64, 4), 1024>>>(Wr, Wk, Wv, Wo, wbuf);
    splitW_kernel<<<dim3(8, 64), 1024>>>(g1, g1buf, HID, 256);
    splitW_kernel<<<dim3(64, 8), 1024>>>(g2, g2buf, 256, HID);

    // fused LN + mix + split
    ln_mix_kernel<<<T_LEN, 256>>>(x, state1, ln1_w, ln1_b,
                                  x_r, x_w, x_k, x_v, x_a, x_g,
                                  abuf, SLOT(S_XW), SLOT(S_XA), SLOT(S_XV), s1_out);

    // batched projections: r, k, v, g-down (sigmoid fused)
    {
        MMJobs jobs;
        jobs.j[0] = { wbuf,             SLOT(S_R),   nullptr, HID, 0 };
        jobs.j[1] = { wbuf + WSLOT,     SLOT(S_K),   nullptr, HID, 0 };
        jobs.j[2] = { wbuf + 2 * WSLOT, SLOT(S_V),   nullptr, HID, 0 };
        jobs.j[3] = { g1buf,            SLOT(S_TMP), nullptr, 256, 2 };
        mm128_kernel<<<dim3(16, 8, 4), 256>>>(abuf, ASLOT, jobs, T_LEN, HID);
    }

    // g-up: split sigmoid output, then @g2
    splitA_kernel<<<(T_LEN * 256 + 255) / 256, 256>>>(SLOT(S_TMP), ghbuf, T_LEN, 256);
    {
        MMJobs jobs;
        jobs.j[0] = { g2buf, SLOT(S_G), nullptr, HID, 0 };
        jobs.j[1] = jobs.j[0]; jobs.j[2] = jobs.j[0]; jobs.j[3] = jobs.j[0];
        mm128_kernel<<<dim3(16, 8, 1), 256>>>(ghbuf, 0, jobs, T_LEN, 256);
    }

    // LoRA chains (a, w, v)
    lora_down_kernel<<<dim3(2, 16, 3), 256>>>(SLOT(S_XA), SLOT(S_XW), SLOT(S_XV),
                                              a1, w1, v1, hbuf);
    lora_up_kernel<<<dim3(32, 16, 3), 256>>>(hbuf, a2, w2, v2, a0, w0, v0, v_first,
                                             SLOT(S_A), SLOT(S_W), SLOT(S_V));

    // prep
    prep_kernel<<<(T_LEN * NHEAD * 32 + 255) / 256, 256>>>(
        SLOT(S_K), SLOT(S_A), SLOT(S_W), SLOT(S_V), SLOT(S_R),
        k_k, k_a, SLOT(S_K2), pscan);

    // scan v2
    scan2_kernel<<<128, 256>>>(pscan, state2, SLOT(S_Y), s2_out);

    // groupnorm + rkv + gate -> split directly into abuf slot 0
    post_kernel<<<(T_LEN * NHEAD * 32 + 255) / 256, 256>>>(
        SLOT(S_Y), SLOT(S_R), SLOT(S_K2), SLOT(S_V), SLOT(S_G),
        r_k, ln_x_w, ln_x_b, abuf);

    // out = x + z@Wo
    {
        MMJobs jobs;
        jobs.j[0] = { wbuf + 3 * WSLOT, out + OFF_OUT, x, HID, 1 };
        jobs.j[1] = jobs.j[0]; jobs.j[2] = jobs.j[0]; jobs.j[3] = jobs.j[0];
        mm128_kernel<<<dim3(16, 8, 1), 256>>>(abuf, 0, jobs, T_LEN, HID);
    }

    // passthrough v_first
    if (full)
        copy_kernel<<<EW_GRID, 256>>>(v_first, out + OFF_VF, NTOK_EL);
}

// round 6
// speedup vs baseline: 3.2797x; 1.2451x over previous
#include <cuda_runtime.h>
#include <cuda_fp16.h>
#include <math.h>
#include <stdint.h>

#define T_LEN 1024
#define HID   2048
#define NHEAD 32
#define HEADD 64
#define NTOK_EL (T_LEN * HID)   // 2097152

#define ASLOT_H ((size_t)T_LEN * 2 * HID)   // A' slot: [M, 2K] fp16 {hi|lo}
#define WSLOT_H ((size_t)HID * HID)         // W' slot: [N, K] fp16 single plane

// ---------------- static device scratch ----------------
__device__ float g_scratch[12u * (unsigned)NTOK_EL];
__device__ float g_hbuf[T_LEN * 256];
__device__ float g_pscan[(size_t)T_LEN * NHEAD * HEADD * 8];
__device__ float g_ypart[(size_t)T_LEN * HID * 4];
__device__ __align__(256) __half g_abuf[4 * ASLOT_H];        // xr',xk',xv',xg'
__device__ __align__(256) __half g_wbuf[4 * WSLOT_H];        // Wr',Wk',Wv',Wo'
__device__ __align__(256) __half g_g1buf[(size_t)256 * HID];
__device__ __align__(256) __half g_g2buf[(size_t)HID * 256];
__device__ __align__(256) __half g_ghbuf[(size_t)T_LEN * 2 * 256];

#define S_XW  0
#define S_XA  1
#define S_XV  2
#define S_R   3
#define S_K   4
#define S_V   5
#define S_K2  6
#define S_G   7
#define S_A   8
#define S_W   9
#define S_TMP 10
#define S_Y   11

// ---------------- helpers ----------------
__device__ __forceinline__ float blk_sum256(float v) {
    __shared__ float sh[8];
    int tid = threadIdx.x;
#pragma unroll
    for (int o = 16; o; o >>= 1) v += __shfl_xor_sync(0xffffffffu, v, o);
    if ((tid & 31) == 0) sh[tid >> 5] = v;
    __syncthreads();
    if (tid == 0) {
        float s = 0.f;
#pragma unroll
        for (int i = 0; i < 8; i++) s += sh[i];
        sh[0] = s;
    }
    __syncthreads();
    float r = sh[0];
    __syncthreads();
    return r;
}

__device__ __forceinline__ float warp_sum(float v) {
#pragma unroll
    for (int o = 16; o; o >>= 1) v += __shfl_xor_sync(0xffffffffu, v, o);
    return v;
}

__device__ __forceinline__ float sigmoidf(float v) {
    return 1.f / (1.f + __expf(-v));
}

__device__ __forceinline__ uint32_t smem_u32(const void* p) {
    uint32_t a;
    asm("{ .reg .u64 t; cvta.to.shared.u64 t, %1; cvt.u32.u64 %0, t; }" : "=r"(a) : "l"(p));
    return a;
}

__device__ __forceinline__ void hsplit(float v, __half& hi, __half& lo) {
    hi = __float2half_rn(v);
    lo = __float2half_rn(v - __half2float(hi));
}

// ======================= mma.sync fp16 GEMM (2-term A split) =======================
// A: [M, 2K] fp16 {hi|lo}; B: [N, K] fp16. D = (Ah+Al) @ B^T, fp32 accum.
// 128x128 tile, chunk = 32 K; stage = {Ah,Al,B} tiles; 3 stages, 1 sync/chunk.
#define MMK_STRIDE 80
#define MMK_TILE   (128 * MMK_STRIDE)     // 10240
#define STAGE_BYTES (3 * MMK_TILE)        // 30720
#define MM_SMEM (3 * STAGE_BYTES)         // 92160

struct MMJob { const __half* B; float* C; const float* Res; int N; int mode; };
struct MMJobs { MMJob j[4]; };

__device__ __forceinline__ void cp16(uint32_t dst, const void* src) {
    asm volatile("cp.async.cg.shared.global [%0], [%1], 16;" :: "r"(dst), "l"(src));
}

__device__ __forceinline__ void ldsm4(uint32_t* r, uint32_t a) {
    asm volatile("ldmatrix.sync.aligned.m8n8.x4.shared.b16 {%0,%1,%2,%3}, [%4];"
                 : "=r"(r[0]), "=r"(r[1]), "=r"(r[2]), "=r"(r[3]) : "r"(a));
}

__device__ __forceinline__ void mma16816(float* c, const uint32_t* a, const uint32_t* b) {
    asm volatile(
        "mma.sync.aligned.m16n8k16.row.col.f32.f16.f16.f32 "
        "{%0,%1,%2,%3}, {%4,%5,%6,%7}, {%8,%9}, {%0,%1,%2,%3};"
        : "+f"(c[0]), "+f"(c[1]), "+f"(c[2]), "+f"(c[3])
        : "r"(a[0]), "r"(a[1]), "r"(a[2]), "r"(a[3]), "r"(b[0]), "r"(b[1]));
}

__global__ void __launch_bounds__(256, 2) mm128_kernel(
    const __half* __restrict__ A, size_t aStride,
    MMJobs jobs, int M, int K)
{
    extern __shared__ __align__(16) char smem[];
    uint32_t sbase = smem_u32(smem);

    const MMJob job = jobs.j[blockIdx.z];
    const int N = job.N;
    int n0 = blockIdx.x * 128;
    if (n0 >= N) return;
    int m0 = blockIdx.y * 128;

    const __half* Ab = A + blockIdx.z * aStride;
    const __half* Bb = job.B;
    const int K2 = 2 * K;
    const int nk = K >> 5;

    int tid = threadIdx.x;
    int wid = tid >> 5, lane = tid & 31;
    int g = lane >> 2, tig = lane & 3;
    int warp_m = wid >> 2;
    int warp_n = wid & 3;

    float acc[4][4][4];
#pragma unroll
    for (int i = 0; i < 4; i++)
#pragma unroll
        for (int j = 0; j < 4; j++)
#pragma unroll
            for (int q = 0; q < 4; q++) acc[i][j][q] = 0.f;

    auto load_stage = [&](int s, int kc) {
        uint32_t st = sbase + s * STAGE_BYTES;
        int k0 = kc << 5;
#pragma unroll
        for (int it = 0; it < 2; it++) {       // Ah
            int idx = tid + it * 256;
            int r = idx >> 2, c = idx & 3;
            cp16(st + r * MMK_STRIDE + c * 16, Ab + ((size_t)(m0 + r) * K2 + k0 + c * 8));
        }
#pragma unroll
        for (int it = 0; it < 2; it++) {       // Al
            int idx = tid + it * 256;
            int r = idx >> 2, c = idx & 3;
            cp16(st + MMK_TILE + r * MMK_STRIDE + c * 16,
                 Ab + ((size_t)(m0 + r) * K2 + K + k0 + c * 8));
        }
#pragma unroll
        for (int it = 0; it < 2; it++) {       // B
            int idx = tid + it * 256;
            int r = idx >> 2, c = idx & 3;
            cp16(st + 2 * MMK_TILE + r * MMK_STRIDE + c * 16,
                 Bb + ((size_t)(n0 + r) * K + k0 + c * 8));
        }
        asm volatile("cp.async.commit_group;" ::: "memory");
    };

    load_stage(0, 0);
    if (nk > 1) load_stage(1, 1);
    else asm volatile("cp.async.commit_group;" ::: "memory");  // keep group count consistent

    int aRowSel = (lane & 15);
    int aColSel = (lane & 16) ? 16 : 0;
    int bRowSel = ((lane & 16) ? 8 : 0) + (lane & 7);
    int bColSel = (lane & 8) ? 16 : 0;

    for (int kc = 0; kc < nk; kc++) {
        asm volatile("cp.async.wait_group 1;" ::: "memory");
        __syncthreads();
        if (kc + 2 < nk) load_stage((kc + 2) % 3, kc + 2);
        else asm volatile("cp.async.commit_group;" ::: "memory");

        uint32_t st = sbase + (kc % 3) * STAGE_BYTES;
#pragma unroll
        for (int ks = 0; ks < 2; ks++) {
            uint32_t afr[4][4], bfr[2][4];
#pragma unroll
            for (int ap = 0; ap < 2; ap++) {
                uint32_t addr = st + 2 * MMK_TILE
                                + (uint32_t)(warp_n * 32 + ap * 16 + bRowSel) * MMK_STRIDE
                                + ks * 32 + bColSel;
                ldsm4(bfr[ap], addr);
            }
            // hi plane
#pragma unroll
            for (int am = 0; am < 4; am++) {
                uint32_t addr = st + (uint32_t)(warp_m * 64 + am * 16 + aRowSel) * MMK_STRIDE
                                + ks * 32 + aColSel;
                ldsm4(afr[am], addr);
            }
#pragma unroll
            for (int am = 0; am < 4; am++) {
                mma16816(acc[am][0], afr[am], &bfr[0][0]);
                mma16816(acc[am][1], afr[am], &bfr[0][2]);
                mma16816(acc[am][2], afr[am], &bfr[1][0]);
                mma16816(acc[am][3], afr[am], &bfr[1][2]);
            }
            // lo plane (reuse afr regs)
#pragma unroll
            for (int am = 0; am < 4; am++) {
                uint32_t addr = st + MMK_TILE
                                + (uint32_t)(warp_m * 64 + am * 16 + aRowSel) * MMK_STRIDE
                                + ks * 32 + aColSel;
                ldsm4(afr[am], addr);
            }
#pragma unroll
            for (int am = 0; am < 4; am++) {
                mma16816(acc[am][0], afr[am], &bfr[0][0]);
                mma16816(acc[am][1], afr[am], &bfr[0][2]);
                mma16816(acc[am][2], afr[am], &bfr[1][0]);
                mma16816(acc[am][3], afr[am], &bfr[1][2]);
            }
        }
    }

    __syncthreads();

    float* C = job.C;
    const float* Res = job.Res;
    int mode = job.mode;
#pragma unroll
    for (int am = 0; am < 4; am++) {
#pragma unroll
        for (int an = 0; an < 4; an++) {
            int row = m0 + warp_m * 64 + am * 16 + g;
            int col = n0 + warp_n * 32 + an * 8 + tig * 2;
            float2 v0 = make_float2(acc[am][an][0], acc[am][an][1]);
            float2 v1 = make_float2(acc[am][an][2], acc[am][an][3]);
            if (mode == 1) {
                const float2 r0 = *(const float2*)(Res + (size_t)row * N + col);
                const float2 r1 = *(const float2*)(Res + (size_t)(row + 8) * N + col);
                v0.x += r0.x; v0.y += r0.y;
                v1.x += r1.x; v1.y += r1.y;
            } else if (mode == 2) {
                v0.x = sigmoidf(v0.x); v0.y = sigmoidf(v0.y);
                v1.x = sigmoidf(v1.x); v1.y = sigmoidf(v1.y);
            }
            *(float2*)(C + (size_t)row * N + col) = v0;
            *(float2*)(C + (size_t)(row + 8) * N + col) = v1;
        }
    }
}

// ---------------- fp16 split of activations: [M,K] fp32 -> [M,2K] {h|l} ----------------
__global__ void __launch_bounds__(256) splitA_kernel(
    const float* __restrict__ A, __half* __restrict__ out, int M, int K)
{
    int i = blockIdx.x * 256 + threadIdx.x;
    if (i >= M * K) return;
    int m = i / K, k = i - m * K;
    __half hi, lo;
    hsplit(A[i], hi, lo);
    size_t base = (size_t)m * 2 * K;
    out[base + k] = hi;
    out[base + K + k] = lo;
}

// ---------------- W [K,N] fp32 -> transposed fp16 [N,K] single plane ----------------
__global__ void __launch_bounds__(1024) splitW_kernel(
    const float* __restrict__ W, __half* __restrict__ out, int K, int N)
{
    __shared__ float tile[32][33];
    int k0 = blockIdx.y * 32, n0 = blockIdx.x * 32;
    int tx = threadIdx.x & 31, ty = threadIdx.x >> 5;
    tile[ty][tx] = W[(size_t)(k0 + ty) * N + n0 + tx];
    __syncthreads();
    int tid = threadIdx.x;
    if (tid >= 512) return;
    int nl = tid >> 4, kp = (tid & 15) * 2;
    __half2 h = __floats2half2_rn(tile[kp][nl], tile[kp + 1][nl]);
    *(__half2*)(out + (size_t)(n0 + nl) * K + k0 + kp) = h;
}

// batched for the 4 big 2048x2048 weights
__global__ void __launch_bounds__(1024) splitW4_kernel(
    const float* __restrict__ W0, const float* __restrict__ W1,
    const float* __restrict__ W2, const float* __restrict__ W3,
    __half* __restrict__ out)
{
    const float* W = blockIdx.z == 0 ? W0 : blockIdx.z == 1 ? W1 : blockIdx.z == 2 ? W2 : W3;
    __half* o = out + blockIdx.z * WSLOT_H;
    __shared__ float tile[32][33];
    int k0 = blockIdx.y * 32, n0 = blockIdx.x * 32;
    int tx = threadIdx.x & 31, ty = threadIdx.x >> 5;
    tile[ty][tx] = W[(size_t)(k0 + ty) * HID + n0 + tx];
    __syncthreads();
    int tid = threadIdx.x;
    if (tid >= 512) return;
    int nl = tid >> 4, kp = (tid & 15) * 2;
    __half2 h = __floats2half2_rn(tile[kp][nl], tile[kp + 1][nl]);
    *(__half2*)(o + (size_t)(n0 + nl) * HID + k0 + kp) = h;
}

// ---------------- fused LN + token-shift mix + fp16 split ----------------
__global__ void __launch_bounds__(256) ln_mix_kernel(
    const float* __restrict__ x, const float* __restrict__ state1,
    const float* __restrict__ lnw, const float* __restrict__ lnb,
    const float* __restrict__ cr, const float* __restrict__ cw,
    const float* __restrict__ ck, const float* __restrict__ cv,
    const float* __restrict__ ca, const float* __restrict__ cg,
    __half* __restrict__ abuf,
    float* __restrict__ xw, float* __restrict__ xa, float* __restrict__ xvf,
    float* __restrict__ state1_out)
{
    int t = blockIdx.x;
    const float* xt = x + (size_t)t * HID;
    const float* xp = x + (size_t)(t - 1) * HID;

    float2 v0[4], v1[4];
    float s0 = 0.f, s1 = 0.f;
#pragma unroll
    for (int j = 0; j < 4; j++) {
        int c = threadIdx.x * 2 + j * 512;
        v0[j] = *(const float2*)(xt + c);
        s0 += v0[j].x + v0[j].y;
        v1[j] = t ? *(const float2*)(xp + c) : make_float2(0.f, 0.f);
        s1 += v1[j].x + v1[j].y;
    }
    float mu0 = blk_sum256(s0) * (1.f / HID);
    float mu1 = blk_sum256(s1) * (1.f / HID);
    float q0 = 0.f, q1 = 0.f;
#pragma unroll
    for (int j = 0; j < 4; j++) {
        float d;
        d = v0[j].x - mu0; q0 += d * d;
        d = v0[j].y - mu0; q0 += d * d;
        d = v1[j].x - mu1; q1 += d * d;
        d = v1[j].y - mu1; q1 += d * d;
    }
    float inv0 = rsqrtf(blk_sum256(q0) * (1.f / HID) + 1e-5f);
    float inv1 = rsqrtf(blk_sum256(q1) * (1.f / HID) + 1e-5f);

#pragma unroll
    for (int j = 0; j < 4; j++) {
        int c = threadIdx.x * 2 + j * 512;
        float2 wv = *(const float2*)(lnw + c);
        float2 bv = *(const float2*)(lnb + c);
        float xn0 = (v0[j].x - mu0) * inv0 * wv.x + bv.x;
        float xn1 = (v0[j].y - mu0) * inv0 * wv.y + bv.y;
        float pv0 = t ? (v1[j].x - mu1) * inv1 * wv.x + bv.x : state1[c];
        float pv1 = t ? (v1[j].y - mu1) * inv1 * wv.y + bv.y : state1[c + 1];
        float sx0 = pv0 - xn0, sx1 = pv1 - xn1;

        __half* arow = abuf + (size_t)t * 2 * HID + c;
#pragma unroll
        for (int s = 0; s < 4; s++) {
            const float* coefA = (s == 0) ? cr : (s == 1) ? ck : (s == 2) ? cv : cg;
            float a0 = xn0 + coefA[c] * sx0;
            float a1 = xn1 + coefA[c + 1] * sx1;
            __half h0, l0, h1, l1;
            hsplit(a0, h0, l0);
            hsplit(a1, h1, l1);
            __half* p = arow + (size_t)s * ASLOT_H;
            *(__half2*)(p) = __half2(h0, h1);
            *(__half2*)(p + HID) = __half2(l0, l1);
        }
        size_t gi = (size_t)t * HID + c;
        *(float2*)(xw + gi)  = make_float2(xn0 + cw[c] * sx0, xn1 + cw[c + 1] * sx1);
        *(float2*)(xa + gi)  = make_float2(xn0 + ca[c] * sx0, xn1 + ca[c + 1] * sx1);
        *(float2*)(xvf + gi) = make_float2(xn0 + cv[c] * sx0, xn1 + cv[c + 1] * sx1);
        if (state1_out && t == T_LEN - 1) {
            state1_out[c] = xn0;
            state1_out[c + 1] = xn1;
        }
    }
}

// ---------------- batched LoRA down (fp32 SIMT) ----------------
__global__ void __launch_bounds__(256) lora_down_kernel(
    const float* __restrict__ Aa, const float* __restrict__ Aw, const float* __restrict__ Av,
    const float* __restrict__ Ba, const float* __restrict__ Bw, const float* __restrict__ Bv,
    float* __restrict__ hbuf)
{
    int z = blockIdx.z;
    const float* A = z == 0 ? Aa : z == 1 ? Aw : Av;
    const float* B = z == 0 ? Ba : z == 1 ? Bw : Bv;
    int N = (z == 2) ? 64 : 96;
    int zoff = z * 96;
    const int K = HID;

    __shared__ float As[16][64 + 1];
    __shared__ float Bs[16][64 + 1];
    int tid = threadIdx.x;
    int tx = tid & 15, ty = tid >> 4;
    int row0 = blockIdx.y * 64, col0 = blockIdx.x * 64;
    if (col0 >= N) return;
    float acc[4][4] = {};
    for (int k0 = 0; k0 < K; k0 += 16) {
#pragma unroll
        for (int i = tid; i < 64 * 16; i += 256) {
            int r = i >> 4, c = i & 15;
            As[c][r] = A[(size_t)(row0 + r) * K + k0 + c];
        }
#pragma unroll
        for (int i = tid; i < 16 * 64; i += 256) {
            int r = i >> 6, c = i & 63;
            int gc = col0 + c;
            Bs[r][c] = (gc < N) ? B[(size_t)(k0 + r) * N + gc] : 0.f;
        }
        __syncthreads();
#pragma unroll
        for (int kk = 0; kk < 16; kk++) {
            float a[4], b[4];
#pragma unroll
            for (int i = 0; i < 4; i++) a[i] = As[kk][ty * 4 + i];
#pragma unroll
            for (int jj = 0; jj < 4; jj++) b[jj] = Bs[kk][tx * 4 + jj];
#pragma unroll
            for (int i = 0; i < 4; i++)
#pragma unroll
                for (int jj = 0; jj < 4; jj++) acc[i][jj] = fmaf(a[i], b[jj], acc[i][jj]);
        }
        __syncthreads();
    }
#pragma unroll
    for (int i = 0; i < 4; i++) {
        int gr = row0 + ty * 4 + i;
#pragma unroll
        for (int jj = 0; jj < 4; jj++) {
            int gc = col0 + tx * 4 + jj;
            if (gc < N) {
                float v = acc[i][jj];
                if (z == 1) v = tanhf(v);
                hbuf[(size_t)gr * 256 + zoff + gc] = v;
            }
        }
    }
}

// ---------------- batched LoRA up + fused activations ----------------
__global__ void __launch_bounds__(256) lora_up_kernel(
    const float* __restrict__ hbuf,
    const float* __restrict__ Ba, const float* __restrict__ Bw, const float* __restrict__ Bv,
    const float* __restrict__ a0, const float* __restrict__ w0, const float* __restrict__ v0b,
    const float* __restrict__ vf,
    float* __restrict__ outA, float* __restrict__ outW, float* __restrict__ outV)
{
    int z = blockIdx.z;
    const float* B = z == 0 ? Ba : z == 1 ? Bw : Bv;
    const float* bias = z == 0 ? a0 : z == 1 ? w0 : v0b;
    int K = (z == 2) ? 64 : 96;
    int zoff = z * 96;
    const int N = HID;

    __shared__ float As[16][64 + 1];
    __shared__ float Bs[16][64 + 1];
    int tid = threadIdx.x;
    int tx = tid & 15, ty = tid >> 4;
    int row0 = blockIdx.y * 64, col0 = blockIdx.x * 64;
    float acc[4][4] = {};
    for (int k0 = 0; k0 < K; k0 += 16) {
#pragma unroll
        for (int i = tid; i < 64 * 16; i += 256) {
            int r = i >> 4, c = i & 15;
            As[c][r] = hbuf[(size_t)(row0 + r) * 256 + zoff + k0 + c];
        }
#pragma unroll
        for (int i = tid; i < 16 * 64; i += 256) {
            int r = i >> 6, c = i & 63;
            Bs[r][c] = B[(size_t)(k0 + r) * N + col0 + c];
        }
        __syncthreads();
#pragma unroll
        for (int kk = 0; kk < 16; kk++) {
            float a[4], b[4];
#pragma unroll
            for (int i = 0; i < 4; i++) a[i] = As[kk][ty * 4 + i];
#pragma unroll
            for (int jj = 0; jj < 4; jj++) b[jj] = Bs[kk][tx * 4 + jj];
#pragma unroll
            for (int i = 0; i < 4; i++)
#pragma unroll
                for (int jj = 0; jj < 4; jj++) acc[i][jj] = fmaf(a[i], b[jj], acc[i][jj]);
        }
        __syncthreads();
    }
#pragma unroll
    for (int i = 0; i < 4; i++) {
        int gr = row0 + ty * 4 + i;
#pragma unroll
        for (int jj = 0; jj < 4; jj++) {
            int gc = col0 + tx * 4 + jj;
            size_t idx = (size_t)gr * N + gc;
            float s = sigmoidf(bias[gc] + acc[i][jj]);
            if (z == 0) outA[idx] = s;
            else if (z == 1) outW[idx] = __expf(-0.606531f * s);
            else {
                float vv = outV[idx];
                outV[idx] = vv + (vf[idx] - vv) * s;
            }
        }
    }
}

// ---------------- prep: kk normalize, k2, pack scan operands ----------------
__global__ void __launch_bounds__(256) prep_kernel(
    const float* __restrict__ k, const float* __restrict__ a,
    const float* __restrict__ w, const float* __restrict__ v,
    const float* __restrict__ r,
    const float* __restrict__ k_k, const float* __restrict__ k_a,
    float* __restrict__ k2out, float* __restrict__ pscan)
{
    int gw = (blockIdx.x * 256 + threadIdx.x) >> 5;
    int lane = threadIdx.x & 31;
    if (gw >= T_LEN * NHEAD) return;
    int t = gw >> 5, h = gw & 31;
    int base = t * HID + h * HEADD;
    int cb = h * HEADD;

    float k0v = k[base + lane], k1v = k[base + lane + 32];
    float q0 = k0v * k_k[cb + lane], q1 = k1v * k_k[cb + lane + 32];
    float ss = warp_sum(q0 * q0 + q1 * q1);
    float inv = 1.f / fmaxf(sqrtf(ss), 1e-12f);
    float kk0 = q0 * inv, kk1 = q1 * inv;

    float a0v = a[base + lane], a1v = a[base + lane + 32];
    float k20 = k0v * (1.f + (a0v - 1.f) * k_a[cb + lane]);
    float k21 = k1v * (1.f + (a1v - 1.f) * k_a[cb + lane + 32]);
    k2out[base + lane] = k20;
    k2out[base + lane + 32] = k21;

    size_t pb = ((size_t)(t * NHEAD + h) * HEADD + lane) * 8;
    *(float4*)(pscan + pb)     = make_float4(w[base + lane], kk0, kk0 * a0v, k20);
    *(float4*)(pscan + pb + 4) = make_float4(v[base + lane], r[base + lane], 0.f, 0.f);

    size_t pb2 = pb + 32 * 8;
    *(float4*)(pscan + pb2)     = make_float4(w[base + lane + 32], kk1, kk1 * a1v, k21);
    *(float4*)(pscan + pb2 + 4) = make_float4(v[base + lane + 32], r[base + lane + 32], 0.f, 0.f);
}

// ---------------- scan v2.1: depth-2 prefetch, deferred 4-wide y partials ----------------
struct ScanBuf { float a[6][64]; };

__global__ void __launch_bounds__(256) scan2_kernel(
    const float* __restrict__ pscan,
    const float* __restrict__ state2, float* __restrict__ ypart,
    float* __restrict__ Sout)
{
    int h = blockIdx.x >> 2;
    int q = blockIdx.x & 3;
    int tid = threadIdx.x;
    int wrp = tid >> 5, lane = tid & 31;
    int rsel = lane >> 4, colg = lane & 15;
    int row = q * 16 + 2 * wrp + rsel;   // 0..63

    float4 S = *(const float4*)(state2 + (size_t)h * 4096 + row * 64 + colg * 4);

    __shared__ ScanBuf buf[2];

    const float* pb_base = pscan + (size_t)h * 512;
    const size_t tstride = (size_t)NHEAD * 512;
    int f = tid & 3, i4 = tid >> 2;

    // stage t=0
    {
        float2 p0 = *(const float2*)(pb_base + (size_t)tid * 2);
        if (f == 0)      { buf[0].a[0][i4] = p0.x; buf[0].a[1][i4] = p0.y; }
        else if (f == 1) { buf[0].a[2][i4] = p0.x; buf[0].a[3][i4] = p0.y; }
        else if (f == 2) { buf[0].a[4][i4] = p0.x; buf[0].a[5][i4] = p0.y; }
    }
    float2 preA = *(const float2*)(pb_base + tstride + tid * 2);   // t=1
    float2 preB;

    for (int t = 0; t < T_LEN; t++) {
        __syncthreads();
        preB = (t + 2 < T_LEN) ? *(const float2*)(pb_base + (size_t)(t + 2) * tstride + tid * 2)
                               : preA;
        ScanBuf& b = buf[t & 1];
        float4 w4  = *(const float4*)&b.a[0][colg * 4];
        float4 kk4 = *(const float4*)&b.a[1][colg * 4];
        float4 ka4 = *(const float4*)&b.a[2][colg * 4];
        float4 k4  = *(const float4*)&b.a[3][colg * 4];
        float4 r4  = *(const float4*)&b.a[5][colg * 4];
        float vi   = b.a[4][row];

        float p = S.x * kk4.x + S.y * kk4.y + S.z * kk4.z + S.w * kk4.w;
        p += __shfl_xor_sync(0xffffffffu, p, 1);
        p += __shfl_xor_sync(0xffffffffu, p, 2);
        p += __shfl_xor_sync(0xffffffffu, p, 4);
        p += __shfl_xor_sync(0xffffffffu, p, 8);

        S.x = S.x * w4.x - p * ka4.x + vi * k4.x;
        S.y = S.y * w4.y - p * ka4.y + vi * k4.y;
        S.z = S.z * w4.z - p * ka4.z + vi * k4.z;
        S.w = S.w * w4.w - p * ka4.w + vi * k4.w;

        // stage t+1 (independent of y chain)
        if (t + 1 < T_LEN) {
            ScanBuf& nb = buf[(t + 1) & 1];
            if (f == 0)      { nb.a[0][i4] = preA.x; nb.a[1][i4] = preA.y; }
            else if (f == 1) { nb.a[2][i4] = preA.x; nb.a[3][i4] = preA.y; }
            else if (f == 2) { nb.a[4][i4] = preA.x; nb.a[5][i4] = preA.y; }
        }
        preA = preB;

        // y: 4-wide partial, 2 shfl, store
        float y = S.x * r4.x + S.y * r4.y + S.z * r4.z + S.w * r4.w;
        y += __shfl_xor_sync(0xffffffffu, y, 1);
        y += __shfl_xor_sync(0xffffffffu, y, 2);
        if ((colg & 3) == 0)
            ypart[((size_t)t * HID + h * HEADD + row) * 4 + (colg >> 2)] = y;
    }
    *(float4*)(Sout + (size_t)h * 4096 + row * 64 + colg * 4) = S;
}

// ---------------- groupnorm + rkv + gate -> fp16 split into abuf ----------------
__global__ void __launch_bounds__(256) post_kernel(
    const float* __restrict__ ypart, const float* __restrict__ r,
    const float* __restrict__ k2, const float* __restrict__ v,
    const float* __restrict__ g, const float* __restrict__ r_k,
    const float* __restrict__ lnxw, const float* __restrict__ lnxb,
    __half* __restrict__ zsplit)
{
    int gw = (blockIdx.x * 256 + threadIdx.x) >> 5;
    int lane = threadIdx.x & 31;
    if (gw >= T_LEN * NHEAD) return;
    int t = gw >> 5, h = gw & 31;
    int base = t * HID + h * HEADD;
    int cb = h * HEADD;

    float4 yp0 = *(const float4*)(ypart + (size_t)(base + lane) * 4);
    float4 yp1 = *(const float4*)(ypart + (size_t)(base + lane + 32) * 4);
    float y0 = (yp0.x + yp0.y) + (yp0.z + yp0.w);
    float y1 = (yp1.x + yp1.y) + (yp1.z + yp1.w);

    float mu = warp_sum(y0 + y1) * (1.f / HEADD);
    float d0 = y0 - mu, d1 = y1 - mu;
    float var = warp_sum(d0 * d0 + d1 * d1) * (1.f / HEADD);
    float inv = rsqrtf(var + 0.00064f);

    float rs = warp_sum(r[base + lane] * k2[base + lane] * r_k[cb + lane] +
                        r[base + lane + 32] * k2[base + lane + 32] * r_k[cb + lane + 32]);

    float z0 = (d0 * inv * lnxw[cb + lane] + lnxb[cb + lane] + rs * v[base + lane]) * g[base + lane];
    float z1 = (d1 * inv * lnxw[cb + lane + 32] + lnxb[cb + lane + 32] + rs * v[base + lane + 32]) * g[base + lane + 32];

    size_t zb = (size_t)t * 2 * HID;
    __half h0, l0, h1, l1;
    hsplit(z0, h0, l0);
    hsplit(z1, h1, l1);
    zsplit[zb + cb + lane] = h0;
    zsplit[zb + HID + cb + lane] = l0;
    zsplit[zb + cb + lane + 32] = h1;
    zsplit[zb + HID + cb + lane + 32] = l1;
}

__global__ void __launch_bounds__(256) copy_kernel(const float* __restrict__ src,
                                                   float* __restrict__ dst, int n)
{
    int i = blockIdx.x * 256 + threadIdx.x;
    if (i < n) dst[i] = src[i];
}

// ---------------- host launcher ----------------
extern "C" void kernel_launch(void* const* d_in, const int* in_sizes, int n_in,
                              void* d_out, int out_size)
{
    const float* x       = (const float*)d_in[0];
    const float* state1  = (const float*)d_in[1];
    const float* state2  = (const float*)d_in[2];
    const float* v_first = (const float*)d_in[3];
    const float* ln1_w   = (const float*)d_in[4];
    const float* ln1_b   = (const float*)d_in[5];
    const float* x_r     = (const float*)d_in[6];
    const float* x_w     = (const float*)d_in[7];
    const float* x_k     = (const float*)d_in[8];
    const float* x_v     = (const float*)d_in[9];
    const float* x_a     = (const float*)d_in[10];
    const float* x_g     = (const float*)d_in[11];
    const float* Wr      = (const float*)d_in[12];
    const float* Wk      = (const float*)d_in[13];
    const float* Wv      = (const float*)d_in[14];
    const float* Wo      = (const float*)d_in[15];
    const float* w0      = (const float*)d_in[16];
    const float* w1      = (const float*)d_in[17];
    const float* w2      = (const float*)d_in[18];
    const float* a0      = (const float*)d_in[19];
    const float* a1      = (const float*)d_in[20];
    const float* a2      = (const float*)d_in[21];
    const float* v0      = (const float*)d_in[22];
    const float* v1      = (const float*)d_in[23];
    const float* v2      = (const float*)d_in[24];
    const float* g1      = (const float*)d_in[25];
    const float* g2      = (const float*)d_in[26];
    const float* k_k     = (const float*)d_in[27];
    const float* k_a     = (const float*)d_in[28];
    const float* r_k     = (const float*)d_in[29];
    const float* ln_x_w  = (const float*)d_in[30];
    const float* ln_x_b  = (const float*)d_in[31];

    float* sc = nullptr;      cudaGetSymbolAddress((void**)&sc, g_scratch);
    float* hbuf = nullptr;    cudaGetSymbolAddress((void**)&hbuf, g_hbuf);
    float* pscan = nullptr;   cudaGetSymbolAddress((void**)&pscan, g_pscan);
    float* ypart = nullptr;   cudaGetSymbolAddress((void**)&ypart, g_ypart);
    __half* abuf = nullptr;   cudaGetSymbolAddress((void**)&abuf, g_abuf);
    __half* wbuf = nullptr;   cudaGetSymbolAddress((void**)&wbuf, g_wbuf);
    __half* g1buf = nullptr;  cudaGetSymbolAddress((void**)&g1buf, g_g1buf);
    __half* g2buf = nullptr;  cudaGetSymbolAddress((void**)&g2buf, g_g2buf);
    __half* ghbuf = nullptr;  cudaGetSymbolAddress((void**)&ghbuf, g_ghbuf);

    cudaFuncSetAttribute(mm128_kernel, cudaFuncAttributeMaxDynamicSharedMemorySize, MM_SMEM);

#define SLOT(s) (sc + (size_t)(s) * NTOK_EL)

    float* out = (float*)d_out;
    const int OFF_OUT = 0;
    const int OFF_S1  = NTOK_EL;
    const int OFF_S2  = OFF_S1 + HID;
    const int OFF_VF  = OFF_S2 + NHEAD * HEADD * HEADD;
    const int TOTAL   = OFF_VF + NTOK_EL;
    bool full = (out_size >= TOTAL);

    float* s1_out = full ? out + OFF_S1 : nullptr;
    float* s2_out = full ? out + OFF_S2 : SLOT(S_TMP);

    const int EW_GRID = (NTOK_EL + 255) / 256;

    // weight conversions (single fp16 plane)
    splitW4_kernel<<<dim3(64, 64, 4), 1024>>>(Wr, Wk, Wv, Wo, wbuf);
    splitW_kernel<<<dim3(8, 64), 1024>>>(g1, g1buf, HID, 256);
    splitW_kernel<<<dim3(64, 8), 1024>>>(g2, g2buf, 256, HID);

    // fused LN + mix + fp16 split
    ln_mix_kernel<<<T_LEN, 256>>>(x, state1, ln1_w, ln1_b,
                                  x_r, x_w, x_k, x_v, x_a, x_g,
                                  abuf, SLOT(S_XW), SLOT(S_XA), SLOT(S_XV), s1_out);

    // batched projections: r, k, v, g-down (sigmoid fused)
    {
        MMJobs jobs;
        jobs.j[0] = { wbuf,               SLOT(S_R),   nullptr, HID, 0 };
        jobs.j[1] = { wbuf + WSLOT_H,     SLOT(S_K),   nullptr, HID, 0 };
        jobs.j[2] = { wbuf + 2 * WSLOT_H, SLOT(S_V),   nullptr, HID, 0 };
        jobs.j[3] = { g1buf,              SLOT(S_TMP), nullptr, 256, 2 };
        mm128_kernel<<<dim3(16, 8, 4), 256, MM_SMEM>>>(abuf, ASLOT_H, jobs, T_LEN, HID);
    }

    // g-up: split sigmoid output, then @g2
    splitA_kernel<<<(T_LEN * 256 + 255) / 256, 256>>>(SLOT(S_TMP), ghbuf, T_LEN, 256);
    {
        MMJobs jobs;
        jobs.j[0] = { g2buf, SLOT(S_G), nullptr, HID, 0 };
        jobs.j[1] = jobs.j[0]; jobs.j[2] = jobs.j[0]; jobs.j[3] = jobs.j[0];
        mm128_kernel<<<dim3(16, 8, 1), 256, MM_SMEM>>>(ghbuf, 0, jobs, T_LEN, 256);
    }

    // LoRA chains (a, w, v) fp32
    lora_down_kernel<<<dim3(2, 16, 3), 256>>>(SLOT(S_XA), SLOT(S_XW), SLOT(S_XV),
                                              a1, w1, v1, hbuf);
    lora_up_kernel<<<dim3(32, 16, 3), 256>>>(hbuf, a2, w2, v2, a0, w0, v0, v_first,
                                             SLOT(S_A), SLOT(S_W), SLOT(S_V));

    // prep
    prep_kernel<<<(T_LEN * NHEAD * 32 + 255) / 256, 256>>>(
        SLOT(S_K), SLOT(S_A), SLOT(S_W), SLOT(S_V), SLOT(S_R),
        k_k, k_a, SLOT(S_K2), pscan);

    // scan
    scan2_kernel<<<128, 256>>>(pscan, state2, ypart, s2_out);

    // groupnorm + rkv + gate -> fp16 split into abuf slot 0
    post_kernel<<<(T_LEN * NHEAD * 32 + 255) / 256, 256>>>(
        ypart, SLOT(S_R), SLOT(S_K2), SLOT(S_V), SLOT(S_G),
        r_k, ln_x_w, ln_x_b, abuf);

    // out = x + z@Wo
    {
        MMJobs jobs;
        jobs.j[0] = { wbuf + 3 * WSLOT_H, out + OFF_OUT, x, HID, 1 };
        jobs.j[1] = jobs.j[0]; jobs.j[2] = jobs.j[0]; jobs.j[3] = jobs.j[0];
        mm128_kernel<<<dim3(16, 8, 1), 256, MM_SMEM>>>(abuf, 0, jobs, T_LEN, HID);
    }

    // passthrough v_first
    if (full)
        copy_kernel<<<EW_GRID, 256>>>(v_first, out + OFF_VF, NTOK_EL);
}

// round 9
// speedup vs baseline: 4.8671x; 1.4840x over previous
#include <cuda_runtime.h>
#include <cuda_fp16.h>
#include <math.h>
#include <stdint.h>

#define T_LEN 1024
#define HID   2048
#define NHEAD 32
#define HEADD 64
#define NTOK_EL (T_LEN * HID)   // 2097152
#define NPAIR (T_LEN / 2)

#define ASLOT_H ((size_t)T_LEN * 2 * HID)   // A' slot: [M, 2K] fp16 {hi|lo}
#define WSLOT_H ((size_t)HID * HID)         // W' slot: [N, K] fp16 single plane
#define LSLOT_H ((size_t)128 * HID)         // lora-down W' slot (padded 128 rows)

// ---------------- static device scratch ----------------
__device__ float g_scratch[10u * (unsigned)NTOK_EL];
__device__ float g_hbuf[(size_t)T_LEN * 384];
__device__ float g_pscan2[(size_t)NPAIR * NHEAD * 1024];   // 16 planes x 64
__device__ float g_ypart[(size_t)T_LEN * HID * 4];
__device__ __align__(256) __half g_abuf[6 * ASLOT_H];      // xr,xk,xv,xg,xa,xw splits
__device__ __align__(256) __half g_wbuf[4 * WSLOT_H];      // Wr',Wk',Wv',Wo'
__device__ __align__(256) __half g_g1buf[(size_t)256 * HID];
__device__ __align__(256) __half g_g2buf[(size_t)HID * 256];
__device__ __align__(256) __half g_ghbuf[(size_t)T_LEN * 2 * 256];
__device__ __align__(256) __half g_lorabuf[3 * LSLOT_H];   // a1',w1',v1' (zero-padded)

#define S_R   0
#define S_K   1
#define S_V   2
#define S_K2  3
#define S_G   4
#define S_A   5
#define S_W   6
#define S_TMP 7

// ---------------- helpers ----------------
__device__ __forceinline__ float blk_sum256(float v) {
    __shared__ float sh[8];
    int tid = threadIdx.x;
#pragma unroll
    for (int o = 16; o; o >>= 1) v += __shfl_xor_sync(0xffffffffu, v, o);
    if ((tid & 31) == 0) sh[tid >> 5] = v;
    __syncthreads();
    if (tid == 0) {
        float s = 0.f;
#pragma unroll
        for (int i = 0; i < 8; i++) s += sh[i];
        sh[0] = s;
    }
    __syncthreads();
    float r = sh[0];
    __syncthreads();
    return r;
}

__device__ __forceinline__ float warp_sum(float v) {
#pragma unroll
    for (int o = 16; o; o >>= 1) v += __shfl_xor_sync(0xffffffffu, v, o);
    return v;
}

__device__ __forceinline__ float sigmoidf(float v) {
    return 1.f / (1.f + __expf(-v));
}

__device__ __forceinline__ uint32_t smem_u32(const void* p) {
    uint32_t a;
    asm("{ .reg .u64 t; cvta.to.shared.u64 t, %1; cvt.u32.u64 %0, t; }" : "=r"(a) : "l"(p));
    return a;
}

__device__ __forceinline__ void hsplit(float v, __half& hi, __half& lo) {
    hi = __float2half_rn(v);
    lo = __float2half_rn(v - __half2float(hi));
}

// ======================= mma.sync fp16 GEMM (2-term A split) =======================
#define MMK_STRIDE 80
#define MMK_TILE   (128 * MMK_STRIDE)
#define STAGE_BYTES (3 * MMK_TILE)
#define MM_SMEM (3 * STAGE_BYTES)

struct MMJob { const __half* B; float* C; const float* Res; int N; int ldc; int mode; int aslot; };
struct MMJobs { MMJob j[7]; };

__device__ __forceinline__ void cp16(uint32_t dst, const void* src) {
    asm volatile("cp.async.cg.shared.global [%0], [%1], 16;" :: "r"(dst), "l"(src));
}

__device__ __forceinline__ void ldsm4(uint32_t* r, uint32_t a) {
    asm volatile("ldmatrix.sync.aligned.m8n8.x4.shared.b16 {%0,%1,%2,%3}, [%4];"
                 : "=r"(r[0]), "=r"(r[1]), "=r"(r[2]), "=r"(r[3]) : "r"(a));
}

__device__ __forceinline__ void mma16816(float* c, const uint32_t* a, const uint32_t* b) {
    asm volatile(
        "mma.sync.aligned.m16n8k16.row.col.f32.f16.f16.f32 "
        "{%0,%1,%2,%3}, {%4,%5,%6,%7}, {%8,%9}, {%0,%1,%2,%3};"
        : "+f"(c[0]), "+f"(c[1]), "+f"(c[2]), "+f"(c[3])
        : "r"(a[0]), "r"(a[1]), "r"(a[2]), "r"(a[3]), "r"(b[0]), "r"(b[1]));
}

__global__ void __launch_bounds__(256, 2) mm128_kernel(
    const __half* __restrict__ A, MMJobs jobs, int K)
{
    extern __shared__ __align__(16) char smem[];
    uint32_t sbase = smem_u32(smem);

    const MMJob job = jobs.j[blockIdx.z];
    const int N = job.N;
    int n0 = blockIdx.x * 128;
    if (n0 >= N) return;
    int m0 = blockIdx.y * 128;

    const __half* Ab = A + (size_t)job.aslot * ASLOT_H;
    const __half* Bb = job.B;
    const int K2 = 2 * K;
    const int nk = K >> 5;

    int tid = threadIdx.x;
    int wid = tid >> 5, lane = tid & 31;
    int g = lane >> 2, tig = lane & 3;
    int warp_m = wid >> 2;
    int warp_n = wid & 3;

    float acc[4][4][4];
#pragma unroll
    for (int i = 0; i < 4; i++)
#pragma unroll
        for (int j = 0; j < 4; j++)
#pragma unroll
            for (int q = 0; q < 4; q++) acc[i][j][q] = 0.f;

    auto load_stage = [&](int s, int kc) {
        uint32_t st = sbase + s * STAGE_BYTES;
        int k0 = kc << 5;
#pragma unroll
        for (int it = 0; it < 2; it++) {       // Ah
            int idx = tid + it * 256;
            int r = idx >> 2, c = idx & 3;
            cp16(st + r * MMK_STRIDE + c * 16, Ab + ((size_t)(m0 + r) * K2 + k0 + c * 8));
        }
#pragma unroll
        for (int it = 0; it < 2; it++) {       // Al
            int idx = tid + it * 256;
            int r = idx >> 2, c = idx & 3;
            cp16(st + MMK_TILE + r * MMK_STRIDE + c * 16,
                 Ab + ((size_t)(m0 + r) * K2 + K + k0 + c * 8));
        }
#pragma unroll
        for (int it = 0; it < 2; it++) {       // B
            int idx = tid + it * 256;
            int r = idx >> 2, c = idx & 3;
            cp16(st + 2 * MMK_TILE + r * MMK_STRIDE + c * 16,
                 Bb + ((size_t)(n0 + r) * K + k0 + c * 8));
        }
        asm volatile("cp.async.commit_group;" ::: "memory");
    };

    load_stage(0, 0);
    if (nk > 1) load_stage(1, 1);
    else asm volatile("cp.async.commit_group;" ::: "memory");

    int aRowSel = (lane & 15);
    int aColSel = (lane & 16) ? 16 : 0;
    int bRowSel = ((lane & 16) ? 8 : 0) + (lane & 7);
    int bColSel = (lane & 8) ? 16 : 0;

    for (int kc = 0; kc < nk; kc++) {
        asm volatile("cp.async.wait_group 1;" ::: "memory");
        __syncthreads();
        if (kc + 2 < nk) load_stage((kc + 2) % 3, kc + 2);
        else asm volatile("cp.async.commit_group;" ::: "memory");

        uint32_t st = sbase + (kc % 3) * STAGE_BYTES;
#pragma unroll
        for (int ks = 0; ks < 2; ks++) {
            uint32_t afr[4][4], bfr[2][4];
#pragma unroll
            for (int ap = 0; ap < 2; ap++) {
                uint32_t addr = st + 2 * MMK_TILE
                                + (uint32_t)(warp_n * 32 + ap * 16 + bRowSel) * MMK_STRIDE
                                + ks * 32 + bColSel;
                ldsm4(bfr[ap], addr);
            }
#pragma unroll
            for (int am = 0; am < 4; am++) {
                uint32_t addr = st + (uint32_t)(warp_m * 64 + am * 16 + aRowSel) * MMK_STRIDE
                                + ks * 32 + aColSel;
                ldsm4(afr[am], addr);
            }
#pragma unroll
            for (int am = 0; am < 4; am++) {
                mma16816(acc[am][0], afr[am], &bfr[0][0]);
                mma16816(acc[am][1], afr[am], &bfr[0][2]);
                mma16816(acc[am][2], afr[am], &bfr[1][0]);
                mma16816(acc[am][3], afr[am], &bfr[1][2]);
            }
#pragma unroll
            for (int am = 0; am < 4; am++) {
                uint32_t addr = st + MMK_TILE
                                + (uint32_t)(warp_m * 64 + am * 16 + aRowSel) * MMK_STRIDE
                                + ks * 32 + aColSel;
                ldsm4(afr[am], addr);
            }
#pragma unroll
            for (int am = 0; am < 4; am++) {
                mma16816(acc[am][0], afr[am], &bfr[0][0]);
                mma16816(acc[am][1], afr[am], &bfr[0][2]);
                mma16816(acc[am][2], afr[am], &bfr[1][0]);
                mma16816(acc[am][3], afr[am], &bfr[1][2]);
            }
        }
    }

    __syncthreads();

    float* C = job.C;
    const float* Res = job.Res;
    int mode = job.mode;
    int ldc = job.ldc;
#pragma unroll
    for (int am = 0; am < 4; am++) {
#pragma unroll
        for (int an = 0; an < 4; an++) {
            int row = m0 + warp_m * 64 + am * 16 + g;
            int col = n0 + warp_n * 32 + an * 8 + tig * 2;
            float2 v0 = make_float2(acc[am][an][0], acc[am][an][1]);
            float2 v1 = make_float2(acc[am][an][2], acc[am][an][3]);
            if (mode == 1) {
                const float2 r0 = *(const float2*)(Res + (size_t)row * ldc + col);
                const float2 r1 = *(const float2*)(Res + (size_t)(row + 8) * ldc + col);
                v0.x += r0.x; v0.y += r0.y;
                v1.x += r1.x; v1.y += r1.y;
            } else if (mode == 2) {
                v0.x = sigmoidf(v0.x); v0.y = sigmoidf(v0.y);
                v1.x = sigmoidf(v1.x); v1.y = sigmoidf(v1.y);
            } else if (mode == 3) {
                v0.x = tanhf(v0.x); v0.y = tanhf(v0.y);
                v1.x = tanhf(v1.x); v1.y = tanhf(v1.y);
            }
            *(float2*)(C + (size_t)row * ldc + col) = v0;
            *(float2*)(C + (size_t)(row + 8) * ldc + col) = v1;
        }
    }
}

// ---------------- fp16 split of activations: [M,K] fp32 -> [M,2K] {h|l} ----------------
__global__ void __launch_bounds__(256) splitA_kernel(
    const float* __restrict__ A, __half* __restrict__ out, int M, int K)
{
    int i = blockIdx.x * 256 + threadIdx.x;
    if (i >= M * K) return;
    int m = i / K, k = i - m * K;
    __half hi, lo;
    hsplit(A[i], hi, lo);
    size_t base = (size_t)m * 2 * K;
    out[base + k] = hi;
    out[base + K + k] = lo;
}

// ---------------- W [K,N] fp32 -> transposed fp16 [N,K] ----------------
__global__ void __launch_bounds__(1024) splitW_kernel(
    const float* __restrict__ W, __half* __restrict__ out, int K, int N)
{
    __shared__ float tile[32][33];
    int k0 = blockIdx.y * 32, n0 = blockIdx.x * 32;
    int tx = threadIdx.x & 31, ty = threadIdx.x >> 5;
    tile[ty][tx] = W[(size_t)(k0 + ty) * N + n0 + tx];
    __syncthreads();
    int tid = threadIdx.x;
    if (tid >= 512) return;
    int nl = tid >> 4, kp = (tid & 15) * 2;
    __half2 h = __floats2half2_rn(tile[kp][nl], tile[kp + 1][nl]);
    *(__half2*)(out + (size_t)(n0 + nl) * K + k0 + kp) = h;
}

__global__ void __launch_bounds__(1024) splitW4_kernel(
    const float* __restrict__ W0, const float* __restrict__ W1,
    const float* __restrict__ W2, const float* __restrict__ W3,
    __half* __restrict__ out)
{
    const float* W = blockIdx.z == 0 ? W0 : blockIdx.z == 1 ? W1 : blockIdx.z == 2 ? W2 : W3;
    __half* o = out + blockIdx.z * WSLOT_H;
    __shared__ float tile[32][33];
    int k0 = blockIdx.y * 32, n0 = blockIdx.x * 32;
    int tx = threadIdx.x & 31, ty = threadIdx.x >> 5;
    tile[ty][tx] = W[(size_t)(k0 + ty) * HID + n0 + tx];
    __syncthreads();
    int tid = threadIdx.x;
    if (tid >= 512) return;
    int nl = tid >> 4, kp = (tid & 15) * 2;
    __half2 h = __floats2half2_rn(tile[kp][nl], tile[kp + 1][nl]);
    *(__half2*)(o + (size_t)(n0 + nl) * HID + k0 + kp) = h;
}

// ---------------- fused LN + token-shift mix + fp16 split (6 slots) ----------------
__global__ void __launch_bounds__(256) ln_mix_kernel(
    const float* __restrict__ x, const float* __restrict__ state1,
    const float* __restrict__ lnw, const float* __restrict__ lnb,
    const float* __restrict__ cr, const float* __restrict__ ck,
    const float* __restrict__ cv, const float* __restrict__ cg,
    const float* __restrict__ ca, const float* __restrict__ cw,
    __half* __restrict__ abuf,
    float* __restrict__ state1_out)
{
    int t = blockIdx.x;
    const float* xt = x + (size_t)t * HID;
    const float* xp = x + (size_t)(t - 1) * HID;

    float2 v0[4], v1[4];
    float s0 = 0.f, s1 = 0.f;
#pragma unroll
    for (int j = 0; j < 4; j++) {
        int c = threadIdx.x * 2 + j * 512;
        v0[j] = *(const float2*)(xt + c);
        s0 += v0[j].x + v0[j].y;
        v1[j] = t ? *(const float2*)(xp + c) : make_float2(0.f, 0.f);
        s1 += v1[j].x + v1[j].y;
    }
    float mu0 = blk_sum256(s0) * (1.f / HID);
    float mu1 = blk_sum256(s1) * (1.f / HID);
    float q0 = 0.f, q1 = 0.f;
#pragma unroll
    for (int j = 0; j < 4; j++) {
        float d;
        d = v0[j].x - mu0; q0 += d * d;
        d = v0[j].y - mu0; q0 += d * d;
        d = v1[j].x - mu1; q1 += d * d;
        d = v1[j].y - mu1; q1 += d * d;
    }
    float inv0 = rsqrtf(blk_sum256(q0) * (1.f / HID) + 1e-5f);
    float inv1 = rsqrtf(blk_sum256(q1) * (1.f / HID) + 1e-5f);

#pragma unroll
    for (int j = 0; j < 4; j++) {
        int c = threadIdx.x * 2 + j * 512;
        float2 wv = *(const float2*)(lnw + c);
        float2 bv = *(const float2*)(lnb + c);
        float xn0 = (v0[j].x - mu0) * inv0 * wv.x + bv.x;
        float xn1 = (v0[j].y - mu0) * inv0 * wv.y + bv.y;
        float pv0 = t ? (v1[j].x - mu1) * inv1 * wv.x + bv.x : state1[c];
        float pv1 = t ? (v1[j].y - mu1) * inv1 * wv.y + bv.y : state1[c + 1];
        float sx0 = pv0 - xn0, sx1 = pv1 - xn1;

        __half* arow = abuf + (size_t)t * 2 * HID + c;
#pragma unroll
        for (int s = 0; s < 6; s++) {
            const float* coefA = (s == 0) ? cr : (s == 1) ? ck : (s == 2) ? cv
                               : (s == 3) ? cg : (s == 4) ? ca : cw;
            float a0 = xn0 + coefA[c] * sx0;
            float a1 = xn1 + coefA[c + 1] * sx1;
            __half h0, l0, h1, l1;
            hsplit(a0, h0, l0);
            hsplit(a1, h1, l1);
            __half* p = arow + (size_t)s * ASLOT_H;
            *(__half2*)(p) = __half2(h0, h1);
            *(__half2*)(p + HID) = __half2(l0, l1);
        }
        if (state1_out && t == T_LEN - 1) {
            state1_out[c] = xn0;
            state1_out[c + 1] = xn1;
        }
    }
}

// ---------------- batched LoRA up + fused activations (hbuf stride 384) ----------------
__global__ void __launch_bounds__(256) lora_up_kernel(
    const float* __restrict__ hbuf,
    const float* __restrict__ Ba, const float* __restrict__ Bw, const float* __restrict__ Bv,
    const float* __restrict__ a0, const float* __restrict__ w0, const float* __restrict__ v0b,
    const float* __restrict__ vf,
    float* __restrict__ outA, float* __restrict__ outW, float* __restrict__ outV)
{
    int z = blockIdx.z;
    const float* B = z == 0 ? Ba : z == 1 ? Bw : Bv;
    const float* bias = z == 0 ? a0 : z == 1 ? w0 : v0b;
    int K = (z == 2) ? 64 : 96;
    int zoff = z * 128;
    const int N = HID;

    __shared__ float As[16][64 + 1];
    __shared__ float Bs[16][64 + 1];
    int tid = threadIdx.x;
    int tx = tid & 15, ty = tid >> 4;
    int row0 = blockIdx.y * 64, col0 = blockIdx.x * 64;
    float acc[4][4] = {};
    for (int k0 = 0; k0 < K; k0 += 16) {
#pragma unroll
        for (int i = tid; i < 64 * 16; i += 256) {
            int r = i >> 4, c = i & 15;
            As[c][r] = hbuf[(size_t)(row0 + r) * 384 + zoff + k0 + c];
        }
#pragma unroll
        for (int i = tid; i < 16 * 64; i += 256) {
            int r = i >> 6, c = i & 63;
            Bs[r][c] = B[(size_t)(k0 + r) * N + col0 + c];
        }
        __syncthreads();
#pragma unroll
        for (int kk = 0; kk < 16; kk++) {
            float a[4], b[4];
#pragma unroll
            for (int i = 0; i < 4; i++) a[i] = As[kk][ty * 4 + i];
#pragma unroll
            for (int jj = 0; jj < 4; jj++) b[jj] = Bs[kk][tx * 4 + jj];
#pragma unroll
            for (int i = 0; i < 4; i++)
#pragma unroll
                for (int jj = 0; jj < 4; jj++) acc[i][jj] = fmaf(a[i], b[jj], acc[i][jj]);
        }
        __syncthreads();
    }
#pragma unroll
    for (int i = 0; i < 4; i++) {
        int gr = row0 + ty * 4 + i;
#pragma unroll
        for (int jj = 0; jj < 4; jj++) {
            int gc = col0 + tx * 4 + jj;
            size_t idx = (size_t)gr * N + gc;
            float s = sigmoidf(bias[gc] + acc[i][jj]);
            if (z == 0) outA[idx] = s;
            else if (z == 1) outW[idx] = __expf(-0.606531f * s);
            else {
                float vv = outV[idx];
                outV[idx] = vv + (vf[idx] - vv) * s;
            }
        }
    }
}

// ---------------- prep2: per (pair, head) — kk/k2 both steps + pair scalars ----------------
__global__ void __launch_bounds__(256) prep2_kernel(
    const float* __restrict__ k, const float* __restrict__ a,
    const float* __restrict__ w, const float* __restrict__ v,
    const float* __restrict__ r,
    const float* __restrict__ k_k, const float* __restrict__ k_a,
    float* __restrict__ k2out, float* __restrict__ pscan2)
{
    int gw = (blockIdx.x * 256 + threadIdx.x) >> 5;
    int lane = threadIdx.x & 31;
    if (gw >= NPAIR * NHEAD) return;
    int pr = gw >> 5, h = gw & 31;
    int b0 = (2 * pr) * HID + h * HEADD;
    int b1 = b0 + HID;
    int cb = h * HEADD;

    // step t (even)
    float kA0 = k[b0 + lane], kB0 = k[b0 + lane + 32];
    float qA0 = kA0 * k_k[cb + lane], qB0 = kB0 * k_k[cb + lane + 32];
    float inv0 = 1.f / fmaxf(sqrtf(warp_sum(qA0 * qA0 + qB0 * qB0)), 1e-12f);
    float kkA0 = qA0 * inv0, kkB0 = qB0 * inv0;
    float aA0 = a[b0 + lane], aB0 = a[b0 + lane + 32];
    float k2A0 = kA0 * (1.f + (aA0 - 1.f) * k_a[cb + lane]);
    float k2B0 = kB0 * (1.f + (aB0 - 1.f) * k_a[cb + lane + 32]);
    k2out[b0 + lane] = k2A0;
    k2out[b0 + lane + 32] = k2B0;

    // step t+1
    float kA1 = k[b1 + lane], kB1 = k[b1 + lane + 32];
    float qA1 = kA1 * k_k[cb + lane], qB1 = kB1 * k_k[cb + lane + 32];
    float inv1 = 1.f / fmaxf(sqrtf(warp_sum(qA1 * qA1 + qB1 * qB1)), 1e-12f);
    float kkA1 = qA1 * inv1, kkB1 = qB1 * inv1;
    float aA1 = a[b1 + lane], aB1 = a[b1 + lane + 32];
    float k2A1 = kA1 * (1.f + (aA1 - 1.f) * k_a[cb + lane]);
    float k2B1 = kB1 * (1.f + (aB1 - 1.f) * k_a[cb + lane + 32]);
    k2out[b1 + lane] = k2A1;
    k2out[b1 + lane + 32] = k2B1;

    float wA0 = w[b0 + lane], wB0 = w[b0 + lane + 32];
    float kaA0 = kkA0 * aA0, kaB0 = kkB0 * aB0;

    // pair scalars: c1 = kk1·ka0 ; c2 = kk1·k2_0
    float c1 = warp_sum(kkA1 * kaA0 + kkB1 * kaB0);
    float c2 = warp_sum(kkA1 * k2A0 + kkB1 * k2B0);

    float* P = pscan2 + ((size_t)pr * NHEAD + h) * 1024;
    // plane 0: kk0 | 1: kkw=kk1*w0 | 2: w0 | 3: ka0 | 4: k2_0 | 5: r0
    // 6: w1 | 7: ka1 | 8: k2_1 | 9: r1 | 10: v0 | 11: v1 | 12[0]=c1,[1]=c2
    P[0 * 64 + lane] = kkA0;           P[0 * 64 + lane + 32] = kkB0;
    P[1 * 64 + lane] = kkA1 * wA0;     P[1 * 64 + lane + 32] = kkB1 * wB0;
    P[2 * 64 + lane] = wA0;            P[2 * 64 + lane + 32] = wB0;
    P[3 * 64 + lane] = kaA0;           P[3 * 64 + lane + 32] = kaB0;
    P[4 * 64 + lane] = k2A0;           P[4 * 64 + lane + 32] = k2B0;
    P[5 * 64 + lane] = r[b0 + lane];   P[5 * 64 + lane + 32] = r[b0 + lane + 32];
    P[6 * 64 + lane] = w[b1 + lane];   P[6 * 64 + lane + 32] = w[b1 + lane + 32];
    P[7 * 64 + lane] = kkA1 * aA1;     P[7 * 64 + lane + 32] = kkB1 * aB1;
    P[8 * 64 + lane] = k2A1;           P[8 * 64 + lane + 32] = k2B1;
    P[9 * 64 + lane] = r[b1 + lane];   P[9 * 64 + lane + 32] = r[b1 + lane + 32];
    P[10 * 64 + lane] = v[b0 + lane];  P[10 * 64 + lane + 32] = v[b0 + lane + 32];
    P[11 * 64 + lane] = v[b1 + lane];  P[11 * 64 + lane + 32] = v[b1 + lane + 32];
    if (lane == 0) { P[12 * 64] = c1; P[12 * 64 + 1] = c2; }
}

// ---------------- scan v3: two steps per reduction round ----------------
__global__ void __launch_bounds__(256) scan3_kernel(
    const float* __restrict__ pscan2,
    const float* __restrict__ state2, float* __restrict__ ypart,
    float* __restrict__ Sout)
{
    int h = blockIdx.x >> 2;
    int q = blockIdx.x & 3;
    int tid = threadIdx.x;
    int wrp = tid >> 5, lane = tid & 31;
    int rsel = lane >> 4, colg = lane & 15;
    int row = q * 16 + 2 * wrp + rsel;   // 0..63

    float4 S = *(const float4*)(state2 + (size_t)h * 4096 + row * 64 + colg * 4);

    __shared__ float buf[2][1024];

    const float* pB = pscan2 + (size_t)h * 1024;
    const size_t pstride = (size_t)NHEAD * 1024;

    ((float4*)buf[0])[tid] = *(const float4*)(pB + tid * 4);
    float4 preA = *(const float4*)(pB + pstride + tid * 4);
    float4 preB;

    for (int pr = 0; pr < NPAIR; pr++) {
        __syncthreads();
        preB = (pr + 2 < NPAIR) ? *(const float4*)(pB + (size_t)(pr + 2) * pstride + tid * 4)
                                : preA;
        const float* b = buf[pr & 1];
        float4 kk4  = *(const float4*)(b + 0 * 64 + colg * 4);
        float4 kkw4 = *(const float4*)(b + 1 * 64 + colg * 4);
        float4 w4   = *(const float4*)(b + 2 * 64 + colg * 4);
        float4 ka4  = *(const float4*)(b + 3 * 64 + colg * 4);
        float4 k4   = *(const float4*)(b + 4 * 64 + colg * 4);
        float4 r4   = *(const float4*)(b + 5 * 64 + colg * 4);
        float4 w14  = *(const float4*)(b + 6 * 64 + colg * 4);
        float4 ka14 = *(const float4*)(b + 7 * 64 + colg * 4);
        float4 k14  = *(const float4*)(b + 8 * 64 + colg * 4);
        float4 r14  = *(const float4*)(b + 9 * 64 + colg * 4);
        float v0 = b[10 * 64 + row];
        float v1 = b[11 * 64 + row];
        float c1 = b[12 * 64];
        float c2 = b[12 * 64 + 1];

        float d0 = S.x * kk4.x + S.y * kk4.y + S.z * kk4.z + S.w * kk4.w;
        float d1 = S.x * kkw4.x + S.y * kkw4.y + S.z * kkw4.z + S.w * kkw4.w;
#pragma unroll
        for (int o = 1; o <= 8; o <<= 1) {
            d0 += __shfl_xor_sync(0xffffffffu, d0, o);
            d1 += __shfl_xor_sync(0xffffffffu, d1, o);
        }
        float p0 = d0;
        float p1 = d1 - p0 * c1 + v0 * c2;

        S.x = S.x * w4.x - p0 * ka4.x + v0 * k4.x;
        S.y = S.y * w4.y - p0 * ka4.y + v0 * k4.y;
        S.z = S.z * w4.z - p0 * ka4.z + v0 * k4.z;
        S.w = S.w * w4.w - p0 * ka4.w + v0 * k4.w;

        float y0 = S.x * r4.x + S.y * r4.y + S.z * r4.z + S.w * r4.w;
        y0 += __shfl_xor_sync(0xffffffffu, y0, 1);
        y0 += __shfl_xor_sync(0xffffffffu, y0, 2);
        if ((colg & 3) == 0)
            ypart[((size_t)(2 * pr) * HID + h * HEADD + row) * 4 + (colg >> 2)] = y0;

        // stage next pair (independent of second update)
        if (pr + 1 < NPAIR)
            ((float4*)buf[(pr + 1) & 1])[tid] = preA;
        preA = preB;

        S.x = S.x * w14.x - p1 * ka14.x + v1 * k14.x;
        S.y = S.y * w14.y - p1 * ka14.y + v1 * k14.y;
        S.z = S.z * w14.z - p1 * ka14.z + v1 * k14.z;
        S.w = S.w * w14.w - p1 * ka14.w + v1 * k14.w;

        float y1 = S.x * r14.x + S.y * r14.y + S.z * r14.z + S.w * r14.w;
        y1 += __shfl_xor_sync(0xffffffffu, y1, 1);
        y1 += __shfl_xor_sync(0xffffffffu, y1, 2);
        if ((colg & 3) == 0)
            ypart[((size_t)(2 * pr + 1) * HID + h * HEADD + row) * 4 + (colg >> 2)] = y1;
    }
    *(float4*)(Sout + (size_t)h * 4096 + row * 64 + colg * 4) = S;
}

// ---------------- groupnorm + rkv + gate -> fp16 split into abuf ----------------
__global__ void __launch_bounds__(256) post_kernel(
    const float* __restrict__ ypart, const float* __restrict__ r,
    const float* __restrict__ k2, const float* __restrict__ v,
    const float* __restrict__ g, const float* __restrict__ r_k,
    const float* __restrict__ lnxw, const float* __restrict__ lnxb,
    __half* __restrict__ zsplit)
{
    int gw = (blockIdx.x * 256 + threadIdx.x) >> 5;
    int lane = threadIdx.x & 31;
    if (gw >= T_LEN * NHEAD) return;
    int t = gw >> 5, h = gw & 31;
    int base = t * HID + h * HEADD;
    int cb = h * HEADD;

    float4 yp0 = *(const float4*)(ypart + (size_t)(base + lane) * 4);
    float4 yp1 = *(const float4*)(ypart + (size_t)(base + lane + 32) * 4);
    float y0 = (yp0.x + yp0.y) + (yp0.z + yp0.w);
    float y1 = (yp1.x + yp1.y) + (yp1.z + yp1.w);

    float mu = warp_sum(y0 + y1) * (1.f / HEADD);
    float d0 = y0 - mu, d1 = y1 - mu;
    float var = warp_sum(d0 * d0 + d1 * d1) * (1.f / HEADD);
    float inv = rsqrtf(var + 0.00064f);

    float rs = warp_sum(r[base + lane] * k2[base + lane] * r_k[cb + lane] +
                        r[base + lane + 32] * k2[base + lane + 32] * r_k[cb + lane + 32]);

    float z0 = (d0 * inv * lnxw[cb + lane] + lnxb[cb + lane] + rs * v[base + lane]) * g[base + lane];
    float z1 = (d1 * inv * lnxw[cb + lane + 32] + lnxb[cb + lane + 32] + rs * v[base + lane + 32]) * g[base + lane + 32];

    size_t zb = (size_t)t * 2 * HID;
    __half h0, l0, h1, l1;
    hsplit(z0, h0, l0);
    hsplit(z1, h1, l1);
    zsplit[zb + cb + lane] = h0;
    zsplit[zb + HID + cb + lane] = l0;
    zsplit[zb + cb + lane + 32] = h1;
    zsplit[zb + HID + cb + lane + 32] = l1;
}

__global__ void __launch_bounds__(256) copy_kernel(const float* __restrict__ src,
                                                   float* __restrict__ dst, int n)
{
    int i = blockIdx.x * 256 + threadIdx.x;
    if (i < n) dst[i] = src[i];
}

// ---------------- host launcher ----------------
extern "C" void kernel_launch(void* const* d_in, const int* in_sizes, int n_in,
                              void* d_out, int out_size)
{
    const float* x       = (const float*)d_in[0];
    const float* state1  = (const float*)d_in[1];
    const float* state2  = (const float*)d_in[2];
    const float* v_first = (const float*)d_in[3];
    const float* ln1_w   = (const float*)d_in[4];
    const float* ln1_b   = (const float*)d_in[5];
    const float* x_r     = (const float*)d_in[6];
    const float* x_w     = (const float*)d_in[7];
    const float* x_k     = (const float*)d_in[8];
    const float* x_v     = (const float*)d_in[9];
    const float* x_a     = (const float*)d_in[10];
    const float* x_g     = (const float*)d_in[11];
    const float* Wr      = (const float*)d_in[12];
    const float* Wk      = (const float*)d_in[13];
    const float* Wv      = (const float*)d_in[14];
    const float* Wo      = (const float*)d_in[15];
    const float* w0      = (const float*)d_in[16];
    const float* w1      = (const float*)d_in[17];
    const float* w2      = (const float*)d_in[18];
    const float* a0      = (const float*)d_in[19];
    const float* a1      = (const float*)d_in[20];
    const float* a2      = (const float*)d_in[21];
    const float* v0      = (const float*)d_in[22];
    const float* v1      = (const float*)d_in[23];
    const float* v2      = (const float*)d_in[24];
    const float* g1      = (const float*)d_in[25];
    const float* g2      = (const float*)d_in[26];
    const float* k_k     = (const float*)d_in[27];
    const float* k_a     = (const float*)d_in[28];
    const float* r_k     = (const float*)d_in[29];
    const float* ln_x_w  = (const float*)d_in[30];
    const float* ln_x_b  = (const float*)d_in[31];

    float* sc = nullptr;      cudaGetSymbolAddress((void**)&sc, g_scratch);
    float* hbuf = nullptr;    cudaGetSymbolAddress((void**)&hbuf, g_hbuf);
    float* pscan2 = nullptr;  cudaGetSymbolAddress((void**)&pscan2, g_pscan2);
    float* ypart = nullptr;   cudaGetSymbolAddress((void**)&ypart, g_ypart);
    __half* abuf = nullptr;   cudaGetSymbolAddress((void**)&abuf, g_abuf);
    __half* wbuf = nullptr;   cudaGetSymbolAddress((void**)&wbuf, g_wbuf);
    __half* g1buf = nullptr;  cudaGetSymbolAddress((void**)&g1buf, g_g1buf);
    __half* g2buf = nullptr;  cudaGetSymbolAddress((void**)&g2buf, g_g2buf);
    __half* ghbuf = nullptr;  cudaGetSymbolAddress((void**)&ghbuf, g_ghbuf);
    __half* lorabuf = nullptr; cudaGetSymbolAddress((void**)&lorabuf, g_lorabuf);

    cudaFuncSetAttribute(mm128_kernel, cudaFuncAttributeMaxDynamicSharedMemorySize, MM_SMEM);

#define SLOT(s) (sc + (size_t)(s) * NTOK_EL)

    float* out = (float*)d_out;
    const int OFF_OUT = 0;
    const int OFF_S1  = NTOK_EL;
    const int OFF_S2  = OFF_S1 + HID;
    const int OFF_VF  = OFF_S2 + NHEAD * HEADD * HEADD;
    const int TOTAL   = OFF_VF + NTOK_EL;
    bool full = (out_size >= TOTAL);

    float* s1_out = full ? out + OFF_S1 : nullptr;
    float* s2_out = full ? out + OFF_S2 : SLOT(S_TMP);

    const int EW_GRID = (NTOK_EL + 255) / 256;

    // weight conversions
    splitW4_kernel<<<dim3(64, 64, 4), 1024>>>(Wr, Wk, Wv, Wo, wbuf);
    splitW_kernel<<<dim3(8, 64), 1024>>>(g1, g1buf, HID, 256);
    splitW_kernel<<<dim3(64, 8), 1024>>>(g2, g2buf, 256, HID);
    splitW_kernel<<<dim3(3, 64), 1024>>>(a1, lorabuf, HID, 96);
    splitW_kernel<<<dim3(3, 64), 1024>>>(w1, lorabuf + LSLOT_H, HID, 96);
    splitW_kernel<<<dim3(2, 64), 1024>>>(v1, lorabuf + 2 * LSLOT_H, HID, 64);

    // fused LN + mix + fp16 split (6 slots: r,k,v,g,a,w)
    ln_mix_kernel<<<T_LEN, 256>>>(x, state1, ln1_w, ln1_b,
                                  x_r, x_k, x_v, x_g, x_a, x_w,
                                  abuf, s1_out);

    // mega-batch: r, k, v, g-down, a-down, w-down(tanh), v-down
    {
        MMJobs jobs;
        jobs.j[0] = { wbuf,                 SLOT(S_R),   nullptr, HID, HID, 0, 0 };
        jobs.j[1] = { wbuf + WSLOT_H,       SLOT(S_K),   nullptr, HID, HID, 0, 1 };
        jobs.j[2] = { wbuf + 2 * WSLOT_H,   SLOT(S_V),   nullptr, HID, HID, 0, 2 };
        jobs.j[3] = { g1buf,                SLOT(S_TMP), nullptr, 256, 256, 2, 3 };
        jobs.j[4] = { lorabuf,              hbuf,        nullptr, 128, 384, 0, 4 };
        jobs.j[5] = { lorabuf + LSLOT_H,    hbuf + 128,  nullptr, 128, 384, 3, 5 };
        jobs.j[6] = { lorabuf + 2 * LSLOT_H, hbuf + 256, nullptr, 128, 384, 0, 2 };
        mm128_kernel<<<dim3(16, 8, 7), 256, MM_SMEM>>>(abuf, jobs, HID);
    }

    // g-up: split sigmoid output, then @g2
    splitA_kernel<<<(T_LEN * 256 + 255) / 256, 256>>>(SLOT(S_TMP), ghbuf, T_LEN, 256);
    {
        MMJobs jobs;
        jobs.j[0] = { g2buf, SLOT(S_G), nullptr, HID, HID, 0, 0 };
        for (int i = 1; i < 7; i++) jobs.j[i] = jobs.j[0];
        mm128_kernel<<<dim3(16, 8, 1), 256, MM_SMEM>>>(ghbuf, jobs, 256);
    }

    // LoRA up (a, w, v) fp32
    lora_up_kernel<<<dim3(32, 16, 3), 256>>>(hbuf, a2, w2, v2, a0, w0, v0, v_first,
                                             SLOT(S_A), SLOT(S_W), SLOT(S_V));

    // prep pairs
    prep2_kernel<<<(NPAIR * NHEAD * 32 + 255) / 256, 256>>>(
        SLOT(S_K), SLOT(S_A), SLOT(S_W), SLOT(S_V), SLOT(S_R),
        k_k, k_a, SLOT(S_K2), pscan2);

    // two-step scan
    scan3_kernel<<<128, 256>>>(pscan2, state2, ypart, s2_out);

    // groupnorm + rkv + gate -> fp16 split into abuf slot 0
    post_kernel<<<(T_LEN * NHEAD * 32 + 255) / 256, 256>>>(
        ypart, SLOT(S_R), SLOT(S_K2), SLOT(S_V), SLOT(S_G),
        r_k, ln_x_w, ln_x_b, abuf);

    // out = x + z@Wo
    {
        MMJobs jobs;
        jobs.j[0] = { wbuf + 3 * WSLOT_H, out + OFF_OUT, x, HID, HID, 1, 0 };
        for (int i = 1; i < 7; i++) jobs.j[i] = jobs.j[0];
        mm128_kernel<<<dim3(16, 8, 1), 256, MM_SMEM>>>(abuf, jobs, HID);
    }

    // passthrough v_first
    if (full)
        copy_kernel<<<EW_GRID, 256>>>(v_first, out + OFF_VF, NTOK_EL);
}

// round 10
// speedup vs baseline: 4.9639x; 1.0199x over previous
#include <cuda_runtime.h>
#include <cuda_fp16.h>
#include <math.h>
#include <stdint.h>

#define T_LEN 1024
#define HID   2048
#define NHEAD 32
#define HEADD 64
#define NTOK_EL (T_LEN * HID)   // 2097152
#define NPAIR (T_LEN / 2)

#define ASLOT_H ((size_t)T_LEN * 2 * HID)   // A' slot: [M, 2K] fp16 {hi|lo}
#define WSLOT_H ((size_t)HID * HID)         // W' slot: [N, K] fp16 single plane
#define LSLOT_H ((size_t)128 * HID)         // lora-down W' slot (padded 128 rows)

// ---------------- static device scratch ----------------
__device__ float g_scratch[8u * (unsigned)NTOK_EL];
__device__ float g_hbuf[(size_t)T_LEN * 384];
__device__ float g_pscan2[(size_t)NPAIR * NHEAD * 1024];   // 16 planes x 64
__device__ float g_ypart[(size_t)T_LEN * HID * 4];
__device__ __align__(256) __half g_abuf[6 * ASLOT_H];      // xr,xk,xv,xg,xa,xw splits
__device__ __align__(256) __half g_wbuf[4 * WSLOT_H];      // Wr',Wk',Wv',Wo'
__device__ __align__(256) __half g_g1buf[(size_t)256 * HID];
__device__ __align__(256) __half g_g2buf[(size_t)HID * 256];
__device__ __align__(256) __half g_ghbuf[(size_t)T_LEN * 256];  // sigmoid(g-down), 1 plane
__device__ __align__(256) __half g_lorabuf[3 * LSLOT_H];   // a1',w1',v1' (zero-padded)

#define S_R   0
#define S_K   1
#define S_V   2
#define S_K2  3
#define S_G   4
#define S_TMP 5

// ---------------- helpers ----------------
__device__ __forceinline__ float blk_sum256(float v) {
    __shared__ float sh[8];
    int tid = threadIdx.x;
#pragma unroll
    for (int o = 16; o; o >>= 1) v += __shfl_xor_sync(0xffffffffu, v, o);
    if ((tid & 31) == 0) sh[tid >> 5] = v;
    __syncthreads();
    if (tid == 0) {
        float s = 0.f;
#pragma unroll
        for (int i = 0; i < 8; i++) s += sh[i];
        sh[0] = s;
    }
    __syncthreads();
    float r = sh[0];
    __syncthreads();
    return r;
}

__device__ __forceinline__ float warp_sum(float v) {
#pragma unroll
    for (int o = 16; o; o >>= 1) v += __shfl_xor_sync(0xffffffffu, v, o);
    return v;
}

__device__ __forceinline__ float sigmoidf(float v) {
    return 1.f / (1.f + __expf(-v));
}

__device__ __forceinline__ uint32_t smem_u32(const void* p) {
    uint32_t a;
    asm("{ .reg .u64 t; cvta.to.shared.u64 t, %1; cvt.u32.u64 %0, t; }" : "=r"(a) : "l"(p));
    return a;
}

__device__ __forceinline__ void hsplit(float v, __half& hi, __half& lo) {
    hi = __float2half_rn(v);
    lo = __float2half_rn(v - __half2float(hi));
}

// ======================= mma.sync fp16 GEMM =======================
#define MMK_STRIDE 80
#define MMK_TILE   (128 * MMK_STRIDE)
#define STAGE_BYTES (3 * MMK_TILE)
#define MM_SMEM (3 * STAGE_BYTES)

struct MMJob { const __half* B; float* C; const float* Res; int N; int ldc; int mode; int aslot; int planes; };
struct MMJobs { MMJob j[7]; };

__device__ __forceinline__ void cp16(uint32_t dst, const void* src) {
    asm volatile("cp.async.cg.shared.global [%0], [%1], 16;" :: "r"(dst), "l"(src));
}

__device__ __forceinline__ void ldsm4(uint32_t* r, uint32_t a) {
    asm volatile("ldmatrix.sync.aligned.m8n8.x4.shared.b16 {%0,%1,%2,%3}, [%4];"
                 : "=r"(r[0]), "=r"(r[1]), "=r"(r[2]), "=r"(r[3]) : "r"(a));
}

__device__ __forceinline__ void mma16816(float* c, const uint32_t* a, const uint32_t* b) {
    asm volatile(
        "mma.sync.aligned.m16n8k16.row.col.f32.f16.f16.f32 "
        "{%0,%1,%2,%3}, {%4,%5,%6,%7}, {%8,%9}, {%0,%1,%2,%3};"
        : "+f"(c[0]), "+f"(c[1]), "+f"(c[2]), "+f"(c[3])
        : "r"(a[0]), "r"(a[1]), "r"(a[2]), "r"(a[3]), "r"(b[0]), "r"(b[1]));
}

// aMul: A row stride = aMul*K (2 = {hi|lo} split layout, 1 = single plane)
__global__ void __launch_bounds__(256, 2) mm128_kernel(
    const __half* __restrict__ A, MMJobs jobs, int K, int aMul)
{
    extern __shared__ __align__(16) char smem[];
    uint32_t sbase = smem_u32(smem);

    const MMJob job = jobs.j[blockIdx.z];
    const int N = job.N;
    int n0 = blockIdx.x * 128;
    if (n0 >= N) return;
    int m0 = blockIdx.y * 128;

    const __half* Ab = A + (size_t)job.aslot * ASLOT_H;
    const __half* Bb = job.B;
    const int KA = aMul * K;
    const int nk = K >> 5;
    const int planes = job.planes;

    int tid = threadIdx.x;
    int wid = tid >> 5, lane = tid & 31;
    int g = lane >> 2, tig = lane & 3;
    int warp_m = wid >> 2;
    int warp_n = wid & 3;

    float acc[4][4][4];
#pragma unroll
    for (int i = 0; i < 4; i++)
#pragma unroll
        for (int j = 0; j < 4; j++)
#pragma unroll
            for (int q = 0; q < 4; q++) acc[i][j][q] = 0.f;

    auto load_stage = [&](int s, int kc) {
        uint32_t st = sbase + s * STAGE_BYTES;
        int k0 = kc << 5;
#pragma unroll
        for (int it = 0; it < 2; it++) {       // Ah
            int idx = tid + it * 256;
            int r = idx >> 2, c = idx & 3;
            cp16(st + r * MMK_STRIDE + c * 16, Ab + ((size_t)(m0 + r) * KA + k0 + c * 8));
        }
        if (planes == 2) {
#pragma unroll
            for (int it = 0; it < 2; it++) {   // Al
                int idx = tid + it * 256;
                int r = idx >> 2, c = idx & 3;
                cp16(st + MMK_TILE + r * MMK_STRIDE + c * 16,
                     Ab + ((size_t)(m0 + r) * KA + K + k0 + c * 8));
            }
        }
#pragma unroll
        for (int it = 0; it < 2; it++) {       // B
            int idx = tid + it * 256;
            int r = idx >> 2, c = idx & 3;
            cp16(st + 2 * MMK_TILE + r * MMK_STRIDE + c * 16,
                 Bb + ((size_t)(n0 + r) * K + k0 + c * 8));
        }
        asm volatile("cp.async.commit_group;" ::: "memory");
    };

    load_stage(0, 0);
    if (nk > 1) load_stage(1, 1);
    else asm volatile("cp.async.commit_group;" ::: "memory");

    int aRowSel = (lane & 15);
    int aColSel = (lane & 16) ? 16 : 0;
    int bRowSel = ((lane & 16) ? 8 : 0) + (lane & 7);
    int bColSel = (lane & 8) ? 16 : 0;

    for (int kc = 0; kc < nk; kc++) {
        asm volatile("cp.async.wait_group 1;" ::: "memory");
        __syncthreads();
        if (kc + 2 < nk) load_stage((kc + 2) % 3, kc + 2);
        else asm volatile("cp.async.commit_group;" ::: "memory");

        uint32_t st = sbase + (kc % 3) * STAGE_BYTES;
#pragma unroll
        for (int ks = 0; ks < 2; ks++) {
            uint32_t afr[4][4], bfr[2][4];
#pragma unroll
            for (int ap = 0; ap < 2; ap++) {
                uint32_t addr = st + 2 * MMK_TILE
                                + (uint32_t)(warp_n * 32 + ap * 16 + bRowSel) * MMK_STRIDE
                                + ks * 32 + bColSel;
                ldsm4(bfr[ap], addr);
            }
#pragma unroll
            for (int am = 0; am < 4; am++) {
                uint32_t addr = st + (uint32_t)(warp_m * 64 + am * 16 + aRowSel) * MMK_STRIDE
                                + ks * 32 + aColSel;
                ldsm4(afr[am], addr);
            }
#pragma unroll
            for (int am = 0; am < 4; am++) {
                mma16816(acc[am][0], afr[am], &bfr[0][0]);
                mma16816(acc[am][1], afr[am], &bfr[0][2]);
                mma16816(acc[am][2], afr[am], &bfr[1][0]);
                mma16816(acc[am][3], afr[am], &bfr[1][2]);
            }
            if (planes == 2) {
#pragma unroll
                for (int am = 0; am < 4; am++) {
                    uint32_t addr = st + MMK_TILE
                                    + (uint32_t)(warp_m * 64 + am * 16 + aRowSel) * MMK_STRIDE
                                    + ks * 32 + aColSel;
                    ldsm4(afr[am], addr);
                }
#pragma unroll
                for (int am = 0; am < 4; am++) {
                    mma16816(acc[am][0], afr[am], &bfr[0][0]);
                    mma16816(acc[am][1], afr[am], &bfr[0][2]);
                    mma16816(acc[am][2], afr[am], &bfr[1][0]);
                    mma16816(acc[am][3], afr[am], &bfr[1][2]);
                }
            }
        }
    }

    __syncthreads();

    float* C = job.C;
    const float* Res = job.Res;
    int mode = job.mode;
    int ldc = job.ldc;
#pragma unroll
    for (int am = 0; am < 4; am++) {
#pragma unroll
        for (int an = 0; an < 4; an++) {
            int row = m0 + warp_m * 64 + am * 16 + g;
            int col = n0 + warp_n * 32 + an * 8 + tig * 2;
            float2 v0 = make_float2(acc[am][an][0], acc[am][an][1]);
            float2 v1 = make_float2(acc[am][an][2], acc[am][an][3]);
            if (mode == 4) {
                // sigmoid -> fp16 single-plane store
                __half* Ch = (__half*)C;
                *(__half2*)(Ch + (size_t)row * ldc + col) =
                    __floats2half2_rn(sigmoidf(v0.x), sigmoidf(v0.y));
                *(__half2*)(Ch + (size_t)(row + 8) * ldc + col) =
                    __floats2half2_rn(sigmoidf(v1.x), sigmoidf(v1.y));
                continue;
            }
            if (mode == 1) {
                const float2 r0 = *(const float2*)(Res + (size_t)row * ldc + col);
                const float2 r1 = *(const float2*)(Res + (size_t)(row + 8) * ldc + col);
                v0.x += r0.x; v0.y += r0.y;
                v1.x += r1.x; v1.y += r1.y;
            } else if (mode == 3) {
                v0.x = tanhf(v0.x); v0.y = tanhf(v0.y);
                v1.x = tanhf(v1.x); v1.y = tanhf(v1.y);
            }
            *(float2*)(C + (size_t)row * ldc + col) = v0;
            *(float2*)(C + (size_t)(row + 8) * ldc + col) = v1;
        }
    }
}

// ---------------- unified weight conversion + v_first copy (one launch) ----------------
__device__ __forceinline__ void conv_tile(const float* __restrict__ W, __half* __restrict__ out,
                                          int K, int N, int bx, int by, float (*tile)[33])
{
    int k0 = by * 32, n0 = bx * 32;
    int tx = threadIdx.x & 31, ty = threadIdx.x >> 5;
    tile[ty][tx] = W[(size_t)(k0 + ty) * N + n0 + tx];
    __syncthreads();
    int tid = threadIdx.x;
    if (tid >= 512) return;
    int nl = tid >> 4, kp = (tid & 15) * 2;
    __half2 h = __floats2half2_rn(tile[kp][nl], tile[kp + 1][nl]);
    *(__half2*)(out + (size_t)(n0 + nl) * K + k0 + kp) = h;
}

__global__ void __launch_bounds__(1024) prepw_kernel(
    const float* __restrict__ Wr, const float* __restrict__ Wk,
    const float* __restrict__ Wv, const float* __restrict__ Wo,
    const float* __restrict__ g1, const float* __restrict__ g2,
    const float* __restrict__ a1, const float* __restrict__ w1,
    const float* __restrict__ v1, const float* __restrict__ vf,
    __half* __restrict__ wbuf, __half* __restrict__ g1buf,
    __half* __restrict__ g2buf, __half* __restrict__ lorabuf,
    float* __restrict__ vfout)
{
    __shared__ float tile[32][33];
    int b = blockIdx.x;
    if (b < 16384) {
        int z = b >> 12, rem = b & 4095;
        const float* W = z == 0 ? Wr : z == 1 ? Wk : z == 2 ? Wv : Wo;
        conv_tile(W, wbuf + (size_t)z * WSLOT_H, HID, HID, rem & 63, rem >> 6, tile);
    } else if (b < 16896) {
        int rem = b - 16384;
        conv_tile(g1, g1buf, HID, 256, rem & 7, rem >> 3, tile);
    } else if (b < 17408) {
        int rem = b - 16896;
        conv_tile(g2, g2buf, 256, HID, rem & 63, rem >> 6, tile);
    } else if (b < 17600) {
        int rem = b - 17408;
        conv_tile(a1, lorabuf, HID, 96, rem % 3, rem / 3, tile);
    } else if (b < 17792) {
        int rem = b - 17600;
        conv_tile(w1, lorabuf + LSLOT_H, HID, 96, rem % 3, rem / 3, tile);
    } else if (b < 17920) {
        int rem = b - 17792;
        conv_tile(v1, lorabuf + 2 * LSLOT_H, HID, 64, rem & 1, rem >> 1, tile);
    } else {
        if (!vfout) return;
        int rem = b - 17920;                       // 0..511
        size_t i = (size_t)rem * 4096 + threadIdx.x * 4;
        *(float4*)(vfout + i) = *(const float4*)(vf + i);
    }
}

// ---------------- fused LN + token-shift mix + fp16 split (6 slots) ----------------
__global__ void __launch_bounds__(256) ln_mix_kernel(
    const float* __restrict__ x, const float* __restrict__ state1,
    const float* __restrict__ lnw, const float* __restrict__ lnb,
    const float* __restrict__ cr, const float* __restrict__ ck,
    const float* __restrict__ cv, const float* __restrict__ cg,
    const float* __restrict__ ca, const float* __restrict__ cw,
    __half* __restrict__ abuf,
    float* __restrict__ state1_out)
{
    int t = blockIdx.x;
    const float* xt = x + (size_t)t * HID;
    const float* xp = x + (size_t)(t - 1) * HID;

    float2 v0[4], v1[4];
    float s0 = 0.f, s1 = 0.f;
#pragma unroll
    for (int j = 0; j < 4; j++) {
        int c = threadIdx.x * 2 + j * 512;
        v0[j] = *(const float2*)(xt + c);
        s0 += v0[j].x + v0[j].y;
        v1[j] = t ? *(const float2*)(xp + c) : make_float2(0.f, 0.f);
        s1 += v1[j].x + v1[j].y;
    }
    float mu0 = blk_sum256(s0) * (1.f / HID);
    float mu1 = blk_sum256(s1) * (1.f / HID);
    float q0 = 0.f, q1 = 0.f;
#pragma unroll
    for (int j = 0; j < 4; j++) {
        float d;
        d = v0[j].x - mu0; q0 += d * d;
        d = v0[j].y - mu0; q0 += d * d;
        d = v1[j].x - mu1; q1 += d * d;
        d = v1[j].y - mu1; q1 += d * d;
    }
    float inv0 = rsqrtf(blk_sum256(q0) * (1.f / HID) + 1e-5f);
    float inv1 = rsqrtf(blk_sum256(q1) * (1.f / HID) + 1e-5f);

#pragma unroll
    for (int j = 0; j < 4; j++) {
        int c = threadIdx.x * 2 + j * 512;
        float2 wv = *(const float2*)(lnw + c);
        float2 bv = *(const float2*)(lnb + c);
        float xn0 = (v0[j].x - mu0) * inv0 * wv.x + bv.x;
        float xn1 = (v0[j].y - mu0) * inv0 * wv.y + bv.y;
        float pv0 = t ? (v1[j].x - mu1) * inv1 * wv.x + bv.x : state1[c];
        float pv1 = t ? (v1[j].y - mu1) * inv1 * wv.y + bv.y : state1[c + 1];
        float sx0 = pv0 - xn0, sx1 = pv1 - xn1;

        __half* arow = abuf + (size_t)t * 2 * HID + c;
#pragma unroll
        for (int s = 0; s < 6; s++) {
            const float* coefA = (s == 0) ? cr : (s == 1) ? ck : (s == 2) ? cv
                               : (s == 3) ? cg : (s == 4) ? ca : cw;
            float a0 = xn0 + coefA[c] * sx0;
            float a1 = xn1 + coefA[c + 1] * sx1;
            __half h0, l0, h1, l1;
            hsplit(a0, h0, l0);
            hsplit(a1, h1, l1);
            __half* p = arow + (size_t)s * ASLOT_H;
            *(__half2*)(p) = __half2(h0, h1);
            if (s != 4)   // slot 4 (xa) is consumed single-plane
                *(__half2*)(p + HID) = __half2(l0, l1);
        }
        if (state1_out && t == T_LEN - 1) {
            state1_out[c] = xn0;
            state1_out[c + 1] = xn1;
        }
    }
}

// ---------------- fused LoRA-up (+activations) + scan prep ----------------
// Block = (64 tokens, 1 head). Phase 1: a/w/v up-GEMMs -> smem (+v to global).
// Phase 2: kk norm, k2, pair scalars, pscan2 planes.
#define FIN_SP 66
#define FIN_SMEM ((3 * 64 * FIN_SP + 16 * 65 * 2) * 4)

__global__ void __launch_bounds__(256) finish_kernel(
    const float* __restrict__ hbuf,
    const float* __restrict__ a2, const float* __restrict__ w2, const float* __restrict__ v2,
    const float* __restrict__ a0, const float* __restrict__ w0, const float* __restrict__ v0b,
    const float* __restrict__ vf,
    const float* __restrict__ kbuf, const float* __restrict__ rbuf,
    float* __restrict__ vslot,
    const float* __restrict__ k_k, const float* __restrict__ k_a,
    float* __restrict__ k2out, float* __restrict__ pscan2)
{
    extern __shared__ float fs[];
    float* a_s = fs;
    float* w_s = fs + 64 * FIN_SP;
    float* v_s = fs + 2 * 64 * FIN_SP;
    float* As = fs + 3 * 64 * FIN_SP;          // [16][65]
    float* Bs = As + 16 * 65;                  // [16][65]

    int tb = blockIdx.x >> 5;     // token block 0..15
    int h = blockIdx.x & 31;      // head
    int t0 = tb * 64;
    int cb = h * HEADD;

    int tid = threadIdx.x;
    int tx = tid & 15, ty = tid >> 4;

    // -------- phase 1: three up-GEMMs with fused activations --------
#pragma unroll
    for (int z = 0; z < 3; z++) {
        const float* B = z == 0 ? a2 : z == 1 ? w2 : v2;
        const float* bias = z == 0 ? a0 : z == 1 ? w0 : v0b;
        int K = (z == 2) ? 64 : 96;
        int zoff = z * 128;
        float acc[4][4] = {};
        for (int k0 = 0; k0 < K; k0 += 16) {
#pragma unroll
            for (int i = tid; i < 64 * 16; i += 256) {
                int r = i >> 4, c = i & 15;
                As[c * 65 + r] = hbuf[(size_t)(t0 + r) * 384 + zoff + k0 + c];
            }
#pragma unroll
            for (int i = tid; i < 16 * 64; i += 256) {
                int r = i >> 6, c = i & 63;
                Bs[r * 65 + c] = B[(size_t)(k0 + r) * HID + cb + c];
            }
            __syncthreads();
#pragma unroll
            for (int kk = 0; kk < 16; kk++) {
                float a[4], b[4];
#pragma unroll
                for (int i = 0; i < 4; i++) a[i] = As[kk * 65 + ty * 4 + i];
#pragma unroll
                for (int jj = 0; jj < 4; jj++) b[jj] = Bs[kk * 65 + tx * 4 + jj];
#pragma unroll
                for (int i = 0; i < 4; i++)
#pragma unroll
                    for (int jj = 0; jj < 4; jj++) acc[i][jj] = fmaf(a[i], b[jj], acc[i][jj]);
            }
            __syncthreads();
        }
#pragma unroll
        for (int i = 0; i < 4; i++) {
            int lr = ty * 4 + i;
#pragma unroll
            for (int jj = 0; jj < 4; jj++) {
                int lc = tx * 4 + jj;
                float s = sigmoidf(bias[cb + lc] + acc[i][jj]);
                if (z == 0) a_s[lr * FIN_SP + lc] = s;
                else if (z == 1) w_s[lr * FIN_SP + lc] = __expf(-0.606531f * s);
                else {
                    size_t gi = (size_t)(t0 + lr) * HID + cb + lc;
                    float vv = vslot[gi];
                    float nv = vv + (vf[gi] - vv) * s;
                    v_s[lr * FIN_SP + lc] = nv;
                    vslot[gi] = nv;
                }
            }
        }
        __syncthreads();
    }

    // -------- phase 2: pair prep (8 warps x 4 pairs) --------
    int wrp = tid >> 5, lane = tid & 31;
#pragma unroll
    for (int pi = 0; pi < 4; pi++) {
        int pp = wrp * 4 + pi;            // local pair 0..31
        int r0 = 2 * pp, r1 = r0 + 1;
        int pr = tb * 32 + pp;            // global pair
        int b0 = (t0 + r0) * HID + cb;
        int b1 = b0 + HID;

        // step 0
        float kA0 = kbuf[b0 + lane], kB0 = kbuf[b0 + lane + 32];
        float qA0 = kA0 * k_k[cb + lane], qB0 = kB0 * k_k[cb + lane + 32];
        float inv0 = 1.f / fmaxf(sqrtf(warp_sum(qA0 * qA0 + qB0 * qB0)), 1e-12f);
        float kkA0 = qA0 * inv0, kkB0 = qB0 * inv0;
        float aA0 = a_s[r0 * FIN_SP + lane], aB0 = a_s[r0 * FIN_SP + lane + 32];
        float k2A0 = kA0 * (1.f + (aA0 - 1.f) * k_a[cb + lane]);
        float k2B0 = kB0 * (1.f + (aB0 - 1.f) * k_a[cb + lane + 32]);
        k2out[b0 + lane] = k2A0;
        k2out[b0 + lane + 32] = k2B0;

        // step 1
        float kA1 = kbuf[b1 + lane], kB1 = kbuf[b1 + lane + 32];
        float qA1 = kA1 * k_k[cb + lane], qB1 = kB1 * k_k[cb + lane + 32];
        float inv1 = 1.f / fmaxf(sqrtf(warp_sum(qA1 * qA1 + qB1 * qB1)), 1e-12f);
        float kkA1 = qA1 * inv1, kkB1 = qB1 * inv1;
        float aA1 = a_s[r1 * FIN_SP + lane], aB1 = a_s[r1 * FIN_SP + lane + 32];
        float k2A1 = kA1 * (1.f + (aA1 - 1.f) * k_a[cb + lane]);
        float k2B1 = kB1 * (1.f + (aB1 - 1.f) * k_a[cb + lane + 32]);
        k2out[b1 + lane] = k2A1;
        k2out[b1 + lane + 32] = k2B1;

        float wA0 = w_s[r0 * FIN_SP + lane], wB0 = w_s[r0 * FIN_SP + lane + 32];
        float kaA0 = kkA0 * aA0, kaB0 = kkB0 * aB0;

        float c1 = warp_sum(kkA1 * kaA0 + kkB1 * kaB0);
        float c2 = warp_sum(kkA1 * k2A0 + kkB1 * k2B0);

        float* P = pscan2 + ((size_t)pr * NHEAD + h) * 1024;
        P[0 * 64 + lane] = kkA0;           P[0 * 64 + lane + 32] = kkB0;
        P[1 * 64 + lane] = kkA1 * wA0;     P[1 * 64 + lane + 32] = kkB1 * wB0;
        P[2 * 64 + lane] = wA0;            P[2 * 64 + lane + 32] = wB0;
        P[3 * 64 + lane] = kaA0;           P[3 * 64 + lane + 32] = kaB0;
        P[4 * 64 + lane] = k2A0;           P[4 * 64 + lane + 32] = k2B0;
        P[5 * 64 + lane] = rbuf[b0 + lane]; P[5 * 64 + lane + 32] = rbuf[b0 + lane + 32];
        P[6 * 64 + lane] = w_s[r1 * FIN_SP + lane]; P[6 * 64 + lane + 32] = w_s[r1 * FIN_SP + lane + 32];
        P[7 * 64 + lane] = kkA1 * aA1;     P[7 * 64 + lane + 32] = kkB1 * aB1;
        P[8 * 64 + lane] = k2A1;           P[8 * 64 + lane + 32] = k2B1;
        P[9 * 64 + lane] = rbuf[b1 + lane]; P[9 * 64 + lane + 32] = rbuf[b1 + lane + 32];
        P[10 * 64 + lane] = v_s[r0 * FIN_SP + lane]; P[10 * 64 + lane + 32] = v_s[r0 * FIN_SP + lane + 32];
        P[11 * 64 + lane] = v_s[r1 * FIN_SP + lane]; P[11 * 64 + lane + 32] = v_s[r1 * FIN_SP + lane + 32];
        if (lane == 0) { P[12 * 64] = c1; P[12 * 64 + 1] = c2; }
    }
}

// ---------------- scan v3: two steps per reduction round ----------------
__global__ void __launch_bounds__(256) scan3_kernel(
    const float* __restrict__ pscan2,
    const float* __restrict__ state2, float* __restrict__ ypart,
    float* __restrict__ Sout)
{
    int h = blockIdx.x >> 2;
    int q = blockIdx.x & 3;
    int tid = threadIdx.x;
    int wrp = tid >> 5, lane = tid & 31;
    int rsel = lane >> 4, colg = lane & 15;
    int row = q * 16 + 2 * wrp + rsel;

    float4 S = *(const float4*)(state2 + (size_t)h * 4096 + row * 64 + colg * 4);

    __shared__ float buf[2][1024];

    const float* pB = pscan2 + (size_t)h * 1024;
    const size_t pstride = (size_t)NHEAD * 1024;

    ((float4*)buf[0])[tid] = *(const float4*)(pB + tid * 4);
    float4 preA = *(const float4*)(pB + pstride + tid * 4);
    float4 preB;

    for (int pr = 0; pr < NPAIR; pr++) {
        __syncthreads();
        preB = (pr + 2 < NPAIR) ? *(const float4*)(pB + (size_t)(pr + 2) * pstride + tid * 4)
                                : preA;
        const float* b = buf[pr & 1];
        float4 kk4  = *(const float4*)(b + 0 * 64 + colg * 4);
        float4 kkw4 = *(const float4*)(b + 1 * 64 + colg * 4);
        float4 w4   = *(const float4*)(b + 2 * 64 + colg * 4);
        float4 ka4  = *(const float4*)(b + 3 * 64 + colg * 4);
        float4 k4   = *(const float4*)(b + 4 * 64 + colg * 4);
        float4 r4   = *(const float4*)(b + 5 * 64 + colg * 4);
        float4 w14  = *(const float4*)(b + 6 * 64 + colg * 4);
        float4 ka14 = *(const float4*)(b + 7 * 64 + colg * 4);
        float4 k14  = *(const float4*)(b + 8 * 64 + colg * 4);
        float4 r14  = *(const float4*)(b + 9 * 64 + colg * 4);
        float v0 = b[10 * 64 + row];
        float v1 = b[11 * 64 + row];
        float c1 = b[12 * 64];
        float c2 = b[12 * 64 + 1];

        float d0 = S.x * kk4.x + S.y * kk4.y + S.z * kk4.z + S.w * kk4.w;
        float d1 = S.x * kkw4.x + S.y * kkw4.y + S.z * kkw4.z + S.w * kkw4.w;
#pragma unroll
        for (int o = 1; o <= 8; o <<= 1) {
            d0 += __shfl_xor_sync(0xffffffffu, d0, o);
            d1 += __shfl_xor_sync(0xffffffffu, d1, o);
        }
        float p0 = d0;
        float p1 = d1 - p0 * c1 + v0 * c2;

        S.x = S.x * w4.x - p0 * ka4.x + v0 * k4.x;
        S.y = S.y * w4.y - p0 * ka4.y + v0 * k4.y;
        S.z = S.z * w4.z - p0 * ka4.z + v0 * k4.z;
        S.w = S.w * w4.w - p0 * ka4.w + v0 * k4.w;

        float y0 = S.x * r4.x + S.y * r4.y + S.z * r4.z + S.w * r4.w;
        y0 += __shfl_xor_sync(0xffffffffu, y0, 1);
        y0 += __shfl_xor_sync(0xffffffffu, y0, 2);
        if ((colg & 3) == 0)
            ypart[((size_t)(2 * pr) * HID + h * HEADD + row) * 4 + (colg >> 2)] = y0;

        if (pr + 1 < NPAIR)
            ((float4*)buf[(pr + 1) & 1])[tid] = preA;
        preA = preB;

        S.x = S.x * w14.x - p1 * ka14.x + v1 * k14.x;
        S.y = S.y * w14.y - p1 * ka14.y + v1 * k14.y;
        S.z = S.z * w14.z - p1 * ka14.z + v1 * k14.z;
        S.w = S.w * w14.w - p1 * ka14.w + v1 * k14.w;

        float y1 = S.x * r14.x + S.y * r14.y + S.z * r14.z + S.w * r14.w;
        y1 += __shfl_xor_sync(0xffffffffu, y1, 1);
        y1 += __shfl_xor_sync(0xffffffffu, y1, 2);
        if ((colg & 3) == 0)
            ypart[((size_t)(2 * pr + 1) * HID + h * HEADD + row) * 4 + (colg >> 2)] = y1;
    }
    *(float4*)(Sout + (size_t)h * 4096 + row * 64 + colg * 4) = S;
}

// ---------------- groupnorm + rkv + gate -> fp16 split into abuf ----------------
__global__ void __launch_bounds__(256) post_kernel(
    const float* __restrict__ ypart, const float* __restrict__ r,
    const float* __restrict__ k2, const float* __restrict__ v,
    const float* __restrict__ g, const float* __restrict__ r_k,
    const float* __restrict__ lnxw, const float* __restrict__ lnxb,
    __half* __restrict__ zsplit)
{
    int gw = (blockIdx.x * 256 + threadIdx.x) >> 5;
    int lane = threadIdx.x & 31;
    if (gw >= T_LEN * NHEAD) return;
    int t = gw >> 5, h = gw & 31;
    int base = t * HID + h * HEADD;
    int cb = h * HEADD;

    float4 yp0 = *(const float4*)(ypart + (size_t)(base + lane) * 4);
    float4 yp1 = *(const float4*)(ypart + (size_t)(base + lane + 32) * 4);
    float y0 = (yp0.x + yp0.y) + (yp0.z + yp0.w);
    float y1 = (yp1.x + yp1.y) + (yp1.z + yp1.w);

    float mu = warp_sum(y0 + y1) * (1.f / HEADD);
    float d0 = y0 - mu, d1 = y1 - mu;
    float var = warp_sum(d0 * d0 + d1 * d1) * (1.f / HEADD);
    float inv = rsqrtf(var + 0.00064f);

    float rs = warp_sum(r[base + lane] * k2[base + lane] * r_k[cb + lane] +
                        r[base + lane + 32] * k2[base + lane + 32] * r_k[cb + lane + 32]);

    float z0 = (d0 * inv * lnxw[cb + lane] + lnxb[cb + lane] + rs * v[base + lane]) * g[base + lane];
    float z1 = (d1 * inv * lnxw[cb + lane + 32] + lnxb[cb + lane + 32] + rs * v[base + lane + 32]) * g[base + lane + 32];

    size_t zb = (size_t)t * 2 * HID;
    __half h0, l0, h1, l1;
    hsplit(z0, h0, l0);
    hsplit(z1, h1, l1);
    zsplit[zb + cb + lane] = h0;
    zsplit[zb + HID + cb + lane] = l0;
    zsplit[zb + cb + lane + 32] = h1;
    zsplit[zb + HID + cb + lane + 32] = l1;
}

// ---------------- host launcher ----------------
extern "C" void kernel_launch(void* const* d_in, const int* in_sizes, int n_in,
                              void* d_out, int out_size)
{
    const float* x       = (const float*)d_in[0];
    const float* state1  = (const float*)d_in[1];
    const float* state2  = (const float*)d_in[2];
    const float* v_first = (const float*)d_in[3];
    const float* ln1_w   = (const float*)d_in[4];
    const float* ln1_b   = (const float*)d_in[5];
    const float* x_r     = (const float*)d_in[6];
    const float* x_w     = (const float*)d_in[7];
    const float* x_k     = (const float*)d_in[8];
    const float* x_v     = (const float*)d_in[9];
    const float* x_a     = (const float*)d_in[10];
    const float* x_g     = (const float*)d_in[11];
    const float* Wr      = (const float*)d_in[12];
    const float* Wk      = (const float*)d_in[13];
    const float* Wv      = (const float*)d_in[14];
    const float* Wo      = (const float*)d_in[15];
    const float* w0      = (const float*)d_in[16];
    const float* w1      = (const float*)d_in[17];
    const float* w2      = (const float*)d_in[18];
    const float* a0      = (const float*)d_in[19];
    const float* a1      = (const float*)d_in[20];
    const float* a2      = (const float*)d_in[21];
    const float* v0      = (const float*)d_in[22];
    const float* v1      = (const float*)d_in[23];
    const float* v2      = (const float*)d_in[24];
    const float* g1      = (const float*)d_in[25];
    const float* g2      = (const float*)d_in[26];
    const float* k_k     = (const float*)d_in[27];
    const float* k_a     = (const float*)d_in[28];
    const float* r_k     = (const float*)d_in[29];
    const float* ln_x_w  = (const float*)d_in[30];
    const float* ln_x_b  = (const float*)d_in[31];

    float* sc = nullptr;      cudaGetSymbolAddress((void**)&sc, g_scratch);
    float* hbuf = nullptr;    cudaGetSymbolAddress((void**)&hbuf, g_hbuf);
    float* pscan2 = nullptr;  cudaGetSymbolAddress((void**)&pscan2, g_pscan2);
    float* ypart = nullptr;   cudaGetSymbolAddress((void**)&ypart, g_ypart);
    __half* abuf = nullptr;   cudaGetSymbolAddress((void**)&abuf, g_abuf);
    __half* wbuf = nullptr;   cudaGetSymbolAddress((void**)&wbuf, g_wbuf);
    __half* g1buf = nullptr;  cudaGetSymbolAddress((void**)&g1buf, g_g1buf);
    __half* g2buf = nullptr;  cudaGetSymbolAddress((void**)&g2buf, g_g2buf);
    __half* ghbuf = nullptr;  cudaGetSymbolAddress((void**)&ghbuf, g_ghbuf);
    __half* lorabuf = nullptr; cudaGetSymbolAddress((void**)&lorabuf, g_lorabuf);

    cudaFuncSetAttribute(mm128_kernel, cudaFuncAttributeMaxDynamicSharedMemorySize, MM_SMEM);
    cudaFuncSetAttribute(finish_kernel, cudaFuncAttributeMaxDynamicSharedMemorySize, FIN_SMEM);

#define SLOT(s) (sc + (size_t)(s) * NTOK_EL)

    float* out = (float*)d_out;
    const int OFF_OUT = 0;
    const int OFF_S1  = NTOK_EL;
    const int OFF_S2  = OFF_S1 + HID;
    const int OFF_VF  = OFF_S2 + NHEAD * HEADD * HEADD;
    const int TOTAL   = OFF_VF + NTOK_EL;
    bool full = (out_size >= TOTAL);

    float* s1_out = full ? out + OFF_S1 : nullptr;
    float* s2_out = full ? out + OFF_S2 : SLOT(S_TMP);
    float* vf_out = full ? out + OFF_VF : nullptr;

    // 1. unified weight conversion + v_first passthrough
    prepw_kernel<<<18432, 1024>>>(Wr, Wk, Wv, Wo, g1, g2, a1, w1, v1, v_first,
                                  wbuf, g1buf, g2buf, lorabuf, vf_out);

    // 2. fused LN + mix + fp16 split (6 slots: r,k,v,g,a,w)
    ln_mix_kernel<<<T_LEN, 256>>>(x, state1, ln1_w, ln1_b,
                                  x_r, x_k, x_v, x_g, x_a, x_w,
                                  abuf, s1_out);

    // 3. mega-batch: r, k, v, g-down(sigmoid->fp16), a-down(1-plane), w-down(tanh), v-down
    {
        MMJobs jobs;
        jobs.j[0] = { wbuf,                  SLOT(S_R),      nullptr, HID, HID, 0, 0, 2 };
        jobs.j[1] = { wbuf + WSLOT_H,        SLOT(S_K),      nullptr, HID, HID, 0, 1, 2 };
        jobs.j[2] = { wbuf + 2 * WSLOT_H,    SLOT(S_V),      nullptr, HID, HID, 0, 2, 2 };
        jobs.j[3] = { g1buf,                 (float*)ghbuf,  nullptr, 256, 256, 4, 3, 2 };
        jobs.j[4] = { lorabuf,               hbuf,           nullptr, 128, 384, 0, 4, 1 };
        jobs.j[5] = { lorabuf + LSLOT_H,     hbuf + 128,     nullptr, 128, 384, 3, 5, 2 };
        jobs.j[6] = { lorabuf + 2 * LSLOT_H, hbuf + 256,     nullptr, 128, 384, 0, 2, 2 };
        mm128_kernel<<<dim3(16, 8, 7), 256, MM_SMEM>>>(abuf, jobs, HID, 2);
    }

    // 4. g-up: single-plane fp16 A (sigmoid output), @g2
    {
        MMJobs jobs;
        jobs.j[0] = { g2buf, SLOT(S_G), nullptr, HID, HID, 0, 0, 1 };
        for (int i = 1; i < 7; i++) jobs.j[i] = jobs.j[0];
        mm128_kernel<<<dim3(16, 8, 1), 256, MM_SMEM>>>(ghbuf, jobs, 256, 1);
    }

    // 5. fused LoRA-up + prep
    finish_kernel<<<512, 256, FIN_SMEM>>>(hbuf, a2, w2, v2, a0, w0, v0, v_first,
                                          SLOT(S_K), SLOT(S_R), SLOT(S_V),
                                          k_k, k_a, SLOT(S_K2), pscan2);

    // 6. two-step scan
    scan3_kernel<<<128, 256>>>(pscan2, state2, ypart, s2_out);

    // 7. groupnorm + rkv + gate -> fp16 split into abuf slot 0
    post_kernel<<<(T_LEN * NHEAD * 32 + 255) / 256, 256>>>(
        ypart, SLOT(S_R), SLOT(S_K2), SLOT(S_V), SLOT(S_G),
        r_k, ln_x_w, ln_x_b, abuf);

    // 8. out = x + z@Wo
    {
        MMJobs jobs;
        jobs.j[0] = { wbuf + 3 * WSLOT_H, out + OFF_OUT, x, HID, HID, 1, 0, 2 };
        for (int i = 1; i < 7; i++) jobs.j[i] = jobs.j[0];
        mm128_kernel<<<dim3(16, 8, 1), 256, MM_SMEM>>>(abuf, jobs, HID, 2);
    }
}

// round 11
// speedup vs baseline: 5.3775x; 1.0833x over previous
#include <cuda_runtime.h>
#include <cuda_fp16.h>
#include <math.h>
#include <stdint.h>

#define T_LEN 1024
#define HID   2048
#define NHEAD 32
#define HEADD 64
#define NTOK_EL (T_LEN * HID)   // 2097152
#define NPAIR (T_LEN / 2)

#define ASLOT_H ((size_t)T_LEN * 2 * HID)   // A' slot: [M, 2K] fp16 {hi|lo}
#define WSLOT_H ((size_t)HID * HID)         // W' slot: [N, K] fp16 single plane
#define LSLOT_H ((size_t)128 * HID)         // lora-down W' slot (padded 128 rows)

// ---------------- static device scratch ----------------
__device__ float g_scratch[8u * (unsigned)NTOK_EL];
__device__ float g_hbuf[(size_t)T_LEN * 384];
__device__ float g_pscan2[(size_t)NPAIR * NHEAD * 1024];   // 16 planes x 64
__device__ float g_ypart[(size_t)T_LEN * HID * 4];
__device__ __align__(256) __half g_abuf[6 * ASLOT_H];      // xr,xk,xv,xg,xa,xw splits
__device__ __align__(256) __half g_wbuf[4 * WSLOT_H];      // Wr',Wk',Wv',Wo'
__device__ __align__(256) __half g_g1buf[(size_t)256 * HID];
__device__ __align__(256) __half g_g2buf[(size_t)HID * 256];
__device__ __align__(256) __half g_ghbuf[(size_t)T_LEN * 256];  // sigmoid(g-down), 1 plane
__device__ __align__(256) __half g_lorabuf[3 * LSLOT_H];   // a1',w1',v1' (zero-padded)

#define S_R   0
#define S_K   1
#define S_V   2
#define S_K2  3
#define S_G   4
#define S_TMP 5

// ---------------- helpers ----------------
__device__ __forceinline__ float blk_sum256(float v) {
    __shared__ float sh[8];
    int tid = threadIdx.x;
#pragma unroll
    for (int o = 16; o; o >>= 1) v += __shfl_xor_sync(0xffffffffu, v, o);
    if ((tid & 31) == 0) sh[tid >> 5] = v;
    __syncthreads();
    if (tid == 0) {
        float s = 0.f;
#pragma unroll
        for (int i = 0; i < 8; i++) s += sh[i];
        sh[0] = s;
    }
    __syncthreads();
    float r = sh[0];
    __syncthreads();
    return r;
}

__device__ __forceinline__ float warp_sum(float v) {
#pragma unroll
    for (int o = 16; o; o >>= 1) v += __shfl_xor_sync(0xffffffffu, v, o);
    return v;
}

__device__ __forceinline__ float sigmoidf(float v) {
    return 1.f / (1.f + __expf(-v));
}

__device__ __forceinline__ uint32_t smem_u32(const void* p) {
    uint32_t a;
    asm("{ .reg .u64 t; cvta.to.shared.u64 t, %1; cvt.u32.u64 %0, t; }" : "=r"(a) : "l"(p));
    return a;
}

__device__ __forceinline__ void hsplit(float v, __half& hi, __half& lo) {
    hi = __float2half_rn(v);
    lo = __float2half_rn(v - __half2float(hi));
}

// ======================= mma.sync fp16 GEMM =======================
#define MMK_STRIDE 80
#define MMK_TILE   (128 * MMK_STRIDE)
#define STAGE_BYTES (3 * MMK_TILE)
#define MM_SMEM (3 * STAGE_BYTES)

struct MMJob { const __half* B; float* C; const float* Res; int N; int ldc; int mode; int aslot; int planes; };
struct MMJobs { MMJob j[7]; };

__device__ __forceinline__ void cp16(uint32_t dst, const void* src) {
    asm volatile("cp.async.cg.shared.global [%0], [%1], 16;" :: "r"(dst), "l"(src));
}

__device__ __forceinline__ void ldsm4(uint32_t* r, uint32_t a) {
    asm volatile("ldmatrix.sync.aligned.m8n8.x4.shared.b16 {%0,%1,%2,%3}, [%4];"
                 : "=r"(r[0]), "=r"(r[1]), "=r"(r[2]), "=r"(r[3]) : "r"(a));
}

__device__ __forceinline__ void mma16816(float* c, const uint32_t* a, const uint32_t* b) {
    asm volatile(
        "mma.sync.aligned.m16n8k16.row.col.f32.f16.f16.f32 "
        "{%0,%1,%2,%3}, {%4,%5,%6,%7}, {%8,%9}, {%0,%1,%2,%3};"
        : "+f"(c[0]), "+f"(c[1]), "+f"(c[2]), "+f"(c[3])
        : "r"(a[0]), "r"(a[1]), "r"(a[2]), "r"(a[3]), "r"(b[0]), "r"(b[1]));
}

// aMul: A row stride = aMul*K (2 = {hi|lo} split layout, 1 = single plane)
__global__ void __launch_bounds__(256, 2) mm128_kernel(
    const __half* __restrict__ A, MMJobs jobs, int K, int aMul)
{
    extern __shared__ __align__(16) char smem[];
    uint32_t sbase = smem_u32(smem);

    const MMJob job = jobs.j[blockIdx.z];
    const int N = job.N;
    int n0 = blockIdx.x * 128;
    if (n0 >= N) return;
    int m0 = blockIdx.y * 128;

    const __half* Ab = A + (size_t)job.aslot * ASLOT_H;
    const __half* Bb = job.B;
    const int KA = aMul * K;
    const int nk = K >> 5;
    const int planes = job.planes;

    int tid = threadIdx.x;
    int wid = tid >> 5, lane = tid & 31;
    int g = lane >> 2, tig = lane & 3;
    int warp_m = wid >> 2;
    int warp_n = wid & 3;

    float acc[4][4][4];
#pragma unroll
    for (int i = 0; i < 4; i++)
#pragma unroll
        for (int j = 0; j < 4; j++)
#pragma unroll
            for (int q = 0; q < 4; q++) acc[i][j][q] = 0.f;

    auto load_stage = [&](int s, int kc) {
        uint32_t st = sbase + s * STAGE_BYTES;
        int k0 = kc << 5;
#pragma unroll
        for (int it = 0; it < 2; it++) {       // Ah
            int idx = tid + it * 256;
            int r = idx >> 2, c = idx & 3;
            cp16(st + r * MMK_STRIDE + c * 16, Ab + ((size_t)(m0 + r) * KA + k0 + c * 8));
        }
        if (planes == 2) {
#pragma unroll
            for (int it = 0; it < 2; it++) {   // Al
                int idx = tid + it * 256;
                int r = idx >> 2, c = idx & 3;
                cp16(st + MMK_TILE + r * MMK_STRIDE + c * 16,
                     Ab + ((size_t)(m0 + r) * KA + K + k0 + c * 8));
            }
        }
#pragma unroll
        for (int it = 0; it < 2; it++) {       // B
            int idx = tid + it * 256;
            int r = idx >> 2, c = idx & 3;
            cp16(st + 2 * MMK_TILE + r * MMK_STRIDE + c * 16,
                 Bb + ((size_t)(n0 + r) * K + k0 + c * 8));
        }
        asm volatile("cp.async.commit_group;" ::: "memory");
    };

    load_stage(0, 0);
    if (nk > 1) load_stage(1, 1);
    else asm volatile("cp.async.commit_group;" ::: "memory");

    int aRowSel = (lane & 15);
    int aColSel = (lane & 16) ? 16 : 0;
    int bRowSel = ((lane & 16) ? 8 : 0) + (lane & 7);
    int bColSel = (lane & 8) ? 16 : 0;

    for (int kc = 0; kc < nk; kc++) {
        asm volatile("cp.async.wait_group 1;" ::: "memory");
        __syncthreads();
        if (kc + 2 < nk) load_stage((kc + 2) % 3, kc + 2);
        else asm volatile("cp.async.commit_group;" ::: "memory");

        uint32_t st = sbase + (kc % 3) * STAGE_BYTES;
#pragma unroll
        for (int ks = 0; ks < 2; ks++) {
            uint32_t afr[4][4], bfr[2][4];
#pragma unroll
            for (int ap = 0; ap < 2; ap++) {
                uint32_t addr = st + 2 * MMK_TILE
                                + (uint32_t)(warp_n * 32 + ap * 16 + bRowSel) * MMK_STRIDE
                                + ks * 32 + bColSel;
                ldsm4(bfr[ap], addr);
            }
#pragma unroll
            for (int am = 0; am < 4; am++) {
                uint32_t addr = st + (uint32_t)(warp_m * 64 + am * 16 + aRowSel) * MMK_STRIDE
                                + ks * 32 + aColSel;
                ldsm4(afr[am], addr);
            }
#pragma unroll
            for (int am = 0; am < 4; am++) {
                mma16816(acc[am][0], afr[am], &bfr[0][0]);
                mma16816(acc[am][1], afr[am], &bfr[0][2]);
                mma16816(acc[am][2], afr[am], &bfr[1][0]);
                mma16816(acc[am][3], afr[am], &bfr[1][2]);
            }
            if (planes == 2) {
#pragma unroll
                for (int am = 0; am < 4; am++) {
                    uint32_t addr = st + MMK_TILE
                                    + (uint32_t)(warp_m * 64 + am * 16 + aRowSel) * MMK_STRIDE
                                    + ks * 32 + aColSel;
                    ldsm4(afr[am], addr);
                }
#pragma unroll
                for (int am = 0; am < 4; am++) {
                    mma16816(acc[am][0], afr[am], &bfr[0][0]);
                    mma16816(acc[am][1], afr[am], &bfr[0][2]);
                    mma16816(acc[am][2], afr[am], &bfr[1][0]);
                    mma16816(acc[am][3], afr[am], &bfr[1][2]);
                }
            }
        }
    }

    __syncthreads();

    float* C = job.C;
    const float* Res = job.Res;
    int mode = job.mode;
    int ldc = job.ldc;
#pragma unroll
    for (int am = 0; am < 4; am++) {
#pragma unroll
        for (int an = 0; an < 4; an++) {
            int row = m0 + warp_m * 64 + am * 16 + g;
            int col = n0 + warp_n * 32 + an * 8 + tig * 2;
            float2 v0 = make_float2(acc[am][an][0], acc[am][an][1]);
            float2 v1 = make_float2(acc[am][an][2], acc[am][an][3]);
            if (mode == 4) {
                __half* Ch = (__half*)C;
                *(__half2*)(Ch + (size_t)row * ldc + col) =
                    __floats2half2_rn(sigmoidf(v0.x), sigmoidf(v0.y));
                *(__half2*)(Ch + (size_t)(row + 8) * ldc + col) =
                    __floats2half2_rn(sigmoidf(v1.x), sigmoidf(v1.y));
                continue;
            }
            if (mode == 1) {
                const float2 r0 = *(const float2*)(Res + (size_t)row * ldc + col);
                const float2 r1 = *(const float2*)(Res + (size_t)(row + 8) * ldc + col);
                v0.x += r0.x; v0.y += r0.y;
                v1.x += r1.x; v1.y += r1.y;
            } else if (mode == 3) {
                v0.x = tanhf(v0.x); v0.y = tanhf(v0.y);
                v1.x = tanhf(v1.x); v1.y = tanhf(v1.y);
            }
            *(float2*)(C + (size_t)row * ldc + col) = v0;
            *(float2*)(C + (size_t)(row + 8) * ldc + col) = v1;
        }
    }
}

// ---------------- unified weight conversion + v_first copy (one launch) ----------------
__device__ __forceinline__ void conv_tile(const float* __restrict__ W, __half* __restrict__ out,
                                          int K, int N, int bx, int by, float (*tile)[33])
{
    int k0 = by * 32, n0 = bx * 32;
    int tx = threadIdx.x & 31, ty = threadIdx.x >> 5;
    tile[ty][tx] = W[(size_t)(k0 + ty) * N + n0 + tx];
    __syncthreads();
    int tid = threadIdx.x;
    if (tid >= 512) return;
    int nl = tid >> 4, kp = (tid & 15) * 2;
    __half2 h = __floats2half2_rn(tile[kp][nl], tile[kp + 1][nl]);
    *(__half2*)(out + (size_t)(n0 + nl) * K + k0 + kp) = h;
}

__global__ void __launch_bounds__(1024) prepw_kernel(
    const float* __restrict__ Wr, const float* __restrict__ Wk,
    const float* __restrict__ Wv, const float* __restrict__ Wo,
    const float* __restrict__ g1, const float* __restrict__ g2,
    const float* __restrict__ a1, const float* __restrict__ w1,
    const float* __restrict__ v1, const float* __restrict__ vf,
    __half* __restrict__ wbuf, __half* __restrict__ g1buf,
    __half* __restrict__ g2buf, __half* __restrict__ lorabuf,
    float* __restrict__ vfout)
{
    __shared__ float tile[32][33];
    int b = blockIdx.x;
    if (b < 16384) {
        int z = b >> 12, rem = b & 4095;
        const float* W = z == 0 ? Wr : z == 1 ? Wk : z == 2 ? Wv : Wo;
        conv_tile(W, wbuf + (size_t)z * WSLOT_H, HID, HID, rem & 63, rem >> 6, tile);
    } else if (b < 16896) {
        int rem = b - 16384;
        conv_tile(g1, g1buf, HID, 256, rem & 7, rem >> 3, tile);
    } else if (b < 17408) {
        int rem = b - 16896;
        conv_tile(g2, g2buf, 256, HID, rem & 63, rem >> 6, tile);
    } else if (b < 17600) {
        int rem = b - 17408;
        conv_tile(a1, lorabuf, HID, 96, rem % 3, rem / 3, tile);
    } else if (b < 17792) {
        int rem = b - 17600;
        conv_tile(w1, lorabuf + LSLOT_H, HID, 96, rem % 3, rem / 3, tile);
    } else if (b < 17920) {
        int rem = b - 17792;
        conv_tile(v1, lorabuf + 2 * LSLOT_H, HID, 64, rem & 1, rem >> 1, tile);
    } else {
        if (!vfout) return;
        int rem = b - 17920;                       // 0..511
        size_t i = (size_t)rem * 4096 + threadIdx.x * 4;
        *(float4*)(vfout + i) = *(const float4*)(vf + i);
    }
}

// ---------------- fused LN + token-shift mix + fp16 split ----------------
// Slots 0..4 (r,k,v,g,a) single-plane; slot 5 (w) two-plane.
__global__ void __launch_bounds__(256) ln_mix_kernel(
    const float* __restrict__ x, const float* __restrict__ state1,
    const float* __restrict__ lnw, const float* __restrict__ lnb,
    const float* __restrict__ cr, const float* __restrict__ ck,
    const float* __restrict__ cv, const float* __restrict__ cg,
    const float* __restrict__ ca, const float* __restrict__ cw,
    __half* __restrict__ abuf,
    float* __restrict__ state1_out)
{
    int t = blockIdx.x;
    const float* xt = x + (size_t)t * HID;
    const float* xp = x + (size_t)(t - 1) * HID;

    float2 v0[4], v1[4];
    float s0 = 0.f, s1 = 0.f;
#pragma unroll
    for (int j = 0; j < 4; j++) {
        int c = threadIdx.x * 2 + j * 512;
        v0[j] = *(const float2*)(xt + c);
        s0 += v0[j].x + v0[j].y;
        v1[j] = t ? *(const float2*)(xp + c) : make_float2(0.f, 0.f);
        s1 += v1[j].x + v1[j].y;
    }
    float mu0 = blk_sum256(s0) * (1.f / HID);
    float mu1 = blk_sum256(s1) * (1.f / HID);
    float q0 = 0.f, q1 = 0.f;
#pragma unroll
    for (int j = 0; j < 4; j++) {
        float d;
        d = v0[j].x - mu0; q0 += d * d;
        d = v0[j].y - mu0; q0 += d * d;
        d = v1[j].x - mu1; q1 += d * d;
        d = v1[j].y - mu1; q1 += d * d;
    }
    float inv0 = rsqrtf(blk_sum256(q0) * (1.f / HID) + 1e-5f);
    float inv1 = rsqrtf(blk_sum256(q1) * (1.f / HID) + 1e-5f);

#pragma unroll
    for (int j = 0; j < 4; j++) {
        int c = threadIdx.x * 2 + j * 512;
        float2 wv = *(const float2*)(lnw + c);
        float2 bv = *(const float2*)(lnb + c);
        float xn0 = (v0[j].x - mu0) * inv0 * wv.x + bv.x;
        float xn1 = (v0[j].y - mu0) * inv0 * wv.y + bv.y;
        float pv0 = t ? (v1[j].x - mu1) * inv1 * wv.x + bv.x : state1[c];
        float pv1 = t ? (v1[j].y - mu1) * inv1 * wv.y + bv.y : state1[c + 1];
        float sx0 = pv0 - xn0, sx1 = pv1 - xn1;

        __half* arow = abuf + (size_t)t * 2 * HID + c;
#pragma unroll
        for (int s = 0; s < 6; s++) {
            const float* coefA = (s == 0) ? cr : (s == 1) ? ck : (s == 2) ? cv
                               : (s == 3) ? cg : (s == 4) ? ca : cw;
            float a0 = xn0 + coefA[c] * sx0;
            float a1 = xn1 + coefA[c + 1] * sx1;
            __half* p = arow + (size_t)s * ASLOT_H;
            if (s == 5) {
                __half h0, l0, h1, l1;
                hsplit(a0, h0, l0);
                hsplit(a1, h1, l1);
                *(__half2*)(p) = __half2(h0, h1);
                *(__half2*)(p + HID) = __half2(l0, l1);
            } else {
                *(__half2*)(p) = __floats2half2_rn(a0, a1);
            }
        }
        if (state1_out && t == T_LEN - 1) {
            state1_out[c] = xn0;
            state1_out[c + 1] = xn1;
        }
    }
}

// ---------------- fused LoRA-up (+activations) + scan prep ----------------
#define FIN_SP 66
#define FIN_SMEM ((3 * 64 * FIN_SP + 16 * 65 * 2) * 4)

__global__ void __launch_bounds__(256) finish_kernel(
    const float* __restrict__ hbuf,
    const float* __restrict__ a2, const float* __restrict__ w2, const float* __restrict__ v2,
    const float* __restrict__ a0, const float* __restrict__ w0, const float* __restrict__ v0b,
    const float* __restrict__ vf,
    const float* __restrict__ kbuf, const float* __restrict__ rbuf,
    float* __restrict__ vslot,
    const float* __restrict__ k_k, const float* __restrict__ k_a,
    float* __restrict__ k2out, float* __restrict__ pscan2)
{
    extern __shared__ float fs[];
    float* a_s = fs;
    float* w_s = fs + 64 * FIN_SP;
    float* v_s = fs + 2 * 64 * FIN_SP;
    float* As = fs + 3 * 64 * FIN_SP;
    float* Bs = As + 16 * 65;

    int tb = blockIdx.x >> 5;
    int h = blockIdx.x & 31;
    int t0 = tb * 64;
    int cb = h * HEADD;

    int tid = threadIdx.x;
    int tx = tid & 15, ty = tid >> 4;

#pragma unroll
    for (int z = 0; z < 3; z++) {
        const float* B = z == 0 ? a2 : z == 1 ? w2 : v2;
        const float* bias = z == 0 ? a0 : z == 1 ? w0 : v0b;
        int K = (z == 2) ? 64 : 96;
        int zoff = z * 128;
        float acc[4][4] = {};
        for (int k0 = 0; k0 < K; k0 += 16) {
#pragma unroll
            for (int i = tid; i < 64 * 16; i += 256) {
                int r = i >> 4, c = i & 15;
                As[c * 65 + r] = hbuf[(size_t)(t0 + r) * 384 + zoff + k0 + c];
            }
#pragma unroll
            for (int i = tid; i < 16 * 64; i += 256) {
                int r = i >> 6, c = i & 63;
                Bs[r * 65 + c] = B[(size_t)(k0 + r) * HID + cb + c];
            }
            __syncthreads();
#pragma unroll
            for (int kk = 0; kk < 16; kk++) {
                float a[4], b[4];
#pragma unroll
                for (int i = 0; i < 4; i++) a[i] = As[kk * 65 + ty * 4 + i];
#pragma unroll
                for (int jj = 0; jj < 4; jj++) b[jj] = Bs[kk * 65 + tx * 4 + jj];
#pragma unroll
                for (int i = 0; i < 4; i++)
#pragma unroll
                    for (int jj = 0; jj < 4; jj++) acc[i][jj] = fmaf(a[i], b[jj], acc[i][jj]);
            }
            __syncthreads();
        }
#pragma unroll
        for (int i = 0; i < 4; i++) {
            int lr = ty * 4 + i;
#pragma unroll
            for (int jj = 0; jj < 4; jj++) {
                int lc = tx * 4 + jj;
                float s = sigmoidf(bias[cb + lc] + acc[i][jj]);
                if (z == 0) a_s[lr * FIN_SP + lc] = s;
                else if (z == 1) w_s[lr * FIN_SP + lc] = __expf(-0.606531f * s);
                else {
                    size_t gi = (size_t)(t0 + lr) * HID + cb + lc;
                    float vv = vslot[gi];
                    float nv = vv + (vf[gi] - vv) * s;
                    v_s[lr * FIN_SP + lc] = nv;
                    vslot[gi] = nv;
                }
            }
        }
        __syncthreads();
    }

    int wrp = tid >> 5, lane = tid & 31;
#pragma unroll
    for (int pi = 0; pi < 4; pi++) {
        int pp = wrp * 4 + pi;
        int r0 = 2 * pp, r1 = r0 + 1;
        int pr = tb * 32 + pp;
        int b0 = (t0 + r0) * HID + cb;
        int b1 = b0 + HID;

        float kA0 = kbuf[b0 + lane], kB0 = kbuf[b0 + lane + 32];
        float qA0 = kA0 * k_k[cb + lane], qB0 = kB0 * k_k[cb + lane + 32];
        float inv0 = 1.f / fmaxf(sqrtf(warp_sum(qA0 * qA0 + qB0 * qB0)), 1e-12f);
        float kkA0 = qA0 * inv0, kkB0 = qB0 * inv0;
        float aA0 = a_s[r0 * FIN_SP + lane], aB0 = a_s[r0 * FIN_SP + lane + 32];
        float k2A0 = kA0 * (1.f + (aA0 - 1.f) * k_a[cb + lane]);
        float k2B0 = kB0 * (1.f + (aB0 - 1.f) * k_a[cb + lane + 32]);
        k2out[b0 + lane] = k2A0;
        k2out[b0 + lane + 32] = k2B0;

        float kA1 = kbuf[b1 + lane], kB1 = kbuf[b1 + lane + 32];
        float qA1 = kA1 * k_k[cb + lane], qB1 = kB1 * k_k[cb + lane + 32];
        float inv1 = 1.f / fmaxf(sqrtf(warp_sum(qA1 * qA1 + qB1 * qB1)), 1e-12f);
        float kkA1 = qA1 * inv1, kkB1 = qB1 * inv1;
        float aA1 = a_s[r1 * FIN_SP + lane], aB1 = a_s[r1 * FIN_SP + lane + 32];
        float k2A1 = kA1 * (1.f + (aA1 - 1.f) * k_a[cb + lane]);
        float k2B1 = kB1 * (1.f + (aB1 - 1.f) * k_a[cb + lane + 32]);
        k2out[b1 + lane] = k2A1;
        k2out[b1 + lane + 32] = k2B1;

        float wA0 = w_s[r0 * FIN_SP + lane], wB0 = w_s[r0 * FIN_SP + lane + 32];
        float kaA0 = kkA0 * aA0, kaB0 = kkB0 * aB0;

        float c1 = warp_sum(kkA1 * kaA0 + kkB1 * kaB0);
        float c2 = warp_sum(kkA1 * k2A0 + kkB1 * k2B0);

        float* P = pscan2 + ((size_t)pr * NHEAD + h) * 1024;
        P[0 * 64 + lane] = kkA0;           P[0 * 64 + lane + 32] = kkB0;
        P[1 * 64 + lane] = kkA1 * wA0;     P[1 * 64 + lane + 32] = kkB1 * wB0;
        P[2 * 64 + lane] = wA0;            P[2 * 64 + lane + 32] = wB0;
        P[3 * 64 + lane] = kaA0;           P[3 * 64 + lane + 32] = kaB0;
        P[4 * 64 + lane] = k2A0;           P[4 * 64 + lane + 32] = k2B0;
        P[5 * 64 + lane] = rbuf[b0 + lane]; P[5 * 64 + lane + 32] = rbuf[b0 + lane + 32];
        P[6 * 64 + lane] = w_s[r1 * FIN_SP + lane]; P[6 * 64 + lane + 32] = w_s[r1 * FIN_SP + lane + 32];
        P[7 * 64 + lane] = kkA1 * aA1;     P[7 * 64 + lane + 32] = kkB1 * aB1;
        P[8 * 64 + lane] = k2A1;           P[8 * 64 + lane + 32] = k2B1;
        P[9 * 64 + lane] = rbuf[b1 + lane]; P[9 * 64 + lane + 32] = rbuf[b1 + lane + 32];
        P[10 * 64 + lane] = v_s[r0 * FIN_SP + lane]; P[10 * 64 + lane + 32] = v_s[r0 * FIN_SP + lane + 32];
        P[11 * 64 + lane] = v_s[r1 * FIN_SP + lane]; P[11 * 64 + lane + 32] = v_s[r1 * FIN_SP + lane + 32];
        if (lane == 0) { P[12 * 64] = c1; P[12 * 64 + 1] = c2; }
    }
}

// ---------------- scan v3: two steps per reduction round ----------------
__global__ void __launch_bounds__(256) scan3_kernel(
    const float* __restrict__ pscan2,
    const float* __restrict__ state2, float* __restrict__ ypart,
    float* __restrict__ Sout)
{
    int h = blockIdx.x >> 2;
    int q = blockIdx.x & 3;
    int tid = threadIdx.x;
    int wrp = tid >> 5, lane = tid & 31;
    int rsel = lane >> 4, colg = lane & 15;
    int row = q * 16 + 2 * wrp + rsel;

    float4 S = *(const float4*)(state2 + (size_t)h * 4096 + row * 64 + colg * 4);

    __shared__ float buf[2][1024];

    const float* pB = pscan2 + (size_t)h * 1024;
    const size_t pstride = (size_t)NHEAD * 1024;

    ((float4*)buf[0])[tid] = *(const float4*)(pB + tid * 4);
    float4 preA = *(const float4*)(pB + pstride + tid * 4);
    float4 preB;

    for (int pr = 0; pr < NPAIR; pr++) {
        __syncthreads();
        preB = (pr + 2 < NPAIR) ? *(const float4*)(pB + (size_t)(pr + 2) * pstride + tid * 4)
                                : preA;
        const float* b = buf[pr & 1];
        float4 kk4  = *(const float4*)(b + 0 * 64 + colg * 4);
        float4 kkw4 = *(const float4*)(b + 1 * 64 + colg * 4);
        float4 w4   = *(const float4*)(b + 2 * 64 + colg * 4);
        float4 ka4  = *(const float4*)(b + 3 * 64 + colg * 4);
        float4 k4   = *(const float4*)(b + 4 * 64 + colg * 4);
        float4 r4   = *(const float4*)(b + 5 * 64 + colg * 4);
        float4 w14  = *(const float4*)(b + 6 * 64 + colg * 4);
        float4 ka14 = *(const float4*)(b + 7 * 64 + colg * 4);
        float4 k14  = *(const float4*)(b + 8 * 64 + colg * 4);
        float4 r14  = *(const float4*)(b + 9 * 64 + colg * 4);
        float v0 = b[10 * 64 + row];
        float v1 = b[11 * 64 + row];
        float c1 = b[12 * 64];
        float c2 = b[12 * 64 + 1];

        float d0 = S.x * kk4.x + S.y * kk4.y + S.z * kk4.z + S.w * kk4.w;
        float d1 = S.x * kkw4.x + S.y * kkw4.y + S.z * kkw4.z + S.w * kkw4.w;
#pragma unroll
        for (int o = 1; o <= 8; o <<= 1) {
            d0 += __shfl_xor_sync(0xffffffffu, d0, o);
            d1 += __shfl_xor_sync(0xffffffffu, d1, o);
        }
        float p0 = d0;
        float p1 = d1 - p0 * c1 + v0 * c2;

        S.x = S.x * w4.x - p0 * ka4.x + v0 * k4.x;
        S.y = S.y * w4.y - p0 * ka4.y + v0 * k4.y;
        S.z = S.z * w4.z - p0 * ka4.z + v0 * k4.z;
        S.w = S.w * w4.w - p0 * ka4.w + v0 * k4.w;

        float y0 = S.x * r4.x + S.y * r4.y + S.z * r4.z + S.w * r4.w;
        y0 += __shfl_xor_sync(0xffffffffu, y0, 1);
        y0 += __shfl_xor_sync(0xffffffffu, y0, 2);
        if ((colg & 3) == 0)
            ypart[((size_t)(2 * pr) * HID + h * HEADD + row) * 4 + (colg >> 2)] = y0;

        if (pr + 1 < NPAIR)
            ((float4*)buf[(pr + 1) & 1])[tid] = preA;
        preA = preB;

        S.x = S.x * w14.x - p1 * ka14.x + v1 * k14.x;
        S.y = S.y * w14.y - p1 * ka14.y + v1 * k14.y;
        S.z = S.z * w14.z - p1 * ka14.z + v1 * k14.z;
        S.w = S.w * w14.w - p1 * ka14.w + v1 * k14.w;

        float y1 = S.x * r14.x + S.y * r14.y + S.z * r14.z + S.w * r14.w;
        y1 += __shfl_xor_sync(0xffffffffu, y1, 1);
        y1 += __shfl_xor_sync(0xffffffffu, y1, 2);
        if ((colg & 3) == 0)
            ypart[((size_t)(2 * pr + 1) * HID + h * HEADD + row) * 4 + (colg >> 2)] = y1;
    }
    *(float4*)(Sout + (size_t)h * 4096 + row * 64 + colg * 4) = S;
}

// ---------------- groupnorm + rkv + gate -> fp16 split into abuf ----------------
__global__ void __launch_bounds__(256) post_kernel(
    const float* __restrict__ ypart, const float* __restrict__ r,
    const float* __restrict__ k2, const float* __restrict__ v,
    const float* __restrict__ g, const float* __restrict__ r_k,
    const float* __restrict__ lnxw, const float* __restrict__ lnxb,
    __half* __restrict__ zsplit)
{
    int gw = (blockIdx.x * 256 + threadIdx.x) >> 5;
    int lane = threadIdx.x & 31;
    if (gw >= T_LEN * NHEAD) return;
    int t = gw >> 5, h = gw & 31;
    int base = t * HID + h * HEADD;
    int cb = h * HEADD;

    float4 yp0 = *(const float4*)(ypart + (size_t)(base + lane) * 4);
    float4 yp1 = *(const float4*)(ypart + (size_t)(base + lane + 32) * 4);
    float y0 = (yp0.x + yp0.y) + (yp0.z + yp0.w);
    float y1 = (yp1.x + yp1.y) + (yp1.z + yp1.w);

    float mu = warp_sum(y0 + y1) * (1.f / HEADD);
    float d0 = y0 - mu, d1 = y1 - mu;
    float var = warp_sum(d0 * d0 + d1 * d1) * (1.f / HEADD);
    float inv = rsqrtf(var + 0.00064f);

    float rs = warp_sum(r[base + lane] * k2[base + lane] * r_k[cb + lane] +
                        r[base + lane + 32] * k2[base + lane + 32] * r_k[cb + lane + 32]);

    float z0 = (d0 * inv * lnxw[cb + lane] + lnxb[cb + lane] + rs * v[base + lane]) * g[base + lane];
    float z1 = (d1 * inv * lnxw[cb + lane + 32] + lnxb[cb + lane + 32] + rs * v[base + lane + 32]) * g[base + lane + 32];

    size_t zb = (size_t)t * 2 * HID;
    __half h0, l0, h1, l1;
    hsplit(z0, h0, l0);
    hsplit(z1, h1, l1);
    zsplit[zb + cb + lane] = h0;
    zsplit[zb + HID + cb + lane] = l0;
    zsplit[zb + cb + lane + 32] = h1;
    zsplit[zb + HID + cb + lane + 32] = l1;
}

// ---------------- host launcher ----------------
extern "C" void kernel_launch(void* const* d_in, const int* in_sizes, int n_in,
                              void* d_out, int out_size)
{
    const float* x       = (const float*)d_in[0];
    const float* state1  = (const float*)d_in[1];
    const float* state2  = (const float*)d_in[2];
    const float* v_first = (const float*)d_in[3];
    const float* ln1_w   = (const float*)d_in[4];
    const float* ln1_b   = (const float*)d_in[5];
    const float* x_r     = (const float*)d_in[6];
    const float* x_w     = (const float*)d_in[7];
    const float* x_k     = (const float*)d_in[8];
    const float* x_v     = (const float*)d_in[9];
    const float* x_a     = (const float*)d_in[10];
    const float* x_g     = (const float*)d_in[11];
    const float* Wr      = (const float*)d_in[12];
    const float* Wk      = (const float*)d_in[13];
    const float* Wv      = (const float*)d_in[14];
    const float* Wo      = (const float*)d_in[15];
    const float* w0      = (const float*)d_in[16];
    const float* w1      = (const float*)d_in[17];
    const float* w2      = (const float*)d_in[18];
    const float* a0      = (const float*)d_in[19];
    const float* a1      = (const float*)d_in[20];
    const float* a2      = (const float*)d_in[21];
    const float* v0      = (const float*)d_in[22];
    const float* v1      = (const float*)d_in[23];
    const float* v2      = (const float*)d_in[24];
    const float* g1      = (const float*)d_in[25];
    const float* g2      = (const float*)d_in[26];
    const float* k_k     = (const float*)d_in[27];
    const float* k_a     = (const float*)d_in[28];
    const float* r_k     = (const float*)d_in[29];
    const float* ln_x_w  = (const float*)d_in[30];
    const float* ln_x_b  = (const float*)d_in[31];

    float* sc = nullptr;      cudaGetSymbolAddress((void**)&sc, g_scratch);
    float* hbuf = nullptr;    cudaGetSymbolAddress((void**)&hbuf, g_hbuf);
    float* pscan2 = nullptr;  cudaGetSymbolAddress((void**)&pscan2, g_pscan2);
    float* ypart = nullptr;   cudaGetSymbolAddress((void**)&ypart, g_ypart);
    __half* abuf = nullptr;   cudaGetSymbolAddress((void**)&abuf, g_abuf);
    __half* wbuf = nullptr;   cudaGetSymbolAddress((void**)&wbuf, g_wbuf);
    __half* g1buf = nullptr;  cudaGetSymbolAddress((void**)&g1buf, g_g1buf);
    __half* g2buf = nullptr;  cudaGetSymbolAddress((void**)&g2buf, g_g2buf);
    __half* ghbuf = nullptr;  cudaGetSymbolAddress((void**)&ghbuf, g_ghbuf);
    __half* lorabuf = nullptr; cudaGetSymbolAddress((void**)&lorabuf, g_lorabuf);

    cudaFuncSetAttribute(mm128_kernel, cudaFuncAttributeMaxDynamicSharedMemorySize, MM_SMEM);
    cudaFuncSetAttribute(finish_kernel, cudaFuncAttributeMaxDynamicSharedMemorySize, FIN_SMEM);

#define SLOT(s) (sc + (size_t)(s) * NTOK_EL)

    float* out = (float*)d_out;
    const int OFF_OUT = 0;
    const int OFF_S1  = NTOK_EL;
    const int OFF_S2  = OFF_S1 + HID;
    const int OFF_VF  = OFF_S2 + NHEAD * HEADD * HEADD;
    const int TOTAL   = OFF_VF + NTOK_EL;
    bool full = (out_size >= TOTAL);

    float* s1_out = full ? out + OFF_S1 : nullptr;
    float* s2_out = full ? out + OFF_S2 : SLOT(S_TMP);
    float* vf_out = full ? out + OFF_VF : nullptr;

    // 1. unified weight conversion + v_first passthrough
    prepw_kernel<<<18432, 1024>>>(Wr, Wk, Wv, Wo, g1, g2, a1, w1, v1, v_first,
                                  wbuf, g1buf, g2buf, lorabuf, vf_out);

    // 2. fused LN + mix + fp16 split (slots r,k,v,g,a single-plane; w 2-plane)
    ln_mix_kernel<<<T_LEN, 256>>>(x, state1, ln1_w, ln1_b,
                                  x_r, x_k, x_v, x_g, x_a, x_w,
                                  abuf, s1_out);

    // 3. mega-batch: r,k,v,g-down,a-down single-plane; w-down 2-plane
    {
        MMJobs jobs;
        jobs.j[0] = { wbuf,                  SLOT(S_R),      nullptr, HID, HID, 0, 0, 1 };
        jobs.j[1] = { wbuf + WSLOT_H,        SLOT(S_K),      nullptr, HID, HID, 0, 1, 1 };
        jobs.j[2] = { wbuf + 2 * WSLOT_H,    SLOT(S_V),      nullptr, HID, HID, 0, 2, 1 };
        jobs.j[3] = { g1buf,                 (float*)ghbuf,  nullptr, 256, 256, 4, 3, 1 };
        jobs.j[4] = { lorabuf,               hbuf,           nullptr, 128, 384, 0, 4, 1 };
        jobs.j[5] = { lorabuf + LSLOT_H,     hbuf + 128,     nullptr, 128, 384, 3, 5, 2 };
        jobs.j[6] = { lorabuf + 2 * LSLOT_H, hbuf + 256,     nullptr, 128, 384, 0, 2, 1 };
        mm128_kernel<<<dim3(16, 8, 7), 256, MM_SMEM>>>(abuf, jobs, HID, 2);
    }

    // 4. g-up: single-plane fp16 A (sigmoid output), @g2
    {
        MMJobs jobs;
        jobs.j[0] = { g2buf, SLOT(S_G), nullptr, HID, HID, 0, 0, 1 };
        for (int i = 1; i < 7; i++) jobs.j[i] = jobs.j[0];
        mm128_kernel<<<dim3(16, 8, 1), 256, MM_SMEM>>>(ghbuf, jobs, 256, 1);
    }

    // 5. fused LoRA-up + prep
    finish_kernel<<<512, 256, FIN_SMEM>>>(hbuf, a2, w2, v2, a0, w0, v0, v_first,
                                          SLOT(S_K), SLOT(S_R), SLOT(S_V),
                                          k_k, k_a, SLOT(S_K2), pscan2);

    // 6. two-step scan
    scan3_kernel<<<128, 256>>>(pscan2, state2, ypart, s2_out);

    // 7. groupnorm + rkv + gate -> 2-plane fp16 split into abuf slot 0
    post_kernel<<<(T_LEN * NHEAD * 32 + 255) / 256, 256>>>(
        ypart, SLOT(S_R), SLOT(S_K2), SLOT(S_V), SLOT(S_G),
        r_k, ln_x_w, ln_x_b, abuf);

    // 8. out = x + z@Wo (2-plane, residual fused)
    {
        MMJobs jobs;
        jobs.j[0] = { wbuf + 3 * WSLOT_H, out + OFF_OUT, x, HID, HID, 1, 0, 2 };
        for (int i = 1; i < 7; i++) jobs.j[i] = jobs.j[0];
        mm128_kernel<<<dim3(16, 8, 1), 256, MM_SMEM>>>(abuf, jobs, HID, 2);
    }
}

// round 12
// speedup vs baseline: 6.0435x; 1.1239x over previous
#include <cuda_runtime.h>
#include <cuda_fp16.h>
#include <math.h>
#include <stdint.h>

#define T_LEN 1024
#define HID   2048
#define NHEAD 32
#define HEADD 64
#define NTOK_EL (T_LEN * HID)   // 2097152
#define NPAIR (T_LEN / 2)

#define ASLOT_H ((size_t)T_LEN * 2 * HID)   // A' slot: [M, 2K] fp16 {hi|lo}
#define WSLOT_H ((size_t)HID * HID)         // W' slot: [N, K] fp16 single plane
#define LSLOT_H ((size_t)128 * HID)         // lora-down W' slot (padded 128 rows)

// ---------------- static device scratch ----------------
__device__ float g_scratch[8u * (unsigned)NTOK_EL];
__device__ float g_hbuf[(size_t)T_LEN * 384];
__device__ float g_pscan2[(size_t)NPAIR * NHEAD * 1024];   // 16 planes x 64
__device__ float g_ypart[(size_t)T_LEN * HID * 4];
__device__ __align__(256) __half g_abuf[6 * ASLOT_H];      // xr,xk,xv,xg,xa,xw splits
__device__ __align__(256) __half g_wbuf[4 * WSLOT_H];      // Wr',Wk',Wv',Wo'
__device__ __align__(256) __half g_g1buf[(size_t)256 * HID];
__device__ __align__(256) __half g_g2buf[(size_t)HID * 256];
__device__ __align__(256) __half g_ghbuf[(size_t)T_LEN * 256];  // sigmoid(g-down), 1 plane
__device__ __align__(256) __half g_lorabuf[3 * LSLOT_H];   // a1',w1',v1' (zero-padded)

#define S_R   0
#define S_K   1
#define S_V   2
#define S_K2  3
#define S_G   4
#define S_TMP 5

// ---------------- helpers ----------------
__device__ __forceinline__ float blk_sum256(float v) {
    __shared__ float sh[8];
    int tid = threadIdx.x;
#pragma unroll
    for (int o = 16; o; o >>= 1) v += __shfl_xor_sync(0xffffffffu, v, o);
    if ((tid & 31) == 0) sh[tid >> 5] = v;
    __syncthreads();
    if (tid == 0) {
        float s = 0.f;
#pragma unroll
        for (int i = 0; i < 8; i++) s += sh[i];
        sh[0] = s;
    }
    __syncthreads();
    float r = sh[0];
    __syncthreads();
    return r;
}

__device__ __forceinline__ float warp_sum(float v) {
#pragma unroll
    for (int o = 16; o; o >>= 1) v += __shfl_xor_sync(0xffffffffu, v, o);
    return v;
}

__device__ __forceinline__ float sigmoidf(float v) {
    return 1.f / (1.f + __expf(-v));
}

__device__ __forceinline__ uint32_t smem_u32(const void* p) {
    uint32_t a;
    asm("{ .reg .u64 t; cvta.to.shared.u64 t, %1; cvt.u32.u64 %0, t; }" : "=r"(a) : "l"(p));
    return a;
}

__device__ __forceinline__ void hsplit(float v, __half& hi, __half& lo) {
    hi = __float2half_rn(v);
    lo = __float2half_rn(v - __half2float(hi));
}

// ======================= mma.sync fp16 GEMM =======================
#define MMK_STRIDE 80
#define MMK_TILE   (128 * MMK_STRIDE)
#define STAGE_BYTES (3 * MMK_TILE)
#define MM_SMEM (3 * STAGE_BYTES)

struct MMJob { const __half* B; float* C; const float* Res; int N; int ldc; int mode; int aslot; int planes; };
struct MMJobs { MMJob j[7]; };

__device__ __forceinline__ void cp16(uint32_t dst, const void* src) {
    asm volatile("cp.async.cg.shared.global [%0], [%1], 16;" :: "r"(dst), "l"(src));
}

__device__ __forceinline__ void ldsm4(uint32_t* r, uint32_t a) {
    asm volatile("ldmatrix.sync.aligned.m8n8.x4.shared.b16 {%0,%1,%2,%3}, [%4];"
                 : "=r"(r[0]), "=r"(r[1]), "=r"(r[2]), "=r"(r[3]) : "r"(a));
}

__device__ __forceinline__ void mma16816(float* c, const uint32_t* a, const uint32_t* b) {
    asm volatile(
        "mma.sync.aligned.m16n8k16.row.col.f32.f16.f16.f32 "
        "{%0,%1,%2,%3}, {%4,%5,%6,%7}, {%8,%9}, {%0,%1,%2,%3};"
        : "+f"(c[0]), "+f"(c[1]), "+f"(c[2]), "+f"(c[3])
        : "r"(a[0]), "r"(a[1]), "r"(a[2]), "r"(a[3]), "r"(b[0]), "r"(b[1]));
}

// aMul: A row stride = aMul*K (2 = {hi|lo} split layout, 1 = single plane)
__global__ void __launch_bounds__(256, 2) mm128_kernel(
    const __half* __restrict__ A, MMJobs jobs, int K, int aMul)
{
    extern __shared__ __align__(16) char smem[];
    uint32_t sbase = smem_u32(smem);

    const MMJob job = jobs.j[blockIdx.z];
    const int N = job.N;
    int n0 = blockIdx.x * 128;
    if (n0 >= N) return;
    int m0 = blockIdx.y * 128;

    const __half* Ab = A + (size_t)job.aslot * ASLOT_H;
    const __half* Bb = job.B;
    const int KA = aMul * K;
    const int nk = K >> 5;
    const int planes = job.planes;

    int tid = threadIdx.x;
    int wid = tid >> 5, lane = tid & 31;
    int g = lane >> 2, tig = lane & 3;
    int warp_m = wid >> 2;
    int warp_n = wid & 3;

    float acc[4][4][4];
#pragma unroll
    for (int i = 0; i < 4; i++)
#pragma unroll
        for (int j = 0; j < 4; j++)
#pragma unroll
            for (int q = 0; q < 4; q++) acc[i][j][q] = 0.f;

    auto load_stage = [&](int s, int kc) {
        uint32_t st = sbase + s * STAGE_BYTES;
        int k0 = kc << 5;
#pragma unroll
        for (int it = 0; it < 2; it++) {       // Ah
            int idx = tid + it * 256;
            int r = idx >> 2, c = idx & 3;
            cp16(st + r * MMK_STRIDE + c * 16, Ab + ((size_t)(m0 + r) * KA + k0 + c * 8));
        }
        if (planes == 2) {
#pragma unroll
            for (int it = 0; it < 2; it++) {   // Al
                int idx = tid + it * 256;
                int r = idx >> 2, c = idx & 3;
                cp16(st + MMK_TILE + r * MMK_STRIDE + c * 16,
                     Ab + ((size_t)(m0 + r) * KA + K + k0 + c * 8));
            }
        }
#pragma unroll
        for (int it = 0; it < 2; it++) {       // B
            int idx = tid + it * 256;
            int r = idx >> 2, c = idx & 3;
            cp16(st + 2 * MMK_TILE + r * MMK_STRIDE + c * 16,
                 Bb + ((size_t)(n0 + r) * K + k0 + c * 8));
        }
        asm volatile("cp.async.commit_group;" ::: "memory");
    };

    load_stage(0, 0);
    if (nk > 1) load_stage(1, 1);
    else asm volatile("cp.async.commit_group;" ::: "memory");

    int aRowSel = (lane & 15);
    int aColSel = (lane & 16) ? 16 : 0;
    int bRowSel = ((lane & 16) ? 8 : 0) + (lane & 7);
    int bColSel = (lane & 8) ? 16 : 0;

    for (int kc = 0; kc < nk; kc++) {
        asm volatile("cp.async.wait_group 1;" ::: "memory");
        __syncthreads();
        if (kc + 2 < nk) load_stage((kc + 2) % 3, kc + 2);
        else asm volatile("cp.async.commit_group;" ::: "memory");

        uint32_t st = sbase + (kc % 3) * STAGE_BYTES;
#pragma unroll
        for (int ks = 0; ks < 2; ks++) {
            uint32_t afr[4][4], bfr[2][4];
#pragma unroll
            for (int ap = 0; ap < 2; ap++) {
                uint32_t addr = st + 2 * MMK_TILE
                                + (uint32_t)(warp_n * 32 + ap * 16 + bRowSel) * MMK_STRIDE
                                + ks * 32 + bColSel;
                ldsm4(bfr[ap], addr);
            }
#pragma unroll
            for (int am = 0; am < 4; am++) {
                uint32_t addr = st + (uint32_t)(warp_m * 64 + am * 16 + aRowSel) * MMK_STRIDE
                                + ks * 32 + aColSel;
                ldsm4(afr[am], addr);
            }
#pragma unroll
            for (int am = 0; am < 4; am++) {
                mma16816(acc[am][0], afr[am], &bfr[0][0]);
                mma16816(acc[am][1], afr[am], &bfr[0][2]);
                mma16816(acc[am][2], afr[am], &bfr[1][0]);
                mma16816(acc[am][3], afr[am], &bfr[1][2]);
            }
            if (planes == 2) {
#pragma unroll
                for (int am = 0; am < 4; am++) {
                    uint32_t addr = st + MMK_TILE
                                    + (uint32_t)(warp_m * 64 + am * 16 + aRowSel) * MMK_STRIDE
                                    + ks * 32 + aColSel;
                    ldsm4(afr[am], addr);
                }
#pragma unroll
                for (int am = 0; am < 4; am++) {
                    mma16816(acc[am][0], afr[am], &bfr[0][0]);
                    mma16816(acc[am][1], afr[am], &bfr[0][2]);
                    mma16816(acc[am][2], afr[am], &bfr[1][0]);
                    mma16816(acc[am][3], afr[am], &bfr[1][2]);
                }
            }
        }
    }

    __syncthreads();

    float* C = job.C;
    const float* Res = job.Res;
    int mode = job.mode;
    int ldc = job.ldc;
#pragma unroll
    for (int am = 0; am < 4; am++) {
#pragma unroll
        for (int an = 0; an < 4; an++) {
            int row = m0 + warp_m * 64 + am * 16 + g;
            int col = n0 + warp_n * 32 + an * 8 + tig * 2;
            float2 v0 = make_float2(acc[am][an][0], acc[am][an][1]);
            float2 v1 = make_float2(acc[am][an][2], acc[am][an][3]);
            if (mode == 4) {
                __half* Ch = (__half*)C;
                *(__half2*)(Ch + (size_t)row * ldc + col) =
                    __floats2half2_rn(sigmoidf(v0.x), sigmoidf(v0.y));
                *(__half2*)(Ch + (size_t)(row + 8) * ldc + col) =
                    __floats2half2_rn(sigmoidf(v1.x), sigmoidf(v1.y));
                continue;
            }
            if (mode == 1) {
                const float2 r0 = *(const float2*)(Res + (size_t)row * ldc + col);
                const float2 r1 = *(const float2*)(Res + (size_t)(row + 8) * ldc + col);
                v0.x += r0.x; v0.y += r0.y;
                v1.x += r1.x; v1.y += r1.y;
            } else if (mode == 3) {
                v0.x = tanhf(v0.x); v0.y = tanhf(v0.y);
                v1.x = tanhf(v1.x); v1.y = tanhf(v1.y);
            }
            *(float2*)(C + (size_t)row * ldc + col) = v0;
            *(float2*)(C + (size_t)(row + 8) * ldc + col) = v1;
        }
    }
}

// ---------------- weight conversion v2: 64(k) x 32(n) tiles, uint4 stores ----------------
__device__ __forceinline__ void conv_tile2(const float* __restrict__ W, __half* __restrict__ out,
                                           int K, int N, int bx, int by, float* tile /*64x33*/)
{
    int k0 = by * 64, n0 = bx * 32;
    int tid = threadIdx.x;
#pragma unroll
    for (int it = 0; it < 8; it++) {
        int i = tid + it * 256;          // 0..2047
        int r = i >> 5, c = i & 31;      // k row, n col
        tile[r * 33 + c] = W[(size_t)(k0 + r) * N + n0 + c];
    }
    __syncthreads();
    int nl = tid >> 3;                    // 0..31
    int kq = (tid & 7) * 8;               // 0..56
    __half h8[8];
#pragma unroll
    for (int j = 0; j < 8; j++)
        h8[j] = __float2half_rn(tile[(kq + j) * 33 + nl]);
    *(uint4*)(out + (size_t)(n0 + nl) * K + k0 + kq) = *(uint4*)h8;
    __syncthreads();
}

__global__ void __launch_bounds__(256) prepw_kernel(
    const float* __restrict__ Wr, const float* __restrict__ Wk,
    const float* __restrict__ Wv, const float* __restrict__ Wo,
    const float* __restrict__ g1, const float* __restrict__ g2,
    const float* __restrict__ a1, const float* __restrict__ w1,
    const float* __restrict__ v1, const float* __restrict__ vf,
    __half* __restrict__ wbuf, __half* __restrict__ g1buf,
    __half* __restrict__ g2buf, __half* __restrict__ lorabuf,
    float* __restrict__ vfout)
{
    __shared__ float tile[64 * 33];
    int b = blockIdx.x;
    if (b < 8192) {
        int z = b >> 11, rem = b & 2047;
        const float* W = z == 0 ? Wr : z == 1 ? Wk : z == 2 ? Wv : Wo;
        conv_tile2(W, wbuf + (size_t)z * WSLOT_H, HID, HID, rem & 63, rem >> 6, tile);
    } else if (b < 8448) {
        int rem = b - 8192;                      // g1: K=2048,N=256 -> 8 x 32
        conv_tile2(g1, g1buf, HID, 256, rem & 7, rem >> 3, tile);
    } else if (b < 8704) {
        int rem = b - 8448;                      // g2: K=256,N=2048 -> 64 x 4
        conv_tile2(g2, g2buf, 256, HID, rem & 63, rem >> 6, tile);
    } else if (b < 8800) {
        int rem = b - 8704;                      // a1: K=2048,N=96 -> 3 x 32
        conv_tile2(a1, lorabuf, HID, 96, rem % 3, rem / 3, tile);
    } else if (b < 8896) {
        int rem = b - 8800;                      // w1
        conv_tile2(w1, lorabuf + LSLOT_H, HID, 96, rem % 3, rem / 3, tile);
    } else if (b < 8960) {
        int rem = b - 8896;                      // v1: K=2048,N=64 -> 2 x 32
        conv_tile2(v1, lorabuf + 2 * LSLOT_H, HID, 64, rem & 1, rem >> 1, tile);
    } else {
        if (!vfout) return;
        int rem = b - 8960;                      // 0..511, copy 4096 floats each
#pragma unroll
        for (int j = 0; j < 4; j++) {
            size_t i = (size_t)rem * 4096 + j * 1024 + threadIdx.x * 4;
            *(float4*)(vfout + i) = *(const float4*)(vf + i);
        }
    }
}
#define PREPW_BLOCKS 9472

// ---------------- fused LN + token-shift mix + fp16 split ----------------
// Slots 0..4 (r,k,v,g,a) single-plane; slot 5 (w) two-plane.
__global__ void __launch_bounds__(256) ln_mix_kernel(
    const float* __restrict__ x, const float* __restrict__ state1,
    const float* __restrict__ lnw, const float* __restrict__ lnb,
    const float* __restrict__ cr, const float* __restrict__ ck,
    const float* __restrict__ cv, const float* __restrict__ cg,
    const float* __restrict__ ca, const float* __restrict__ cw,
    __half* __restrict__ abuf,
    float* __restrict__ state1_out)
{
    int t = blockIdx.x;
    const float* xt = x + (size_t)t * HID;
    const float* xp = x + (size_t)(t - 1) * HID;

    float2 v0[4], v1[4];
    float s0 = 0.f, s1 = 0.f;
#pragma unroll
    for (int j = 0; j < 4; j++) {
        int c = threadIdx.x * 2 + j * 512;
        v0[j] = *(const float2*)(xt + c);
        s0 += v0[j].x + v0[j].y;
        v1[j] = t ? *(const float2*)(xp + c) : make_float2(0.f, 0.f);
        s1 += v1[j].x + v1[j].y;
    }
    float mu0 = blk_sum256(s0) * (1.f / HID);
    float mu1 = blk_sum256(s1) * (1.f / HID);
    float q0 = 0.f, q1 = 0.f;
#pragma unroll
    for (int j = 0; j < 4; j++) {
        float d;
        d = v0[j].x - mu0; q0 += d * d;
        d = v0[j].y - mu0; q0 += d * d;
        d = v1[j].x - mu1; q1 += d * d;
        d = v1[j].y - mu1; q1 += d * d;
    }
    float inv0 = rsqrtf(blk_sum256(q0) * (1.f / HID) + 1e-5f);
    float inv1 = rsqrtf(blk_sum256(q1) * (1.f / HID) + 1e-5f);

#pragma unroll
    for (int j = 0; j < 4; j++) {
        int c = threadIdx.x * 2 + j * 512;
        float2 wv = *(const float2*)(lnw + c);
        float2 bv = *(const float2*)(lnb + c);
        float xn0 = (v0[j].x - mu0) * inv0 * wv.x + bv.x;
        float xn1 = (v0[j].y - mu0) * inv0 * wv.y + bv.y;
        float pv0 = t ? (v1[j].x - mu1) * inv1 * wv.x + bv.x : state1[c];
        float pv1 = t ? (v1[j].y - mu1) * inv1 * wv.y + bv.y : state1[c + 1];
        float sx0 = pv0 - xn0, sx1 = pv1 - xn1;

        __half* arow = abuf + (size_t)t * 2 * HID + c;
#pragma unroll
        for (int s = 0; s < 6; s++) {
            const float* coefA = (s == 0) ? cr : (s == 1) ? ck : (s == 2) ? cv
                               : (s == 3) ? cg : (s == 4) ? ca : cw;
            float a0 = xn0 + coefA[c] * sx0;
            float a1 = xn1 + coefA[c + 1] * sx1;
            __half* p = arow + (size_t)s * ASLOT_H;
            if (s == 5) {
                __half h0, l0, h1, l1;
                hsplit(a0, h0, l0);
                hsplit(a1, h1, l1);
                *(__half2*)(p) = __half2(h0, h1);
                *(__half2*)(p + HID) = __half2(l0, l1);
            } else {
                *(__half2*)(p) = __floats2half2_rn(a0, a1);
            }
        }
        if (state1_out && t == T_LEN - 1) {
            state1_out[c] = xn0;
            state1_out[c + 1] = xn1;
        }
    }
}

// ---------------- fused LoRA-up (+activations) + scan prep ----------------
#define FIN_SP 66
#define FIN_SMEM ((3 * 64 * FIN_SP + 16 * 65 * 2) * 4)

__global__ void __launch_bounds__(256) finish_kernel(
    const float* __restrict__ hbuf,
    const float* __restrict__ a2, const float* __restrict__ w2, const float* __restrict__ v2,
    const float* __restrict__ a0, const float* __restrict__ w0, const float* __restrict__ v0b,
    const float* __restrict__ vf,
    const float* __restrict__ kbuf, const float* __restrict__ rbuf,
    float* __restrict__ vslot,
    const float* __restrict__ k_k, const float* __restrict__ k_a,
    float* __restrict__ k2out, float* __restrict__ pscan2)
{
    extern __shared__ float fs[];
    float* a_s = fs;
    float* w_s = fs + 64 * FIN_SP;
    float* v_s = fs + 2 * 64 * FIN_SP;
    float* As = fs + 3 * 64 * FIN_SP;
    float* Bs = As + 16 * 65;

    int tb = blockIdx.x >> 5;
    int h = blockIdx.x & 31;
    int t0 = tb * 64;
    int cb = h * HEADD;

    int tid = threadIdx.x;
    int tx = tid & 15, ty = tid >> 4;

#pragma unroll
    for (int z = 0; z < 3; z++) {
        const float* B = z == 0 ? a2 : z == 1 ? w2 : v2;
        const float* bias = z == 0 ? a0 : z == 1 ? w0 : v0b;
        int K = (z == 2) ? 64 : 96;
        int zoff = z * 128;
        float acc[4][4] = {};
        for (int k0 = 0; k0 < K; k0 += 16) {
#pragma unroll
            for (int i = tid; i < 64 * 16; i += 256) {
                int r = i >> 4, c = i & 15;
                As[c * 65 + r] = hbuf[(size_t)(t0 + r) * 384 + zoff + k0 + c];
            }
#pragma unroll
            for (int i = tid; i < 16 * 64; i += 256) {
                int r = i >> 6, c = i & 63;
                Bs[r * 65 + c] = B[(size_t)(k0 + r) * HID + cb + c];
            }
            __syncthreads();
#pragma unroll
            for (int kk = 0; kk < 16; kk++) {
                float a[4], b[4];
#pragma unroll
                for (int i = 0; i < 4; i++) a[i] = As[kk * 65 + ty * 4 + i];
#pragma unroll
                for (int jj = 0; jj < 4; jj++) b[jj] = Bs[kk * 65 + tx * 4 + jj];
#pragma unroll
                for (int i = 0; i < 4; i++)
#pragma unroll
                    for (int jj = 0; jj < 4; jj++) acc[i][jj] = fmaf(a[i], b[jj], acc[i][jj]);
            }
            __syncthreads();
        }
#pragma unroll
        for (int i = 0; i < 4; i++) {
            int lr = ty * 4 + i;
#pragma unroll
            for (int jj = 0; jj < 4; jj++) {
                int lc = tx * 4 + jj;
                float s = sigmoidf(bias[cb + lc] + acc[i][jj]);
                if (z == 0) a_s[lr * FIN_SP + lc] = s;
                else if (z == 1) w_s[lr * FIN_SP + lc] = __expf(-0.606531f * s);
                else {
                    size_t gi = (size_t)(t0 + lr) * HID + cb + lc;
                    float vv = vslot[gi];
                    float nv = vv + (vf[gi] - vv) * s;
                    v_s[lr * FIN_SP + lc] = nv;
                    vslot[gi] = nv;
                }
            }
        }
        __syncthreads();
    }

    int wrp = tid >> 5, lane = tid & 31;
#pragma unroll
    for (int pi = 0; pi < 4; pi++) {
        int pp = wrp * 4 + pi;
        int r0 = 2 * pp, r1 = r0 + 1;
        int pr = tb * 32 + pp;
        int b0 = (t0 + r0) * HID + cb;
        int b1 = b0 + HID;

        float kA0 = kbuf[b0 + lane], kB0 = kbuf[b0 + lane + 32];
        float qA0 = kA0 * k_k[cb + lane], qB0 = kB0 * k_k[cb + lane + 32];
        float inv0 = 1.f / fmaxf(sqrtf(warp_sum(qA0 * qA0 + qB0 * qB0)), 1e-12f);
        float kkA0 = qA0 * inv0, kkB0 = qB0 * inv0;
        float aA0 = a_s[r0 * FIN_SP + lane], aB0 = a_s[r0 * FIN_SP + lane + 32];
        float k2A0 = kA0 * (1.f + (aA0 - 1.f) * k_a[cb + lane]);
        float k2B0 = kB0 * (1.f + (aB0 - 1.f) * k_a[cb + lane + 32]);
        k2out[b0 + lane] = k2A0;
        k2out[b0 + lane + 32] = k2B0;

        float kA1 = kbuf[b1 + lane], kB1 = kbuf[b1 + lane + 32];
        float qA1 = kA1 * k_k[cb + lane], qB1 = kB1 * k_k[cb + lane + 32];
        float inv1 = 1.f / fmaxf(sqrtf(warp_sum(qA1 * qA1 + qB1 * qB1)), 1e-12f);
        float kkA1 = qA1 * inv1, kkB1 = qB1 * inv1;
        float aA1 = a_s[r1 * FIN_SP + lane], aB1 = a_s[r1 * FIN_SP + lane + 32];
        float k2A1 = kA1 * (1.f + (aA1 - 1.f) * k_a[cb + lane]);
        float k2B1 = kB1 * (1.f + (aB1 - 1.f) * k_a[cb + lane + 32]);
        k2out[b1 + lane] = k2A1;
        k2out[b1 + lane + 32] = k2B1;

        float wA0 = w_s[r0 * FIN_SP + lane], wB0 = w_s[r0 * FIN_SP + lane + 32];
        float kaA0 = kkA0 * aA0, kaB0 = kkB0 * aB0;

        float c1 = warp_sum(kkA1 * kaA0 + kkB1 * kaB0);
        float c2 = warp_sum(kkA1 * k2A0 + kkB1 * k2B0);

        float* P = pscan2 + ((size_t)pr * NHEAD + h) * 1024;
        P[0 * 64 + lane] = kkA0;           P[0 * 64 + lane + 32] = kkB0;
        P[1 * 64 + lane] = kkA1 * wA0;     P[1 * 64 + lane + 32] = kkB1 * wB0;
        P[2 * 64 + lane] = wA0;            P[2 * 64 + lane + 32] = wB0;
        P[3 * 64 + lane] = kaA0;           P[3 * 64 + lane + 32] = kaB0;
        P[4 * 64 + lane] = k2A0;           P[4 * 64 + lane + 32] = k2B0;
        P[5 * 64 + lane] = rbuf[b0 + lane]; P[5 * 64 + lane + 32] = rbuf[b0 + lane + 32];
        P[6 * 64 + lane] = w_s[r1 * FIN_SP + lane]; P[6 * 64 + lane + 32] = w_s[r1 * FIN_SP + lane + 32];
        P[7 * 64 + lane] = kkA1 * aA1;     P[7 * 64 + lane + 32] = kkB1 * aB1;
        P[8 * 64 + lane] = k2A1;           P[8 * 64 + lane + 32] = k2B1;
        P[9 * 64 + lane] = rbuf[b1 + lane]; P[9 * 64 + lane + 32] = rbuf[b1 + lane + 32];
        P[10 * 64 + lane] = v_s[r0 * FIN_SP + lane]; P[10 * 64 + lane + 32] = v_s[r0 * FIN_SP + lane + 32];
        P[11 * 64 + lane] = v_s[r1 * FIN_SP + lane]; P[11 * 64 + lane + 32] = v_s[r1 * FIN_SP + lane + 32];
        if (lane == 0) { P[12 * 64] = c1; P[12 * 64 + 1] = c2; }
    }
}

// ---------------- scan v3: two steps per reduction round ----------------
__global__ void __launch_bounds__(256) scan3_kernel(
    const float* __restrict__ pscan2,
    const float* __restrict__ state2, float* __restrict__ ypart,
    float* __restrict__ Sout)
{
    int h = blockIdx.x >> 2;
    int q = blockIdx.x & 3;
    int tid = threadIdx.x;
    int wrp = tid >> 5, lane = tid & 31;
    int rsel = lane >> 4, colg = lane & 15;
    int row = q * 16 + 2 * wrp + rsel;

    float4 S = *(const float4*)(state2 + (size_t)h * 4096 + row * 64 + colg * 4);

    __shared__ float buf[2][1024];

    const float* pB = pscan2 + (size_t)h * 1024;
    const size_t pstride = (size_t)NHEAD * 1024;

    ((float4*)buf[0])[tid] = *(const float4*)(pB + tid * 4);
    float4 preA = *(const float4*)(pB + pstride + tid * 4);
    float4 preB;

    for (int pr = 0; pr < NPAIR; pr++) {
        __syncthreads();
        preB = (pr + 2 < NPAIR) ? *(const float4*)(pB + (size_t)(pr + 2) * pstride + tid * 4)
                                : preA;
        const float* b = buf[pr & 1];
        float4 kk4  = *(const float4*)(b + 0 * 64 + colg * 4);
        float4 kkw4 = *(const float4*)(b + 1 * 64 + colg * 4);
        float4 w4   = *(const float4*)(b + 2 * 64 + colg * 4);
        float4 ka4  = *(const float4*)(b + 3 * 64 + colg * 4);
        float4 k4   = *(const float4*)(b + 4 * 64 + colg * 4);
        float4 r4   = *(const float4*)(b + 5 * 64 + colg * 4);
        float4 w14  = *(const float4*)(b + 6 * 64 + colg * 4);
        float4 ka14 = *(const float4*)(b + 7 * 64 + colg * 4);
        float4 k14  = *(const float4*)(b + 8 * 64 + colg * 4);
        float4 r14  = *(const float4*)(b + 9 * 64 + colg * 4);
        float v0 = b[10 * 64 + row];
        float v1 = b[11 * 64 + row];
        float c1 = b[12 * 64];
        float c2 = b[12 * 64 + 1];

        float d0 = S.x * kk4.x + S.y * kk4.y + S.z * kk4.z + S.w * kk4.w;
        float d1 = S.x * kkw4.x + S.y * kkw4.y + S.z * kkw4.z + S.w * kkw4.w;
#pragma unroll
        for (int o = 1; o <= 8; o <<= 1) {
            d0 += __shfl_xor_sync(0xffffffffu, d0, o);
            d1 += __shfl_xor_sync(0xffffffffu, d1, o);
        }
        float p0 = d0;
        float p1 = d1 - p0 * c1 + v0 * c2;

        S.x = S.x * w4.x - p0 * ka4.x + v0 * k4.x;
        S.y = S.y * w4.y - p0 * ka4.y + v0 * k4.y;
        S.z = S.z * w4.z - p0 * ka4.z + v0 * k4.z;
        S.w = S.w * w4.w - p0 * ka4.w + v0 * k4.w;

        float y0 = S.x * r4.x + S.y * r4.y + S.z * r4.z + S.w * r4.w;
        y0 += __shfl_xor_sync(0xffffffffu, y0, 1);
        y0 += __shfl_xor_sync(0xffffffffu, y0, 2);
        if ((colg & 3) == 0)
            ypart[((size_t)(2 * pr) * HID + h * HEADD + row) * 4 + (colg >> 2)] = y0;

        if (pr + 1 < NPAIR)
            ((float4*)buf[(pr + 1) & 1])[tid] = preA;
        preA = preB;

        S.x = S.x * w14.x - p1 * ka14.x + v1 * k14.x;
        S.y = S.y * w14.y - p1 * ka14.y + v1 * k14.y;
        S.z = S.z * w14.z - p1 * ka14.z + v1 * k14.z;
        S.w = S.w * w14.w - p1 * ka14.w + v1 * k14.w;

        float y1 = S.x * r14.x + S.y * r14.y + S.z * r14.z + S.w * r14.w;
        y1 += __shfl_xor_sync(0xffffffffu, y1, 1);
        y1 += __shfl_xor_sync(0xffffffffu, y1, 2);
        if ((colg & 3) == 0)
            ypart[((size_t)(2 * pr + 1) * HID + h * HEADD + row) * 4 + (colg >> 2)] = y1;
    }
    *(float4*)(Sout + (size_t)h * 4096 + row * 64 + colg * 4) = S;
}

// ---------------- groupnorm + rkv + gate -> single-plane fp16 into abuf ----------------
__global__ void __launch_bounds__(256) post_kernel(
    const float* __restrict__ ypart, const float* __restrict__ r,
    const float* __restrict__ k2, const float* __restrict__ v,
    const float* __restrict__ g, const float* __restrict__ r_k,
    const float* __restrict__ lnxw, const float* __restrict__ lnxb,
    __half* __restrict__ zsplit)
{
    int gw = (blockIdx.x * 256 + threadIdx.x) >> 5;
    int lane = threadIdx.x & 31;
    if (gw >= T_LEN * NHEAD) return;
    int t = gw >> 5, h = gw & 31;
    int base = t * HID + h * HEADD;
    int cb = h * HEADD;

    float4 yp0 = *(const float4*)(ypart + (size_t)(base + lane) * 4);
    float4 yp1 = *(const float4*)(ypart + (size_t)(base + lane + 32) * 4);
    float y0 = (yp0.x + yp0.y) + (yp0.z + yp0.w);
    float y1 = (yp1.x + yp1.y) + (yp1.z + yp1.w);

    float mu = warp_sum(y0 + y1) * (1.f / HEADD);
    float d0 = y0 - mu, d1 = y1 - mu;
    float var = warp_sum(d0 * d0 + d1 * d1) * (1.f / HEADD);
    float inv = rsqrtf(var + 0.00064f);

    float rs = warp_sum(r[base + lane] * k2[base + lane] * r_k[cb + lane] +
                        r[base + lane + 32] * k2[base + lane + 32] * r_k[cb + lane + 32]);

    float z0 = (d0 * inv * lnxw[cb + lane] + lnxb[cb + lane] + rs * v[base + lane]) * g[base + lane];
    float z1 = (d1 * inv * lnxw[cb + lane + 32] + lnxb[cb + lane + 32] + rs * v[base + lane + 32]) * g[base + lane + 32];

    size_t zb = (size_t)t * 2 * HID;
    zsplit[zb + cb + lane] = __float2half_rn(z0);
    zsplit[zb + cb + lane + 32] = __float2half_rn(z1);
}

// ---------------- host launcher ----------------
extern "C" void kernel_launch(void* const* d_in, const int* in_sizes, int n_in,
                              void* d_out, int out_size)
{
    const float* x       = (const float*)d_in[0];
    const float* state1  = (const float*)d_in[1];
    const float* state2  = (const float*)d_in[2];
    const float* v_first = (const float*)d_in[3];
    const float* ln1_w   = (const float*)d_in[4];
    const float* ln1_b   = (const float*)d_in[5];
    const float* x_r     = (const float*)d_in[6];
    const float* x_w     = (const float*)d_in[7];
    const float* x_k     = (const float*)d_in[8];
    const float* x_v     = (const float*)d_in[9];
    const float* x_a     = (const float*)d_in[10];
    const float* x_g     = (const float*)d_in[11];
    const float* Wr      = (const float*)d_in[12];
    const float* Wk      = (const float*)d_in[13];
    const float* Wv      = (const float*)d_in[14];
    const float* Wo      = (const float*)d_in[15];
    const float* w0      = (const float*)d_in[16];
    const float* w1      = (const float*)d_in[17];
    const float* w2      = (const float*)d_in[18];
    const float* a0      = (const float*)d_in[19];
    const float* a1      = (const float*)d_in[20];
    const float* a2      = (const float*)d_in[21];
    const float* v0      = (const float*)d_in[22];
    const float* v1      = (const float*)d_in[23];
    const float* v2      = (const float*)d_in[24];
    const float* g1      = (const float*)d_in[25];
    const float* g2      = (const float*)d_in[26];
    const float* k_k     = (const float*)d_in[27];
    const float* k_a     = (const float*)d_in[28];
    const float* r_k     = (const float*)d_in[29];
    const float* ln_x_w  = (const float*)d_in[30];
    const float* ln_x_b  = (const float*)d_in[31];

    float* sc = nullptr;      cudaGetSymbolAddress((void**)&sc, g_scratch);
    float* hbuf = nullptr;    cudaGetSymbolAddress((void**)&hbuf, g_hbuf);
    float* pscan2 = nullptr;  cudaGetSymbolAddress((void**)&pscan2, g_pscan2);
    float* ypart = nullptr;   cudaGetSymbolAddress((void**)&ypart, g_ypart);
    __half* abuf = nullptr;   cudaGetSymbolAddress((void**)&abuf, g_abuf);
    __half* wbuf = nullptr;   cudaGetSymbolAddress((void**)&wbuf, g_wbuf);
    __half* g1buf = nullptr;  cudaGetSymbolAddress((void**)&g1buf, g_g1buf);
    __half* g2buf = nullptr;  cudaGetSymbolAddress((void**)&g2buf, g_g2buf);
    __half* ghbuf = nullptr;  cudaGetSymbolAddress((void**)&ghbuf, g_ghbuf);
    __half* lorabuf = nullptr; cudaGetSymbolAddress((void**)&lorabuf, g_lorabuf);

    cudaFuncSetAttribute(mm128_kernel, cudaFuncAttributeMaxDynamicSharedMemorySize, MM_SMEM);
    cudaFuncSetAttribute(finish_kernel, cudaFuncAttributeMaxDynamicSharedMemorySize, FIN_SMEM);

#define SLOT(s) (sc + (size_t)(s) * NTOK_EL)

    float* out = (float*)d_out;
    const int OFF_OUT = 0;
    const int OFF_S1  = NTOK_EL;
    const int OFF_S2  = OFF_S1 + HID;
    const int OFF_VF  = OFF_S2 + NHEAD * HEADD * HEADD;
    const int TOTAL   = OFF_VF + NTOK_EL;
    bool full = (out_size >= TOTAL);

    float* s1_out = full ? out + OFF_S1 : nullptr;
    float* s2_out = full ? out + OFF_S2 : SLOT(S_TMP);
    float* vf_out = full ? out + OFF_VF : nullptr;

    // 1. unified weight conversion + v_first passthrough
    prepw_kernel<<<PREPW_BLOCKS, 256>>>(Wr, Wk, Wv, Wo, g1, g2, a1, w1, v1, v_first,
                                        wbuf, g1buf, g2buf, lorabuf, vf_out);

    // 2. fused LN + mix + fp16 split (slots r,k,v,g,a single-plane; w 2-plane)
    ln_mix_kernel<<<T_LEN, 256>>>(x, state1, ln1_w, ln1_b,
                                  x_r, x_k, x_v, x_g, x_a, x_w,
                                  abuf, s1_out);

    // 3. mega-batch: r,k,v,g-down,a-down single-plane; w-down 2-plane
    {
        MMJobs jobs;
        jobs.j[0] = { wbuf,                  SLOT(S_R),      nullptr, HID, HID, 0, 0, 1 };
        jobs.j[1] = { wbuf + WSLOT_H,        SLOT(S_K),      nullptr, HID, HID, 0, 1, 1 };
        jobs.j[2] = { wbuf + 2 * WSLOT_H,    SLOT(S_V),      nullptr, HID, HID, 0, 2, 1 };
        jobs.j[3] = { g1buf,                 (float*)ghbuf,  nullptr, 256, 256, 4, 3, 1 };
        jobs.j[4] = { lorabuf,               hbuf,           nullptr, 128, 384, 0, 4, 1 };
        jobs.j[5] = { lorabuf + LSLOT_H,     hbuf + 128,     nullptr, 128, 384, 3, 5, 2 };
        jobs.j[6] = { lorabuf + 2 * LSLOT_H, hbuf + 256,     nullptr, 128, 384, 0, 2, 1 };
        mm128_kernel<<<dim3(16, 8, 7), 256, MM_SMEM>>>(abuf, jobs, HID, 2);
    }

    // 4. g-up: single-plane fp16 A (sigmoid output), @g2
    {
        MMJobs jobs;
        jobs.j[0] = { g2buf, SLOT(S_G), nullptr, HID, HID, 0, 0, 1 };
        for (int i = 1; i < 7; i++) jobs.j[i] = jobs.j[0];
        mm128_kernel<<<dim3(16, 8, 1), 256, MM_SMEM>>>(ghbuf, jobs, 256, 1);
    }

    // 5. fused LoRA-up + prep
    finish_kernel<<<512, 256, FIN_SMEM>>>(hbuf, a2, w2, v2, a0, w0, v0, v_first,
                                          SLOT(S_K), SLOT(S_R), SLOT(S_V),
                                          k_k, k_a, SLOT(S_K2), pscan2);

    // 6. two-step scan
    scan3_kernel<<<128, 256>>>(pscan2, state2, ypart, s2_out);

    // 7. groupnorm + rkv + gate -> single-plane fp16 into abuf slot 0
    post_kernel<<<(T_LEN * NHEAD * 32 + 255) / 256, 256>>>(
        ypart, SLOT(S_R), SLOT(S_K2), SLOT(S_V), SLOT(S_G),
        r_k, ln_x_w, ln_x_b, abuf);

    // 8. out = x + z@Wo (single-plane, residual fused)
    {
        MMJobs jobs;
        jobs.j[0] = { wbuf + 3 * WSLOT_H, out + OFF_OUT, x, HID, HID, 1, 0, 1 };
        for (int i = 1; i < 7; i++) jobs.j[i] = jobs.j[0];
        mm128_kernel<<<dim3(16, 8, 1), 256, MM_SMEM>>>(abuf, jobs, HID, 2);
    }
}

// round 13
// speedup vs baseline: 6.0781x; 1.0057x over previous
#include <cuda_runtime.h>
#include <cuda_fp16.h>
#include <math.h>
#include <stdint.h>

#define T_LEN 1024
#define HID   2048
#define NHEAD 32
#define HEADD 64
#define NTOK_EL (T_LEN * HID)   // 2097152
#define NPAIR (T_LEN / 2)

#define ASLOT_H ((size_t)T_LEN * 2 * HID)   // A' slot: [M, 2K] fp16 {hi|lo}
#define WSLOT_H ((size_t)HID * HID)         // W' slot: [N, K] fp16 single plane
#define LSLOT_H ((size_t)128 * HID)         // lora-down W' slot (padded 128 rows)

// ---------------- static device scratch ----------------
__device__ float g_scratch[8u * (unsigned)NTOK_EL];
__device__ float g_hbuf[(size_t)T_LEN * 384];
__device__ float g_pscan2[(size_t)NPAIR * NHEAD * 1024];   // 16 planes x 64
__device__ float g_ypart[(size_t)T_LEN * HID * 4];
__device__ __align__(256) __half g_abuf[6 * ASLOT_H];      // xr,xk,xv,xg,xa,xw splits
__device__ __align__(256) __half g_wbuf[4 * WSLOT_H];      // Wr',Wk',Wv',Wo'
__device__ __align__(256) __half g_g1buf[(size_t)256 * HID];
__device__ __align__(256) __half g_g2buf[(size_t)HID * 256];
__device__ __align__(256) __half g_ghbuf[(size_t)T_LEN * 256];  // sigmoid(g-down), 1 plane
__device__ __align__(256) __half g_lorabuf[3 * LSLOT_H];   // a1',w1',v1' (zero-padded)

#define S_R   0
#define S_K   1
#define S_V   2
#define S_K2  3
#define S_G   4
#define S_TMP 5

// ---------------- helpers ----------------
__device__ __forceinline__ float blk_sum256(float v) {
    __shared__ float sh[8];
    int tid = threadIdx.x;
#pragma unroll
    for (int o = 16; o; o >>= 1) v += __shfl_xor_sync(0xffffffffu, v, o);
    if ((tid & 31) == 0) sh[tid >> 5] = v;
    __syncthreads();
    if (tid == 0) {
        float s = 0.f;
#pragma unroll
        for (int i = 0; i < 8; i++) s += sh[i];
        sh[0] = s;
    }
    __syncthreads();
    float r = sh[0];
    __syncthreads();
    return r;
}

__device__ __forceinline__ float warp_sum(float v) {
#pragma unroll
    for (int o = 16; o; o >>= 1) v += __shfl_xor_sync(0xffffffffu, v, o);
    return v;
}

__device__ __forceinline__ float sigmoidf(float v) {
    return 1.f / (1.f + __expf(-v));
}

__device__ __forceinline__ uint32_t smem_u32(const void* p) {
    uint32_t a;
    asm("{ .reg .u64 t; cvta.to.shared.u64 t, %1; cvt.u32.u64 %0, t; }" : "=r"(a) : "l"(p));
    return a;
}

__device__ __forceinline__ void hsplit(float v, __half& hi, __half& lo) {
    hi = __float2half_rn(v);
    lo = __float2half_rn(v - __half2float(hi));
}

// ======================= mma.sync fp16 GEMM =======================
#define MMK_STRIDE 80
#define MMK_TILE   (128 * MMK_STRIDE)
#define STAGE_BYTES (3 * MMK_TILE)
#define MM_SMEM (3 * STAGE_BYTES)

struct MMJob { const __half* B; float* C; const float* Res; int N; int ldc; int mode; int aslot; int planes; };
struct MMJobs { MMJob j[7]; };

__device__ __forceinline__ void cp16(uint32_t dst, const void* src) {
    asm volatile("cp.async.cg.shared.global [%0], [%1], 16;" :: "r"(dst), "l"(src));
}

__device__ __forceinline__ void ldsm4(uint32_t* r, uint32_t a) {
    asm volatile("ldmatrix.sync.aligned.m8n8.x4.shared.b16 {%0,%1,%2,%3}, [%4];"
                 : "=r"(r[0]), "=r"(r[1]), "=r"(r[2]), "=r"(r[3]) : "r"(a));
}

__device__ __forceinline__ void mma16816(float* c, const uint32_t* a, const uint32_t* b) {
    asm volatile(
        "mma.sync.aligned.m16n8k16.row.col.f32.f16.f16.f32 "
        "{%0,%1,%2,%3}, {%4,%5,%6,%7}, {%8,%9}, {%0,%1,%2,%3};"
        : "+f"(c[0]), "+f"(c[1]), "+f"(c[2]), "+f"(c[3])
        : "r"(a[0]), "r"(a[1]), "r"(a[2]), "r"(a[3]), "r"(b[0]), "r"(b[1]));
}

// aMul: A row stride = aMul*K (2 = {hi|lo} split layout, 1 = single plane)
__global__ void __launch_bounds__(256, 2) mm128_kernel(
    const __half* __restrict__ A, MMJobs jobs, int K, int aMul)
{
    extern __shared__ __align__(16) char smem[];
    uint32_t sbase = smem_u32(smem);

    const MMJob job = jobs.j[blockIdx.z];
    const int N = job.N;
    int n0 = blockIdx.x * 128;
    if (n0 >= N) return;
    int m0 = blockIdx.y * 128;

    const __half* Ab = A + (size_t)job.aslot * ASLOT_H;
    const __half* Bb = job.B;
    const int KA = aMul * K;
    const int nk = K >> 5;
    const int planes = job.planes;

    int tid = threadIdx.x;
    int wid = tid >> 5, lane = tid & 31;
    int g = lane >> 2, tig = lane & 3;
    int warp_m = wid >> 2;
    int warp_n = wid & 3;

    float acc[4][4][4];
#pragma unroll
    for (int i = 0; i < 4; i++)
#pragma unroll
        for (int j = 0; j < 4; j++)
#pragma unroll
            for (int q = 0; q < 4; q++) acc[i][j][q] = 0.f;

    auto load_stage = [&](int s, int kc) {
        uint32_t st = sbase + s * STAGE_BYTES;
        int k0 = kc << 5;
#pragma unroll
        for (int it = 0; it < 2; it++) {       // Ah
            int idx = tid + it * 256;
            int r = idx >> 2, c = idx & 3;
            cp16(st + r * MMK_STRIDE + c * 16, Ab + ((size_t)(m0 + r) * KA + k0 + c * 8));
        }
        if (planes == 2) {
#pragma unroll
            for (int it = 0; it < 2; it++) {   // Al
                int idx = tid + it * 256;
                int r = idx >> 2, c = idx & 3;
                cp16(st + MMK_TILE + r * MMK_STRIDE + c * 16,
                     Ab + ((size_t)(m0 + r) * KA + K + k0 + c * 8));
            }
        }
#pragma unroll
        for (int it = 0; it < 2; it++) {       // B
            int idx = tid + it * 256;
            int r = idx >> 2, c = idx & 3;
            cp16(st + 2 * MMK_TILE + r * MMK_STRIDE + c * 16,
                 Bb + ((size_t)(n0 + r) * K + k0 + c * 8));
        }
        asm volatile("cp.async.commit_group;" ::: "memory");
    };

    load_stage(0, 0);
    if (nk > 1) load_stage(1, 1);
    else asm volatile("cp.async.commit_group;" ::: "memory");

    int aRowSel = (lane & 15);
    int aColSel = (lane & 16) ? 16 : 0;
    int bRowSel = ((lane & 16) ? 8 : 0) + (lane & 7);
    int bColSel = (lane & 8) ? 16 : 0;

    for (int kc = 0; kc < nk; kc++) {
        asm volatile("cp.async.wait_group 1;" ::: "memory");
        __syncthreads();
        if (kc + 2 < nk) load_stage((kc + 2) % 3, kc + 2);
        else asm volatile("cp.async.commit_group;" ::: "memory");

        uint32_t st = sbase + (kc % 3) * STAGE_BYTES;
#pragma unroll
        for (int ks = 0; ks < 2; ks++) {
            uint32_t afr[4][4], bfr[2][4];
#pragma unroll
            for (int ap = 0; ap < 2; ap++) {
                uint32_t addr = st + 2 * MMK_TILE
                                + (uint32_t)(warp_n * 32 + ap * 16 + bRowSel) * MMK_STRIDE
                                + ks * 32 + bColSel;
                ldsm4(bfr[ap], addr);
            }
#pragma unroll
            for (int am = 0; am < 4; am++) {
                uint32_t addr = st + (uint32_t)(warp_m * 64 + am * 16 + aRowSel) * MMK_STRIDE
                                + ks * 32 + aColSel;
                ldsm4(afr[am], addr);
            }
#pragma unroll
            for (int am = 0; am < 4; am++) {
                mma16816(acc[am][0], afr[am], &bfr[0][0]);
                mma16816(acc[am][1], afr[am], &bfr[0][2]);
                mma16816(acc[am][2], afr[am], &bfr[1][0]);
                mma16816(acc[am][3], afr[am], &bfr[1][2]);
            }
            if (planes == 2) {
#pragma unroll
                for (int am = 0; am < 4; am++) {
                    uint32_t addr = st + MMK_TILE
                                    + (uint32_t)(warp_m * 64 + am * 16 + aRowSel) * MMK_STRIDE
                                    + ks * 32 + aColSel;
                    ldsm4(afr[am], addr);
                }
#pragma unroll
                for (int am = 0; am < 4; am++) {
                    mma16816(acc[am][0], afr[am], &bfr[0][0]);
                    mma16816(acc[am][1], afr[am], &bfr[0][2]);
                    mma16816(acc[am][2], afr[am], &bfr[1][0]);
                    mma16816(acc[am][3], afr[am], &bfr[1][2]);
                }
            }
        }
    }

    __syncthreads();

    float* C = job.C;
    const float* Res = job.Res;
    int mode = job.mode;
    int ldc = job.ldc;
#pragma unroll
    for (int am = 0; am < 4; am++) {
#pragma unroll
        for (int an = 0; an < 4; an++) {
            int row = m0 + warp_m * 64 + am * 16 + g;
            int col = n0 + warp_n * 32 + an * 8 + tig * 2;
            float2 v0 = make_float2(acc[am][an][0], acc[am][an][1]);
            float2 v1 = make_float2(acc[am][an][2], acc[am][an][3]);
            if (mode == 4) {
                __half* Ch = (__half*)C;
                *(__half2*)(Ch + (size_t)row * ldc + col) =
                    __floats2half2_rn(sigmoidf(v0.x), sigmoidf(v0.y));
                *(__half2*)(Ch + (size_t)(row + 8) * ldc + col) =
                    __floats2half2_rn(sigmoidf(v1.x), sigmoidf(v1.y));
                continue;
            }
            if (mode == 1) {
                const float2 r0 = *(const float2*)(Res + (size_t)row * ldc + col);
                const float2 r1 = *(const float2*)(Res + (size_t)(row + 8) * ldc + col);
                v0.x += r0.x; v0.y += r0.y;
                v1.x += r1.x; v1.y += r1.y;
            } else if (mode == 3) {
                v0.x = tanhf(v0.x); v0.y = tanhf(v0.y);
                v1.x = tanhf(v1.x); v1.y = tanhf(v1.y);
            }
            *(float2*)(C + (size_t)row * ldc + col) = v0;
            *(float2*)(C + (size_t)(row + 8) * ldc + col) = v1;
        }
    }
}

// ---------------- mm64: 64x128 tile variant for small-grid tail GEMMs ----------------
#define MM64_A_TILE (64 * MMK_STRIDE)             // 5120
#define MM64_STAGE  (2 * MM64_A_TILE + MMK_TILE)  // 20480
#define MM64_SMEM   (3 * MM64_STAGE)              // 61440

__global__ void __launch_bounds__(256) mm64_kernel(
    const __half* __restrict__ A, MMJob job, int K, int aMul)
{
    extern __shared__ __align__(16) char smem[];
    uint32_t sbase = smem_u32(smem);

    const int N = job.N;
    int n0 = blockIdx.x * 128;
    if (n0 >= N) return;
    int m0 = blockIdx.y * 64;

    const __half* Ab = A + (size_t)job.aslot * ASLOT_H;
    const __half* Bb = job.B;
    const int KA = aMul * K;
    const int nk = K >> 5;
    const int planes = job.planes;

    int tid = threadIdx.x;
    int wid = tid >> 5, lane = tid & 31;
    int g = lane >> 2, tig = lane & 3;
    int warp_m = wid >> 2;   // 0..1, 32 rows each
    int warp_n = wid & 3;    // 0..3, 32 cols each

    float acc[2][4][4];
#pragma unroll
    for (int i = 0; i < 2; i++)
#pragma unroll
        for (int j = 0; j < 4; j++)
#pragma unroll
            for (int q = 0; q < 4; q++) acc[i][j][q] = 0.f;

    auto load_stage = [&](int s, int kc) {
        uint32_t st = sbase + s * MM64_STAGE;
        int k0 = kc << 5;
        {   // Ah: 64 rows x 4 x 16B = 256 transfers
            int r = tid >> 2, c = tid & 3;
            cp16(st + r * MMK_STRIDE + c * 16, Ab + ((size_t)(m0 + r) * KA + k0 + c * 8));
        }
        if (planes == 2) {
            int r = tid >> 2, c = tid & 3;
            cp16(st + MM64_A_TILE + r * MMK_STRIDE + c * 16,
                 Ab + ((size_t)(m0 + r) * KA + K + k0 + c * 8));
        }
#pragma unroll
        for (int it = 0; it < 2; it++) {   // B: 128 rows
            int idx = tid + it * 256;
            int r = idx >> 2, c = idx & 3;
            cp16(st + 2 * MM64_A_TILE + r * MMK_STRIDE + c * 16,
                 Bb + ((size_t)(n0 + r) * K + k0 + c * 8));
        }
        asm volatile("cp.async.commit_group;" ::: "memory");
    };

    load_stage(0, 0);
    if (nk > 1) load_stage(1, 1);
    else asm volatile("cp.async.commit_group;" ::: "memory");

    int aRowSel = (lane & 15);
    int aColSel = (lane & 16) ? 16 : 0;
    int bRowSel = ((lane & 16) ? 8 : 0) + (lane & 7);
    int bColSel = (lane & 8) ? 16 : 0;

    for (int kc = 0; kc < nk; kc++) {
        asm volatile("cp.async.wait_group 1;" ::: "memory");
        __syncthreads();
        if (kc + 2 < nk) load_stage((kc + 2) % 3, kc + 2);
        else asm volatile("cp.async.commit_group;" ::: "memory");

        uint32_t st = sbase + (kc % 3) * MM64_STAGE;
#pragma unroll
        for (int ks = 0; ks < 2; ks++) {
            uint32_t afr[2][4], bfr[2][4];
#pragma unroll
            for (int ap = 0; ap < 2; ap++) {
                uint32_t addr = st + 2 * MM64_A_TILE
                                + (uint32_t)(warp_n * 32 + ap * 16 + bRowSel) * MMK_STRIDE
                                + ks * 32 + bColSel;
                ldsm4(bfr[ap], addr);
            }
#pragma unroll
            for (int am = 0; am < 2; am++) {
                uint32_t addr = st + (uint32_t)(warp_m * 32 + am * 16 + aRowSel) * MMK_STRIDE
                                + ks * 32 + aColSel;
                ldsm4(afr[am], addr);
            }
#pragma unroll
            for (int am = 0; am < 2; am++) {
                mma16816(acc[am][0], afr[am], &bfr[0][0]);
                mma16816(acc[am][1], afr[am], &bfr[0][2]);
                mma16816(acc[am][2], afr[am], &bfr[1][0]);
                mma16816(acc[am][3], afr[am], &bfr[1][2]);
            }
            if (planes == 2) {
#pragma unroll
                for (int am = 0; am < 2; am++) {
                    uint32_t addr = st + MM64_A_TILE
                                    + (uint32_t)(warp_m * 32 + am * 16 + aRowSel) * MMK_STRIDE
                                    + ks * 32 + aColSel;
                    ldsm4(afr[am], addr);
                }
#pragma unroll
                for (int am = 0; am < 2; am++) {
                    mma16816(acc[am][0], afr[am], &bfr[0][0]);
                    mma16816(acc[am][1], afr[am], &bfr[0][2]);
                    mma16816(acc[am][2], afr[am], &bfr[1][0]);
                    mma16816(acc[am][3], afr[am], &bfr[1][2]);
                }
            }
        }
    }

    __syncthreads();

    float* C = job.C;
    const float* Res = job.Res;
    int mode = job.mode;
    int ldc = job.ldc;
#pragma unroll
    for (int am = 0; am < 2; am++) {
#pragma unroll
        for (int an = 0; an < 4; an++) {
            int row = m0 + warp_m * 32 + am * 16 + g;
            int col = n0 + warp_n * 32 + an * 8 + tig * 2;
            float2 v0 = make_float2(acc[am][an][0], acc[am][an][1]);
            float2 v1 = make_float2(acc[am][an][2], acc[am][an][3]);
            if (mode == 1) {
                const float2 r0 = *(const float2*)(Res + (size_t)row * ldc + col);
                const float2 r1 = *(const float2*)(Res + (size_t)(row + 8) * ldc + col);
                v0.x += r0.x; v0.y += r0.y;
                v1.x += r1.x; v1.y += r1.y;
            }
            *(float2*)(C + (size_t)row * ldc + col) = v0;
            *(float2*)(C + (size_t)(row + 8) * ldc + col) = v1;
        }
    }
}

// ---------------- combined front-end: ln_mix (blocks 0..1023) + weight conv ----------------
__device__ __forceinline__ void conv_tile2(const float* __restrict__ W, __half* __restrict__ out,
                                           int K, int N, int bx, int by, float* tile /*64x33*/)
{
    int k0 = by * 64, n0 = bx * 32;
    int tid = threadIdx.x;
#pragma unroll
    for (int it = 0; it < 8; it++) {
        int i = tid + it * 256;
        int r = i >> 5, c = i & 31;
        tile[r * 33 + c] = W[(size_t)(k0 + r) * N + n0 + c];
    }
    __syncthreads();
    int nl = tid >> 3;
    int kq = (tid & 7) * 8;
    __half h8[8];
#pragma unroll
    for (int j = 0; j < 8; j++)
        h8[j] = __float2half_rn(tile[(kq + j) * 33 + nl]);
    *(uint4*)(out + (size_t)(n0 + nl) * K + k0 + kq) = *(uint4*)h8;
}

__device__ void ln_mix_body(
    int t,
    const float* __restrict__ x, const float* __restrict__ state1,
    const float* __restrict__ lnw, const float* __restrict__ lnb,
    const float* __restrict__ cr, const float* __restrict__ ck,
    const float* __restrict__ cv, const float* __restrict__ cg,
    const float* __restrict__ ca, const float* __restrict__ cw,
    __half* __restrict__ abuf, float* __restrict__ state1_out)
{
    const float* xt = x + (size_t)t * HID;
    const float* xp = x + (size_t)(t - 1) * HID;

    float2 v0[4], v1[4];
    float s0 = 0.f, s1 = 0.f;
#pragma unroll
    for (int j = 0; j < 4; j++) {
        int c = threadIdx.x * 2 + j * 512;
        v0[j] = *(const float2*)(xt + c);
        s0 += v0[j].x + v0[j].y;
        v1[j] = t ? *(const float2*)(xp + c) : make_float2(0.f, 0.f);
        s1 += v1[j].x + v1[j].y;
    }
    float mu0 = blk_sum256(s0) * (1.f / HID);
    float mu1 = blk_sum256(s1) * (1.f / HID);
    float q0 = 0.f, q1 = 0.f;
#pragma unroll
    for (int j = 0; j < 4; j++) {
        float d;
        d = v0[j].x - mu0; q0 += d * d;
        d = v0[j].y - mu0; q0 += d * d;
        d = v1[j].x - mu1; q1 += d * d;
        d = v1[j].y - mu1; q1 += d * d;
    }
    float inv0 = rsqrtf(blk_sum256(q0) * (1.f / HID) + 1e-5f);
    float inv1 = rsqrtf(blk_sum256(q1) * (1.f / HID) + 1e-5f);

#pragma unroll
    for (int j = 0; j < 4; j++) {
        int c = threadIdx.x * 2 + j * 512;
        float2 wv = *(const float2*)(lnw + c);
        float2 bv = *(const float2*)(lnb + c);
        float xn0 = (v0[j].x - mu0) * inv0 * wv.x + bv.x;
        float xn1 = (v0[j].y - mu0) * inv0 * wv.y + bv.y;
        float pv0 = t ? (v1[j].x - mu1) * inv1 * wv.x + bv.x : state1[c];
        float pv1 = t ? (v1[j].y - mu1) * inv1 * wv.y + bv.y : state1[c + 1];
        float sx0 = pv0 - xn0, sx1 = pv1 - xn1;

        __half* arow = abuf + (size_t)t * 2 * HID + c;
#pragma unroll
        for (int s = 0; s < 6; s++) {
            const float* coefA = (s == 0) ? cr : (s == 1) ? ck : (s == 2) ? cv
                               : (s == 3) ? cg : (s == 4) ? ca : cw;
            float a0 = xn0 + coefA[c] * sx0;
            float a1 = xn1 + coefA[c + 1] * sx1;
            __half* p = arow + (size_t)s * ASLOT_H;
            if (s == 5) {
                __half h0, l0, h1, l1;
                hsplit(a0, h0, l0);
                hsplit(a1, h1, l1);
                *(__half2*)(p) = __half2(h0, h1);
                *(__half2*)(p + HID) = __half2(l0, l1);
            } else {
                *(__half2*)(p) = __floats2half2_rn(a0, a1);
            }
        }
        if (state1_out && t == T_LEN - 1) {
            state1_out[c] = xn0;
            state1_out[c + 1] = xn1;
        }
    }
}

#define FRONT_BLOCKS (1024 + 9472)

__global__ void __launch_bounds__(256) front_kernel(
    const float* __restrict__ x, const float* __restrict__ state1,
    const float* __restrict__ lnw, const float* __restrict__ lnb,
    const float* __restrict__ cr, const float* __restrict__ ck,
    const float* __restrict__ cv, const float* __restrict__ cg,
    const float* __restrict__ ca, const float* __restrict__ cw,
    __half* __restrict__ abuf, float* __restrict__ state1_out,
    const float* __restrict__ Wr, const float* __restrict__ Wk,
    const float* __restrict__ Wv, const float* __restrict__ Wo,
    const float* __restrict__ g1, const float* __restrict__ g2,
    const float* __restrict__ a1, const float* __restrict__ w1,
    const float* __restrict__ v1, const float* __restrict__ vf,
    __half* __restrict__ wbuf, __half* __restrict__ g1buf,
    __half* __restrict__ g2buf, __half* __restrict__ lorabuf,
    float* __restrict__ vfout)
{
    __shared__ float tile[64 * 33];
    int bb = blockIdx.x;
    if (bb < 1024) {
        ln_mix_body(bb, x, state1, lnw, lnb, cr, ck, cv, cg, ca, cw, abuf, state1_out);
        return;
    }
    int b = bb - 1024;
    if (b < 8192) {
        int z = b >> 11, rem = b & 2047;
        const float* W = z == 0 ? Wr : z == 1 ? Wk : z == 2 ? Wv : Wo;
        conv_tile2(W, wbuf + (size_t)z * WSLOT_H, HID, HID, rem & 63, rem >> 6, tile);
    } else if (b < 8448) {
        int rem = b - 8192;
        conv_tile2(g1, g1buf, HID, 256, rem & 7, rem >> 3, tile);
    } else if (b < 8704) {
        int rem = b - 8448;
        conv_tile2(g2, g2buf, 256, HID, rem & 63, rem >> 6, tile);
    } else if (b < 8800) {
        int rem = b - 8704;
        conv_tile2(a1, lorabuf, HID, 96, rem % 3, rem / 3, tile);
    } else if (b < 8896) {
        int rem = b - 8800;
        conv_tile2(w1, lorabuf + LSLOT_H, HID, 96, rem % 3, rem / 3, tile);
    } else if (b < 8960) {
        int rem = b - 8896;
        conv_tile2(v1, lorabuf + 2 * LSLOT_H, HID, 64, rem & 1, rem >> 1, tile);
    } else {
        if (!vfout) return;
        int rem = b - 8960;
#pragma unroll
        for (int j = 0; j < 4; j++) {
            size_t i = (size_t)rem * 4096 + j * 1024 + threadIdx.x * 4;
            *(float4*)(vfout + i) = *(const float4*)(vf + i);
        }
    }
}

// ---------------- fused LoRA-up (+activations) + scan prep ----------------
#define FIN_SP 66
#define FIN_SMEM ((3 * 64 * FIN_SP + 16 * 65 * 2) * 4)

__global__ void __launch_bounds__(256) finish_kernel(
    const float* __restrict__ hbuf,
    const float* __restrict__ a2, const float* __restrict__ w2, const float* __restrict__ v2,
    const float* __restrict__ a0, const float* __restrict__ w0, const float* __restrict__ v0b,
    const float* __restrict__ vf,
    const float* __restrict__ kbuf, const float* __restrict__ rbuf,
    float* __restrict__ vslot,
    const float* __restrict__ k_k, const float* __restrict__ k_a,
    float* __restrict__ k2out, float* __restrict__ pscan2)
{
    extern __shared__ float fs[];
    float* a_s = fs;
    float* w_s = fs + 64 * FIN_SP;
    float* v_s = fs + 2 * 64 * FIN_SP;
    float* As = fs + 3 * 64 * FIN_SP;
    float* Bs = As + 16 * 65;

    int tb = blockIdx.x >> 5;
    int h = blockIdx.x & 31;
    int t0 = tb * 64;
    int cb = h * HEADD;

    int tid = threadIdx.x;
    int tx = tid & 15, ty = tid >> 4;

#pragma unroll
    for (int z = 0; z < 3; z++) {
        const float* B = z == 0 ? a2 : z == 1 ? w2 : v2;
        const float* bias = z == 0 ? a0 : z == 1 ? w0 : v0b;
        int K = (z == 2) ? 64 : 96;
        int zoff = z * 128;
        float acc[4][4] = {};
        for (int k0 = 0; k0 < K; k0 += 16) {
#pragma unroll
            for (int i = tid; i < 64 * 16; i += 256) {
                int r = i >> 4, c = i & 15;
                As[c * 65 + r] = hbuf[(size_t)(t0 + r) * 384 + zoff + k0 + c];
            }
#pragma unroll
            for (int i = tid; i < 16 * 64; i += 256) {
                int r = i >> 6, c = i & 63;
                Bs[r * 65 + c] = B[(size_t)(k0 + r) * HID + cb + c];
            }
            __syncthreads();
#pragma unroll
            for (int kk = 0; kk < 16; kk++) {
                float a[4], b[4];
#pragma unroll
                for (int i = 0; i < 4; i++) a[i] = As[kk * 65 + ty * 4 + i];
#pragma unroll
                for (int jj = 0; jj < 4; jj++) b[jj] = Bs[kk * 65 + tx * 4 + jj];
#pragma unroll
                for (int i = 0; i < 4; i++)
#pragma unroll
                    for (int jj = 0; jj < 4; jj++) acc[i][jj] = fmaf(a[i], b[jj], acc[i][jj]);
            }
            __syncthreads();
        }
#pragma unroll
        for (int i = 0; i < 4; i++) {
            int lr = ty * 4 + i;
#pragma unroll
            for (int jj = 0; jj < 4; jj++) {
                int lc = tx * 4 + jj;
                float s = sigmoidf(bias[cb + lc] + acc[i][jj]);
                if (z == 0) a_s[lr * FIN_SP + lc] = s;
                else if (z == 1) w_s[lr * FIN_SP + lc] = __expf(-0.606531f * s);
                else {
                    size_t gi = (size_t)(t0 + lr) * HID + cb + lc;
                    float vv = vslot[gi];
                    float nv = vv + (vf[gi] - vv) * s;
                    v_s[lr * FIN_SP + lc] = nv;
                    vslot[gi] = nv;
                }
            }
        }
        __syncthreads();
    }

    int wrp = tid >> 5, lane = tid & 31;
#pragma unroll
    for (int pi = 0; pi < 4; pi++) {
        int pp = wrp * 4 + pi;
        int r0 = 2 * pp, r1 = r0 + 1;
        int pr = tb * 32 + pp;
        int b0 = (t0 + r0) * HID + cb;
        int b1 = b0 + HID;

        float kA0 = kbuf[b0 + lane], kB0 = kbuf[b0 + lane + 32];
        float qA0 = kA0 * k_k[cb + lane], qB0 = kB0 * k_k[cb + lane + 32];
        float inv0 = 1.f / fmaxf(sqrtf(warp_sum(qA0 * qA0 + qB0 * qB0)), 1e-12f);
        float kkA0 = qA0 * inv0, kkB0 = qB0 * inv0;
        float aA0 = a_s[r0 * FIN_SP + lane], aB0 = a_s[r0 * FIN_SP + lane + 32];
        float k2A0 = kA0 * (1.f + (aA0 - 1.f) * k_a[cb + lane]);
        float k2B0 = kB0 * (1.f + (aB0 - 1.f) * k_a[cb + lane + 32]);
        k2out[b0 + lane] = k2A0;
        k2out[b0 + lane + 32] = k2B0;

        float kA1 = kbuf[b1 + lane], kB1 = kbuf[b1 + lane + 32];
        float qA1 = kA1 * k_k[cb + lane], qB1 = kB1 * k_k[cb + lane + 32];
        float inv1 = 1.f / fmaxf(sqrtf(warp_sum(qA1 * qA1 + qB1 * qB1)), 1e-12f);
        float kkA1 = qA1 * inv1, kkB1 = qB1 * inv1;
        float aA1 = a_s[r1 * FIN_SP + lane], aB1 = a_s[r1 * FIN_SP + lane + 32];
        float k2A1 = kA1 * (1.f + (aA1 - 1.f) * k_a[cb + lane]);
        float k2B1 = kB1 * (1.f + (aB1 - 1.f) * k_a[cb + lane + 32]);
        k2out[b1 + lane] = k2A1;
        k2out[b1 + lane + 32] = k2B1;

        float wA0 = w_s[r0 * FIN_SP + lane], wB0 = w_s[r0 * FIN_SP + lane + 32];
        float kaA0 = kkA0 * aA0, kaB0 = kkB0 * aB0;

        float c1 = warp_sum(kkA1 * kaA0 + kkB1 * kaB0);
        float c2 = warp_sum(kkA1 * k2A0 + kkB1 * k2B0);

        float* P = pscan2 + ((size_t)pr * NHEAD + h) * 1024;
        P[0 * 64 + lane] = kkA0;           P[0 * 64 + lane + 32] = kkB0;
        P[1 * 64 + lane] = kkA1 * wA0;     P[1 * 64 + lane + 32] = kkB1 * wB0;
        P[2 * 64 + lane] = wA0;            P[2 * 64 + lane + 32] = wB0;
        P[3 * 64 + lane] = kaA0;           P[3 * 64 + lane + 32] = kaB0;
        P[4 * 64 + lane] = k2A0;           P[4 * 64 + lane + 32] = k2B0;
        P[5 * 64 + lane] = rbuf[b0 + lane]; P[5 * 64 + lane + 32] = rbuf[b0 + lane + 32];
        P[6 * 64 + lane] = w_s[r1 * FIN_SP + lane]; P[6 * 64 + lane + 32] = w_s[r1 * FIN_SP + lane + 32];
        P[7 * 64 + lane] = kkA1 * aA1;     P[7 * 64 + lane + 32] = kkB1 * aB1;
        P[8 * 64 + lane] = k2A1;           P[8 * 64 + lane + 32] = k2B1;
        P[9 * 64 + lane] = rbuf[b1 + lane]; P[9 * 64 + lane + 32] = rbuf[b1 + lane + 32];
        P[10 * 64 + lane] = v_s[r0 * FIN_SP + lane]; P[10 * 64 + lane + 32] = v_s[r0 * FIN_SP + lane + 32];
        P[11 * 64 + lane] = v_s[r1 * FIN_SP + lane]; P[11 * 64 + lane + 32] = v_s[r1 * FIN_SP + lane + 32];
        if (lane == 0) { P[12 * 64] = c1; P[12 * 64 + 1] = c2; }
    }
}

// ---------------- scan v3: two steps per reduction round ----------------
__global__ void __launch_bounds__(256) scan3_kernel(
    const float* __restrict__ pscan2,
    const float* __restrict__ state2, float* __restrict__ ypart,
    float* __restrict__ Sout)
{
    int h = blockIdx.x >> 2;
    int q = blockIdx.x & 3;
    int tid = threadIdx.x;
    int wrp = tid >> 5, lane = tid & 31;
    int rsel = lane >> 4, colg = lane & 15;
    int row = q * 16 + 2 * wrp + rsel;

    float4 S = *(const float4*)(state2 + (size_t)h * 4096 + row * 64 + colg * 4);

    __shared__ float buf[2][1024];

    const float* pB = pscan2 + (size_t)h * 1024;
    const size_t pstride = (size_t)NHEAD * 1024;

    ((float4*)buf[0])[tid] = *(const float4*)(pB + tid * 4);
    float4 preA = *(const float4*)(pB + pstride + tid * 4);
    float4 preB;

    for (int pr = 0; pr < NPAIR; pr++) {
        __syncthreads();
        preB = (pr + 2 < NPAIR) ? *(const float4*)(pB + (size_t)(pr + 2) * pstride + tid * 4)
                                : preA;
        const float* b = buf[pr & 1];
        float4 kk4  = *(const float4*)(b + 0 * 64 + colg * 4);
        float4 kkw4 = *(const float4*)(b + 1 * 64 + colg * 4);
        float4 w4   = *(const float4*)(b + 2 * 64 + colg * 4);
        float4 ka4  = *(const float4*)(b + 3 * 64 + colg * 4);
        float4 k4   = *(const float4*)(b + 4 * 64 + colg * 4);
        float4 r4   = *(const float4*)(b + 5 * 64 + colg * 4);
        float4 w14  = *(const float4*)(b + 6 * 64 + colg * 4);
        float4 ka14 = *(const float4*)(b + 7 * 64 + colg * 4);
        float4 k14  = *(const float4*)(b + 8 * 64 + colg * 4);
        float4 r14  = *(const float4*)(b + 9 * 64 + colg * 4);
        float v0 = b[10 * 64 + row];
        float v1 = b[11 * 64 + row];
        float c1 = b[12 * 64];
        float c2 = b[12 * 64 + 1];

        float d0 = S.x * kk4.x + S.y * kk4.y + S.z * kk4.z + S.w * kk4.w;
        float d1 = S.x * kkw4.x + S.y * kkw4.y + S.z * kkw4.z + S.w * kkw4.w;
#pragma unroll
        for (int o = 1; o <= 8; o <<= 1) {
            d0 += __shfl_xor_sync(0xffffffffu, d0, o);
            d1 += __shfl_xor_sync(0xffffffffu, d1, o);
        }
        float p0 = d0;
        float p1 = d1 - p0 * c1 + v0 * c2;

        S.x = S.x * w4.x - p0 * ka4.x + v0 * k4.x;
        S.y = S.y * w4.y - p0 * ka4.y + v0 * k4.y;
        S.z = S.z * w4.z - p0 * ka4.z + v0 * k4.z;
        S.w = S.w * w4.w - p0 * ka4.w + v0 * k4.w;

        float y0 = S.x * r4.x + S.y * r4.y + S.z * r4.z + S.w * r4.w;
        y0 += __shfl_xor_sync(0xffffffffu, y0, 1);
        y0 += __shfl_xor_sync(0xffffffffu, y0, 2);
        if ((colg & 3) == 0)
            ypart[((size_t)(2 * pr) * HID + h * HEADD + row) * 4 + (colg >> 2)] = y0;

        if (pr + 1 < NPAIR)
            ((float4*)buf[(pr + 1) & 1])[tid] = preA;
        preA = preB;

        S.x = S.x * w14.x - p1 * ka14.x + v1 * k14.x;
        S.y = S.y * w14.y - p1 * ka14.y + v1 * k14.y;
        S.z = S.z * w14.z - p1 * ka14.z + v1 * k14.z;
        S.w = S.w * w14.w - p1 * ka14.w + v1 * k14.w;

        float y1 = S.x * r14.x + S.y * r14.y + S.z * r14.z + S.w * r14.w;
        y1 += __shfl_xor_sync(0xffffffffu, y1, 1);
        y1 += __shfl_xor_sync(0xffffffffu, y1, 2);
        if ((colg & 3) == 0)
            ypart[((size_t)(2 * pr + 1) * HID + h * HEADD + row) * 4 + (colg >> 2)] = y1;
    }
    *(float4*)(Sout + (size_t)h * 4096 + row * 64 + colg * 4) = S;
}

// ---------------- groupnorm + rkv + gate -> single-plane fp16 into abuf ----------------
__global__ void __launch_bounds__(256) post_kernel(
    const float* __restrict__ ypart, const float* __restrict__ r,
    const float* __restrict__ k2, const float* __restrict__ v,
    const float* __restrict__ g, const float* __restrict__ r_k,
    const float* __restrict__ lnxw, const float* __restrict__ lnxb,
    __half* __restrict__ zsplit)
{
    int gw = (blockIdx.x * 256 + threadIdx.x) >> 5;
    int lane = threadIdx.x & 31;
    if (gw >= T_LEN * NHEAD) return;
    int t = gw >> 5, h = gw & 31;
    int base = t * HID + h * HEADD;
    int cb = h * HEADD;

    float4 yp0 = *(const float4*)(ypart + (size_t)(base + lane) * 4);
    float4 yp1 = *(const float4*)(ypart + (size_t)(base + lane + 32) * 4);
    float y0 = (yp0.x + yp0.y) + (yp0.z + yp0.w);
    float y1 = (yp1.x + yp1.y) + (yp1.z + yp1.w);

    float mu = warp_sum(y0 + y1) * (1.f / HEADD);
    float d0 = y0 - mu, d1 = y1 - mu;
    float var = warp_sum(d0 * d0 + d1 * d1) * (1.f / HEADD);
    float inv = rsqrtf(var + 0.00064f);

    float rs = warp_sum(r[base + lane] * k2[base + lane] * r_k[cb + lane] +
                        r[base + lane + 32] * k2[base + lane + 32] * r_k[cb + lane + 32]);

    float z0 = (d0 * inv * lnxw[cb + lane] + lnxb[cb + lane] + rs * v[base + lane]) * g[base + lane];
    float z1 = (d1 * inv * lnxw[cb + lane + 32] + lnxb[cb + lane + 32] + rs * v[base + lane + 32]) * g[base + lane + 32];

    size_t zb = (size_t)t * 2 * HID;
    zsplit[zb + cb + lane] = __float2half_rn(z0);
    zsplit[zb + cb + lane + 32] = __float2half_rn(z1);
}

// ---------------- host launcher ----------------
extern "C" void kernel_launch(void* const* d_in, const int* in_sizes, int n_in,
                              void* d_out, int out_size)
{
    const float* x       = (const float*)d_in[0];
    const float* state1  = (const float*)d_in[1];
    const float* state2  = (const float*)d_in[2];
    const float* v_first = (const float*)d_in[3];
    const float* ln1_w   = (const float*)d_in[4];
    const float* ln1_b   = (const float*)d_in[5];
    const float* x_r     = (const float*)d_in[6];
    const float* x_w     = (const float*)d_in[7];
    const float* x_k     = (const float*)d_in[8];
    const float* x_v     = (const float*)d_in[9];
    const float* x_a     = (const float*)d_in[10];
    const float* x_g     = (const float*)d_in[11];
    const float* Wr      = (const float*)d_in[12];
    const float* Wk      = (const float*)d_in[13];
    const float* Wv      = (const float*)d_in[14];
    const float* Wo      = (const float*)d_in[15];
    const float* w0      = (const float*)d_in[16];
    const float* w1      = (const float*)d_in[17];
    const float* w2      = (const float*)d_in[18];
    const float* a0      = (const float*)d_in[19];
    const float* a1      = (const float*)d_in[20];
    const float* a2      = (const float*)d_in[21];
    const float* v0      = (const float*)d_in[22];
    const float* v1      = (const float*)d_in[23];
    const float* v2      = (const float*)d_in[24];
    const float* g1      = (const float*)d_in[25];
    const float* g2      = (const float*)d_in[26];
    const float* k_k     = (const float*)d_in[27];
    const float* k_a     = (const float*)d_in[28];
    const float* r_k     = (const float*)d_in[29];
    const float* ln_x_w  = (const float*)d_in[30];
    const float* ln_x_b  = (const float*)d_in[31];

    float* sc = nullptr;      cudaGetSymbolAddress((void**)&sc, g_scratch);
    float* hbuf = nullptr;    cudaGetSymbolAddress((void**)&hbuf, g_hbuf);
    float* pscan2 = nullptr;  cudaGetSymbolAddress((void**)&pscan2, g_pscan2);
    float* ypart = nullptr;   cudaGetSymbolAddress((void**)&ypart, g_ypart);
    __half* abuf = nullptr;   cudaGetSymbolAddress((void**)&abuf, g_abuf);
    __half* wbuf = nullptr;   cudaGetSymbolAddress((void**)&wbuf, g_wbuf);
    __half* g1buf = nullptr;  cudaGetSymbolAddress((void**)&g1buf, g_g1buf);
    __half* g2buf = nullptr;  cudaGetSymbolAddress((void**)&g2buf, g_g2buf);
    __half* ghbuf = nullptr;  cudaGetSymbolAddress((void**)&ghbuf, g_ghbuf);
    __half* lorabuf = nullptr; cudaGetSymbolAddress((void**)&lorabuf, g_lorabuf);

    cudaFuncSetAttribute(mm128_kernel, cudaFuncAttributeMaxDynamicSharedMemorySize, MM_SMEM);
    cudaFuncSetAttribute(mm64_kernel, cudaFuncAttributeMaxDynamicSharedMemorySize, MM64_SMEM);
    cudaFuncSetAttribute(finish_kernel, cudaFuncAttributeMaxDynamicSharedMemorySize, FIN_SMEM);

#define SLOT(s) (sc + (size_t)(s) * NTOK_EL)

    float* out = (float*)d_out;
    const int OFF_OUT = 0;
    const int OFF_S1  = NTOK_EL;
    const int OFF_S2  = OFF_S1 + HID;
    const int OFF_VF  = OFF_S2 + NHEAD * HEADD * HEADD;
    const int TOTAL   = OFF_VF + NTOK_EL;
    bool full = (out_size >= TOTAL);

    float* s1_out = full ? out + OFF_S1 : nullptr;
    float* s2_out = full ? out + OFF_S2 : SLOT(S_TMP);
    float* vf_out = full ? out + OFF_VF : nullptr;

    // 1. combined front end: ln_mix + weight conversion + v_first passthrough
    front_kernel<<<FRONT_BLOCKS, 256>>>(x, state1, ln1_w, ln1_b,
                                        x_r, x_k, x_v, x_g, x_a, x_w,
                                        abuf, s1_out,
                                        Wr, Wk, Wv, Wo, g1, g2, a1, w1, v1, v_first,
                                        wbuf, g1buf, g2buf, lorabuf, vf_out);

    // 2. mega-batch: r,k,v,g-down,a-down single-plane; w-down 2-plane
    {
        MMJobs jobs;
        jobs.j[0] = { wbuf,                  SLOT(S_R),      nullptr, HID, HID, 0, 0, 1 };
        jobs.j[1] = { wbuf + WSLOT_H,        SLOT(S_K),      nullptr, HID, HID, 0, 1, 1 };
        jobs.j[2] = { wbuf + 2 * WSLOT_H,    SLOT(S_V),      nullptr, HID, HID, 0, 2, 1 };
        jobs.j[3] = { g1buf,                 (float*)ghbuf,  nullptr, 256, 256, 4, 3, 1 };
        jobs.j[4] = { lorabuf,               hbuf,           nullptr, 128, 384, 0, 4, 1 };
        jobs.j[5] = { lorabuf + LSLOT_H,     hbuf + 128,     nullptr, 128, 384, 3, 5, 2 };
        jobs.j[6] = { lorabuf + 2 * LSLOT_H, hbuf + 256,     nullptr, 128, 384, 0, 2, 1 };
        mm128_kernel<<<dim3(16, 8, 7), 256, MM_SMEM>>>(abuf, jobs, HID, 2);
    }

    // 3. g-up: single-plane fp16 A (sigmoid output), @g2 — mm64 (256 CTAs)
    {
        MMJob job = { g2buf, SLOT(S_G), nullptr, HID, HID, 0, 0, 1 };
        mm64_kernel<<<dim3(16, 16), 256, MM64_SMEM>>>(ghbuf, job, 256, 1);
    }

    // 4. fused LoRA-up + prep
    finish_kernel<<<512, 256, FIN_SMEM>>>(hbuf, a2, w2, v2, a0, w0, v0, v_first,
                                          SLOT(S_K), SLOT(S_R), SLOT(S_V),
                                          k_k, k_a, SLOT(S_K2), pscan2);

    // 5. two-step scan
    scan3_kernel<<<128, 256>>>(pscan2, state2, ypart, s2_out);

    // 6. groupnorm + rkv + gate -> single-plane fp16 into abuf slot 0
    post_kernel<<<(T_LEN * NHEAD * 32 + 255) / 256, 256>>>(
        ypart, SLOT(S_R), SLOT(S_K2), SLOT(S_V), SLOT(S_G),
        r_k, ln_x_w, ln_x_b, abuf);

    // 7. out = x + z@Wo (single-plane, residual fused) — mm64 (256 CTAs)
    {
        MMJob job = { wbuf + 3 * WSLOT_H, out + OFF_OUT, x, HID, HID, 1, 0, 1 };
        mm64_kernel<<<dim3(16, 16), 256, MM64_SMEM>>>(abuf, job, HID, 2);
    }
}

// round 14
// speedup vs baseline: 6.5157x; 1.0720x over previous
#include <cuda_runtime.h>
#include <cuda_fp16.h>
#include <math.h>
#include <stdint.h>

#define T_LEN 1024
#define HID   2048
#define NHEAD 32
#define HEADD 64
#define NTOK_EL (T_LEN * HID)
#define NPAIR (T_LEN / 2)

#define ASLOT_H ((size_t)T_LEN * 2 * HID)   // activation slot: [M, 2K] fp16
#define WSLOT_H ((size_t)HID * HID)         // big W slot: [N, K] fp16
#define LSLOT_H ((size_t)128 * HID)         // lora-down W slot (padded 128 rows)
#define USLOT_H ((size_t)HID * 128)         // lora-up W slot: [2048, 128] fp16 padded

// ---------------- static device scratch ----------------
__device__ float g_scratch[8u * (unsigned)NTOK_EL];
__device__ float g_pscan2[(size_t)NPAIR * NHEAD * 1024];
__device__ float g_ypart[(size_t)T_LEN * HID * 4];
__device__ __align__(256) __half g_abuf[6 * ASLOT_H];
__device__ __align__(256) __half g_wbuf[4 * WSLOT_H];
__device__ __align__(256) __half g_g1buf[(size_t)256 * HID];
__device__ __align__(256) __half g_g2buf[(size_t)HID * 256];
__device__ __align__(256) __half g_ghbuf[(size_t)T_LEN * 256];
__device__ __align__(256) __half g_lorabuf[3 * LSLOT_H];
__device__ __align__(256) __half g_upbuf[3 * USLOT_H];     // a2',w2',v2' fp16 padded
__device__ __align__(256) __half g_hbuf_h[(size_t)T_LEN * 384];  // lora-down outputs fp16

#define S_R   0
#define S_K   1
#define S_V   2
#define S_K2  3
#define S_G   4
#define S_TMP 5
#define S_A   6
#define S_W   7

// ---------------- helpers ----------------
__device__ __forceinline__ float blk_sum256(float v) {
    __shared__ float sh[8];
    int tid = threadIdx.x;
#pragma unroll
    for (int o = 16; o; o >>= 1) v += __shfl_xor_sync(0xffffffffu, v, o);
    if ((tid & 31) == 0) sh[tid >> 5] = v;
    __syncthreads();
    if (tid == 0) {
        float s = 0.f;
#pragma unroll
        for (int i = 0; i < 8; i++) s += sh[i];
        sh[0] = s;
    }
    __syncthreads();
    float r = sh[0];
    __syncthreads();
    return r;
}

__device__ __forceinline__ float warp_sum(float v) {
#pragma unroll
    for (int o = 16; o; o >>= 1) v += __shfl_xor_sync(0xffffffffu, v, o);
    return v;
}

__device__ __forceinline__ float sigmoidf(float v) {
    return 1.f / (1.f + __expf(-v));
}

__device__ __forceinline__ uint32_t smem_u32(const void* p) {
    uint32_t a;
    asm("{ .reg .u64 t; cvta.to.shared.u64 t, %1; cvt.u32.u64 %0, t; }" : "=r"(a) : "l"(p));
    return a;
}

__device__ __forceinline__ void hsplit(float v, __half& hi, __half& lo) {
    hi = __float2half_rn(v);
    lo = __float2half_rn(v - __half2float(hi));
}

// ======================= mma.sync fp16 GEMM =======================
#define MMK_STRIDE 80
#define MMK_TILE   (128 * MMK_STRIDE)
#define STAGE_BYTES (3 * MMK_TILE)
#define MM_SMEM (3 * STAGE_BYTES)

// modes: 0 fp32 store | 1 +Res fp32 | 4 sigmoid->fp16 | 5 fp16 | 6 tanh->fp16
//        7 sigmoid(bias+x)->fp32 | 8 exp(-.606531*sigmoid(bias+x))->fp32
//        9 C = C + (Res-C)*sigmoid(bias+x)  (fp32 rmw)
struct MMJob {
    const __half* A; const __half* B; float* C; const float* Res; const float* bias;
    int N; int K; int lda; int ldc; int mode; int planes;
};
struct MMJobs { MMJob j[7]; };

__device__ __forceinline__ void cp16(uint32_t dst, const void* src) {
    asm volatile("cp.async.cg.shared.global [%0], [%1], 16;" :: "r"(dst), "l"(src));
}

__device__ __forceinline__ void ldsm4(uint32_t* r, uint32_t a) {
    asm volatile("ldmatrix.sync.aligned.m8n8.x4.shared.b16 {%0,%1,%2,%3}, [%4];"
                 : "=r"(r[0]), "=r"(r[1]), "=r"(r[2]), "=r"(r[3]) : "r"(a));
}

__device__ __forceinline__ void mma16816(float* c, const uint32_t* a, const uint32_t* b) {
    asm volatile(
        "mma.sync.aligned.m16n8k16.row.col.f32.f16.f16.f32 "
        "{%0,%1,%2,%3}, {%4,%5,%6,%7}, {%8,%9}, {%0,%1,%2,%3};"
        : "+f"(c[0]), "+f"(c[1]), "+f"(c[2]), "+f"(c[3])
        : "r"(a[0]), "r"(a[1]), "r"(a[2]), "r"(a[3]), "r"(b[0]), "r"(b[1]));
}

__device__ __forceinline__ void mm_epilogue(
    const MMJob& job, int row, int col, float2 v0, float2 v1)
{
    float* C = job.C;
    int ldc = job.ldc;
    int mode = job.mode;
    if (mode == 4 || mode == 5 || mode == 6) {
        __half* Ch = (__half*)C;
        if (mode == 4) {
            v0.x = sigmoidf(v0.x); v0.y = sigmoidf(v0.y);
            v1.x = sigmoidf(v1.x); v1.y = sigmoidf(v1.y);
        } else if (mode == 6) {
            v0.x = tanhf(v0.x); v0.y = tanhf(v0.y);
            v1.x = tanhf(v1.x); v1.y = tanhf(v1.y);
        }
        *(__half2*)(Ch + (size_t)row * ldc + col) = __floats2half2_rn(v0.x, v0.y);
        *(__half2*)(Ch + (size_t)(row + 8) * ldc + col) = __floats2half2_rn(v1.x, v1.y);
        return;
    }
    if (mode == 1) {
        const float2 r0 = *(const float2*)(job.Res + (size_t)row * ldc + col);
        const float2 r1 = *(const float2*)(job.Res + (size_t)(row + 8) * ldc + col);
        v0.x += r0.x; v0.y += r0.y;
        v1.x += r1.x; v1.y += r1.y;
    } else if (mode == 7 || mode == 8 || mode == 9) {
        float b0 = job.bias[col], b1 = job.bias[col + 1];
        float s00 = sigmoidf(b0 + v0.x), s01 = sigmoidf(b1 + v0.y);
        float s10 = sigmoidf(b0 + v1.x), s11 = sigmoidf(b1 + v1.y);
        if (mode == 7) {
            v0 = make_float2(s00, s01); v1 = make_float2(s10, s11);
        } else if (mode == 8) {
            v0 = make_float2(__expf(-0.606531f * s00), __expf(-0.606531f * s01));
            v1 = make_float2(__expf(-0.606531f * s10), __expf(-0.606531f * s11));
        } else {
            float2 c0 = *(const float2*)(C + (size_t)row * ldc + col);
            float2 c1 = *(const float2*)(C + (size_t)(row + 8) * ldc + col);
            const float2 f0 = *(const float2*)(job.Res + (size_t)row * ldc + col);
            const float2 f1 = *(const float2*)(job.Res + (size_t)(row + 8) * ldc + col);
            v0 = make_float2(c0.x + (f0.x - c0.x) * s00, c0.y + (f0.y - c0.y) * s01);
            v1 = make_float2(c1.x + (f1.x - c1.x) * s10, c1.y + (f1.y - c1.y) * s11);
        }
    }
    *(float2*)(C + (size_t)row * ldc + col) = v0;
    *(float2*)(C + (size_t)(row + 8) * ldc + col) = v1;
}

__global__ void __launch_bounds__(256, 2) mm128_kernel(MMJobs jobs, int nz)
{
    extern __shared__ __align__(16) char smem[];
    uint32_t sbase = smem_u32(smem);

    const MMJob job = jobs.j[blockIdx.z];
    const int N = job.N;
    int n0 = blockIdx.x * 128;
    if (n0 >= N) return;
    int m0 = blockIdx.y * 128;

    const __half* Ab = job.A;
    const __half* Bb = job.B;
    const int K = job.K;
    const int lda = job.lda;
    const int nk = K >> 5;
    const int planes = job.planes;

    int tid = threadIdx.x;
    int wid = tid >> 5, lane = tid & 31;
    int g = lane >> 2, tig = lane & 3;
    int warp_m = wid >> 2;
    int warp_n = wid & 3;

    float acc[4][4][4];
#pragma unroll
    for (int i = 0; i < 4; i++)
#pragma unroll
        for (int j = 0; j < 4; j++)
#pragma unroll
            for (int q = 0; q < 4; q++) acc[i][j][q] = 0.f;

    auto load_stage = [&](int s, int kc) {
        uint32_t st = sbase + s * STAGE_BYTES;
        int k0 = kc << 5;
#pragma unroll
        for (int it = 0; it < 2; it++) {
            int idx = tid + it * 256;
            int r = idx >> 2, c = idx & 3;
            cp16(st + r * MMK_STRIDE + c * 16, Ab + ((size_t)(m0 + r) * lda + k0 + c * 8));
        }
        if (planes == 2) {
#pragma unroll
            for (int it = 0; it < 2; it++) {
                int idx = tid + it * 256;
                int r = idx >> 2, c = idx & 3;
                cp16(st + MMK_TILE + r * MMK_STRIDE + c * 16,
                     Ab + ((size_t)(m0 + r) * lda + K + k0 + c * 8));
            }
        }
#pragma unroll
        for (int it = 0; it < 2; it++) {
            int idx = tid + it * 256;
            int r = idx >> 2, c = idx & 3;
            cp16(st + 2 * MMK_TILE + r * MMK_STRIDE + c * 16,
                 Bb + ((size_t)(n0 + r) * K + k0 + c * 8));
        }
        asm volatile("cp.async.commit_group;" ::: "memory");
    };

    load_stage(0, 0);
    if (nk > 1) load_stage(1, 1);
    else asm volatile("cp.async.commit_group;" ::: "memory");

    int aRowSel = (lane & 15);
    int aColSel = (lane & 16) ? 16 : 0;
    int bRowSel = ((lane & 16) ? 8 : 0) + (lane & 7);
    int bColSel = (lane & 8) ? 16 : 0;

    for (int kc = 0; kc < nk; kc++) {
        asm volatile("cp.async.wait_group 1;" ::: "memory");
        __syncthreads();
        if (kc + 2 < nk) load_stage((kc + 2) % 3, kc + 2);
        else asm volatile("cp.async.commit_group;" ::: "memory");

        uint32_t st = sbase + (kc % 3) * STAGE_BYTES;
#pragma unroll
        for (int ks = 0; ks < 2; ks++) {
            uint32_t afr[4][4], bfr[2][4];
#pragma unroll
            for (int ap = 0; ap < 2; ap++) {
                uint32_t addr = st + 2 * MMK_TILE
                                + (uint32_t)(warp_n * 32 + ap * 16 + bRowSel) * MMK_STRIDE
                                + ks * 32 + bColSel;
                ldsm4(bfr[ap], addr);
            }
#pragma unroll
            for (int am = 0; am < 4; am++) {
                uint32_t addr = st + (uint32_t)(warp_m * 64 + am * 16 + aRowSel) * MMK_STRIDE
                                + ks * 32 + aColSel;
                ldsm4(afr[am], addr);
            }
#pragma unroll
            for (int am = 0; am < 4; am++) {
                mma16816(acc[am][0], afr[am], &bfr[0][0]);
                mma16816(acc[am][1], afr[am], &bfr[0][2]);
                mma16816(acc[am][2], afr[am], &bfr[1][0]);
                mma16816(acc[am][3], afr[am], &bfr[1][2]);
            }
            if (planes == 2) {
#pragma unroll
                for (int am = 0; am < 4; am++) {
                    uint32_t addr = st + MMK_TILE
                                    + (uint32_t)(warp_m * 64 + am * 16 + aRowSel) * MMK_STRIDE
                                    + ks * 32 + aColSel;
                    ldsm4(afr[am], addr);
                }
#pragma unroll
                for (int am = 0; am < 4; am++) {
                    mma16816(acc[am][0], afr[am], &bfr[0][0]);
                    mma16816(acc[am][1], afr[am], &bfr[0][2]);
                    mma16816(acc[am][2], afr[am], &bfr[1][0]);
                    mma16816(acc[am][3], afr[am], &bfr[1][2]);
                }
            }
        }
    }

    __syncthreads();

#pragma unroll
    for (int am = 0; am < 4; am++) {
#pragma unroll
        for (int an = 0; an < 4; an++) {
            int row = m0 + warp_m * 64 + am * 16 + g;
            int col = n0 + warp_n * 32 + an * 8 + tig * 2;
            mm_epilogue(job, row, col,
                        make_float2(acc[am][an][0], acc[am][an][1]),
                        make_float2(acc[am][an][2], acc[am][an][3]));
        }
    }
}

// ---------------- mm64: 64x128 tile variant ----------------
#define MM64_A_TILE (64 * MMK_STRIDE)
#define MM64_STAGE  (2 * MM64_A_TILE + MMK_TILE)
#define MM64_SMEM   (3 * MM64_STAGE)

__global__ void __launch_bounds__(256) mm64_kernel(MMJob job)
{
    extern __shared__ __align__(16) char smem[];
    uint32_t sbase = smem_u32(smem);

    const int N = job.N;
    int n0 = blockIdx.x * 128;
    if (n0 >= N) return;
    int m0 = blockIdx.y * 64;

    const __half* Ab = job.A;
    const __half* Bb = job.B;
    const int K = job.K;
    const int lda = job.lda;
    const int nk = K >> 5;
    const int planes = job.planes;

    int tid = threadIdx.x;
    int wid = tid >> 5, lane = tid & 31;
    int g = lane >> 2, tig = lane & 3;
    int warp_m = wid >> 2;
    int warp_n = wid & 3;

    float acc[2][4][4];
#pragma unroll
    for (int i = 0; i < 2; i++)
#pragma unroll
        for (int j = 0; j < 4; j++)
#pragma unroll
            for (int q = 0; q < 4; q++) acc[i][j][q] = 0.f;

    auto load_stage = [&](int s, int kc) {
        uint32_t st = sbase + s * MM64_STAGE;
        int k0 = kc << 5;
        {
            int r = tid >> 2, c = tid & 3;
            cp16(st + r * MMK_STRIDE + c * 16, Ab + ((size_t)(m0 + r) * lda + k0 + c * 8));
        }
        if (planes == 2) {
            int r = tid >> 2, c = tid & 3;
            cp16(st + MM64_A_TILE + r * MMK_STRIDE + c * 16,
                 Ab + ((size_t)(m0 + r) * lda + K + k0 + c * 8));
        }
#pragma unroll
        for (int it = 0; it < 2; it++) {
            int idx = tid + it * 256;
            int r = idx >> 2, c = idx & 3;
            cp16(st + 2 * MM64_A_TILE + r * MMK_STRIDE + c * 16,
                 Bb + ((size_t)(n0 + r) * K + k0 + c * 8));
        }
        asm volatile("cp.async.commit_group;" ::: "memory");
    };

    load_stage(0, 0);
    if (nk > 1) load_stage(1, 1);
    else asm volatile("cp.async.commit_group;" ::: "memory");

    int aRowSel = (lane & 15);
    int aColSel = (lane & 16) ? 16 : 0;
    int bRowSel = ((lane & 16) ? 8 : 0) + (lane & 7);
    int bColSel = (lane & 8) ? 16 : 0;

    for (int kc = 0; kc < nk; kc++) {
        asm volatile("cp.async.wait_group 1;" ::: "memory");
        __syncthreads();
        if (kc + 2 < nk) load_stage((kc + 2) % 3, kc + 2);
        else asm volatile("cp.async.commit_group;" ::: "memory");

        uint32_t st = sbase + (kc % 3) * MM64_STAGE;
#pragma unroll
        for (int ks = 0; ks < 2; ks++) {
            uint32_t afr[2][4], bfr[2][4];
#pragma unroll
            for (int ap = 0; ap < 2; ap++) {
                uint32_t addr = st + 2 * MM64_A_TILE
                                + (uint32_t)(warp_n * 32 + ap * 16 + bRowSel) * MMK_STRIDE
                                + ks * 32 + bColSel;
                ldsm4(bfr[ap], addr);
            }
#pragma unroll
            for (int am = 0; am < 2; am++) {
                uint32_t addr = st + (uint32_t)(warp_m * 32 + am * 16 + aRowSel) * MMK_STRIDE
                                + ks * 32 + aColSel;
                ldsm4(afr[am], addr);
            }
#pragma unroll
            for (int am = 0; am < 2; am++) {
                mma16816(acc[am][0], afr[am], &bfr[0][0]);
                mma16816(acc[am][1], afr[am], &bfr[0][2]);
                mma16816(acc[am][2], afr[am], &bfr[1][0]);
                mma16816(acc[am][3], afr[am], &bfr[1][2]);
            }
            if (planes == 2) {
#pragma unroll
                for (int am = 0; am < 2; am++) {
                    uint32_t addr = st + MM64_A_TILE
                                    + (uint32_t)(warp_m * 32 + am * 16 + aRowSel) * MMK_STRIDE
                                    + ks * 32 + aColSel;
                    ldsm4(afr[am], addr);
                }
#pragma unroll
                for (int am = 0; am < 2; am++) {
                    mma16816(acc[am][0], afr[am], &bfr[0][0]);
                    mma16816(acc[am][1], afr[am], &bfr[0][2]);
                    mma16816(acc[am][2], afr[am], &bfr[1][0]);
                    mma16816(acc[am][3], afr[am], &bfr[1][2]);
                }
            }
        }
    }

    __syncthreads();

#pragma unroll
    for (int am = 0; am < 2; am++) {
#pragma unroll
        for (int an = 0; an < 4; an++) {
            int row = m0 + warp_m * 32 + am * 16 + g;
            int col = n0 + warp_n * 32 + an * 8 + tig * 2;
            mm_epilogue(job, row, col,
                        make_float2(acc[am][an][0], acc[am][an][1]),
                        make_float2(acc[am][an][2], acc[am][an][3]));
        }
    }
}

// ---------------- front-end: ln_mix + weight conversions + v_first copy ----------------
__device__ __forceinline__ void conv_tile2(const float* __restrict__ W, __half* __restrict__ out,
                                           int K, int N, int bx, int by, float* tile,
                                           int kmax)
{
    int k0 = by * 64, n0 = bx * 32;
    int tid = threadIdx.x;
#pragma unroll
    for (int it = 0; it < 8; it++) {
        int i = tid + it * 256;
        int r = i >> 5, c = i & 31;
        tile[r * 33 + c] = (k0 + r < kmax) ? W[(size_t)(k0 + r) * N + n0 + c] : 0.f;
    }
    __syncthreads();
    int nl = tid >> 3;
    int kq = (tid & 7) * 8;
    __half h8[8];
#pragma unroll
    for (int j = 0; j < 8; j++)
        h8[j] = __float2half_rn(tile[(kq + j) * 33 + nl]);
    *(uint4*)(out + (size_t)(n0 + nl) * K + k0 + kq) = *(uint4*)h8;
}

__device__ void ln_mix_body(
    int t,
    const float* __restrict__ x, const float* __restrict__ state1,
    const float* __restrict__ lnw, const float* __restrict__ lnb,
    const float* __restrict__ cr, const float* __restrict__ ck,
    const float* __restrict__ cv, const float* __restrict__ cg,
    const float* __restrict__ ca, const float* __restrict__ cw,
    __half* __restrict__ abuf, float* __restrict__ state1_out)
{
    const float* xt = x + (size_t)t * HID;
    const float* xp = x + (size_t)(t - 1) * HID;

    float2 v0[4], v1[4];
    float s0 = 0.f, s1 = 0.f;
#pragma unroll
    for (int j = 0; j < 4; j++) {
        int c = threadIdx.x * 2 + j * 512;
        v0[j] = *(const float2*)(xt + c);
        s0 += v0[j].x + v0[j].y;
        v1[j] = t ? *(const float2*)(xp + c) : make_float2(0.f, 0.f);
        s1 += v1[j].x + v1[j].y;
    }
    float mu0 = blk_sum256(s0) * (1.f / HID);
    float mu1 = blk_sum256(s1) * (1.f / HID);
    float q0 = 0.f, q1 = 0.f;
#pragma unroll
    for (int j = 0; j < 4; j++) {
        float d;
        d = v0[j].x - mu0; q0 += d * d;
        d = v0[j].y - mu0; q0 += d * d;
        d = v1[j].x - mu1; q1 += d * d;
        d = v1[j].y - mu1; q1 += d * d;
    }
    float inv0 = rsqrtf(blk_sum256(q0) * (1.f / HID) + 1e-5f);
    float inv1 = rsqrtf(blk_sum256(q1) * (1.f / HID) + 1e-5f);

#pragma unroll
    for (int j = 0; j < 4; j++) {
        int c = threadIdx.x * 2 + j * 512;
        float2 wv = *(const float2*)(lnw + c);
        float2 bv = *(const float2*)(lnb + c);
        float xn0 = (v0[j].x - mu0) * inv0 * wv.x + bv.x;
        float xn1 = (v0[j].y - mu0) * inv0 * wv.y + bv.y;
        float pv0 = t ? (v1[j].x - mu1) * inv1 * wv.x + bv.x : state1[c];
        float pv1 = t ? (v1[j].y - mu1) * inv1 * wv.y + bv.y : state1[c + 1];
        float sx0 = pv0 - xn0, sx1 = pv1 - xn1;

        __half* arow = abuf + (size_t)t * 2 * HID + c;
#pragma unroll
        for (int s = 0; s < 6; s++) {
            const float* coefA = (s == 0) ? cr : (s == 1) ? ck : (s == 2) ? cv
                               : (s == 3) ? cg : (s == 4) ? ca : cw;
            float a0 = xn0 + coefA[c] * sx0;
            float a1 = xn1 + coefA[c + 1] * sx1;
            __half* p = arow + (size_t)s * ASLOT_H;
            if (s == 5) {
                __half h0, l0, h1, l1;
                hsplit(a0, h0, l0);
                hsplit(a1, h1, l1);
                *(__half2*)(p) = __half2(h0, h1);
                *(__half2*)(p + HID) = __half2(l0, l1);
            } else {
                *(__half2*)(p) = __floats2half2_rn(a0, a1);
            }
        }
        if (state1_out && t == T_LEN - 1) {
            state1_out[c] = xn0;
            state1_out[c + 1] = xn1;
        }
    }
}

#define FRONT_BLOCKS (1024 + 9472 + 384)

__global__ void __launch_bounds__(256) front_kernel(
    const float* __restrict__ x, const float* __restrict__ state1,
    const float* __restrict__ lnw, const float* __restrict__ lnb,
    const float* __restrict__ cr, const float* __restrict__ ck,
    const float* __restrict__ cv, const float* __restrict__ cg,
    const float* __restrict__ ca, const float* __restrict__ cw,
    __half* __restrict__ abuf, float* __restrict__ state1_out,
    const float* __restrict__ Wr, const float* __restrict__ Wk,
    const float* __restrict__ Wv, const float* __restrict__ Wo,
    const float* __restrict__ g1, const float* __restrict__ g2,
    const float* __restrict__ a1, const float* __restrict__ w1,
    const float* __restrict__ v1, const float* __restrict__ vf,
    const float* __restrict__ a2, const float* __restrict__ w2,
    const float* __restrict__ v2,
    __half* __restrict__ wbuf, __half* __restrict__ g1buf,
    __half* __restrict__ g2buf, __half* __restrict__ lorabuf,
    __half* __restrict__ upbuf, float* __restrict__ vfout)
{
    __shared__ float tile[64 * 33];
    int bb = blockIdx.x;
    if (bb < 1024) {
        ln_mix_body(bb, x, state1, lnw, lnb, cr, ck, cv, cg, ca, cw, abuf, state1_out);
        return;
    }
    int b = bb - 1024;
    if (b < 8192) {
        int z = b >> 11, rem = b & 2047;
        const float* W = z == 0 ? Wr : z == 1 ? Wk : z == 2 ? Wv : Wo;
        conv_tile2(W, wbuf + (size_t)z * WSLOT_H, HID, HID, rem & 63, rem >> 6, tile, HID);
    } else if (b < 8448) {
        int rem = b - 8192;
        conv_tile2(g1, g1buf, HID, 256, rem & 7, rem >> 3, tile, HID);
    } else if (b < 8704) {
        int rem = b - 8448;
        conv_tile2(g2, g2buf, 256, HID, rem & 63, rem >> 6, tile, 256);
    } else if (b < 8800) {
        int rem = b - 8704;
        conv_tile2(a1, lorabuf, HID, 96, rem % 3, rem / 3, tile, HID);
    } else if (b < 8896) {
        int rem = b - 8800;
        conv_tile2(w1, lorabuf + LSLOT_H, HID, 96, rem % 3, rem / 3, tile, HID);
    } else if (b < 8960) {
        int rem = b - 8896;
        conv_tile2(v1, lorabuf + 2 * LSLOT_H, HID, 64, rem & 1, rem >> 1, tile, HID);
    } else if (b < 9472) {
        if (!vfout) return;
        int rem = b - 8960;
#pragma unroll
        for (int j = 0; j < 4; j++) {
            size_t i = (size_t)rem * 4096 + j * 1024 + threadIdx.x * 4;
            *(float4*)(vfout + i) = *(const float4*)(vf + i);
        }
    } else {
        // lora-up weights: [K<=96, 2048] fp32 -> [2048, 128] fp16 zero-padded
        int rem = b - 9472;                 // 0..383
        int z = rem >> 7, sub = rem & 127;  // 128 blocks each: bx=sub&63, by=sub>>6
        const float* W = z == 0 ? a2 : z == 1 ? w2 : v2;
        int kmax = (z == 2) ? 64 : 96;
        conv_tile2(W, upbuf + (size_t)z * USLOT_H, 128, HID, sub & 63, sub >> 6, tile, kmax);
    }
}

// ---------------- prep2: kk/k2 + pair scalars + pscan2 packing ----------------
__global__ void __launch_bounds__(256) prep2_kernel(
    const float* __restrict__ k, const float* __restrict__ a,
    const float* __restrict__ w, const float* __restrict__ v,
    const float* __restrict__ r,
    const float* __restrict__ k_k, const float* __restrict__ k_a,
    float* __restrict__ k2out, float* __restrict__ pscan2)
{
    int gw = (blockIdx.x * 256 + threadIdx.x) >> 5;
    int lane = threadIdx.x & 31;
    if (gw >= NPAIR * NHEAD) return;
    int pr = gw >> 5, h = gw & 31;
    int b0 = (2 * pr) * HID + h * HEADD;
    int b1 = b0 + HID;
    int cb = h * HEADD;

    float kA0 = k[b0 + lane], kB0 = k[b0 + lane + 32];
    float qA0 = kA0 * k_k[cb + lane], qB0 = kB0 * k_k[cb + lane + 32];
    float inv0 = 1.f / fmaxf(sqrtf(warp_sum(qA0 * qA0 + qB0 * qB0)), 1e-12f);
    float kkA0 = qA0 * inv0, kkB0 = qB0 * inv0;
    float aA0 = a[b0 + lane], aB0 = a[b0 + lane + 32];
    float k2A0 = kA0 * (1.f + (aA0 - 1.f) * k_a[cb + lane]);
    float k2B0 = kB0 * (1.f + (aB0 - 1.f) * k_a[cb + lane + 32]);
    k2out[b0 + lane] = k2A0;
    k2out[b0 + lane + 32] = k2B0;

    float kA1 = k[b1 + lane], kB1 = k[b1 + lane + 32];
    float qA1 = kA1 * k_k[cb + lane], qB1 = kB1 * k_k[cb + lane + 32];
    float inv1 = 1.f / fmaxf(sqrtf(warp_sum(qA1 * qA1 + qB1 * qB1)), 1e-12f);
    float kkA1 = qA1 * inv1, kkB1 = qB1 * inv1;
    float aA1 = a[b1 + lane], aB1 = a[b1 + lane + 32];
    float k2A1 = kA1 * (1.f + (aA1 - 1.f) * k_a[cb + lane]);
    float k2B1 = kB1 * (1.f + (aB1 - 1.f) * k_a[cb + lane + 32]);
    k2out[b1 + lane] = k2A1;
    k2out[b1 + lane + 32] = k2B1;

    float wA0 = w[b0 + lane], wB0 = w[b0 + lane + 32];
    float kaA0 = kkA0 * aA0, kaB0 = kkB0 * aB0;

    float c1 = warp_sum(kkA1 * kaA0 + kkB1 * kaB0);
    float c2 = warp_sum(kkA1 * k2A0 + kkB1 * k2B0);

    float* P = pscan2 + ((size_t)pr * NHEAD + h) * 1024;
    P[0 * 64 + lane] = kkA0;           P[0 * 64 + lane + 32] = kkB0;
    P[1 * 64 + lane] = kkA1 * wA0;     P[1 * 64 + lane + 32] = kkB1 * wB0;
    P[2 * 64 + lane] = wA0;            P[2 * 64 + lane + 32] = wB0;
    P[3 * 64 + lane] = kaA0;           P[3 * 64 + lane + 32] = kaB0;
    P[4 * 64 + lane] = k2A0;           P[4 * 64 + lane + 32] = k2B0;
    P[5 * 64 + lane] = r[b0 + lane];   P[5 * 64 + lane + 32] = r[b0 + lane + 32];
    P[6 * 64 + lane] = w[b1 + lane];   P[6 * 64 + lane + 32] = w[b1 + lane + 32];
    P[7 * 64 + lane] = kkA1 * aA1;     P[7 * 64 + lane + 32] = kkB1 * aB1;
    P[8 * 64 + lane] = k2A1;           P[8 * 64 + lane + 32] = k2B1;
    P[9 * 64 + lane] = r[b1 + lane];   P[9 * 64 + lane + 32] = r[b1 + lane + 32];
    P[10 * 64 + lane] = v[b0 + lane];  P[10 * 64 + lane + 32] = v[b0 + lane + 32];
    P[11 * 64 + lane] = v[b1 + lane];  P[11 * 64 + lane + 32] = v[b1 + lane + 32];
    if (lane == 0) { P[12 * 64] = c1; P[12 * 64 + 1] = c2; }
}

// ---------------- scan v3: two steps per reduction round ----------------
__global__ void __launch_bounds__(256) scan3_kernel(
    const float* __restrict__ pscan2,
    const float* __restrict__ state2, float* __restrict__ ypart,
    float* __restrict__ Sout)
{
    int h = blockIdx.x >> 2;
    int q = blockIdx.x & 3;
    int tid = threadIdx.x;
    int wrp = tid >> 5, lane = tid & 31;
    int rsel = lane >> 4, colg = lane & 15;
    int row = q * 16 + 2 * wrp + rsel;

    float4 S = *(const float4*)(state2 + (size_t)h * 4096 + row * 64 + colg * 4);

    __shared__ float buf[2][1024];

    const float* pB = pscan2 + (size_t)h * 1024;
    const size_t pstride = (size_t)NHEAD * 1024;

    ((float4*)buf[0])[tid] = *(const float4*)(pB + tid * 4);
    float4 preA = *(const float4*)(pB + pstride + tid * 4);
    float4 preB;

    for (int pr = 0; pr < NPAIR; pr++) {
        __syncthreads();
        preB = (pr + 2 < NPAIR) ? *(const float4*)(pB + (size_t)(pr + 2) * pstride + tid * 4)
                                : preA;
        const float* b = buf[pr & 1];
        float4 kk4  = *(const float4*)(b + 0 * 64 + colg * 4);
        float4 kkw4 = *(const float4*)(b + 1 * 64 + colg * 4);
        float4 w4   = *(const float4*)(b + 2 * 64 + colg * 4);
        float4 ka4  = *(const float4*)(b + 3 * 64 + colg * 4);
        float4 k4   = *(const float4*)(b + 4 * 64 + colg * 4);
        float4 r4   = *(const float4*)(b + 5 * 64 + colg * 4);
        float4 w14  = *(const float4*)(b + 6 * 64 + colg * 4);
        float4 ka14 = *(const float4*)(b + 7 * 64 + colg * 4);
        float4 k14  = *(const float4*)(b + 8 * 64 + colg * 4);
        float4 r14  = *(const float4*)(b + 9 * 64 + colg * 4);
        float v0 = b[10 * 64 + row];
        float v1 = b[11 * 64 + row];
        float c1 = b[12 * 64];
        float c2 = b[12 * 64 + 1];

        float d0 = S.x * kk4.x + S.y * kk4.y + S.z * kk4.z + S.w * kk4.w;
        float d1 = S.x * kkw4.x + S.y * kkw4.y + S.z * kkw4.z + S.w * kkw4.w;
#pragma unroll
        for (int o = 1; o <= 8; o <<= 1) {
            d0 += __shfl_xor_sync(0xffffffffu, d0, o);
            d1 += __shfl_xor_sync(0xffffffffu, d1, o);
        }
        float p0 = d0;
        float p1 = d1 - p0 * c1 + v0 * c2;

        S.x = S.x * w4.x - p0 * ka4.x + v0 * k4.x;
        S.y = S.y * w4.y - p0 * ka4.y + v0 * k4.y;
        S.z = S.z * w4.z - p0 * ka4.z + v0 * k4.z;
        S.w = S.w * w4.w - p0 * ka4.w + v0 * k4.w;

        float y0 = S.x * r4.x + S.y * r4.y + S.z * r4.z + S.w * r4.w;
        y0 += __shfl_xor_sync(0xffffffffu, y0, 1);
        y0 += __shfl_xor_sync(0xffffffffu, y0, 2);
        if ((colg & 3) == 0)
            ypart[((size_t)(2 * pr) * HID + h * HEADD + row) * 4 + (colg >> 2)] = y0;

        if (pr + 1 < NPAIR)
            ((float4*)buf[(pr + 1) & 1])[tid] = preA;
        preA = preB;

        S.x = S.x * w14.x - p1 * ka14.x + v1 * k14.x;
        S.y = S.y * w14.y - p1 * ka14.y + v1 * k14.y;
        S.z = S.z * w14.z - p1 * ka14.z + v1 * k14.z;
        S.w = S.w * w14.w - p1 * ka14.w + v1 * k14.w;

        float y1 = S.x * r14.x + S.y * r14.y + S.z * r14.z + S.w * r14.w;
        y1 += __shfl_xor_sync(0xffffffffu, y1, 1);
        y1 += __shfl_xor_sync(0xffffffffu, y1, 2);
        if ((colg & 3) == 0)
            ypart[((size_t)(2 * pr + 1) * HID + h * HEADD + row) * 4 + (colg >> 2)] = y1;
    }
    *(float4*)(Sout + (size_t)h * 4096 + row * 64 + colg * 4) = S;
}

// ---------------- groupnorm + rkv + gate -> single-plane fp16 into abuf ----------------
__global__ void __launch_bounds__(256) post_kernel(
    const float* __restrict__ ypart, const float* __restrict__ r,
    const float* __restrict__ k2, const float* __restrict__ v,
    const float* __restrict__ g, const float* __restrict__ r_k,
    const float* __restrict__ lnxw, const float* __restrict__ lnxb,
    __half* __restrict__ zsplit)
{
    int gw = (blockIdx.x * 256 + threadIdx.x) >> 5;
    int lane = threadIdx.x & 31;
    if (gw >= T_LEN * NHEAD) return;
    int t = gw >> 5, h = gw & 31;
    int base = t * HID + h * HEADD;
    int cb = h * HEADD;

    float4 yp0 = *(const float4*)(ypart + (size_t)(base + lane) * 4);
    float4 yp1 = *(const float4*)(ypart + (size_t)(base + lane + 32) * 4);
    float y0 = (yp0.x + yp0.y) + (yp0.z + yp0.w);
    float y1 = (yp1.x + yp1.y) + (yp1.z + yp1.w);

    float mu = warp_sum(y0 + y1) * (1.f / HEADD);
    float d0 = y0 - mu, d1 = y1 - mu;
    float var = warp_sum(d0 * d0 + d1 * d1) * (1.f / HEADD);
    float inv = rsqrtf(var + 0.00064f);

    float rs = warp_sum(r[base + lane] * k2[base + lane] * r_k[cb + lane] +
                        r[base + lane + 32] * k2[base + lane + 32] * r_k[cb + lane + 32]);

    float z0 = (d0 * inv * lnxw[cb + lane] + lnxb[cb + lane] + rs * v[base + lane]) * g[base + lane];
    float z1 = (d1 * inv * lnxw[cb + lane + 32] + lnxb[cb + lane + 32] + rs * v[base + lane + 32]) * g[base + lane + 32];

    size_t zb = (size_t)t * 2 * HID;
    zsplit[zb + cb + lane] = __float2half_rn(z0);
    zsplit[zb + cb + lane + 32] = __float2half_rn(z1);
}

// ---------------- host launcher ----------------
extern "C" void kernel_launch(void* const* d_in, const int* in_sizes, int n_in,
                              void* d_out, int out_size)
{
    const float* x       = (const float*)d_in[0];
    const float* state1  = (const float*)d_in[1];
    const float* state2  = (const float*)d_in[2];
    const float* v_first = (const float*)d_in[3];
    const float* ln1_w   = (const float*)d_in[4];
    const float* ln1_b   = (const float*)d_in[5];
    const float* x_r     = (const float*)d_in[6];
    const float* x_w     = (const float*)d_in[7];
    const float* x_k     = (const float*)d_in[8];
    const float* x_v     = (const float*)d_in[9];
    const float* x_a     = (const float*)d_in[10];
    const float* x_g     = (const float*)d_in[11];
    const float* Wr      = (const float*)d_in[12];
    const float* Wk      = (const float*)d_in[13];
    const float* Wv      = (const float*)d_in[14];
    const float* Wo      = (const float*)d_in[15];
    const float* w0      = (const float*)d_in[16];
    const float* w1      = (const float*)d_in[17];
    const float* w2      = (const float*)d_in[18];
    const float* a0      = (const float*)d_in[19];
    const float* a1      = (const float*)d_in[20];
    const float* a2      = (const float*)d_in[21];
    const float* v0      = (const float*)d_in[22];
    const float* v1      = (const float*)d_in[23];
    const float* v2      = (const float*)d_in[24];
    const float* g1      = (const float*)d_in[25];
    const float* g2      = (const float*)d_in[26];
    const float* k_k     = (const float*)d_in[27];
    const float* k_a     = (const float*)d_in[28];
    const float* r_k     = (const float*)d_in[29];
    const float* ln_x_w  = (const float*)d_in[30];
    const float* ln_x_b  = (const float*)d_in[31];

    float* sc = nullptr;      cudaGetSymbolAddress((void**)&sc, g_scratch);
    float* pscan2 = nullptr;  cudaGetSymbolAddress((void**)&pscan2, g_pscan2);
    float* ypart = nullptr;   cudaGetSymbolAddress((void**)&ypart, g_ypart);
    __half* abuf = nullptr;   cudaGetSymbolAddress((void**)&abuf, g_abuf);
    __half* wbuf = nullptr;   cudaGetSymbolAddress((void**)&wbuf, g_wbuf);
    __half* g1buf = nullptr;  cudaGetSymbolAddress((void**)&g1buf, g_g1buf);
    __half* g2buf = nullptr;  cudaGetSymbolAddress((void**)&g2buf, g_g2buf);
    __half* ghbuf = nullptr;  cudaGetSymbolAddress((void**)&ghbuf, g_ghbuf);
    __half* lorabuf = nullptr; cudaGetSymbolAddress((void**)&lorabuf, g_lorabuf);
    __half* upbuf = nullptr;  cudaGetSymbolAddress((void**)&upbuf, g_upbuf);
    __half* hbuf_h = nullptr; cudaGetSymbolAddress((void**)&hbuf_h, g_hbuf_h);

    cudaFuncSetAttribute(mm128_kernel, cudaFuncAttributeMaxDynamicSharedMemorySize, MM_SMEM);
    cudaFuncSetAttribute(mm64_kernel, cudaFuncAttributeMaxDynamicSharedMemorySize, MM64_SMEM);

#define SLOT(s) (sc + (size_t)(s) * NTOK_EL)

    float* out = (float*)d_out;
    const int OFF_OUT = 0;
    const int OFF_S1  = NTOK_EL;
    const int OFF_S2  = OFF_S1 + HID;
    const int OFF_VF  = OFF_S2 + NHEAD * HEADD * HEADD;
    const int TOTAL   = OFF_VF + NTOK_EL;
    bool full = (out_size >= TOTAL);

    float* s1_out = full ? out + OFF_S1 : nullptr;
    float* s2_out = full ? out + OFF_S2 : SLOT(S_TMP);
    float* vf_out = full ? out + OFF_VF : nullptr;

    // 1. front: ln_mix + all weight conversions + v_first passthrough
    front_kernel<<<FRONT_BLOCKS, 256>>>(x, state1, ln1_w, ln1_b,
                                        x_r, x_k, x_v, x_g, x_a, x_w,
                                        abuf, s1_out,
                                        Wr, Wk, Wv, Wo, g1, g2, a1, w1, v1, v_first,
                                        a2, w2, v2,
                                        wbuf, g1buf, g2buf, lorabuf, upbuf, vf_out);

    // 2. mega-batch: r,k,v (fp32 out) + g-down (sigmoid fp16) + a/w/v-down (fp16)
    {
        MMJobs jobs;
        jobs.j[0] = { abuf,             wbuf,               SLOT(S_R), nullptr, nullptr, HID, HID, 2*HID, HID, 0, 1 };
        jobs.j[1] = { abuf + ASLOT_H,   wbuf + WSLOT_H,     SLOT(S_K), nullptr, nullptr, HID, HID, 2*HID, HID, 0, 1 };
        jobs.j[2] = { abuf + 2*ASLOT_H, wbuf + 2*WSLOT_H,   SLOT(S_V), nullptr, nullptr, HID, HID, 2*HID, HID, 0, 1 };
        jobs.j[3] = { abuf + 3*ASLOT_H, g1buf,              (float*)ghbuf, nullptr, nullptr, 256, HID, 2*HID, 256, 4, 1 };
        jobs.j[4] = { abuf + 4*ASLOT_H, lorabuf,            (float*)hbuf_h, nullptr, nullptr, 128, HID, 2*HID, 384, 5, 1 };
        jobs.j[5] = { abuf + 5*ASLOT_H, lorabuf + LSLOT_H,  (float*)(hbuf_h + 128), nullptr, nullptr, 128, HID, 2*HID, 384, 6, 2 };
        jobs.j[6] = { abuf + 2*ASLOT_H, lorabuf + 2*LSLOT_H, (float*)(hbuf_h + 256), nullptr, nullptr, 128, HID, 2*HID, 384, 5, 1 };
        mm128_kernel<<<dim3(16, 8, 7), 256, MM_SMEM>>>(jobs, 7);
    }

    // 3. batch2: g-up + a-up + w-up + v-up (all HMMA, fused activations)
    {
        MMJobs jobs;
        jobs.j[0] = { ghbuf,        g2buf,              SLOT(S_G), nullptr, nullptr, HID, 256, 256, HID, 0, 1 };
        jobs.j[1] = { hbuf_h,       upbuf,              SLOT(S_A), nullptr, a0,      HID, 128, 384, HID, 7, 1 };
        jobs.j[2] = { hbuf_h + 128, upbuf + USLOT_H,    SLOT(S_W), nullptr, w0,      HID, 128, 384, HID, 8, 1 };
        jobs.j[3] = { hbuf_h + 256, upbuf + 2*USLOT_H,  SLOT(S_V), v_first, v0,      HID, 128, 384, HID, 9, 1 };
        mm128_kernel<<<dim3(16, 8, 4), 256, MM_SMEM>>>(jobs, 4);
    }

    // 4. prep pairs
    prep2_kernel<<<(NPAIR * NHEAD * 32 + 255) / 256, 256>>>(
        SLOT(S_K), SLOT(S_A), SLOT(S_W), SLOT(S_V), SLOT(S_R),
        k_k, k_a, SLOT(S_K2), pscan2);

    // 5. two-step scan
    scan3_kernel<<<128, 256>>>(pscan2, state2, ypart, s2_out);

    // 6. groupnorm + rkv + gate -> single-plane fp16 into abuf slot 0
    post_kernel<<<(T_LEN * NHEAD * 32 + 255) / 256, 256>>>(
        ypart, SLOT(S_R), SLOT(S_K2), SLOT(S_V), SLOT(S_G),
        r_k, ln_x_w, ln_x_b, abuf);

    // 7. out = x + z@Wo (single-plane, residual fused)
    {
        MMJob job = { abuf, wbuf + 3*WSLOT_H, out + OFF_OUT, x, nullptr, HID, HID, 2*HID, HID, 1, 1 };
        mm64_kernel<<<dim3(16, 16), 256, MM64_SMEM>>>(job);
    }
}

// round 15
// speedup vs baseline: 6.6683x; 1.0234x over previous
#include <cuda_runtime.h>
#include <cuda_fp16.h>
#include <math.h>
#include <stdint.h>

#define T_LEN 1024
#define HID   2048
#define NHEAD 32
#define HEADD 64
#define NTOK_EL (T_LEN * HID)
#define NPAIR (T_LEN / 2)

#define ASLOT_H ((size_t)T_LEN * 2 * HID)   // activation slot: [M, 2K] fp16
#define WSLOT_H ((size_t)HID * HID)         // big W slot: [N, K] fp16
#define LSLOT_H ((size_t)128 * HID)         // lora-down W slot (padded 128 rows)
#define USLOT_H ((size_t)HID * 128)         // lora-up W slot: [2048, 128] fp16 padded

// ---------------- static device scratch ----------------
__device__ float g_scratch[8u * (unsigned)NTOK_EL];
__device__ float g_pscan2[(size_t)NPAIR * NHEAD * 1024];
__device__ float g_y[(size_t)T_LEN * HID];
__device__ __align__(256) __half g_abuf[6 * ASLOT_H];
__device__ __align__(256) __half g_wbuf[4 * WSLOT_H];
__device__ __align__(256) __half g_g1buf[(size_t)256 * HID];
__device__ __align__(256) __half g_g2buf[(size_t)HID * 256];
__device__ __align__(256) __half g_ghbuf[(size_t)T_LEN * 256];
__device__ __align__(256) __half g_lorabuf[3 * LSLOT_H];
__device__ __align__(256) __half g_upbuf[3 * USLOT_H];
__device__ __align__(256) __half g_hbuf_h[(size_t)T_LEN * 384];

#define S_R   0
#define S_K   1
#define S_V   2
#define S_K2  3
#define S_G   4
#define S_TMP 5
#define S_A   6
#define S_W   7

// ---------------- helpers ----------------
__device__ __forceinline__ float blk_sum256(float v) {
    __shared__ float sh[8];
    int tid = threadIdx.x;
#pragma unroll
    for (int o = 16; o; o >>= 1) v += __shfl_xor_sync(0xffffffffu, v, o);
    if ((tid & 31) == 0) sh[tid >> 5] = v;
    __syncthreads();
    if (tid == 0) {
        float s = 0.f;
#pragma unroll
        for (int i = 0; i < 8; i++) s += sh[i];
        sh[0] = s;
    }
    __syncthreads();
    float r = sh[0];
    __syncthreads();
    return r;
}

__device__ __forceinline__ float warp_sum(float v) {
#pragma unroll
    for (int o = 16; o; o >>= 1) v += __shfl_xor_sync(0xffffffffu, v, o);
    return v;
}

__device__ __forceinline__ float sigmoidf(float v) {
    return 1.f / (1.f + __expf(-v));
}

__device__ __forceinline__ uint32_t smem_u32(const void* p) {
    uint32_t a;
    asm("{ .reg .u64 t; cvta.to.shared.u64 t, %1; cvt.u32.u64 %0, t; }" : "=r"(a) : "l"(p));
    return a;
}

__device__ __forceinline__ void hsplit(float v, __half& hi, __half& lo) {
    hi = __float2half_rn(v);
    lo = __float2half_rn(v - __half2float(hi));
}

// ======================= mma.sync fp16 GEMM =======================
#define MMK_STRIDE 80
#define MMK_TILE   (128 * MMK_STRIDE)
#define STAGE_BYTES (3 * MMK_TILE)
#define MM_SMEM (3 * STAGE_BYTES)

// modes: 0 fp32 store | 1 +Res fp32 | 4 sigmoid->fp16 | 5 fp16 | 6 tanh->fp16
//        7 sigmoid(bias+x)->fp32 | 8 exp(-.606531*sigmoid(bias+x))->fp32
//        9 C = C + (Res-C)*sigmoid(bias+x)  (fp32 rmw)
struct MMJob {
    const __half* A; const __half* B; float* C; const float* Res; const float* bias;
    int N; int K; int lda; int ldc; int mode; int planes;
};
struct MMJobs { MMJob j[7]; };

__device__ __forceinline__ void cp16(uint32_t dst, const void* src) {
    asm volatile("cp.async.cg.shared.global [%0], [%1], 16;" :: "r"(dst), "l"(src));
}

__device__ __forceinline__ void ldsm4(uint32_t* r, uint32_t a) {
    asm volatile("ldmatrix.sync.aligned.m8n8.x4.shared.b16 {%0,%1,%2,%3}, [%4];"
                 : "=r"(r[0]), "=r"(r[1]), "=r"(r[2]), "=r"(r[3]) : "r"(a));
}

__device__ __forceinline__ void mma16816(float* c, const uint32_t* a, const uint32_t* b) {
    asm volatile(
        "mma.sync.aligned.m16n8k16.row.col.f32.f16.f16.f32 "
        "{%0,%1,%2,%3}, {%4,%5,%6,%7}, {%8,%9}, {%0,%1,%2,%3};"
        : "+f"(c[0]), "+f"(c[1]), "+f"(c[2]), "+f"(c[3])
        : "r"(a[0]), "r"(a[1]), "r"(a[2]), "r"(a[3]), "r"(b[0]), "r"(b[1]));
}

__device__ __forceinline__ void mm_epilogue(
    const MMJob& job, int row, int col, float2 v0, float2 v1)
{
    float* C = job.C;
    int ldc = job.ldc;
    int mode = job.mode;
    if (mode == 4 || mode == 5 || mode == 6) {
        __half* Ch = (__half*)C;
        if (mode == 4) {
            v0.x = sigmoidf(v0.x); v0.y = sigmoidf(v0.y);
            v1.x = sigmoidf(v1.x); v1.y = sigmoidf(v1.y);
        } else if (mode == 6) {
            v0.x = tanhf(v0.x); v0.y = tanhf(v0.y);
            v1.x = tanhf(v1.x); v1.y = tanhf(v1.y);
        }
        *(__half2*)(Ch + (size_t)row * ldc + col) = __floats2half2_rn(v0.x, v0.y);
        *(__half2*)(Ch + (size_t)(row + 8) * ldc + col) = __floats2half2_rn(v1.x, v1.y);
        return;
    }
    if (mode == 1) {
        const float2 r0 = *(const float2*)(job.Res + (size_t)row * ldc + col);
        const float2 r1 = *(const float2*)(job.Res + (size_t)(row + 8) * ldc + col);
        v0.x += r0.x; v0.y += r0.y;
        v1.x += r1.x; v1.y += r1.y;
    } else if (mode == 7 || mode == 8 || mode == 9) {
        float b0 = job.bias[col], b1 = job.bias[col + 1];
        float s00 = sigmoidf(b0 + v0.x), s01 = sigmoidf(b1 + v0.y);
        float s10 = sigmoidf(b0 + v1.x), s11 = sigmoidf(b1 + v1.y);
        if (mode == 7) {
            v0 = make_float2(s00, s01); v1 = make_float2(s10, s11);
        } else if (mode == 8) {
            v0 = make_float2(__expf(-0.606531f * s00), __expf(-0.606531f * s01));
            v1 = make_float2(__expf(-0.606531f * s10), __expf(-0.606531f * s11));
        } else {
            float2 c0 = *(const float2*)(C + (size_t)row * ldc + col);
            float2 c1 = *(const float2*)(C + (size_t)(row + 8) * ldc + col);
            const float2 f0 = *(const float2*)(job.Res + (size_t)row * ldc + col);
            const float2 f1 = *(const float2*)(job.Res + (size_t)(row + 8) * ldc + col);
            v0 = make_float2(c0.x + (f0.x - c0.x) * s00, c0.y + (f0.y - c0.y) * s01);
            v1 = make_float2(c1.x + (f1.x - c1.x) * s10, c1.y + (f1.y - c1.y) * s11);
        }
    }
    *(float2*)(C + (size_t)row * ldc + col) = v0;
    *(float2*)(C + (size_t)(row + 8) * ldc + col) = v1;
}

__global__ void __launch_bounds__(256, 2) mm128_kernel(MMJobs jobs, int nz)
{
    extern __shared__ __align__(16) char smem[];
    uint32_t sbase = smem_u32(smem);

    const MMJob job = jobs.j[blockIdx.z];
    const int N = job.N;
    int n0 = blockIdx.x * 128;
    if (n0 >= N) return;
    int m0 = blockIdx.y * 128;

    const __half* Ab = job.A;
    const __half* Bb = job.B;
    const int K = job.K;
    const int lda = job.lda;
    const int nk = K >> 5;
    const int planes = job.planes;

    int tid = threadIdx.x;
    int wid = tid >> 5, lane = tid & 31;
    int g = lane >> 2, tig = lane & 3;
    int warp_m = wid >> 2;
    int warp_n = wid & 3;

    float acc[4][4][4];
#pragma unroll
    for (int i = 0; i < 4; i++)
#pragma unroll
        for (int j = 0; j < 4; j++)
#pragma unroll
            for (int q = 0; q < 4; q++) acc[i][j][q] = 0.f;

    auto load_stage = [&](int s, int kc) {
        uint32_t st = sbase + s * STAGE_BYTES;
        int k0 = kc << 5;
#pragma unroll
        for (int it = 0; it < 2; it++) {
            int idx = tid + it * 256;
            int r = idx >> 2, c = idx & 3;
            cp16(st + r * MMK_STRIDE + c * 16, Ab + ((size_t)(m0 + r) * lda + k0 + c * 8));
        }
        if (planes == 2) {
#pragma unroll
            for (int it = 0; it < 2; it++) {
                int idx = tid + it * 256;
                int r = idx >> 2, c = idx & 3;
                cp16(st + MMK_TILE + r * MMK_STRIDE + c * 16,
                     Ab + ((size_t)(m0 + r) * lda + K + k0 + c * 8));
            }
        }
#pragma unroll
        for (int it = 0; it < 2; it++) {
            int idx = tid + it * 256;
            int r = idx >> 2, c = idx & 3;
            cp16(st + 2 * MMK_TILE + r * MMK_STRIDE + c * 16,
                 Bb + ((size_t)(n0 + r) * K + k0 + c * 8));
        }
        asm volatile("cp.async.commit_group;" ::: "memory");
    };

    load_stage(0, 0);
    if (nk > 1) load_stage(1, 1);
    else asm volatile("cp.async.commit_group;" ::: "memory");

    int aRowSel = (lane & 15);
    int aColSel = (lane & 16) ? 16 : 0;
    int bRowSel = ((lane & 16) ? 8 : 0) + (lane & 7);
    int bColSel = (lane & 8) ? 16 : 0;

    for (int kc = 0; kc < nk; kc++) {
        asm volatile("cp.async.wait_group 1;" ::: "memory");
        __syncthreads();
        if (kc + 2 < nk) load_stage((kc + 2) % 3, kc + 2);
        else asm volatile("cp.async.commit_group;" ::: "memory");

        uint32_t st = sbase + (kc % 3) * STAGE_BYTES;
#pragma unroll
        for (int ks = 0; ks < 2; ks++) {
            uint32_t afr[4][4], bfr[2][4];
#pragma unroll
            for (int ap = 0; ap < 2; ap++) {
                uint32_t addr = st + 2 * MMK_TILE
                                + (uint32_t)(warp_n * 32 + ap * 16 + bRowSel) * MMK_STRIDE
                                + ks * 32 + bColSel;
                ldsm4(bfr[ap], addr);
            }
#pragma unroll
            for (int am = 0; am < 4; am++) {
                uint32_t addr = st + (uint32_t)(warp_m * 64 + am * 16 + aRowSel) * MMK_STRIDE
                                + ks * 32 + aColSel;
                ldsm4(afr[am], addr);
            }
#pragma unroll
            for (int am = 0; am < 4; am++) {
                mma16816(acc[am][0], afr[am], &bfr[0][0]);
                mma16816(acc[am][1], afr[am], &bfr[0][2]);
                mma16816(acc[am][2], afr[am], &bfr[1][0]);
                mma16816(acc[am][3], afr[am], &bfr[1][2]);
            }
            if (planes == 2) {
#pragma unroll
                for (int am = 0; am < 4; am++) {
                    uint32_t addr = st + MMK_TILE
                                    + (uint32_t)(warp_m * 64 + am * 16 + aRowSel) * MMK_STRIDE
                                    + ks * 32 + aColSel;
                    ldsm4(afr[am], addr);
                }
#pragma unroll
                for (int am = 0; am < 4; am++) {
                    mma16816(acc[am][0], afr[am], &bfr[0][0]);
                    mma16816(acc[am][1], afr[am], &bfr[0][2]);
                    mma16816(acc[am][2], afr[am], &bfr[1][0]);
                    mma16816(acc[am][3], afr[am], &bfr[1][2]);
                }
            }
        }
    }

    __syncthreads();

#pragma unroll
    for (int am = 0; am < 4; am++) {
#pragma unroll
        for (int an = 0; an < 4; an++) {
            int row = m0 + warp_m * 64 + am * 16 + g;
            int col = n0 + warp_n * 32 + an * 8 + tig * 2;
            mm_epilogue(job, row, col,
                        make_float2(acc[am][an][0], acc[am][an][1]),
                        make_float2(acc[am][an][2], acc[am][an][3]));
        }
    }
}

// ---------------- mm64: 64x128 tile variant ----------------
#define MM64_A_TILE (64 * MMK_STRIDE)
#define MM64_STAGE  (2 * MM64_A_TILE + MMK_TILE)
#define MM64_SMEM   (3 * MM64_STAGE)

__global__ void __launch_bounds__(256) mm64_kernel(MMJob job)
{
    extern __shared__ __align__(16) char smem[];
    uint32_t sbase = smem_u32(smem);

    const int N = job.N;
    int n0 = blockIdx.x * 128;
    if (n0 >= N) return;
    int m0 = blockIdx.y * 64;

    const __half* Ab = job.A;
    const __half* Bb = job.B;
    const int K = job.K;
    const int lda = job.lda;
    const int nk = K >> 5;
    const int planes = job.planes;

    int tid = threadIdx.x;
    int wid = tid >> 5, lane = tid & 31;
    int g = lane >> 2, tig = lane & 3;
    int warp_m = wid >> 2;
    int warp_n = wid & 3;

    float acc[2][4][4];
#pragma unroll
    for (int i = 0; i < 2; i++)
#pragma unroll
        for (int j = 0; j < 4; j++)
#pragma unroll
            for (int q = 0; q < 4; q++) acc[i][j][q] = 0.f;

    auto load_stage = [&](int s, int kc) {
        uint32_t st = sbase + s * MM64_STAGE;
        int k0 = kc << 5;
        {
            int r = tid >> 2, c = tid & 3;
            cp16(st + r * MMK_STRIDE + c * 16, Ab + ((size_t)(m0 + r) * lda + k0 + c * 8));
        }
        if (planes == 2) {
            int r = tid >> 2, c = tid & 3;
            cp16(st + MM64_A_TILE + r * MMK_STRIDE + c * 16,
                 Ab + ((size_t)(m0 + r) * lda + K + k0 + c * 8));
        }
#pragma unroll
        for (int it = 0; it < 2; it++) {
            int idx = tid + it * 256;
            int r = idx >> 2, c = idx & 3;
            cp16(st + 2 * MM64_A_TILE + r * MMK_STRIDE + c * 16,
                 Bb + ((size_t)(n0 + r) * K + k0 + c * 8));
        }
        asm volatile("cp.async.commit_group;" ::: "memory");
    };

    load_stage(0, 0);
    if (nk > 1) load_stage(1, 1);
    else asm volatile("cp.async.commit_group;" ::: "memory");

    int aRowSel = (lane & 15);
    int aColSel = (lane & 16) ? 16 : 0;
    int bRowSel = ((lane & 16) ? 8 : 0) + (lane & 7);
    int bColSel = (lane & 8) ? 16 : 0;

    for (int kc = 0; kc < nk; kc++) {
        asm volatile("cp.async.wait_group 1;" ::: "memory");
        __syncthreads();
        if (kc + 2 < nk) load_stage((kc + 2) % 3, kc + 2);
        else asm volatile("cp.async.commit_group;" ::: "memory");

        uint32_t st = sbase + (kc % 3) * MM64_STAGE;
#pragma unroll
        for (int ks = 0; ks < 2; ks++) {
            uint32_t afr[2][4], bfr[2][4];
#pragma unroll
            for (int ap = 0; ap < 2; ap++) {
                uint32_t addr = st + 2 * MM64_A_TILE
                                + (uint32_t)(warp_n * 32 + ap * 16 + bRowSel) * MMK_STRIDE
                                + ks * 32 + bColSel;
                ldsm4(bfr[ap], addr);
            }
#pragma unroll
            for (int am = 0; am < 2; am++) {
                uint32_t addr = st + (uint32_t)(warp_m * 32 + am * 16 + aRowSel) * MMK_STRIDE
                                + ks * 32 + aColSel;
                ldsm4(afr[am], addr);
            }
#pragma unroll
            for (int am = 0; am < 2; am++) {
                mma16816(acc[am][0], afr[am], &bfr[0][0]);
                mma16816(acc[am][1], afr[am], &bfr[0][2]);
                mma16816(acc[am][2], afr[am], &bfr[1][0]);
                mma16816(acc[am][3], afr[am], &bfr[1][2]);
            }
            if (planes == 2) {
#pragma unroll
                for (int am = 0; am < 2; am++) {
                    uint32_t addr = st + MM64_A_TILE
                                    + (uint32_t)(warp_m * 32 + am * 16 + aRowSel) * MMK_STRIDE
                                    + ks * 32 + aColSel;
                    ldsm4(afr[am], addr);
                }
#pragma unroll
                for (int am = 0; am < 2; am++) {
                    mma16816(acc[am][0], afr[am], &bfr[0][0]);
                    mma16816(acc[am][1], afr[am], &bfr[0][2]);
                    mma16816(acc[am][2], afr[am], &bfr[1][0]);
                    mma16816(acc[am][3], afr[am], &bfr[1][2]);
                }
            }
        }
    }

    __syncthreads();

#pragma unroll
    for (int am = 0; am < 2; am++) {
#pragma unroll
        for (int an = 0; an < 4; an++) {
            int row = m0 + warp_m * 32 + am * 16 + g;
            int col = n0 + warp_n * 32 + an * 8 + tig * 2;
            mm_epilogue(job, row, col,
                        make_float2(acc[am][an][0], acc[am][an][1]),
                        make_float2(acc[am][an][2], acc[am][an][3]));
        }
    }
}

// ---------------- front-end: ln_mix + weight conversions + v_first copy ----------------
__device__ __forceinline__ void conv_tile2(const float* __restrict__ W, __half* __restrict__ out,
                                           int K, int N, int bx, int by, float* tile,
                                           int kmax)
{
    int k0 = by * 64, n0 = bx * 32;
    int tid = threadIdx.x;
#pragma unroll
    for (int it = 0; it < 8; it++) {
        int i = tid + it * 256;
        int r = i >> 5, c = i & 31;
        tile[r * 33 + c] = (k0 + r < kmax) ? W[(size_t)(k0 + r) * N + n0 + c] : 0.f;
    }
    __syncthreads();
    int nl = tid >> 3;
    int kq = (tid & 7) * 8;
    __half h8[8];
#pragma unroll
    for (int j = 0; j < 8; j++)
        h8[j] = __float2half_rn(tile[(kq + j) * 33 + nl]);
    *(uint4*)(out + (size_t)(n0 + nl) * K + k0 + kq) = *(uint4*)h8;
}

__device__ void ln_mix_body(
    int t,
    const float* __restrict__ x, const float* __restrict__ state1,
    const float* __restrict__ lnw, const float* __restrict__ lnb,
    const float* __restrict__ cr, const float* __restrict__ ck,
    const float* __restrict__ cv, const float* __restrict__ cg,
    const float* __restrict__ ca, const float* __restrict__ cw,
    __half* __restrict__ abuf, float* __restrict__ state1_out)
{
    const float* xt = x + (size_t)t * HID;
    const float* xp = x + (size_t)(t - 1) * HID;

    float2 v0[4], v1[4];
    float s0 = 0.f, s1 = 0.f;
#pragma unroll
    for (int j = 0; j < 4; j++) {
        int c = threadIdx.x * 2 + j * 512;
        v0[j] = *(const float2*)(xt + c);
        s0 += v0[j].x + v0[j].y;
        v1[j] = t ? *(const float2*)(xp + c) : make_float2(0.f, 0.f);
        s1 += v1[j].x + v1[j].y;
    }
    float mu0 = blk_sum256(s0) * (1.f / HID);
    float mu1 = blk_sum256(s1) * (1.f / HID);
    float q0 = 0.f, q1 = 0.f;
#pragma unroll
    for (int j = 0; j < 4; j++) {
        float d;
        d = v0[j].x - mu0; q0 += d * d;
        d = v0[j].y - mu0; q0 += d * d;
        d = v1[j].x - mu1; q1 += d * d;
        d = v1[j].y - mu1; q1 += d * d;
    }
    float inv0 = rsqrtf(blk_sum256(q0) * (1.f / HID) + 1e-5f);
    float inv1 = rsqrtf(blk_sum256(q1) * (1.f / HID) + 1e-5f);

#pragma unroll
    for (int j = 0; j < 4; j++) {
        int c = threadIdx.x * 2 + j * 512;
        float2 wv = *(const float2*)(lnw + c);
        float2 bv = *(const float2*)(lnb + c);
        float xn0 = (v0[j].x - mu0) * inv0 * wv.x + bv.x;
        float xn1 = (v0[j].y - mu0) * inv0 * wv.y + bv.y;
        float pv0 = t ? (v1[j].x - mu1) * inv1 * wv.x + bv.x : state1[c];
        float pv1 = t ? (v1[j].y - mu1) * inv1 * wv.y + bv.y : state1[c + 1];
        float sx0 = pv0 - xn0, sx1 = pv1 - xn1;

        __half* arow = abuf + (size_t)t * 2 * HID + c;
#pragma unroll
        for (int s = 0; s < 6; s++) {
            const float* coefA = (s == 0) ? cr : (s == 1) ? ck : (s == 2) ? cv
                               : (s == 3) ? cg : (s == 4) ? ca : cw;
            float a0 = xn0 + coefA[c] * sx0;
            float a1 = xn1 + coefA[c + 1] * sx1;
            __half* p = arow + (size_t)s * ASLOT_H;
            if (s == 5) {
                __half h0, l0, h1, l1;
                hsplit(a0, h0, l0);
                hsplit(a1, h1, l1);
                *(__half2*)(p) = __half2(h0, h1);
                *(__half2*)(p + HID) = __half2(l0, l1);
            } else {
                *(__half2*)(p) = __floats2half2_rn(a0, a1);
            }
        }
        if (state1_out && t == T_LEN - 1) {
            state1_out[c] = xn0;
            state1_out[c + 1] = xn1;
        }
    }
}

#define FRONT_BLOCKS (1024 + 9472 + 384)

__global__ void __launch_bounds__(256) front_kernel(
    const float* __restrict__ x, const float* __restrict__ state1,
    const float* __restrict__ lnw, const float* __restrict__ lnb,
    const float* __restrict__ cr, const float* __restrict__ ck,
    const float* __restrict__ cv, const float* __restrict__ cg,
    const float* __restrict__ ca, const float* __restrict__ cw,
    __half* __restrict__ abuf, float* __restrict__ state1_out,
    const float* __restrict__ Wr, const float* __restrict__ Wk,
    const float* __restrict__ Wv, const float* __restrict__ Wo,
    const float* __restrict__ g1, const float* __restrict__ g2,
    const float* __restrict__ a1, const float* __restrict__ w1,
    const float* __restrict__ v1, const float* __restrict__ vf,
    const float* __restrict__ a2, const float* __restrict__ w2,
    const float* __restrict__ v2,
    __half* __restrict__ wbuf, __half* __restrict__ g1buf,
    __half* __restrict__ g2buf, __half* __restrict__ lorabuf,
    __half* __restrict__ upbuf, float* __restrict__ vfout)
{
    __shared__ float tile[64 * 33];
    int bb = blockIdx.x;
    if (bb < 1024) {
        ln_mix_body(bb, x, state1, lnw, lnb, cr, ck, cv, cg, ca, cw, abuf, state1_out);
        return;
    }
    int b = bb - 1024;
    if (b < 8192) {
        int z = b >> 11, rem = b & 2047;
        const float* W = z == 0 ? Wr : z == 1 ? Wk : z == 2 ? Wv : Wo;
        conv_tile2(W, wbuf + (size_t)z * WSLOT_H, HID, HID, rem & 63, rem >> 6, tile, HID);
    } else if (b < 8448) {
        int rem = b - 8192;
        conv_tile2(g1, g1buf, HID, 256, rem & 7, rem >> 3, tile, HID);
    } else if (b < 8704) {
        int rem = b - 8448;
        conv_tile2(g2, g2buf, 256, HID, rem & 63, rem >> 6, tile, 256);
    } else if (b < 8800) {
        int rem = b - 8704;
        conv_tile2(a1, lorabuf, HID, 96, rem % 3, rem / 3, tile, HID);
    } else if (b < 8896) {
        int rem = b - 8800;
        conv_tile2(w1, lorabuf + LSLOT_H, HID, 96, rem % 3, rem / 3, tile, HID);
    } else if (b < 8960) {
        int rem = b - 8896;
        conv_tile2(v1, lorabuf + 2 * LSLOT_H, HID, 64, rem & 1, rem >> 1, tile, HID);
    } else if (b < 9472) {
        if (!vfout) return;
        int rem = b - 8960;
#pragma unroll
        for (int j = 0; j < 4; j++) {
            size_t i = (size_t)rem * 4096 + j * 1024 + threadIdx.x * 4;
            *(float4*)(vfout + i) = *(const float4*)(vf + i);
        }
    } else {
        int rem = b - 9472;
        int z = rem >> 7, sub = rem & 127;
        const float* W = z == 0 ? a2 : z == 1 ? w2 : v2;
        int kmax = (z == 2) ? 64 : 96;
        conv_tile2(W, upbuf + (size_t)z * USLOT_H, 128, HID, sub & 63, sub >> 6, tile, kmax);
    }
}

// ---------------- prep2: kk/k2 + pair scalars + pscan2 packing ----------------
__global__ void __launch_bounds__(256) prep2_kernel(
    const float* __restrict__ k, const float* __restrict__ a,
    const float* __restrict__ w, const float* __restrict__ v,
    const float* __restrict__ r,
    const float* __restrict__ k_k, const float* __restrict__ k_a,
    float* __restrict__ k2out, float* __restrict__ pscan2)
{
    int gw = (blockIdx.x * 256 + threadIdx.x) >> 5;
    int lane = threadIdx.x & 31;
    if (gw >= NPAIR * NHEAD) return;
    int pr = gw >> 5, h = gw & 31;
    int b0 = (2 * pr) * HID + h * HEADD;
    int b1 = b0 + HID;
    int cb = h * HEADD;

    float kA0 = k[b0 + lane], kB0 = k[b0 + lane + 32];
    float qA0 = kA0 * k_k[cb + lane], qB0 = kB0 * k_k[cb + lane + 32];
    float inv0 = 1.f / fmaxf(sqrtf(warp_sum(qA0 * qA0 + qB0 * qB0)), 1e-12f);
    float kkA0 = qA0 * inv0, kkB0 = qB0 * inv0;
    float aA0 = a[b0 + lane], aB0 = a[b0 + lane + 32];
    float k2A0 = kA0 * (1.f + (aA0 - 1.f) * k_a[cb + lane]);
    float k2B0 = kB0 * (1.f + (aB0 - 1.f) * k_a[cb + lane + 32]);
    k2out[b0 + lane] = k2A0;
    k2out[b0 + lane + 32] = k2B0;

    float kA1 = k[b1 + lane], kB1 = k[b1 + lane + 32];
    float qA1 = kA1 * k_k[cb + lane], qB1 = kB1 * k_k[cb + lane + 32];
    float inv1 = 1.f / fmaxf(sqrtf(warp_sum(qA1 * qA1 + qB1 * qB1)), 1e-12f);
    float kkA1 = qA1 * inv1, kkB1 = qB1 * inv1;
    float aA1 = a[b1 + lane], aB1 = a[b1 + lane + 32];
    float k2A1 = kA1 * (1.f + (aA1 - 1.f) * k_a[cb + lane]);
    float k2B1 = kB1 * (1.f + (aB1 - 1.f) * k_a[cb + lane + 32]);
    k2out[b1 + lane] = k2A1;
    k2out[b1 + lane + 32] = k2B1;

    float wA0 = w[b0 + lane], wB0 = w[b0 + lane + 32];
    float kaA0 = kkA0 * aA0, kaB0 = kkB0 * aB0;

    float c1 = warp_sum(kkA1 * kaA0 + kkB1 * kaB0);
    float c2 = warp_sum(kkA1 * k2A0 + kkB1 * k2B0);

    float* P = pscan2 + ((size_t)pr * NHEAD + h) * 1024;
    P[0 * 64 + lane] = kkA0;           P[0 * 64 + lane + 32] = kkB0;
    P[1 * 64 + lane] = kkA1 * wA0;     P[1 * 64 + lane + 32] = kkB1 * wB0;
    P[2 * 64 + lane] = wA0;            P[2 * 64 + lane + 32] = wB0;
    P[3 * 64 + lane] = kaA0;           P[3 * 64 + lane + 32] = kaB0;
    P[4 * 64 + lane] = k2A0;           P[4 * 64 + lane + 32] = k2B0;
    P[5 * 64 + lane] = r[b0 + lane];   P[5 * 64 + lane + 32] = r[b0 + lane + 32];
    P[6 * 64 + lane] = w[b1 + lane];   P[6 * 64 + lane + 32] = w[b1 + lane + 32];
    P[7 * 64 + lane] = kkA1 * aA1;     P[7 * 64 + lane + 32] = kkB1 * aB1;
    P[8 * 64 + lane] = k2A1;           P[8 * 64 + lane + 32] = k2B1;
    P[9 * 64 + lane] = r[b1 + lane];   P[9 * 64 + lane + 32] = r[b1 + lane + 32];
    P[10 * 64 + lane] = v[b0 + lane];  P[10 * 64 + lane + 32] = v[b0 + lane + 32];
    P[11 * 64 + lane] = v[b1 + lane];  P[11 * 64 + lane + 32] = v[b1 + lane + 32];
    if (lane == 0) { P[12 * 64] = c1; P[12 * 64 + 1] = c2; }
}

// ---------------- scan v3.1: two steps per round, full y reduction in-scan ----------------
__global__ void __launch_bounds__(256) scan3_kernel(
    const float* __restrict__ pscan2,
    const float* __restrict__ state2, float* __restrict__ ybuf,
    float* __restrict__ Sout)
{
    int h = blockIdx.x >> 2;
    int q = blockIdx.x & 3;
    int tid = threadIdx.x;
    int wrp = tid >> 5, lane = tid & 31;
    int rsel = lane >> 4, colg = lane & 15;
    int row = q * 16 + 2 * wrp + rsel;

    float4 S = *(const float4*)(state2 + (size_t)h * 4096 + row * 64 + colg * 4);

    __shared__ float buf[2][1024];

    const float* pB = pscan2 + (size_t)h * 1024;
    const size_t pstride = (size_t)NHEAD * 1024;

    ((float4*)buf[0])[tid] = *(const float4*)(pB + tid * 4);
    float4 preA = *(const float4*)(pB + pstride + tid * 4);
    float4 preB;

    for (int pr = 0; pr < NPAIR; pr++) {
        __syncthreads();
        preB = (pr + 2 < NPAIR) ? *(const float4*)(pB + (size_t)(pr + 2) * pstride + tid * 4)
                                : preA;
        const float* b = buf[pr & 1];
        float4 kk4  = *(const float4*)(b + 0 * 64 + colg * 4);
        float4 kkw4 = *(const float4*)(b + 1 * 64 + colg * 4);
        float4 w4   = *(const float4*)(b + 2 * 64 + colg * 4);
        float4 ka4  = *(const float4*)(b + 3 * 64 + colg * 4);
        float4 k4   = *(const float4*)(b + 4 * 64 + colg * 4);
        float4 r4   = *(const float4*)(b + 5 * 64 + colg * 4);
        float4 w14  = *(const float4*)(b + 6 * 64 + colg * 4);
        float4 ka14 = *(const float4*)(b + 7 * 64 + colg * 4);
        float4 k14  = *(const float4*)(b + 8 * 64 + colg * 4);
        float4 r14  = *(const float4*)(b + 9 * 64 + colg * 4);
        float v0 = b[10 * 64 + row];
        float v1 = b[11 * 64 + row];
        float c1 = b[12 * 64];
        float c2 = b[12 * 64 + 1];

        float d0 = S.x * kk4.x + S.y * kk4.y + S.z * kk4.z + S.w * kk4.w;
        float d1 = S.x * kkw4.x + S.y * kkw4.y + S.z * kkw4.z + S.w * kkw4.w;
#pragma unroll
        for (int o = 1; o <= 8; o <<= 1) {
            d0 += __shfl_xor_sync(0xffffffffu, d0, o);
            d1 += __shfl_xor_sync(0xffffffffu, d1, o);
        }
        float p0 = d0;
        float p1 = d1 - p0 * c1 + v0 * c2;

        S.x = S.x * w4.x - p0 * ka4.x + v0 * k4.x;
        S.y = S.y * w4.y - p0 * ka4.y + v0 * k4.y;
        S.z = S.z * w4.z - p0 * ka4.z + v0 * k4.z;
        S.w = S.w * w4.w - p0 * ka4.w + v0 * k4.w;

        float y0 = S.x * r4.x + S.y * r4.y + S.z * r4.z + S.w * r4.w;
        y0 += __shfl_xor_sync(0xffffffffu, y0, 1);
        y0 += __shfl_xor_sync(0xffffffffu, y0, 2);
        y0 += __shfl_xor_sync(0xffffffffu, y0, 4);
        y0 += __shfl_xor_sync(0xffffffffu, y0, 8);
        if (colg == 0)
            ybuf[(size_t)(2 * pr) * HID + h * HEADD + row] = y0;

        if (pr + 1 < NPAIR)
            ((float4*)buf[(pr + 1) & 1])[tid] = preA;
        preA = preB;

        S.x = S.x * w14.x - p1 * ka14.x + v1 * k14.x;
        S.y = S.y * w14.y - p1 * ka14.y + v1 * k14.y;
        S.z = S.z * w14.z - p1 * ka14.z + v1 * k14.z;
        S.w = S.w * w14.w - p1 * ka14.w + v1 * k14.w;

        float y1 = S.x * r14.x + S.y * r14.y + S.z * r14.z + S.w * r14.w;
        y1 += __shfl_xor_sync(0xffffffffu, y1, 1);
        y1 += __shfl_xor_sync(0xffffffffu, y1, 2);
        y1 += __shfl_xor_sync(0xffffffffu, y1, 4);
        y1 += __shfl_xor_sync(0xffffffffu, y1, 8);
        if (colg == 0)
            ybuf[(size_t)(2 * pr + 1) * HID + h * HEADD + row] = y1;
    }
    *(float4*)(Sout + (size_t)h * 4096 + row * 64 + colg * 4) = S;
}

// ---------------- groupnorm + rkv + gate -> single-plane fp16 into abuf ----------------
__global__ void __launch_bounds__(256) post_kernel(
    const float* __restrict__ y, const float* __restrict__ r,
    const float* __restrict__ k2, const float* __restrict__ v,
    const float* __restrict__ g, const float* __restrict__ r_k,
    const float* __restrict__ lnxw, const float* __restrict__ lnxb,
    __half* __restrict__ zsplit)
{
    int gw = (blockIdx.x * 256 + threadIdx.x) >> 5;
    int lane = threadIdx.x & 31;
    if (gw >= T_LEN * NHEAD) return;
    int t = gw >> 5, h = gw & 31;
    int base = t * HID + h * HEADD;
    int cb = h * HEADD;

    float y0 = y[base + lane], y1 = y[base + lane + 32];

    float mu = warp_sum(y0 + y1) * (1.f / HEADD);
    float d0 = y0 - mu, d1 = y1 - mu;
    float var = warp_sum(d0 * d0 + d1 * d1) * (1.f / HEADD);
    float inv = rsqrtf(var + 0.00064f);

    float rs = warp_sum(r[base + lane] * k2[base + lane] * r_k[cb + lane] +
                        r[base + lane + 32] * k2[base + lane + 32] * r_k[cb + lane + 32]);

    float z0 = (d0 * inv * lnxw[cb + lane] + lnxb[cb + lane] + rs * v[base + lane]) * g[base + lane];
    float z1 = (d1 * inv * lnxw[cb + lane + 32] + lnxb[cb + lane + 32] + rs * v[base + lane + 32]) * g[base + lane + 32];

    size_t zb = (size_t)t * 2 * HID;
    zsplit[zb + cb + lane] = __float2half_rn(z0);
    zsplit[zb + cb + lane + 32] = __float2half_rn(z1);
}

// ---------------- host launcher ----------------
extern "C" void kernel_launch(void* const* d_in, const int* in_sizes, int n_in,
                              void* d_out, int out_size)
{
    const float* x       = (const float*)d_in[0];
    const float* state1  = (const float*)d_in[1];
    const float* state2  = (const float*)d_in[2];
    const float* v_first = (const float*)d_in[3];
    const float* ln1_w   = (const float*)d_in[4];
    const float* ln1_b   = (const float*)d_in[5];
    const float* x_r     = (const float*)d_in[6];
    const float* x_w     = (const float*)d_in[7];
    const float* x_k     = (const float*)d_in[8];
    const float* x_v     = (const float*)d_in[9];
    const float* x_a     = (const float*)d_in[10];
    const float* x_g     = (const float*)d_in[11];
    const float* Wr      = (const float*)d_in[12];
    const float* Wk      = (const float*)d_in[13];
    const float* Wv      = (const float*)d_in[14];
    const float* Wo      = (const float*)d_in[15];
    const float* w0      = (const float*)d_in[16];
    const float* w1      = (const float*)d_in[17];
    const float* w2      = (const float*)d_in[18];
    const float* a0      = (const float*)d_in[19];
    const float* a1      = (const float*)d_in[20];
    const float* a2      = (const float*)d_in[21];
    const float* v0      = (const float*)d_in[22];
    const float* v1      = (const float*)d_in[23];
    const float* v2      = (const float*)d_in[24];
    const float* g1      = (const float*)d_in[25];
    const float* g2      = (const float*)d_in[26];
    const float* k_k     = (const float*)d_in[27];
    const float* k_a     = (const float*)d_in[28];
    const float* r_k     = (const float*)d_in[29];
    const float* ln_x_w  = (const float*)d_in[30];
    const float* ln_x_b  = (const float*)d_in[31];

    float* sc = nullptr;      cudaGetSymbolAddress((void**)&sc, g_scratch);
    float* pscan2 = nullptr;  cudaGetSymbolAddress((void**)&pscan2, g_pscan2);
    float* ybuf = nullptr;    cudaGetSymbolAddress((void**)&ybuf, g_y);
    __half* abuf = nullptr;   cudaGetSymbolAddress((void**)&abuf, g_abuf);
    __half* wbuf = nullptr;   cudaGetSymbolAddress((void**)&wbuf, g_wbuf);
    __half* g1buf = nullptr;  cudaGetSymbolAddress((void**)&g1buf, g_g1buf);
    __half* g2buf = nullptr;  cudaGetSymbolAddress((void**)&g2buf, g_g2buf);
    __half* ghbuf = nullptr;  cudaGetSymbolAddress((void**)&ghbuf, g_ghbuf);
    __half* lorabuf = nullptr; cudaGetSymbolAddress((void**)&lorabuf, g_lorabuf);
    __half* upbuf = nullptr;  cudaGetSymbolAddress((void**)&upbuf, g_upbuf);
    __half* hbuf_h = nullptr; cudaGetSymbolAddress((void**)&hbuf_h, g_hbuf_h);

    cudaFuncSetAttribute(mm128_kernel, cudaFuncAttributeMaxDynamicSharedMemorySize, MM_SMEM);
    cudaFuncSetAttribute(mm64_kernel, cudaFuncAttributeMaxDynamicSharedMemorySize, MM64_SMEM);

#define SLOT(s) (sc + (size_t)(s) * NTOK_EL)

    float* out = (float*)d_out;
    const int OFF_OUT = 0;
    const int OFF_S1  = NTOK_EL;
    const int OFF_S2  = OFF_S1 + HID;
    const int OFF_VF  = OFF_S2 + NHEAD * HEADD * HEADD;
    const int TOTAL   = OFF_VF + NTOK_EL;
    bool full = (out_size >= TOTAL);

    float* s1_out = full ? out + OFF_S1 : nullptr;
    float* s2_out = full ? out + OFF_S2 : SLOT(S_TMP);
    float* vf_out = full ? out + OFF_VF : nullptr;

    // 1. front: ln_mix + all weight conversions + v_first passthrough
    front_kernel<<<FRONT_BLOCKS, 256>>>(x, state1, ln1_w, ln1_b,
                                        x_r, x_k, x_v, x_g, x_a, x_w,
                                        abuf, s1_out,
                                        Wr, Wk, Wv, Wo, g1, g2, a1, w1, v1, v_first,
                                        a2, w2, v2,
                                        wbuf, g1buf, g2buf, lorabuf, upbuf, vf_out);

    // 2. mega-batch: r,k,v (fp32 out) + g-down (sigmoid fp16) + a/w/v-down (fp16)
    {
        MMJobs jobs;
        jobs.j[0] = { abuf,             wbuf,               SLOT(S_R), nullptr, nullptr, HID, HID, 2*HID, HID, 0, 1 };
        jobs.j[1] = { abuf + ASLOT_H,   wbuf + WSLOT_H,     SLOT(S_K), nullptr, nullptr, HID, HID, 2*HID, HID, 0, 1 };
        jobs.j[2] = { abuf + 2*ASLOT_H, wbuf + 2*WSLOT_H,   SLOT(S_V), nullptr, nullptr, HID, HID, 2*HID, HID, 0, 1 };
        jobs.j[3] = { abuf + 3*ASLOT_H, g1buf,              (float*)ghbuf, nullptr, nullptr, 256, HID, 2*HID, 256, 4, 1 };
        jobs.j[4] = { abuf + 4*ASLOT_H, lorabuf,            (float*)hbuf_h, nullptr, nullptr, 128, HID, 2*HID, 384, 5, 1 };
        jobs.j[5] = { abuf + 5*ASLOT_H, lorabuf + LSLOT_H,  (float*)(hbuf_h + 128), nullptr, nullptr, 128, HID, 2*HID, 384, 6, 2 };
        jobs.j[6] = { abuf + 2*ASLOT_H, lorabuf + 2*LSLOT_H, (float*)(hbuf_h + 256), nullptr, nullptr, 128, HID, 2*HID, 384, 5, 1 };
        mm128_kernel<<<dim3(16, 8, 7), 256, MM_SMEM>>>(jobs, 7);
    }

    // 3. batch2: g-up + a-up + w-up + v-up (all HMMA, fused activations)
    {
        MMJobs jobs;
        jobs.j[0] = { ghbuf,        g2buf,              SLOT(S_G), nullptr, nullptr, HID, 256, 256, HID, 0, 1 };
        jobs.j[1] = { hbuf_h,       upbuf,              SLOT(S_A), nullptr, a0,      HID, 128, 384, HID, 7, 1 };
        jobs.j[2] = { hbuf_h + 128, upbuf + USLOT_H,    SLOT(S_W), nullptr, w0,      HID, 128, 384, HID, 8, 1 };
        jobs.j[3] = { hbuf_h + 256, upbuf + 2*USLOT_H,  SLOT(S_V), v_first, v0,      HID, 128, 384, HID, 9, 1 };
        mm128_kernel<<<dim3(16, 8, 4), 256, MM_SMEM>>>(jobs, 4);
    }

    // 4. prep pairs
    prep2_kernel<<<(NPAIR * NHEAD * 32 + 255) / 256, 256>>>(
        SLOT(S_K), SLOT(S_A), SLOT(S_W), SLOT(S_V), SLOT(S_R),
        k_k, k_a, SLOT(S_K2), pscan2);

    // 5. two-step scan (full y reduction in-scan)
    scan3_kernel<<<128, 256>>>(pscan2, state2, ybuf, s2_out);

    // 6. groupnorm + rkv + gate -> single-plane fp16 into abuf slot 0
    post_kernel<<<(T_LEN * NHEAD * 32 + 255) / 256, 256>>>(
        ybuf, SLOT(S_R), SLOT(S_K2), SLOT(S_V), SLOT(S_G),
        r_k, ln_x_w, ln_x_b, abuf);

    // 7. out = x + z@Wo (single-plane, residual fused)
    {
        MMJob job = { abuf, wbuf + 3*WSLOT_H, out + OFF_OUT, x, nullptr, HID, HID, 2*HID, HID, 1, 1 };
        mm64_kernel<<<dim3(16, 16), 256, MM64_SMEM>>>(job);
    }
}